// round 1
// baseline (speedup 1.0000x reference)
#include <cuda_runtime.h>
#include <math.h>

#define BB     8
#define CDDN   5
#define HISN   50
#define SEQ    64
#define DMODEL 768
#define NHEAD  12
#define DHEAD  64
#define FFDIM  3072
#define KSEL   8

#define NCDD   (BB*CDDN)     // 40
#define NHIS   (BB*HISN)     // 400
#define LUSR   (HISN*KSEL)   // 400
#define ROWS_MAX (NHIS*SEQ)  // 25600

// ---------------- scratch (device globals; allocation-free) ----------------
__device__ float g_x [ (size_t)ROWS_MAX*DMODEL ];
__device__ float g_q [ (size_t)ROWS_MAX*DMODEL ];
__device__ float g_k [ (size_t)ROWS_MAX*DMODEL ];
__device__ float g_v [ (size_t)ROWS_MAX*DMODEL ];
__device__ float g_o [ (size_t)ROWS_MAX*DMODEL ];
__device__ float g_h [ (size_t)ROWS_MAX*DMODEL ];
__device__ float g_ff[ (size_t)ROWS_MAX*FFDIM ];
__device__ float g_lg[ (size_t)NHIS*NHEAD*SEQ*SEQ ];  // >= user: 8*12*400*400
__device__ float g_pre[(size_t)NHIS*SEQ*SEQ ];
__device__ float g_atC[ NCDD*SEQ ];
__device__ float g_atH[ NHIS*SEQ ];
__device__ float g_cls[ (size_t)NHIS*DMODEL ];
__device__ float g_cddr[(size_t)NCDD*DMODEL ];
__device__ float g_u0 [ BB*DMODEL ];
__device__ float g_ur [ BB*DMODEL ];
__device__ float g_psm[ BB*LUSR ];
__device__ int   g_kid[ BB*HISN*KSEL ];

// ---------------- reductions ----------------
__device__ __forceinline__ float warp_sum(float v){
    #pragma unroll
    for(int o=16;o;o>>=1) v += __shfl_xor_sync(0xffffffffu, v, o);
    return v;
}
__device__ __forceinline__ float warp_max(float v){
    #pragma unroll
    for(int o=16;o;o>>=1) v = fmaxf(v, __shfl_xor_sync(0xffffffffu, v, o));
    return v;
}
__device__ float block_sum(float v){
    __shared__ float red[33];
    int lane=threadIdx.x&31, w=threadIdx.x>>5, nw=blockDim.x>>5;
    v = warp_sum(v);
    __syncthreads();
    if(lane==0) red[w]=v;
    __syncthreads();
    if(threadIdx.x==0){ float t=0.f; for(int i=0;i<nw;i++) t+=red[i]; red[32]=t; }
    __syncthreads();
    return red[32];
}
__device__ float block_max(float v){
    __shared__ float red[33];
    int lane=threadIdx.x&31, w=threadIdx.x>>5, nw=blockDim.x>>5;
    v = warp_max(v);
    __syncthreads();
    if(lane==0) red[w]=v;
    __syncthreads();
    if(threadIdx.x==0){ float t=red[0]; for(int i=1;i<nw;i++) t=fmaxf(t,red[i]); red[32]=t; }
    __syncthreads();
    return red[32];
}

// ---------------- prefix build + pooled attention mask ----------------
// grid = NB, block = 256
__global__ void prefix_kernel(const int* __restrict__ sub, const float* __restrict__ mask,
                              const float* __restrict__ amask,
                              float* __restrict__ prefix, float* __restrict__ attn)
{
    __shared__ float P[SEQ*SEQ];
    int bn = blockIdx.x;
    for (int i = threadIdx.x; i < SEQ*SEQ; i += blockDim.x) P[i] = 0.f;
    __syncthreads();
    const int* si = sub + (size_t)bn*SEQ*2;
    for (int s = threadIdx.x; s < SEQ; s += blockDim.x) {
        int i = si[2*s+0], j = si[2*s+1];
        P[i*SEQ + j] = 1.f;                     // set semantics (duplicates benign)
    }
    __syncthreads();
    float m = mask[bn];
    int lane = threadIdx.x & 31, warp = threadIdx.x >> 5;
    for (int i = warp; i < SEQ; i += (blockDim.x >> 5)) {
        float v0 = P[i*SEQ + lane]      * m;
        float v1 = P[i*SEQ + lane + 32] * m;
        float rs = v0 + v1;
        float ad = v0 * amask[bn*SEQ + lane] + v1 * amask[bn*SEQ + lane + 32];
        #pragma unroll
        for (int o=16;o;o>>=1){ rs += __shfl_xor_sync(0xffffffffu,rs,o); ad += __shfl_xor_sync(0xffffffffu,ad,o); }
        float denom = fmaxf(rs, 1e-12f);
        prefix[(size_t)bn*SEQ*SEQ + i*SEQ + lane]      = v0/denom;
        prefix[(size_t)bn*SEQ*SEQ + i*SEQ + lane + 32] = v1/denom;
        if (lane==0) attn[bn*SEQ + i] = ad/denom;
    }
}

// ---------------- embedding gather + prefix pooling ----------------
// grid = (NB, DMODEL/128), block = 128
__global__ void pool_kernel(const float* __restrict__ prefix, const int* __restrict__ enc,
                            const float* __restrict__ emb, float* __restrict__ x)
{
    __shared__ float P[SEQ*SEQ];
    __shared__ int idx[SEQ];
    int bn = blockIdx.x;
    int d  = blockIdx.y*128 + threadIdx.x;
    for (int i = threadIdx.x; i < SEQ*SEQ; i += blockDim.x)
        P[i] = prefix[(size_t)bn*SEQ*SEQ + i];
    if (threadIdx.x < SEQ) idx[threadIdx.x] = enc[(size_t)bn*SEQ + threadIdx.x];
    __syncthreads();
    float acc[SEQ];
    #pragma unroll
    for (int i=0;i<SEQ;i++) acc[i]=0.f;
    for (int j=0;j<SEQ;j++) {
        float e = emb[(size_t)idx[j]*DMODEL + d];
        #pragma unroll
        for (int i=0;i<SEQ;i++) acc[i] = fmaf(P[i*SEQ+j], e, acc[i]);
    }
    for (int i=0;i<SEQ;i++) x[((size_t)bn*SEQ + i)*DMODEL + d] = acc[i];
}

// ---------------- generic SGEMM: C[M,N] = A[M,K] @ B[K,N] ----------------
// EPI: 0=none, 1=gelu(tanh approx), 2=tanh(x+bias[col])
template<int EPI>
__global__ void sgemm_kernel(const float* __restrict__ A, const float* __restrict__ B,
                             float* __restrict__ C, int M, int N, int Kd,
                             const float* __restrict__ bias)
{
    __shared__ float As[16][64];
    __shared__ float Bs[16][68];
    int tid = threadIdx.x;
    int rowBase = blockIdx.y << 6, colBase = blockIdx.x << 6;
    int tx = tid & 15, ty = tid >> 4;
    int am = tid >> 2, ak = (tid & 3) << 2;
    int bk = tid >> 4, bn = (tid & 15) << 2;
    bool aok = (rowBase + am) < M;
    const float* Ap = A + (size_t)(rowBase + am)*Kd + ak;
    const float* Bp = B + (size_t)bk*N + colBase + bn;
    float acc[4][4] = {};
    for (int k0 = 0; k0 < Kd; k0 += 16) {
        float4 a4 = aok ? *(const float4*)Ap : make_float4(0.f,0.f,0.f,0.f);
        As[ak+0][am]=a4.x; As[ak+1][am]=a4.y; As[ak+2][am]=a4.z; As[ak+3][am]=a4.w;
        *(float4*)&Bs[bk][bn] = *(const float4*)Bp;
        __syncthreads();
        #pragma unroll
        for (int kk=0; kk<16; kk++) {
            float av[4], bv[4];
            #pragma unroll
            for (int i=0;i<4;i++) av[i]=As[kk][(ty<<2)+i];
            #pragma unroll
            for (int j=0;j<4;j++) bv[j]=Bs[kk][(tx<<2)+j];
            #pragma unroll
            for (int i=0;i<4;i++)
                #pragma unroll
                for (int j=0;j<4;j++)
                    acc[i][j] = fmaf(av[i], bv[j], acc[i][j]);
        }
        __syncthreads();
        Ap += 16;
        Bp += (size_t)16*N;
    }
    #pragma unroll
    for (int i=0;i<4;i++) {
        int r = rowBase + (ty<<2) + i;
        if (r >= M) continue;
        #pragma unroll
        for (int j=0;j<4;j++) {
            int c = colBase + (tx<<2) + j;
            float v = acc[i][j];
            if (EPI == 1) {
                v = 0.5f*v*(1.f + tanhf(0.7978845608028654f*(v + 0.044715f*v*v*v)));
            } else if (EPI == 2) {
                v = tanhf(v + bias[c]);
            }
            C[(size_t)r*N + c] = v;
        }
    }
}

// ---------------- attention: logits = Q K^T * 0.125 + key-mask bias ----------------
// grid = (TQ*TK, NHEAD, N), block = 256
__global__ void logits_kernel(const float* __restrict__ Q, const float* __restrict__ Kmat,
                              const float* __restrict__ mask, float* __restrict__ lg,
                              int L, int TK)
{
    __shared__ float Qs[64][65];
    __shared__ float Ks[64][65];
    int n = blockIdx.z, h = blockIdx.y;
    int qt = blockIdx.x / TK, kt = blockIdx.x % TK;
    int tid = threadIdx.x;
    for (int i = tid; i < 64*64; i += 256) {
        int r = i >> 6, c = i & 63;
        int lq = qt*64 + r, lk = kt*64 + r;
        Qs[r][c] = (lq < L) ? Q[((size_t)n*L + lq)*DMODEL + h*64 + c] : 0.f;
        Ks[r][c] = (lk < L) ? Kmat[((size_t)n*L + lk)*DMODEL + h*64 + c] : 0.f;
    }
    __syncthreads();
    int tx = tid & 15, ty = tid >> 4;
    float acc[4][4] = {};
    #pragma unroll 8
    for (int d = 0; d < 64; d++) {
        float qv[4], kv[4];
        #pragma unroll
        for (int i=0;i<4;i++) qv[i]=Qs[(ty<<2)+i][d];
        #pragma unroll
        for (int j=0;j<4;j++) kv[j]=Ks[(tx<<2)+j][d];
        #pragma unroll
        for (int i=0;i<4;i++)
            #pragma unroll
            for (int j=0;j<4;j++)
                acc[i][j] = fmaf(qv[i], kv[j], acc[i][j]);
    }
    #pragma unroll
    for (int i=0;i<4;i++) {
        int qr = qt*64 + (ty<<2) + i;
        if (qr >= L) continue;
        #pragma unroll
        for (int j=0;j<4;j++) {
            int kc = kt*64 + (tx<<2) + j;
            if (kc >= L) continue;
            float b = (mask[(size_t)n*L + kc] > 0.f) ? 0.f : -1e9f;
            lg[(((size_t)n*NHEAD + h)*L + qr)*L + kc] = acc[i][j]*0.125f + b;
        }
    }
}

// grid = N*NHEAD*L, block = 128
__global__ void softmax_kernel(float* __restrict__ lg, int L)
{
    float* p = lg + (size_t)blockIdx.x * L;
    int tid = threadIdx.x;
    float m = -3.4e38f;
    for (int i=tid;i<L;i+=blockDim.x) m = fmaxf(m, p[i]);
    m = block_max(m);
    float s = 0.f;
    for (int i=tid;i<L;i+=blockDim.x) { float e = expf(p[i]-m); p[i]=e; s+=e; }
    s = block_sum(s);
    float inv = 1.f/s;
    for (int i=tid;i<L;i+=blockDim.x) p[i] *= inv;
}

// O = A @ V ; grid = (TQ, NHEAD, N), block = 256
__global__ void av_kernel(const float* __restrict__ lg, const float* __restrict__ V,
                          float* __restrict__ O, int L, int TK)
{
    __shared__ float As[64][65];
    __shared__ float Vs[64][65];
    int n = blockIdx.z, h = blockIdx.y, qt = blockIdx.x;
    int tid = threadIdx.x, tx = tid & 15, ty = tid >> 4;
    float acc[4][4] = {};
    for (int kt = 0; kt < TK; kt++) {
        for (int i = tid; i < 64*64; i += 256) {
            int r = i >> 6, c = i & 63;
            int qr = qt*64 + r, kc = kt*64 + c, kr = kt*64 + r;
            As[r][c] = (qr < L && kc < L) ? lg[(((size_t)n*NHEAD + h)*L + qr)*L + kc] : 0.f;
            Vs[r][c] = (kr < L) ? V[((size_t)n*L + kr)*DMODEL + h*64 + c] : 0.f;
        }
        __syncthreads();
        #pragma unroll 8
        for (int kk=0; kk<64; kk++) {
            float av[4], vv[4];
            #pragma unroll
            for (int i=0;i<4;i++) av[i]=As[(ty<<2)+i][kk];
            #pragma unroll
            for (int j=0;j<4;j++) vv[j]=Vs[kk][(tx<<2)+j];
            #pragma unroll
            for (int i=0;i<4;i++)
                #pragma unroll
                for (int j=0;j<4;j++)
                    acc[i][j] = fmaf(av[i], vv[j], acc[i][j]);
        }
        __syncthreads();
    }
    #pragma unroll
    for (int i=0;i<4;i++) {
        int qr = qt*64 + (ty<<2) + i;
        if (qr >= L) continue;
        #pragma unroll
        for (int j=0;j<4;j++)
            O[((size_t)n*L + qr)*DMODEL + h*64 + (tx<<2) + j] = acc[i][j];
    }
}

// out = LayerNorm(x + o); grid = rows, block = 256 (in-place safe: out may alias x)
__global__ void ln_kernel(const float* __restrict__ x, const float* __restrict__ o,
                          float* __restrict__ out)
{
    __shared__ float buf[DMODEL];
    size_t row = blockIdx.x;
    int tid = threadIdx.x;
    float ls = 0.f;
    for (int i=tid;i<DMODEL;i+=blockDim.x) {
        float v = x[row*DMODEL+i] + o[row*DMODEL+i];
        buf[i] = v; ls += v;
    }
    float mu = block_sum(ls) * (1.f/DMODEL);
    float lv = 0.f;
    for (int i=tid;i<DMODEL;i+=blockDim.x) { float d = buf[i]-mu; lv += d*d; }
    float var = block_sum(lv) * (1.f/DMODEL);
    float inv = rsqrtf(var + 1e-12f);
    for (int i=tid;i<DMODEL;i+=blockDim.x) out[row*DMODEL+i] = (buf[i]-mu)*inv;
}

// cls[n] = h[n*L + 0]; grid = N, block = 256
__global__ void gather_cls_kernel(const float* __restrict__ h, float* __restrict__ cls, int L)
{
    int n = blockIdx.x;
    for (int d=threadIdx.x; d<DMODEL; d+=blockDim.x)
        cls[(size_t)n*DMODEL + d] = h[(size_t)n*L*DMODEL + d];
}

// user attention pooling; grid = BB, block = 256
__global__ void user0_kernel(const float* __restrict__ cls, const float* __restrict__ qU,
                             float* __restrict__ u0)
{
    int b = blockIdx.x;
    __shared__ float w[HISN];
    int lane = threadIdx.x & 31, wp = threadIdx.x >> 5;
    for (int n = wp; n < HISN; n += (blockDim.x >> 5)) {
        const float* c = cls + (size_t)(b*HISN + n)*DMODEL;
        float acc = 0.f;
        for (int d = lane; d < DMODEL; d += 32) acc += c[d]*qU[d];
        acc = warp_sum(acc);
        if (lane==0) w[n] = acc / sqrtf(768.f);
    }
    __syncthreads();
    if (threadIdx.x == 0) {
        float m = w[0];
        for (int n=1;n<HISN;n++) m = fmaxf(m, w[n]);
        float s = 0.f;
        for (int n=0;n<HISN;n++){ w[n] = expf(w[n]-m); s += w[n]; }
        float inv = 1.f/s;
        for (int n=0;n<HISN;n++) w[n] *= inv;
    }
    __syncthreads();
    for (int d=threadIdx.x; d<DMODEL; d+=blockDim.x) {
        float acc = 0.f;
        for (int n=0;n<HISN;n++) acc += w[n]*cls[(size_t)(b*HISN+n)*DMODEL + d];
        u0[b*DMODEL + d] = acc;
    }
}

// per-(b,n) scores + stable top-K + gather ps_terms/ps_mask; grid = BB*HISN, block = 256
__global__ void topk_kernel(const float* __restrict__ hidden, const float* __restrict__ u0,
                            const float* __restrict__ attn, int* __restrict__ kid,
                            float* __restrict__ ps, float* __restrict__ psm)
{
    int bn = blockIdx.x;
    int b = bn / HISN, n = bn - b*HISN;
    __shared__ float u[DMODEL];
    __shared__ float sc[SEQ];
    __shared__ int sel[KSEL];
    for (int d=threadIdx.x; d<DMODEL; d+=blockDim.x) u[d] = u0[b*DMODEL + d];
    __syncthreads();
    int lane = threadIdx.x & 31, wp = threadIdx.x >> 5;
    for (int s = wp; s < SEQ; s += (blockDim.x >> 5)) {
        const float* hr = hidden + (size_t)(bn*SEQ + s)*DMODEL;
        float acc = 0.f;
        for (int d = lane; d < DMODEL; d += 32) acc += hr[d]*u[d];
        acc = warp_sum(acc);
        if (lane==0)
            sc[s] = (attn[(size_t)bn*SEQ + s] > 0.f) ? acc / sqrtf(768.f) : -1e9f;
    }
    __syncthreads();
    if (threadIdx.x == 0) {
        bool used[SEQ];
        for (int s=0;s<SEQ;s++) used[s]=false;
        for (int kk=0; kk<KSEL; kk++) {
            float best = -3.4e38f; int bi = 0;
            for (int s=0;s<SEQ;s++)
                if (!used[s] && sc[s] > best) { best = sc[s]; bi = s; }
            used[bi] = true; sel[kk] = bi;
            kid[(size_t)bn*KSEL + kk] = bi;
        }
    }
    __syncthreads();
    for (int kk=0; kk<KSEL; kk++) {
        int s = sel[kk];
        size_t dst = (size_t)(b*LUSR + n*KSEL + kk);
        for (int d=threadIdx.x; d<DMODEL; d+=blockDim.x)
            ps[dst*DMODEL + d] = hidden[(size_t)(bn*SEQ + s)*DMODEL + d];
        if (threadIdx.x == 0) psm[dst] = attn[(size_t)bn*SEQ + s];
    }
}

// final matching + log_softmax; grid = BB, block = 256
__global__ void final_kernel(const float* __restrict__ cddr, const float* __restrict__ ur,
                             float* __restrict__ out)
{
    int b = blockIdx.x;
    __shared__ float s[CDDN];
    int lane = threadIdx.x & 31, wp = threadIdx.x >> 5;
    for (int c = wp; c < CDDN; c += (blockDim.x >> 5)) {
        const float* a = cddr + (size_t)(b*CDDN + c)*DMODEL;
        const float* uu = ur + (size_t)b*DMODEL;
        float acc = 0.f;
        for (int d = lane; d < DMODEL; d += 32) acc += a[d]*uu[d];
        acc = warp_sum(acc);
        if (lane==0) s[c] = acc / sqrtf(768.f);
    }
    __syncthreads();
    if (threadIdx.x == 0) {
        float m = s[0];
        for (int c=1;c<CDDN;c++) m = fmaxf(m, s[c]);
        float sum = 0.f;
        for (int c=0;c<CDDN;c++) sum += expf(s[c]-m);
        float lse = m + logf(sum);
        for (int c=0;c<CDDN;c++) out[b*CDDN + c] = s[c] - lse;
    }
}

__global__ void kidout_kernel(const int* __restrict__ kid, float* __restrict__ out)
{
    int i = blockIdx.x*blockDim.x + threadIdx.x;
    if (i < BB*HISN*KSEL) out[NCDD + i] = (float)kid[i];
}

// ---------------- host orchestration ----------------
static void run_transformer(int N, int L,
    const float* Wq, const float* Wk, const float* Wv, const float* Wo,
    const float* W1, const float* W2, const float* attnMask,
    float* x, float* q, float* k, float* v, float* o, float* h, float* ff, float* lg)
{
    int R = N*L;
    dim3 gD(DMODEL/64, (R+63)/64);
    sgemm_kernel<0><<<gD,256>>>(x, Wq, q, R, DMODEL, DMODEL, nullptr);
    sgemm_kernel<0><<<gD,256>>>(x, Wk, k, R, DMODEL, DMODEL, nullptr);
    sgemm_kernel<0><<<gD,256>>>(x, Wv, v, R, DMODEL, DMODEL, nullptr);
    int T = (L+63)/64;
    logits_kernel<<<dim3(T*T, NHEAD, N),256>>>(q, k, attnMask, lg, L, T);
    softmax_kernel<<<(unsigned)(N*NHEAD*L),128>>>(lg, L);
    av_kernel<<<dim3(T, NHEAD, N),256>>>(lg, v, o, L, T);
    sgemm_kernel<0><<<gD,256>>>(o, Wo, q, R, DMODEL, DMODEL, nullptr);
    ln_kernel<<<R,256>>>(x, q, h);
    sgemm_kernel<1><<<dim3(FFDIM/64,(R+63)/64),256>>>(h, W1, ff, R, FFDIM, DMODEL, nullptr);
    sgemm_kernel<0><<<gD,256>>>(ff, W2, q, R, DMODEL, FFDIM, nullptr);
    ln_kernel<<<R,256>>>(h, q, h);
}

extern "C" void kernel_launch(void* const* d_in, const int* in_sizes, int n_in,
                              void* d_out, int out_size)
{
    const int*   cdd_sub  = (const int*)d_in[0];
    const int*   his_sub  = (const int*)d_in[1];
    const int*   cdd_enc  = (const int*)d_in[2];
    const int*   his_enc  = (const int*)d_in[3];
    const float* cdd_mask = (const float*)d_in[4];
    const float* his_mask = (const float*)d_in[5];
    const float* cdd_am   = (const float*)d_in[6];
    const float* his_am   = (const float*)d_in[7];
    const float* emb      = (const float*)d_in[8];
    const float* bWq = (const float*)d_in[9];
    const float* bWk = (const float*)d_in[10];
    const float* bWv = (const float*)d_in[11];
    const float* bWo = (const float*)d_in[12];
    const float* bW1 = (const float*)d_in[13];
    const float* bW2 = (const float*)d_in[14];
    const float* eWq = (const float*)d_in[15];
    const float* eWk = (const float*)d_in[16];
    const float* eWv = (const float*)d_in[17];
    const float* eWo = (const float*)d_in[18];
    const float* eW1 = (const float*)d_in[19];
    const float* eW2 = (const float*)d_in[20];
    const float* qU    = (const float*)d_in[21];
    const float* projW = (const float*)d_in[22];
    const float* projb = (const float*)d_in[23];
    float* out = (float*)d_out;

    float *x,*q,*k,*v,*o,*h,*ff,*lg,*pre,*atC,*atH,*cls,*cddr,*u0,*ur,*psm; int* kid;
    cudaGetSymbolAddress((void**)&x,   g_x);
    cudaGetSymbolAddress((void**)&q,   g_q);
    cudaGetSymbolAddress((void**)&k,   g_k);
    cudaGetSymbolAddress((void**)&v,   g_v);
    cudaGetSymbolAddress((void**)&o,   g_o);
    cudaGetSymbolAddress((void**)&h,   g_h);
    cudaGetSymbolAddress((void**)&ff,  g_ff);
    cudaGetSymbolAddress((void**)&lg,  g_lg);
    cudaGetSymbolAddress((void**)&pre, g_pre);
    cudaGetSymbolAddress((void**)&atC, g_atC);
    cudaGetSymbolAddress((void**)&atH, g_atH);
    cudaGetSymbolAddress((void**)&cls, g_cls);
    cudaGetSymbolAddress((void**)&cddr,g_cddr);
    cudaGetSymbolAddress((void**)&u0,  g_u0);
    cudaGetSymbolAddress((void**)&ur,  g_ur);
    cudaGetSymbolAddress((void**)&psm, g_psm);
    cudaGetSymbolAddress((void**)&kid, g_kid);

    // ---- candidate path (BERT weights) ----
    prefix_kernel<<<NCDD,256>>>(cdd_sub, cdd_mask, cdd_am, pre, atC);
    pool_kernel<<<dim3(NCDD, DMODEL/128),128>>>(pre, cdd_enc, emb, x);
    run_transformer(NCDD, SEQ, bWq,bWk,bWv,bWo,bW1,bW2, atC, x,q,k,v,o,h,ff,lg);
    gather_cls_kernel<<<NCDD,256>>>(h, cls, SEQ);
    sgemm_kernel<2><<<dim3(DMODEL/64, (NCDD+63)/64),256>>>(cls, projW, cddr, NCDD, DMODEL, DMODEL, projb);

    // ---- history path (encN weights) ----
    prefix_kernel<<<NHIS,256>>>(his_sub, his_mask, his_am, pre, atH);
    pool_kernel<<<dim3(NHIS, DMODEL/128),128>>>(pre, his_enc, emb, x);
    run_transformer(NHIS, SEQ, eWq,eWk,eWv,eWo,eW1,eW2, atH, x,q,k,v,o,h,ff,lg);
    gather_cls_kernel<<<NHIS,256>>>(h, cls, SEQ);
    user0_kernel<<<BB,256>>>(cls, qU, u0);
    topk_kernel<<<BB*HISN,256>>>(h, u0, atH, kid, x /*ps_terms*/, psm);

    // ---- user path over selected terms (BERT weights) ----
    run_transformer(BB, LUSR, bWq,bWk,bWv,bWo,bW1,bW2, psm, x,q,k,v,o,h,ff,lg);
    gather_cls_kernel<<<BB,256>>>(h, cls, LUSR);
    sgemm_kernel<2><<<dim3(DMODEL/64, 1),256>>>(cls, projW, ur, BB, DMODEL, DMODEL, projb);

    // ---- outputs: prob [B,CDD] then kid [B,HIS,K] as float ----
    final_kernel<<<BB,256>>>(cddr, ur, out);
    if (out_size >= NCDD + BB*HISN*KSEL)
        kidout_kernel<<<(BB*HISN*KSEL + 255)/256, 256>>>(kid, out);
}

// round 2
// speedup vs baseline: 1.2656x; 1.2656x over previous
#include <cuda_runtime.h>
#include <math.h>

#define BB     8
#define CDDN   5
#define HISN   50
#define SEQ    64
#define DMODEL 768
#define NHEAD  12
#define DHEAD  64
#define FFDIM  3072
#define KSEL   8

#define NCDD   (BB*CDDN)     // 40
#define NHIS   (BB*HISN)     // 400
#define LUSR   (HISN*KSEL)   // 400
#define ROWS_MAX (NHIS*SEQ)  // 25600

// ---------------- scratch (device globals; allocation-free) ----------------
__device__ float g_x [ (size_t)ROWS_MAX*DMODEL ];
__device__ float g_q [ (size_t)ROWS_MAX*DMODEL ];
__device__ float g_k [ (size_t)ROWS_MAX*DMODEL ];
__device__ float g_v [ (size_t)ROWS_MAX*DMODEL ];
__device__ float g_o [ (size_t)ROWS_MAX*DMODEL ];
__device__ float g_h [ (size_t)ROWS_MAX*DMODEL ];
__device__ float g_ff[ (size_t)ROWS_MAX*FFDIM ];
__device__ float g_lg[ (size_t)BB*NHEAD*LUSR*LUSR ]; // user path logits 8*12*400*400
__device__ float g_pre[(size_t)NHIS*SEQ*SEQ ];
__device__ float g_atC[ NCDD*SEQ ];
__device__ float g_atH[ NHIS*SEQ ];
__device__ float g_cls[ (size_t)NHIS*DMODEL ];
__device__ float g_cddr[(size_t)NCDD*DMODEL ];
__device__ float g_u0 [ BB*DMODEL ];
__device__ float g_ur [ BB*DMODEL ];
__device__ float g_psm[ BB*LUSR ];
__device__ int   g_kid[ BB*HISN*KSEL ];

// ---------------- reductions ----------------
__device__ __forceinline__ float warp_sum(float v){
    #pragma unroll
    for(int o=16;o;o>>=1) v += __shfl_xor_sync(0xffffffffu, v, o);
    return v;
}
__device__ __forceinline__ float warp_max(float v){
    #pragma unroll
    for(int o=16;o;o>>=1) v = fmaxf(v, __shfl_xor_sync(0xffffffffu, v, o));
    return v;
}
__device__ float block_sum(float v){
    __shared__ float red[33];
    int lane=threadIdx.x&31, w=threadIdx.x>>5, nw=blockDim.x>>5;
    v = warp_sum(v);
    __syncthreads();
    if(lane==0) red[w]=v;
    __syncthreads();
    if(threadIdx.x==0){ float t=0.f; for(int i=0;i<nw;i++) t+=red[i]; red[32]=t; }
    __syncthreads();
    return red[32];
}
__device__ float block_max(float v){
    __shared__ float red[33];
    int lane=threadIdx.x&31, w=threadIdx.x>>5, nw=blockDim.x>>5;
    v = warp_max(v);
    __syncthreads();
    if(lane==0) red[w]=v;
    __syncthreads();
    if(threadIdx.x==0){ float t=red[0]; for(int i=1;i<nw;i++) t=fmaxf(t,red[i]); red[32]=t; }
    __syncthreads();
    return red[32];
}

// ---------------- prefix build + pooled attention mask ----------------
__global__ void prefix_kernel(const int* __restrict__ sub, const float* __restrict__ mask,
                              const float* __restrict__ amask,
                              float* __restrict__ prefix, float* __restrict__ attn)
{
    __shared__ float P[SEQ*SEQ];
    int bn = blockIdx.x;
    for (int i = threadIdx.x; i < SEQ*SEQ; i += blockDim.x) P[i] = 0.f;
    __syncthreads();
    const int* si = sub + (size_t)bn*SEQ*2;
    for (int s = threadIdx.x; s < SEQ; s += blockDim.x) {
        int i = si[2*s+0], j = si[2*s+1];
        P[i*SEQ + j] = 1.f;
    }
    __syncthreads();
    float m = mask[bn];
    int lane = threadIdx.x & 31, warp = threadIdx.x >> 5;
    for (int i = warp; i < SEQ; i += (blockDim.x >> 5)) {
        float v0 = P[i*SEQ + lane]      * m;
        float v1 = P[i*SEQ + lane + 32] * m;
        float rs = v0 + v1;
        float ad = v0 * amask[bn*SEQ + lane] + v1 * amask[bn*SEQ + lane + 32];
        #pragma unroll
        for (int o=16;o;o>>=1){ rs += __shfl_xor_sync(0xffffffffu,rs,o); ad += __shfl_xor_sync(0xffffffffu,ad,o); }
        float denom = fmaxf(rs, 1e-12f);
        prefix[(size_t)bn*SEQ*SEQ + i*SEQ + lane]      = v0/denom;
        prefix[(size_t)bn*SEQ*SEQ + i*SEQ + lane + 32] = v1/denom;
        if (lane==0) attn[bn*SEQ + i] = ad/denom;
    }
}

// ---------------- embedding gather + prefix pooling ----------------
__global__ void pool_kernel(const float* __restrict__ prefix, const int* __restrict__ enc,
                            const float* __restrict__ emb, float* __restrict__ x)
{
    __shared__ float P[SEQ*SEQ];
    __shared__ int idx[SEQ];
    int bn = blockIdx.x;
    int d  = blockIdx.y*128 + threadIdx.x;
    for (int i = threadIdx.x; i < SEQ*SEQ; i += blockDim.x)
        P[i] = prefix[(size_t)bn*SEQ*SEQ + i];
    if (threadIdx.x < SEQ) idx[threadIdx.x] = enc[(size_t)bn*SEQ + threadIdx.x];
    __syncthreads();
    float acc[SEQ];
    #pragma unroll
    for (int i=0;i<SEQ;i++) acc[i]=0.f;
    for (int j=0;j<SEQ;j++) {
        float e = emb[(size_t)idx[j]*DMODEL + d];
        #pragma unroll
        for (int i=0;i<SEQ;i++) acc[i] = fmaf(P[i*SEQ+j], e, acc[i]);
    }
    for (int i=0;i<SEQ;i++) x[((size_t)bn*SEQ + i)*DMODEL + d] = acc[i];
}

// ---------------- 128x128 double-buffered SGEMM ----------------
// C[M,N] = A[M,K] @ B[K,N]; EPI: 0=none, 1=gelu(tanh)
// grid (N/128, M/128), block 256; M,N,K multiples of 128/128/16
template<int EPI>
__global__ __launch_bounds__(256) void sgemm128(const float* __restrict__ A,
                                                const float* __restrict__ B,
                                                float* __restrict__ C,
                                                int M, int N, int Kd)
{
    __shared__ float As[2][16][132];
    __shared__ float Bs[2][16][132];
    const int tid = threadIdx.x;
    const int rowBase = blockIdx.y << 7, colBase = blockIdx.x << 7;
    const int tx = tid & 15, ty = tid >> 4;

    // load indexing: 512 float4 per array per tile, 2 per thread
    int arow[2], akq[2], brow[2], bc[2];
    #pragma unroll
    for (int i=0;i<2;i++) {
        int idx = tid + (i<<8);
        arow[i] = idx >> 2;   akq[i] = (idx & 3) << 2;
        brow[i] = idx >> 5;   bc[i]  = (idx & 31) << 2;
    }

    const int nt = Kd >> 4;
    // prologue: tile 0 direct to smem buf 0
    #pragma unroll
    for (int i=0;i<2;i++) {
        float4 a4 = (rowBase+arow[i] < M)
            ? *(const float4*)(A + (size_t)(rowBase+arow[i])*Kd + akq[i])
            : make_float4(0.f,0.f,0.f,0.f);
        As[0][akq[i]+0][arow[i]] = a4.x;
        As[0][akq[i]+1][arow[i]] = a4.y;
        As[0][akq[i]+2][arow[i]] = a4.z;
        As[0][akq[i]+3][arow[i]] = a4.w;
        *(float4*)&Bs[0][brow[i]][bc[i]] =
            *(const float4*)(B + (size_t)brow[i]*N + colBase + bc[i]);
    }
    __syncthreads();

    float acc[8][8] = {};
    int buf = 0;
    for (int t = 0; t < nt; t++) {
        float4 pa[2], pb[2];
        const bool has = (t+1 < nt);
        if (has) {
            int k0 = (t+1) << 4;
            #pragma unroll
            for (int i=0;i<2;i++) {
                pa[i] = (rowBase+arow[i] < M)
                    ? *(const float4*)(A + (size_t)(rowBase+arow[i])*Kd + k0 + akq[i])
                    : make_float4(0.f,0.f,0.f,0.f);
                pb[i] = *(const float4*)(B + (size_t)(k0+brow[i])*N + colBase + bc[i]);
            }
        }
        #pragma unroll
        for (int kk=0; kk<16; kk++) {
            float4 a0 = *(const float4*)&As[buf][kk][ty<<2];
            float4 a1 = *(const float4*)&As[buf][kk][(ty<<2)+64];
            float4 b0 = *(const float4*)&Bs[buf][kk][tx<<2];
            float4 b1 = *(const float4*)&Bs[buf][kk][(tx<<2)+64];
            float av[8] = {a0.x,a0.y,a0.z,a0.w,a1.x,a1.y,a1.z,a1.w};
            float bv[8] = {b0.x,b0.y,b0.z,b0.w,b1.x,b1.y,b1.z,b1.w};
            #pragma unroll
            for (int i=0;i<8;i++)
                #pragma unroll
                for (int j=0;j<8;j++)
                    acc[i][j] = fmaf(av[i], bv[j], acc[i][j]);
        }
        if (has) {
            int nb = buf ^ 1;
            #pragma unroll
            for (int i=0;i<2;i++) {
                As[nb][akq[i]+0][arow[i]] = pa[i].x;
                As[nb][akq[i]+1][arow[i]] = pa[i].y;
                As[nb][akq[i]+2][arow[i]] = pa[i].z;
                As[nb][akq[i]+3][arow[i]] = pa[i].w;
                *(float4*)&Bs[nb][brow[i]][bc[i]] = pb[i];
            }
            __syncthreads();
            buf = nb;
        }
    }

    #pragma unroll
    for (int i=0;i<8;i++) {
        int r = rowBase + (ty<<2) + ((i<4) ? i : 60 + i);
        if (r >= M) continue;
        #pragma unroll
        for (int jh=0;jh<2;jh++) {
            float4 v;
            float* pv = &v.x;
            #pragma unroll
            for (int j=0;j<4;j++) {
                float val = acc[i][jh*4+j];
                if (EPI == 1)
                    val = 0.5f*val*(1.f + tanhf(0.7978845608028654f*(val + 0.044715f*val*val*val)));
                pv[j] = val;
            }
            *(float4*)(C + (size_t)r*N + colBase + (tx<<2) + jh*64) = v;
        }
    }
}

// ---------------- small-M SGEMM (proj): C=tanh(A@B+bias) ----------------
__global__ void sgemm_proj(const float* __restrict__ A, const float* __restrict__ B,
                           float* __restrict__ C, int M, int N, int Kd,
                           const float* __restrict__ bias)
{
    __shared__ float As[16][64];
    __shared__ float Bs[16][68];
    int tid = threadIdx.x;
    int rowBase = blockIdx.y << 6, colBase = blockIdx.x << 6;
    int tx = tid & 15, ty = tid >> 4;
    int am = tid >> 2, ak = (tid & 3) << 2;
    int bk = tid >> 4, bn = (tid & 15) << 2;
    bool aok = (rowBase + am) < M;
    const float* Ap = A + (size_t)(rowBase + am)*Kd + ak;
    const float* Bp = B + (size_t)bk*N + colBase + bn;
    float acc[4][4] = {};
    for (int k0 = 0; k0 < Kd; k0 += 16) {
        float4 a4 = aok ? *(const float4*)Ap : make_float4(0.f,0.f,0.f,0.f);
        As[ak+0][am]=a4.x; As[ak+1][am]=a4.y; As[ak+2][am]=a4.z; As[ak+3][am]=a4.w;
        *(float4*)&Bs[bk][bn] = *(const float4*)Bp;
        __syncthreads();
        #pragma unroll
        for (int kk=0; kk<16; kk++) {
            float av[4], bv[4];
            #pragma unroll
            for (int i=0;i<4;i++) av[i]=As[kk][(ty<<2)+i];
            #pragma unroll
            for (int j=0;j<4;j++) bv[j]=Bs[kk][(tx<<2)+j];
            #pragma unroll
            for (int i=0;i<4;i++)
                #pragma unroll
                for (int j=0;j<4;j++)
                    acc[i][j] = fmaf(av[i], bv[j], acc[i][j]);
        }
        __syncthreads();
        Ap += 16;
        Bp += (size_t)16*N;
    }
    #pragma unroll
    for (int i=0;i<4;i++) {
        int r = rowBase + (ty<<2) + i;
        if (r >= M) continue;
        #pragma unroll
        for (int j=0;j<4;j++) {
            int c = colBase + (tx<<2) + j;
            C[(size_t)r*N + c] = tanhf(acc[i][j] + bias[c]);
        }
    }
}

// ---------------- fused attention for L=64 (one tile) ----------------
// grid (n, h), block 256: S = QK^T/8 + mask -> softmax -> O = S@V
__global__ __launch_bounds__(256) void attn64_kernel(const float* __restrict__ Q,
                                                     const float* __restrict__ Km,
                                                     const float* __restrict__ V,
                                                     const float* __restrict__ mask,
                                                     float* __restrict__ O)
{
    __shared__ float Ts0[64][65];  // Q then P
    __shared__ float Ts1[64][65];  // K then V
    int n = blockIdx.x, h = blockIdx.y;
    int tid = threadIdx.x, tx = tid & 15, ty = tid >> 4;
    for (int i = tid; i < 64*64; i += 256) {
        int r = i >> 6, c = i & 63;
        Ts0[r][c] = Q [((size_t)n*64 + r)*DMODEL + h*64 + c];
        Ts1[r][c] = Km[((size_t)n*64 + r)*DMODEL + h*64 + c];
    }
    __syncthreads();
    float s[4][4] = {};
    #pragma unroll 8
    for (int d = 0; d < 64; d++) {
        float qv[4], kv[4];
        #pragma unroll
        for (int i=0;i<4;i++) qv[i]=Ts0[(ty<<2)+i][d];
        #pragma unroll
        for (int j=0;j<4;j++) kv[j]=Ts1[(tx<<2)+j][d];
        #pragma unroll
        for (int i=0;i<4;i++)
            #pragma unroll
            for (int j=0;j<4;j++)
                s[i][j] = fmaf(qv[i], kv[j], s[i][j]);
    }
    // scale + mask bias
    float bias[4];
    #pragma unroll
    for (int j=0;j<4;j++)
        bias[j] = (mask[(size_t)n*64 + (tx<<2)+j] > 0.f) ? 0.f : -1e9f;
    #pragma unroll
    for (int i=0;i<4;i++)
        #pragma unroll
        for (int j=0;j<4;j++)
            s[i][j] = s[i][j]*0.125f + bias[j];
    // row softmax: reduce over tx (low 4 bits of lane)
    float rmax[4], rsum[4];
    #pragma unroll
    for (int i=0;i<4;i++) {
        float m = fmaxf(fmaxf(s[i][0],s[i][1]), fmaxf(s[i][2],s[i][3]));
        #pragma unroll
        for (int o=8;o;o>>=1) m = fmaxf(m, __shfl_xor_sync(0xffffffffu, m, o));
        rmax[i] = m;
    }
    #pragma unroll
    for (int i=0;i<4;i++) {
        float t = 0.f;
        #pragma unroll
        for (int j=0;j<4;j++) { s[i][j] = expf(s[i][j]-rmax[i]); t += s[i][j]; }
        #pragma unroll
        for (int o=8;o;o>>=1) t += __shfl_xor_sync(0xffffffffu, t, o);
        rsum[i] = 1.f/t;
    }
    __syncthreads();  // done reading Q/K tiles
    #pragma unroll
    for (int i=0;i<4;i++)
        #pragma unroll
        for (int j=0;j<4;j++)
            Ts0[(ty<<2)+i][(tx<<2)+j] = s[i][j]*rsum[i];
    for (int i = tid; i < 64*64; i += 256) {
        int r = i >> 6, c = i & 63;
        Ts1[r][c] = V[((size_t)n*64 + r)*DMODEL + h*64 + c];
    }
    __syncthreads();
    float o[4][4] = {};
    #pragma unroll 8
    for (int kk=0; kk<64; kk++) {
        float pv[4], vv[4];
        #pragma unroll
        for (int i=0;i<4;i++) pv[i]=Ts0[(ty<<2)+i][kk];
        #pragma unroll
        for (int j=0;j<4;j++) vv[j]=Ts1[kk][(tx<<2)+j];
        #pragma unroll
        for (int i=0;i<4;i++)
            #pragma unroll
            for (int j=0;j<4;j++)
                o[i][j] = fmaf(pv[i], vv[j], o[i][j]);
    }
    #pragma unroll
    for (int i=0;i<4;i++)
        #pragma unroll
        for (int j=0;j<4;j++)
            O[((size_t)n*64 + (ty<<2)+i)*DMODEL + h*64 + (tx<<2)+j] = o[i][j];
}

// ---------------- attention (generic, user path L=400) ----------------
__global__ void logits_kernel(const float* __restrict__ Q, const float* __restrict__ Kmat,
                              const float* __restrict__ mask, float* __restrict__ lg,
                              int L, int TK)
{
    __shared__ float Qs[64][65];
    __shared__ float Ks[64][65];
    int n = blockIdx.z, h = blockIdx.y;
    int qt = blockIdx.x / TK, kt = blockIdx.x % TK;
    int tid = threadIdx.x;
    for (int i = tid; i < 64*64; i += 256) {
        int r = i >> 6, c = i & 63;
        int lq = qt*64 + r, lk = kt*64 + r;
        Qs[r][c] = (lq < L) ? Q[((size_t)n*L + lq)*DMODEL + h*64 + c] : 0.f;
        Ks[r][c] = (lk < L) ? Kmat[((size_t)n*L + lk)*DMODEL + h*64 + c] : 0.f;
    }
    __syncthreads();
    int tx = tid & 15, ty = tid >> 4;
    float acc[4][4] = {};
    #pragma unroll 8
    for (int d = 0; d < 64; d++) {
        float qv[4], kv[4];
        #pragma unroll
        for (int i=0;i<4;i++) qv[i]=Qs[(ty<<2)+i][d];
        #pragma unroll
        for (int j=0;j<4;j++) kv[j]=Ks[(tx<<2)+j][d];
        #pragma unroll
        for (int i=0;i<4;i++)
            #pragma unroll
            for (int j=0;j<4;j++)
                acc[i][j] = fmaf(qv[i], kv[j], acc[i][j]);
    }
    #pragma unroll
    for (int i=0;i<4;i++) {
        int qr = qt*64 + (ty<<2) + i;
        if (qr >= L) continue;
        #pragma unroll
        for (int j=0;j<4;j++) {
            int kc = kt*64 + (tx<<2) + j;
            if (kc >= L) continue;
            float b = (mask[(size_t)n*L + kc] > 0.f) ? 0.f : -1e9f;
            lg[(((size_t)n*NHEAD + h)*L + qr)*L + kc] = acc[i][j]*0.125f + b;
        }
    }
}

__global__ void softmax_kernel(float* __restrict__ lg, int L)
{
    float* p = lg + (size_t)blockIdx.x * L;
    int tid = threadIdx.x;
    float m = -3.4e38f;
    for (int i=tid;i<L;i+=blockDim.x) m = fmaxf(m, p[i]);
    m = block_max(m);
    float s = 0.f;
    for (int i=tid;i<L;i+=blockDim.x) { float e = expf(p[i]-m); p[i]=e; s+=e; }
    s = block_sum(s);
    float inv = 1.f/s;
    for (int i=tid;i<L;i+=blockDim.x) p[i] *= inv;
}

__global__ void av_kernel(const float* __restrict__ lg, const float* __restrict__ V,
                          float* __restrict__ O, int L, int TK)
{
    __shared__ float As[64][65];
    __shared__ float Vs[64][65];
    int n = blockIdx.z, h = blockIdx.y, qt = blockIdx.x;
    int tid = threadIdx.x, tx = tid & 15, ty = tid >> 4;
    float acc[4][4] = {};
    for (int kt = 0; kt < TK; kt++) {
        for (int i = tid; i < 64*64; i += 256) {
            int r = i >> 6, c = i & 63;
            int qr = qt*64 + r, kc = kt*64 + c, kr = kt*64 + r;
            As[r][c] = (qr < L && kc < L) ? lg[(((size_t)n*NHEAD + h)*L + qr)*L + kc] : 0.f;
            Vs[r][c] = (kr < L) ? V[((size_t)n*L + kr)*DMODEL + h*64 + c] : 0.f;
        }
        __syncthreads();
        #pragma unroll 8
        for (int kk=0; kk<64; kk++) {
            float av[4], vv[4];
            #pragma unroll
            for (int i=0;i<4;i++) av[i]=As[(ty<<2)+i][kk];
            #pragma unroll
            for (int j=0;j<4;j++) vv[j]=Vs[kk][(tx<<2)+j];
            #pragma unroll
            for (int i=0;i<4;i++)
                #pragma unroll
                for (int j=0;j<4;j++)
                    acc[i][j] = fmaf(av[i], vv[j], acc[i][j]);
        }
        __syncthreads();
    }
    #pragma unroll
    for (int i=0;i<4;i++) {
        int qr = qt*64 + (ty<<2) + i;
        if (qr >= L) continue;
        #pragma unroll
        for (int j=0;j<4;j++)
            O[((size_t)n*L + qr)*DMODEL + h*64 + (tx<<2) + j] = acc[i][j];
    }
}

// out = LayerNorm(x + o); grid = rows
__global__ void ln_kernel(const float* __restrict__ x, const float* __restrict__ o,
                          float* __restrict__ out)
{
    __shared__ float buf[DMODEL];
    size_t row = blockIdx.x;
    int tid = threadIdx.x;
    float ls = 0.f;
    for (int i=tid;i<DMODEL;i+=blockDim.x) {
        float v = x[row*DMODEL+i] + o[row*DMODEL+i];
        buf[i] = v; ls += v;
    }
    float mu = block_sum(ls) * (1.f/DMODEL);
    float lv = 0.f;
    for (int i=tid;i<DMODEL;i+=blockDim.x) { float d = buf[i]-mu; lv += d*d; }
    float var = block_sum(lv) * (1.f/DMODEL);
    float inv = rsqrtf(var + 1e-12f);
    for (int i=tid;i<DMODEL;i+=blockDim.x) out[row*DMODEL+i] = (buf[i]-mu)*inv;
}

__global__ void gather_cls_kernel(const float* __restrict__ h, float* __restrict__ cls, int L)
{
    int n = blockIdx.x;
    for (int d=threadIdx.x; d<DMODEL; d+=blockDim.x)
        cls[(size_t)n*DMODEL + d] = h[(size_t)n*L*DMODEL + d];
}

__global__ void user0_kernel(const float* __restrict__ cls, const float* __restrict__ qU,
                             float* __restrict__ u0)
{
    int b = blockIdx.x;
    __shared__ float w[HISN];
    int lane = threadIdx.x & 31, wp = threadIdx.x >> 5;
    for (int n = wp; n < HISN; n += (blockDim.x >> 5)) {
        const float* c = cls + (size_t)(b*HISN + n)*DMODEL;
        float acc = 0.f;
        for (int d = lane; d < DMODEL; d += 32) acc += c[d]*qU[d];
        acc = warp_sum(acc);
        if (lane==0) w[n] = acc / sqrtf(768.f);
    }
    __syncthreads();
    if (threadIdx.x == 0) {
        float m = w[0];
        for (int n=1;n<HISN;n++) m = fmaxf(m, w[n]);
        float s = 0.f;
        for (int n=0;n<HISN;n++){ w[n] = expf(w[n]-m); s += w[n]; }
        float inv = 1.f/s;
        for (int n=0;n<HISN;n++) w[n] *= inv;
    }
    __syncthreads();
    for (int d=threadIdx.x; d<DMODEL; d+=blockDim.x) {
        float acc = 0.f;
        for (int n=0;n<HISN;n++) acc += w[n]*cls[(size_t)(b*HISN+n)*DMODEL + d];
        u0[b*DMODEL + d] = acc;
    }
}

__global__ void topk_kernel(const float* __restrict__ hidden, const float* __restrict__ u0,
                            const float* __restrict__ attn, int* __restrict__ kid,
                            float* __restrict__ ps, float* __restrict__ psm)
{
    int bn = blockIdx.x;
    int b = bn / HISN, n = bn - b*HISN;
    __shared__ float u[DMODEL];
    __shared__ float sc[SEQ];
    __shared__ int sel[KSEL];
    for (int d=threadIdx.x; d<DMODEL; d+=blockDim.x) u[d] = u0[b*DMODEL + d];
    __syncthreads();
    int lane = threadIdx.x & 31, wp = threadIdx.x >> 5;
    for (int s = wp; s < SEQ; s += (blockDim.x >> 5)) {
        const float* hr = hidden + (size_t)(bn*SEQ + s)*DMODEL;
        float acc = 0.f;
        for (int d = lane; d < DMODEL; d += 32) acc += hr[d]*u[d];
        acc = warp_sum(acc);
        if (lane==0)
            sc[s] = (attn[(size_t)bn*SEQ + s] > 0.f) ? acc / sqrtf(768.f) : -1e9f;
    }
    __syncthreads();
    if (threadIdx.x == 0) {
        bool used[SEQ];
        for (int s=0;s<SEQ;s++) used[s]=false;
        for (int kk=0; kk<KSEL; kk++) {
            float best = -3.4e38f; int bi = 0;
            for (int s=0;s<SEQ;s++)
                if (!used[s] && sc[s] > best) { best = sc[s]; bi = s; }
            used[bi] = true; sel[kk] = bi;
            kid[(size_t)bn*KSEL + kk] = bi;
        }
    }
    __syncthreads();
    for (int kk=0; kk<KSEL; kk++) {
        int s = sel[kk];
        size_t dst = (size_t)(b*LUSR + n*KSEL + kk);
        for (int d=threadIdx.x; d<DMODEL; d+=blockDim.x)
            ps[dst*DMODEL + d] = hidden[(size_t)(bn*SEQ + s)*DMODEL + d];
        if (threadIdx.x == 0) psm[dst] = attn[(size_t)bn*SEQ + s];
    }
}

__global__ void final_kernel(const float* __restrict__ cddr, const float* __restrict__ ur,
                             float* __restrict__ out)
{
    int b = blockIdx.x;
    __shared__ float s[CDDN];
    int lane = threadIdx.x & 31, wp = threadIdx.x >> 5;
    for (int c = wp; c < CDDN; c += (blockDim.x >> 5)) {
        const float* a = cddr + (size_t)(b*CDDN + c)*DMODEL;
        const float* uu = ur + (size_t)b*DMODEL;
        float acc = 0.f;
        for (int d = lane; d < DMODEL; d += 32) acc += a[d]*uu[d];
        acc = warp_sum(acc);
        if (lane==0) s[c] = acc / sqrtf(768.f);
    }
    __syncthreads();
    if (threadIdx.x == 0) {
        float m = s[0];
        for (int c=1;c<CDDN;c++) m = fmaxf(m, s[c]);
        float sum = 0.f;
        for (int c=0;c<CDDN;c++) sum += expf(s[c]-m);
        float lse = m + logf(sum);
        for (int c=0;c<CDDN;c++) out[b*CDDN + c] = s[c] - lse;
    }
}

__global__ void kidout_kernel(const int* __restrict__ kid, float* __restrict__ out)
{
    int i = blockIdx.x*blockDim.x + threadIdx.x;
    if (i < BB*HISN*KSEL) out[NCDD + i] = (float)kid[i];
}

// ---------------- host orchestration ----------------
static void run_transformer(int N, int L,
    const float* Wq, const float* Wk, const float* Wv, const float* Wo,
    const float* W1, const float* W2, const float* attnMask,
    float* x, float* q, float* k, float* v, float* o, float* h, float* ff, float* lg)
{
    int R = N*L;  // always a multiple of 128 here
    dim3 gD(DMODEL/128, R/128);
    sgemm128<0><<<gD,256>>>(x, Wq, q, R, DMODEL, DMODEL);
    sgemm128<0><<<gD,256>>>(x, Wk, k, R, DMODEL, DMODEL);
    sgemm128<0><<<gD,256>>>(x, Wv, v, R, DMODEL, DMODEL);
    if (L == 64) {
        attn64_kernel<<<dim3(N, NHEAD),256>>>(q, k, v, attnMask, o);
    } else {
        int T = (L+63)/64;
        logits_kernel<<<dim3(T*T, NHEAD, N),256>>>(q, k, attnMask, lg, L, T);
        softmax_kernel<<<(unsigned)(N*NHEAD*L),128>>>(lg, L);
        av_kernel<<<dim3(T, NHEAD, N),256>>>(lg, v, o, L, T);
    }
    sgemm128<0><<<gD,256>>>(o, Wo, q, R, DMODEL, DMODEL);
    ln_kernel<<<R,256>>>(x, q, h);
    sgemm128<1><<<dim3(FFDIM/128, R/128),256>>>(h, W1, ff, R, FFDIM, DMODEL);
    sgemm128<0><<<gD,256>>>(ff, W2, q, R, DMODEL, FFDIM);
    ln_kernel<<<R,256>>>(h, q, h);
}

extern "C" void kernel_launch(void* const* d_in, const int* in_sizes, int n_in,
                              void* d_out, int out_size)
{
    const int*   cdd_sub  = (const int*)d_in[0];
    const int*   his_sub  = (const int*)d_in[1];
    const int*   cdd_enc  = (const int*)d_in[2];
    const int*   his_enc  = (const int*)d_in[3];
    const float* cdd_mask = (const float*)d_in[4];
    const float* his_mask = (const float*)d_in[5];
    const float* cdd_am   = (const float*)d_in[6];
    const float* his_am   = (const float*)d_in[7];
    const float* emb      = (const float*)d_in[8];
    const float* bWq = (const float*)d_in[9];
    const float* bWk = (const float*)d_in[10];
    const float* bWv = (const float*)d_in[11];
    const float* bWo = (const float*)d_in[12];
    const float* bW1 = (const float*)d_in[13];
    const float* bW2 = (const float*)d_in[14];
    const float* eWq = (const float*)d_in[15];
    const float* eWk = (const float*)d_in[16];
    const float* eWv = (const float*)d_in[17];
    const float* eWo = (const float*)d_in[18];
    const float* eW1 = (const float*)d_in[19];
    const float* eW2 = (const float*)d_in[20];
    const float* qU    = (const float*)d_in[21];
    const float* projW = (const float*)d_in[22];
    const float* projb = (const float*)d_in[23];
    float* out = (float*)d_out;

    float *x,*q,*k,*v,*o,*h,*ff,*lg,*pre,*atC,*atH,*cls,*cddr,*u0,*ur,*psm; int* kid;
    cudaGetSymbolAddress((void**)&x,   g_x);
    cudaGetSymbolAddress((void**)&q,   g_q);
    cudaGetSymbolAddress((void**)&k,   g_k);
    cudaGetSymbolAddress((void**)&v,   g_v);
    cudaGetSymbolAddress((void**)&o,   g_o);
    cudaGetSymbolAddress((void**)&h,   g_h);
    cudaGetSymbolAddress((void**)&ff,  g_ff);
    cudaGetSymbolAddress((void**)&lg,  g_lg);
    cudaGetSymbolAddress((void**)&pre, g_pre);
    cudaGetSymbolAddress((void**)&atC, g_atC);
    cudaGetSymbolAddress((void**)&atH, g_atH);
    cudaGetSymbolAddress((void**)&cls, g_cls);
    cudaGetSymbolAddress((void**)&cddr,g_cddr);
    cudaGetSymbolAddress((void**)&u0,  g_u0);
    cudaGetSymbolAddress((void**)&ur,  g_ur);
    cudaGetSymbolAddress((void**)&psm, g_psm);
    cudaGetSymbolAddress((void**)&kid, g_kid);

    // ---- candidate path (BERT weights) ----
    prefix_kernel<<<NCDD,256>>>(cdd_sub, cdd_mask, cdd_am, pre, atC);
    pool_kernel<<<dim3(NCDD, DMODEL/128),128>>>(pre, cdd_enc, emb, x);
    run_transformer(NCDD, SEQ, bWq,bWk,bWv,bWo,bW1,bW2, atC, x,q,k,v,o,h,ff,lg);
    gather_cls_kernel<<<NCDD,256>>>(h, cls, SEQ);
    sgemm_proj<<<dim3(DMODEL/64, (NCDD+63)/64),256>>>(cls, projW, cddr, NCDD, DMODEL, DMODEL, projb);

    // ---- history path (encN weights) ----
    prefix_kernel<<<NHIS,256>>>(his_sub, his_mask, his_am, pre, atH);
    pool_kernel<<<dim3(NHIS, DMODEL/128),128>>>(pre, his_enc, emb, x);
    run_transformer(NHIS, SEQ, eWq,eWk,eWv,eWo,eW1,eW2, atH, x,q,k,v,o,h,ff,lg);
    gather_cls_kernel<<<NHIS,256>>>(h, cls, SEQ);
    user0_kernel<<<BB,256>>>(cls, qU, u0);
    topk_kernel<<<BB*HISN,256>>>(h, u0, atH, kid, x /*ps_terms*/, psm);

    // ---- user path over selected terms (BERT weights) ----
    run_transformer(BB, LUSR, bWq,bWk,bWv,bWo,bW1,bW2, psm, x,q,k,v,o,h,ff,lg);
    gather_cls_kernel<<<BB,256>>>(h, cls, LUSR);
    sgemm_proj<<<dim3(DMODEL/64, 1),256>>>(cls, projW, ur, BB, DMODEL, DMODEL, projb);

    // ---- outputs: prob [B,CDD] then kid [B,HIS,K] as float ----
    final_kernel<<<BB,256>>>(cddr, ur, out);
    if (out_size >= NCDD + BB*HISN*KSEL)
        kidout_kernel<<<(BB*HISN*KSEL + 255)/256, 256>>>(kid, out);
}

// round 3
// speedup vs baseline: 1.4925x; 1.1793x over previous
#include <cuda_runtime.h>
#include <math.h>

#define BB     8
#define CDDN   5
#define HISN   50
#define SEQ    64
#define DMODEL 768
#define NHEAD  12
#define DHEAD  64
#define FFDIM  3072
#define KSEL   8

#define NCDD   (BB*CDDN)     // 40
#define NHIS   (BB*HISN)     // 400
#define LUSR   (HISN*KSEL)   // 400
#define ROWS_MAX (NHIS*SEQ)  // 25600

// ---------------- scratch ----------------
__device__ float g_x [ (size_t)ROWS_MAX*DMODEL ];
__device__ float g_q [ (size_t)ROWS_MAX*DMODEL ];
__device__ float g_k [ (size_t)ROWS_MAX*DMODEL ];
__device__ float g_v [ (size_t)ROWS_MAX*DMODEL ];
__device__ float g_o [ (size_t)ROWS_MAX*DMODEL ];
__device__ float g_h [ (size_t)ROWS_MAX*DMODEL ];
__device__ float g_ff[ (size_t)ROWS_MAX*FFDIM ];
__device__ float g_lg[ (size_t)BB*NHEAD*LUSR*LUSR ];
__device__ float g_pre[(size_t)NHIS*SEQ*SEQ ];
__device__ float g_atC[ NCDD*SEQ ];
__device__ float g_atH[ NHIS*SEQ ];
__device__ float g_cls[ (size_t)NHIS*DMODEL ];
__device__ float g_cddr[(size_t)NCDD*DMODEL ];
__device__ float g_u0 [ BB*DMODEL ];
__device__ float g_ur [ BB*DMODEL ];
__device__ float g_psm[ BB*LUSR ];
__device__ int   g_kid[ BB*HISN*KSEL ];

// ---------------- helpers ----------------
__device__ __forceinline__ void cp16(void* s, const void* g){
    unsigned sa = (unsigned)__cvta_generic_to_shared(s);
    asm volatile("cp.async.ca.shared.global [%0], [%1], 16;\n" :: "r"(sa), "l"(g));
}
__device__ __forceinline__ void cp_commit(){ asm volatile("cp.async.commit_group;\n"); }
__device__ __forceinline__ void cp_wait0(){ asm volatile("cp.async.wait_group 0;\n"); }

__device__ __forceinline__ float warp_sum(float v){
    #pragma unroll
    for(int o=16;o;o>>=1) v += __shfl_xor_sync(0xffffffffu, v, o);
    return v;
}
__device__ __forceinline__ float warp_max(float v){
    #pragma unroll
    for(int o=16;o;o>>=1) v = fmaxf(v, __shfl_xor_sync(0xffffffffu, v, o));
    return v;
}
__device__ float block_sum(float v){
    __shared__ float red[33];
    int lane=threadIdx.x&31, w=threadIdx.x>>5, nw=blockDim.x>>5;
    v = warp_sum(v);
    __syncthreads();
    if(lane==0) red[w]=v;
    __syncthreads();
    if(threadIdx.x==0){ float t=0.f; for(int i=0;i<nw;i++) t+=red[i]; red[32]=t; }
    __syncthreads();
    return red[32];
}
__device__ float block_max(float v){
    __shared__ float red[33];
    int lane=threadIdx.x&31, w=threadIdx.x>>5, nw=blockDim.x>>5;
    v = warp_max(v);
    __syncthreads();
    if(lane==0) red[w]=v;
    __syncthreads();
    if(threadIdx.x==0){ float t=red[0]; for(int i=1;i<nw;i++) t=fmaxf(t,red[i]); red[32]=t; }
    __syncthreads();
    return red[32];
}

// ---------------- prefix build + pooled attention mask ----------------
__global__ void prefix_kernel(const int* __restrict__ sub, const float* __restrict__ mask,
                              const float* __restrict__ amask,
                              float* __restrict__ prefix, float* __restrict__ attn)
{
    __shared__ float P[SEQ*SEQ];
    int bn = blockIdx.x;
    for (int i = threadIdx.x; i < SEQ*SEQ; i += blockDim.x) P[i] = 0.f;
    __syncthreads();
    const int* si = sub + (size_t)bn*SEQ*2;
    for (int s = threadIdx.x; s < SEQ; s += blockDim.x) {
        int i = si[2*s+0], j = si[2*s+1];
        P[i*SEQ + j] = 1.f;
    }
    __syncthreads();
    float m = mask[bn];
    int lane = threadIdx.x & 31, warp = threadIdx.x >> 5;
    for (int i = warp; i < SEQ; i += (blockDim.x >> 5)) {
        float v0 = P[i*SEQ + lane]      * m;
        float v1 = P[i*SEQ + lane + 32] * m;
        float rs = v0 + v1;
        float ad = v0 * amask[bn*SEQ + lane] + v1 * amask[bn*SEQ + lane + 32];
        #pragma unroll
        for (int o=16;o;o>>=1){ rs += __shfl_xor_sync(0xffffffffu,rs,o); ad += __shfl_xor_sync(0xffffffffu,ad,o); }
        float denom = fmaxf(rs, 1e-12f);
        prefix[(size_t)bn*SEQ*SEQ + i*SEQ + lane]      = v0/denom;
        prefix[(size_t)bn*SEQ*SEQ + i*SEQ + lane + 32] = v1/denom;
        if (lane==0) attn[bn*SEQ + i] = ad/denom;
    }
}

// ---------------- embedding gather + prefix pooling ----------------
__global__ void pool_kernel(const float* __restrict__ prefix, const int* __restrict__ enc,
                            const float* __restrict__ emb, float* __restrict__ x)
{
    __shared__ float P[SEQ*SEQ];
    __shared__ int idx[SEQ];
    int bn = blockIdx.x;
    int d  = blockIdx.y*128 + threadIdx.x;
    for (int i = threadIdx.x; i < SEQ*SEQ; i += blockDim.x)
        P[i] = prefix[(size_t)bn*SEQ*SEQ + i];
    if (threadIdx.x < SEQ) idx[threadIdx.x] = enc[(size_t)bn*SEQ + threadIdx.x];
    __syncthreads();
    float acc[SEQ];
    #pragma unroll
    for (int i=0;i<SEQ;i++) acc[i]=0.f;
    for (int j=0;j<SEQ;j++) {
        float e = emb[(size_t)idx[j]*DMODEL + d];
        #pragma unroll
        for (int i=0;i<SEQ;i++) acc[i] = fmaf(P[i*SEQ+j], e, acc[i]);
    }
    for (int i=0;i<SEQ;i++) x[((size_t)bn*SEQ + i)*DMODEL + d] = acc[i];
}

// ---------------- 128x128 double-buffered SGEMM body ----------------
// C[M,N] = A[M,K] @ B[K,N]; EPI: 0=none, 1=gelu. M,N,K multiples of 128/128/16.
template<int EPI>
__device__ __forceinline__ void gemm128_body(const float* __restrict__ A,
                                             const float* __restrict__ B,
                                             float* __restrict__ C,
                                             int M, int N, int Kd)
{
    __shared__ float As[2][16][132];
    __shared__ float Bs[2][16][132];
    const int tid = threadIdx.x;
    const int rowBase = blockIdx.y << 7, colBase = blockIdx.x << 7;
    const int tx = tid & 15, ty = tid >> 4;

    int arow[2], akq[2], brow[2], bc[2];
    #pragma unroll
    for (int i=0;i<2;i++) {
        int idx = tid + (i<<8);
        arow[i] = idx >> 2;   akq[i] = (idx & 3) << 2;
        brow[i] = idx >> 5;   bc[i]  = (idx & 31) << 2;
    }

    const int nt = Kd >> 4;
    // prologue: B via cp.async, A via regs
    #pragma unroll
    for (int i=0;i<2;i++)
        cp16(&Bs[0][brow[i]][bc[i]], B + (size_t)brow[i]*N + colBase + bc[i]);
    cp_commit();
    #pragma unroll
    for (int i=0;i<2;i++) {
        float4 a4 = *(const float4*)(A + (size_t)(rowBase+arow[i])*Kd + akq[i]);
        As[0][akq[i]+0][arow[i]] = a4.x;
        As[0][akq[i]+1][arow[i]] = a4.y;
        As[0][akq[i]+2][arow[i]] = a4.z;
        As[0][akq[i]+3][arow[i]] = a4.w;
    }
    cp_wait0();
    __syncthreads();

    float acc[8][8] = {};
    int buf = 0;
    for (int t = 0; t < nt; t++) {
        float4 pa[2];
        const bool has = (t+1 < nt);
        if (has) {
            int k0 = (t+1) << 4;
            int nb = buf ^ 1;
            #pragma unroll
            for (int i=0;i<2;i++)
                cp16(&Bs[nb][brow[i]][bc[i]], B + (size_t)(k0+brow[i])*N + colBase + bc[i]);
            cp_commit();
            #pragma unroll
            for (int i=0;i<2;i++)
                pa[i] = *(const float4*)(A + (size_t)(rowBase+arow[i])*Kd + k0 + akq[i]);
        }
        #pragma unroll
        for (int kk=0; kk<16; kk++) {
            float4 a0 = *(const float4*)&As[buf][kk][ty<<2];
            float4 a1 = *(const float4*)&As[buf][kk][(ty<<2)+64];
            float4 b0 = *(const float4*)&Bs[buf][kk][tx<<2];
            float4 b1 = *(const float4*)&Bs[buf][kk][(tx<<2)+64];
            float av[8] = {a0.x,a0.y,a0.z,a0.w,a1.x,a1.y,a1.z,a1.w};
            float bv[8] = {b0.x,b0.y,b0.z,b0.w,b1.x,b1.y,b1.z,b1.w};
            #pragma unroll
            for (int i=0;i<8;i++)
                #pragma unroll
                for (int j=0;j<8;j++)
                    acc[i][j] = fmaf(av[i], bv[j], acc[i][j]);
        }
        if (has) {
            int nb = buf ^ 1;
            #pragma unroll
            for (int i=0;i<2;i++) {
                As[nb][akq[i]+0][arow[i]] = pa[i].x;
                As[nb][akq[i]+1][arow[i]] = pa[i].y;
                As[nb][akq[i]+2][arow[i]] = pa[i].z;
                As[nb][akq[i]+3][arow[i]] = pa[i].w;
            }
            cp_wait0();
            __syncthreads();
            buf = nb;
        }
    }

    #pragma unroll
    for (int i=0;i<8;i++) {
        int r = rowBase + (ty<<2) + ((i<4) ? i : 60 + i);
        #pragma unroll
        for (int jh=0;jh<2;jh++) {
            float4 v;
            float* pv = &v.x;
            #pragma unroll
            for (int j=0;j<4;j++) {
                float val = acc[i][jh*4+j];
                if (EPI == 1)
                    val = 0.5f*val*(1.f + tanhf(0.7978845608028654f*(val + 0.044715f*val*val*val)));
                pv[j] = val;
            }
            *(float4*)(C + (size_t)r*N + colBase + (tx<<2) + jh*64) = v;
        }
    }
}

template<int EPI>
__global__ __launch_bounds__(256, 2) void sgemm128(const float* __restrict__ A,
                                                   const float* __restrict__ B,
                                                   float* __restrict__ C,
                                                   int M, int N, int Kd)
{
    gemm128_body<EPI>(A, B, C, M, N, Kd);
}

// fused QKV: grid.z selects weight/output
__global__ __launch_bounds__(256, 2) void sgemm128_qkv(const float* __restrict__ A,
                                                       const float* __restrict__ B0,
                                                       const float* __restrict__ B1,
                                                       const float* __restrict__ B2,
                                                       float* __restrict__ C0,
                                                       float* __restrict__ C1,
                                                       float* __restrict__ C2,
                                                       int M)
{
    const float* B = (blockIdx.z==0) ? B0 : (blockIdx.z==1) ? B1 : B2;
    float*       C = (blockIdx.z==0) ? C0 : (blockIdx.z==1) ? C1 : C2;
    gemm128_body<0>(A, B, C, M, DMODEL, DMODEL);
}

// ---------------- small-M SGEMM (proj): C=tanh(A@B+bias) ----------------
__global__ void sgemm_proj(const float* __restrict__ A, const float* __restrict__ B,
                           float* __restrict__ C, int M, int N, int Kd,
                           const float* __restrict__ bias)
{
    __shared__ float As[16][64];
    __shared__ float Bs[16][68];
    int tid = threadIdx.x;
    int rowBase = blockIdx.y << 6, colBase = blockIdx.x << 6;
    int tx = tid & 15, ty = tid >> 4;
    int am = tid >> 2, ak = (tid & 3) << 2;
    int bk = tid >> 4, bn = (tid & 15) << 2;
    bool aok = (rowBase + am) < M;
    const float* Ap = A + (size_t)(rowBase + am)*Kd + ak;
    const float* Bp = B + (size_t)bk*N + colBase + bn;
    float acc[4][4] = {};
    for (int k0 = 0; k0 < Kd; k0 += 16) {
        float4 a4 = aok ? *(const float4*)Ap : make_float4(0.f,0.f,0.f,0.f);
        As[ak+0][am]=a4.x; As[ak+1][am]=a4.y; As[ak+2][am]=a4.z; As[ak+3][am]=a4.w;
        *(float4*)&Bs[bk][bn] = *(const float4*)Bp;
        __syncthreads();
        #pragma unroll
        for (int kk=0; kk<16; kk++) {
            float av[4], bv[4];
            #pragma unroll
            for (int i=0;i<4;i++) av[i]=As[kk][(ty<<2)+i];
            #pragma unroll
            for (int j=0;j<4;j++) bv[j]=Bs[kk][(tx<<2)+j];
            #pragma unroll
            for (int i=0;i<4;i++)
                #pragma unroll
                for (int j=0;j<4;j++)
                    acc[i][j] = fmaf(av[i], bv[j], acc[i][j]);
        }
        __syncthreads();
        Ap += 16;
        Bp += (size_t)16*N;
    }
    #pragma unroll
    for (int i=0;i<4;i++) {
        int r = rowBase + (ty<<2) + i;
        if (r >= M) continue;
        #pragma unroll
        for (int j=0;j<4;j++) {
            int c = colBase + (tx<<2) + j;
            C[(size_t)r*N + c] = tanhf(acc[i][j] + bias[c]);
        }
    }
}

// ---------------- fused attention for L=64 ----------------
__global__ __launch_bounds__(256, 2) void attn64_kernel(const float* __restrict__ Q,
                                                        const float* __restrict__ Km,
                                                        const float* __restrict__ V,
                                                        const float* __restrict__ mask,
                                                        float* __restrict__ O)
{
    __shared__ float Ts0[64][65];
    __shared__ float Ts1[64][65];
    int n = blockIdx.x, h = blockIdx.y;
    int tid = threadIdx.x, tx = tid & 15, ty = tid >> 4;
    for (int i = tid; i < 64*64; i += 256) {
        int r = i >> 6, c = i & 63;
        Ts0[r][c] = Q [((size_t)n*64 + r)*DMODEL + h*64 + c];
        Ts1[r][c] = Km[((size_t)n*64 + r)*DMODEL + h*64 + c];
    }
    __syncthreads();
    float s[4][4] = {};
    #pragma unroll 8
    for (int d = 0; d < 64; d++) {
        float qv[4], kv[4];
        #pragma unroll
        for (int i=0;i<4;i++) qv[i]=Ts0[(ty<<2)+i][d];
        #pragma unroll
        for (int j=0;j<4;j++) kv[j]=Ts1[(tx<<2)+j][d];
        #pragma unroll
        for (int i=0;i<4;i++)
            #pragma unroll
            for (int j=0;j<4;j++)
                s[i][j] = fmaf(qv[i], kv[j], s[i][j]);
    }
    float bias[4];
    #pragma unroll
    for (int j=0;j<4;j++)
        bias[j] = (mask[(size_t)n*64 + (tx<<2)+j] > 0.f) ? 0.f : -1e9f;
    #pragma unroll
    for (int i=0;i<4;i++)
        #pragma unroll
        for (int j=0;j<4;j++)
            s[i][j] = s[i][j]*0.125f + bias[j];
    float rmax[4], rsum[4];
    #pragma unroll
    for (int i=0;i<4;i++) {
        float m = fmaxf(fmaxf(s[i][0],s[i][1]), fmaxf(s[i][2],s[i][3]));
        #pragma unroll
        for (int o=8;o;o>>=1) m = fmaxf(m, __shfl_xor_sync(0xffffffffu, m, o));
        rmax[i] = m;
    }
    #pragma unroll
    for (int i=0;i<4;i++) {
        float t = 0.f;
        #pragma unroll
        for (int j=0;j<4;j++) { s[i][j] = expf(s[i][j]-rmax[i]); t += s[i][j]; }
        #pragma unroll
        for (int o=8;o;o>>=1) t += __shfl_xor_sync(0xffffffffu, t, o);
        rsum[i] = 1.f/t;
    }
    __syncthreads();
    #pragma unroll
    for (int i=0;i<4;i++)
        #pragma unroll
        for (int j=0;j<4;j++)
            Ts0[(ty<<2)+i][(tx<<2)+j] = s[i][j]*rsum[i];
    for (int i = tid; i < 64*64; i += 256) {
        int r = i >> 6, c = i & 63;
        Ts1[r][c] = V[((size_t)n*64 + r)*DMODEL + h*64 + c];
    }
    __syncthreads();
    float o[4][4] = {};
    #pragma unroll 8
    for (int kk=0; kk<64; kk++) {
        float pv[4], vv[4];
        #pragma unroll
        for (int i=0;i<4;i++) pv[i]=Ts0[(ty<<2)+i][kk];
        #pragma unroll
        for (int j=0;j<4;j++) vv[j]=Ts1[kk][(tx<<2)+j];
        #pragma unroll
        for (int i=0;i<4;i++)
            #pragma unroll
            for (int j=0;j<4;j++)
                o[i][j] = fmaf(pv[i], vv[j], o[i][j]);
    }
    #pragma unroll
    for (int i=0;i<4;i++)
        #pragma unroll
        for (int j=0;j<4;j++)
            O[((size_t)n*64 + (ty<<2)+i)*DMODEL + h*64 + (tx<<2)+j] = o[i][j];
}

// ---------------- attention (generic, user path L=400) ----------------
__global__ void logits_kernel(const float* __restrict__ Q, const float* __restrict__ Kmat,
                              const float* __restrict__ mask, float* __restrict__ lg,
                              int L, int TK)
{
    __shared__ float Qs[64][65];
    __shared__ float Ks[64][65];
    int n = blockIdx.z, h = blockIdx.y;
    int qt = blockIdx.x / TK, kt = blockIdx.x % TK;
    int tid = threadIdx.x;
    for (int i = tid; i < 64*64; i += 256) {
        int r = i >> 6, c = i & 63;
        int lq = qt*64 + r, lk = kt*64 + r;
        Qs[r][c] = (lq < L) ? Q[((size_t)n*L + lq)*DMODEL + h*64 + c] : 0.f;
        Ks[r][c] = (lk < L) ? Kmat[((size_t)n*L + lk)*DMODEL + h*64 + c] : 0.f;
    }
    __syncthreads();
    int tx = tid & 15, ty = tid >> 4;
    float acc[4][4] = {};
    #pragma unroll 8
    for (int d = 0; d < 64; d++) {
        float qv[4], kv[4];
        #pragma unroll
        for (int i=0;i<4;i++) qv[i]=Qs[(ty<<2)+i][d];
        #pragma unroll
        for (int j=0;j<4;j++) kv[j]=Ks[(tx<<2)+j][d];
        #pragma unroll
        for (int i=0;i<4;i++)
            #pragma unroll
            for (int j=0;j<4;j++)
                acc[i][j] = fmaf(qv[i], kv[j], acc[i][j]);
    }
    #pragma unroll
    for (int i=0;i<4;i++) {
        int qr = qt*64 + (ty<<2) + i;
        if (qr >= L) continue;
        #pragma unroll
        for (int j=0;j<4;j++) {
            int kc = kt*64 + (tx<<2) + j;
            if (kc >= L) continue;
            float b = (mask[(size_t)n*L + kc] > 0.f) ? 0.f : -1e9f;
            lg[(((size_t)n*NHEAD + h)*L + qr)*L + kc] = acc[i][j]*0.125f + b;
        }
    }
}

__global__ void softmax_kernel(float* __restrict__ lg, int L)
{
    float* p = lg + (size_t)blockIdx.x * L;
    int tid = threadIdx.x;
    float m = -3.4e38f;
    for (int i=tid;i<L;i+=blockDim.x) m = fmaxf(m, p[i]);
    m = block_max(m);
    float s = 0.f;
    for (int i=tid;i<L;i+=blockDim.x) { float e = expf(p[i]-m); p[i]=e; s+=e; }
    s = block_sum(s);
    float inv = 1.f/s;
    for (int i=tid;i<L;i+=blockDim.x) p[i] *= inv;
}

__global__ void av_kernel(const float* __restrict__ lg, const float* __restrict__ V,
                          float* __restrict__ O, int L, int TK)
{
    __shared__ float As[64][65];
    __shared__ float Vs[64][65];
    int n = blockIdx.z, h = blockIdx.y, qt = blockIdx.x;
    int tid = threadIdx.x, tx = tid & 15, ty = tid >> 4;
    float acc[4][4] = {};
    for (int kt = 0; kt < TK; kt++) {
        for (int i = tid; i < 64*64; i += 256) {
            int r = i >> 6, c = i & 63;
            int qr = qt*64 + r, kc = kt*64 + c, kr = kt*64 + r;
            As[r][c] = (qr < L && kc < L) ? lg[(((size_t)n*NHEAD + h)*L + qr)*L + kc] : 0.f;
            Vs[r][c] = (kr < L) ? V[((size_t)n*L + kr)*DMODEL + h*64 + c] : 0.f;
        }
        __syncthreads();
        #pragma unroll 8
        for (int kk=0; kk<64; kk++) {
            float av[4], vv[4];
            #pragma unroll
            for (int i=0;i<4;i++) av[i]=As[(ty<<2)+i][kk];
            #pragma unroll
            for (int j=0;j<4;j++) vv[j]=Vs[kk][(tx<<2)+j];
            #pragma unroll
            for (int i=0;i<4;i++)
                #pragma unroll
                for (int j=0;j<4;j++)
                    acc[i][j] = fmaf(av[i], vv[j], acc[i][j]);
        }
        __syncthreads();
    }
    #pragma unroll
    for (int i=0;i<4;i++) {
        int qr = qt*64 + (ty<<2) + i;
        if (qr >= L) continue;
        #pragma unroll
        for (int j=0;j<4;j++)
            O[((size_t)n*L + qr)*DMODEL + h*64 + (tx<<2) + j] = acc[i][j];
    }
}

__global__ void ln_kernel(const float* __restrict__ x, const float* __restrict__ o,
                          float* __restrict__ out)
{
    __shared__ float buf[DMODEL];
    size_t row = blockIdx.x;
    int tid = threadIdx.x;
    float ls = 0.f;
    for (int i=tid;i<DMODEL;i+=blockDim.x) {
        float v = x[row*DMODEL+i] + o[row*DMODEL+i];
        buf[i] = v; ls += v;
    }
    float mu = block_sum(ls) * (1.f/DMODEL);
    float lv = 0.f;
    for (int i=tid;i<DMODEL;i+=blockDim.x) { float d = buf[i]-mu; lv += d*d; }
    float var = block_sum(lv) * (1.f/DMODEL);
    float inv = rsqrtf(var + 1e-12f);
    for (int i=tid;i<DMODEL;i+=blockDim.x) out[row*DMODEL+i] = (buf[i]-mu)*inv;
}

__global__ void gather_cls_kernel(const float* __restrict__ h, float* __restrict__ cls, int L)
{
    int n = blockIdx.x;
    for (int d=threadIdx.x; d<DMODEL; d+=blockDim.x)
        cls[(size_t)n*DMODEL + d] = h[(size_t)n*L*DMODEL + d];
}

__global__ void user0_kernel(const float* __restrict__ cls, const float* __restrict__ qU,
                             float* __restrict__ u0)
{
    int b = blockIdx.x;
    __shared__ float w[HISN];
    int lane = threadIdx.x & 31, wp = threadIdx.x >> 5;
    for (int n = wp; n < HISN; n += (blockDim.x >> 5)) {
        const float* c = cls + (size_t)(b*HISN + n)*DMODEL;
        float acc = 0.f;
        for (int d = lane; d < DMODEL; d += 32) acc += c[d]*qU[d];
        acc = warp_sum(acc);
        if (lane==0) w[n] = acc / sqrtf(768.f);
    }
    __syncthreads();
    if (threadIdx.x == 0) {
        float m = w[0];
        for (int n=1;n<HISN;n++) m = fmaxf(m, w[n]);
        float s = 0.f;
        for (int n=0;n<HISN;n++){ w[n] = expf(w[n]-m); s += w[n]; }
        float inv = 1.f/s;
        for (int n=0;n<HISN;n++) w[n] *= inv;
    }
    __syncthreads();
    for (int d=threadIdx.x; d<DMODEL; d+=blockDim.x) {
        float acc = 0.f;
        for (int n=0;n<HISN;n++) acc += w[n]*cls[(size_t)(b*HISN+n)*DMODEL + d];
        u0[b*DMODEL + d] = acc;
    }
}

__global__ void topk_kernel(const float* __restrict__ hidden, const float* __restrict__ u0,
                            const float* __restrict__ attn, int* __restrict__ kid,
                            float* __restrict__ ps, float* __restrict__ psm)
{
    int bn = blockIdx.x;
    int b = bn / HISN, n = bn - b*HISN;
    __shared__ float u[DMODEL];
    __shared__ float sc[SEQ];
    __shared__ int sel[KSEL];
    for (int d=threadIdx.x; d<DMODEL; d+=blockDim.x) u[d] = u0[b*DMODEL + d];
    __syncthreads();
    int lane = threadIdx.x & 31, wp = threadIdx.x >> 5;
    for (int s = wp; s < SEQ; s += (blockDim.x >> 5)) {
        const float* hr = hidden + (size_t)(bn*SEQ + s)*DMODEL;
        float acc = 0.f;
        for (int d = lane; d < DMODEL; d += 32) acc += hr[d]*u[d];
        acc = warp_sum(acc);
        if (lane==0)
            sc[s] = (attn[(size_t)bn*SEQ + s] > 0.f) ? acc / sqrtf(768.f) : -1e9f;
    }
    __syncthreads();
    if (threadIdx.x == 0) {
        bool used[SEQ];
        for (int s=0;s<SEQ;s++) used[s]=false;
        for (int kk=0; kk<KSEL; kk++) {
            float best = -3.4e38f; int bi = 0;
            for (int s=0;s<SEQ;s++)
                if (!used[s] && sc[s] > best) { best = sc[s]; bi = s; }
            used[bi] = true; sel[kk] = bi;
            kid[(size_t)bn*KSEL + kk] = bi;
        }
    }
    __syncthreads();
    for (int kk=0; kk<KSEL; kk++) {
        int s = sel[kk];
        size_t dst = (size_t)(b*LUSR + n*KSEL + kk);
        for (int d=threadIdx.x; d<DMODEL; d+=blockDim.x)
            ps[dst*DMODEL + d] = hidden[(size_t)(bn*SEQ + s)*DMODEL + d];
        if (threadIdx.x == 0) psm[dst] = attn[(size_t)bn*SEQ + s];
    }
}

__global__ void final_kernel(const float* __restrict__ cddr, const float* __restrict__ ur,
                             float* __restrict__ out)
{
    int b = blockIdx.x;
    __shared__ float s[CDDN];
    int lane = threadIdx.x & 31, wp = threadIdx.x >> 5;
    for (int c = wp; c < CDDN; c += (blockDim.x >> 5)) {
        const float* a = cddr + (size_t)(b*CDDN + c)*DMODEL;
        const float* uu = ur + (size_t)b*DMODEL;
        float acc = 0.f;
        for (int d = lane; d < DMODEL; d += 32) acc += a[d]*uu[d];
        acc = warp_sum(acc);
        if (lane==0) s[c] = acc / sqrtf(768.f);
    }
    __syncthreads();
    if (threadIdx.x == 0) {
        float m = s[0];
        for (int c=1;c<CDDN;c++) m = fmaxf(m, s[c]);
        float sum = 0.f;
        for (int c=0;c<CDDN;c++) sum += expf(s[c]-m);
        float lse = m + logf(sum);
        for (int c=0;c<CDDN;c++) out[b*CDDN + c] = s[c] - lse;
    }
}

__global__ void kidout_kernel(const int* __restrict__ kid, float* __restrict__ out)
{
    int i = blockIdx.x*blockDim.x + threadIdx.x;
    if (i < BB*HISN*KSEL) out[NCDD + i] = (float)kid[i];
}

// ---------------- host orchestration ----------------
static void run_transformer(int N, int L,
    const float* Wq, const float* Wk, const float* Wv, const float* Wo,
    const float* W1, const float* W2, const float* attnMask,
    float* x, float* q, float* k, float* v, float* o, float* h, float* ff, float* lg)
{
    int R = N*L;  // multiple of 128
    dim3 gD(DMODEL/128, R/128);
    sgemm128_qkv<<<dim3(DMODEL/128, R/128, 3),256>>>(x, Wq, Wk, Wv, q, k, v, R);
    if (L == 64) {
        attn64_kernel<<<dim3(N, NHEAD),256>>>(q, k, v, attnMask, o);
    } else {
        int T = (L+63)/64;
        logits_kernel<<<dim3(T*T, NHEAD, N),256>>>(q, k, attnMask, lg, L, T);
        softmax_kernel<<<(unsigned)(N*NHEAD*L),128>>>(lg, L);
        av_kernel<<<dim3(T, NHEAD, N),256>>>(lg, v, o, L, T);
    }
    sgemm128<0><<<gD,256>>>(o, Wo, q, R, DMODEL, DMODEL);
    ln_kernel<<<R,256>>>(x, q, h);
    sgemm128<1><<<dim3(FFDIM/128, R/128),256>>>(h, W1, ff, R, FFDIM, DMODEL);
    sgemm128<0><<<gD,256>>>(ff, W2, q, R, DMODEL, FFDIM);
    ln_kernel<<<R,256>>>(h, q, h);
}

extern "C" void kernel_launch(void* const* d_in, const int* in_sizes, int n_in,
                              void* d_out, int out_size)
{
    const int*   cdd_sub  = (const int*)d_in[0];
    const int*   his_sub  = (const int*)d_in[1];
    const int*   cdd_enc  = (const int*)d_in[2];
    const int*   his_enc  = (const int*)d_in[3];
    const float* cdd_mask = (const float*)d_in[4];
    const float* his_mask = (const float*)d_in[5];
    const float* cdd_am   = (const float*)d_in[6];
    const float* his_am   = (const float*)d_in[7];
    const float* emb      = (const float*)d_in[8];
    const float* bWq = (const float*)d_in[9];
    const float* bWk = (const float*)d_in[10];
    const float* bWv = (const float*)d_in[11];
    const float* bWo = (const float*)d_in[12];
    const float* bW1 = (const float*)d_in[13];
    const float* bW2 = (const float*)d_in[14];
    const float* eWq = (const float*)d_in[15];
    const float* eWk = (const float*)d_in[16];
    const float* eWv = (const float*)d_in[17];
    const float* eWo = (const float*)d_in[18];
    const float* eW1 = (const float*)d_in[19];
    const float* eW2 = (const float*)d_in[20];
    const float* qU    = (const float*)d_in[21];
    const float* projW = (const float*)d_in[22];
    const float* projb = (const float*)d_in[23];
    float* out = (float*)d_out;

    float *x,*q,*k,*v,*o,*h,*ff,*lg,*pre,*atC,*atH,*cls,*cddr,*u0,*ur,*psm; int* kid;
    cudaGetSymbolAddress((void**)&x,   g_x);
    cudaGetSymbolAddress((void**)&q,   g_q);
    cudaGetSymbolAddress((void**)&k,   g_k);
    cudaGetSymbolAddress((void**)&v,   g_v);
    cudaGetSymbolAddress((void**)&o,   g_o);
    cudaGetSymbolAddress((void**)&h,   g_h);
    cudaGetSymbolAddress((void**)&ff,  g_ff);
    cudaGetSymbolAddress((void**)&lg,  g_lg);
    cudaGetSymbolAddress((void**)&pre, g_pre);
    cudaGetSymbolAddress((void**)&atC, g_atC);
    cudaGetSymbolAddress((void**)&atH, g_atH);
    cudaGetSymbolAddress((void**)&cls, g_cls);
    cudaGetSymbolAddress((void**)&cddr,g_cddr);
    cudaGetSymbolAddress((void**)&u0,  g_u0);
    cudaGetSymbolAddress((void**)&ur,  g_ur);
    cudaGetSymbolAddress((void**)&psm, g_psm);
    cudaGetSymbolAddress((void**)&kid, g_kid);

    // ---- candidate path (BERT weights) ----
    prefix_kernel<<<NCDD,256>>>(cdd_sub, cdd_mask, cdd_am, pre, atC);
    pool_kernel<<<dim3(NCDD, DMODEL/128),128>>>(pre, cdd_enc, emb, x);
    run_transformer(NCDD, SEQ, bWq,bWk,bWv,bWo,bW1,bW2, atC, x,q,k,v,o,h,ff,lg);
    gather_cls_kernel<<<NCDD,256>>>(h, cls, SEQ);
    sgemm_proj<<<dim3(DMODEL/64, (NCDD+63)/64),256>>>(cls, projW, cddr, NCDD, DMODEL, DMODEL, projb);

    // ---- history path (encN weights) ----
    prefix_kernel<<<NHIS,256>>>(his_sub, his_mask, his_am, pre, atH);
    pool_kernel<<<dim3(NHIS, DMODEL/128),128>>>(pre, his_enc, emb, x);
    run_transformer(NHIS, SEQ, eWq,eWk,eWv,eWo,eW1,eW2, atH, x,q,k,v,o,h,ff,lg);
    gather_cls_kernel<<<NHIS,256>>>(h, cls, SEQ);
    user0_kernel<<<BB,256>>>(cls, qU, u0);
    topk_kernel<<<BB*HISN,256>>>(h, u0, atH, kid, x /*ps_terms*/, psm);

    // ---- user path over selected terms (BERT weights) ----
    run_transformer(BB, LUSR, bWq,bWk,bWv,bWo,bW1,bW2, psm, x,q,k,v,o,h,ff,lg);
    gather_cls_kernel<<<BB,256>>>(h, cls, LUSR);
    sgemm_proj<<<dim3(DMODEL/64, 1),256>>>(cls, projW, ur, BB, DMODEL, DMODEL, projb);

    // ---- outputs ----
    final_kernel<<<BB,256>>>(cddr, ur, out);
    if (out_size >= NCDD + BB*HISN*KSEL)
        kidout_kernel<<<(BB*HISN*KSEL + 255)/256, 256>>>(kid, out);
}

// round 5
// speedup vs baseline: 2.9090x; 1.9491x over previous
#include <cuda_runtime.h>
#include <cuda_bf16.h>
#include <math.h>
#include <stdint.h>

#define BB     8
#define CDDN   5
#define HISN   50
#define SEQ    64
#define DMODEL 768
#define NHEAD  12
#define FFDIM  3072
#define KSEL   8

#define NCDD   (BB*CDDN)     // 40
#define NHIS   (BB*HISN)     // 400
#define LUSR   (HISN*KSEL)   // 400
#define ROWS_MAX (NHIS*SEQ)  // 25600

// weight set layout (elements) inside bf16 buffers
#define WOFF_Q  0
#define WOFF_K  589824
#define WOFF_V  1179648
#define WOFF_O  1769472
#define WOFF_1  2359296
#define WOFF_2  4718592
#define WSET    7077888

// ---------------- scratch ----------------
__device__ float g_x [ (size_t)ROWS_MAX*DMODEL ];
__device__ float g_q [ (size_t)ROWS_MAX*DMODEL ];
__device__ float g_k [ (size_t)ROWS_MAX*DMODEL ];
__device__ float g_v [ (size_t)ROWS_MAX*DMODEL ];
__device__ float g_o [ (size_t)ROWS_MAX*DMODEL ];
__device__ float g_h [ (size_t)ROWS_MAX*DMODEL ];
__device__ float g_ff[ (size_t)ROWS_MAX*FFDIM ];
__device__ float g_lg[ (size_t)BB*NHEAD*LUSR*LUSR ];
__device__ float g_pre[(size_t)NHIS*SEQ*SEQ ];
__device__ float g_atC[ NCDD*SEQ ];
__device__ float g_atH[ NHIS*SEQ ];
__device__ float g_cls[ (size_t)NHIS*DMODEL ];
__device__ float g_cddr[(size_t)NCDD*DMODEL ];
__device__ float g_u0 [ BB*DMODEL ];
__device__ float g_ur [ BB*DMODEL ];
__device__ float g_psm[ BB*LUSR ];
__device__ int   g_kid[ BB*HISN*KSEL ];
// transposed split-bf16 weights: [N,K] layout, two sets (bert, encN)
__device__ unsigned short g_whi[ (size_t)2*WSET ];
__device__ unsigned short g_wlo[ (size_t)2*WSET ];
// split-bf16 activations (A operand), sized for largest (ff)
__device__ unsigned short g_ah[ (size_t)ROWS_MAX*FFDIM ];
__device__ unsigned short g_al[ (size_t)ROWS_MAX*FFDIM ];

// ---------------- low-level helpers ----------------
__device__ __forceinline__ void cp16(uint32_t s, const void* g){
    asm volatile("cp.async.ca.shared.global [%0], [%1], 16;\n" :: "r"(s), "l"(g));
}
__device__ __forceinline__ void cp_commit(){ asm volatile("cp.async.commit_group;\n"); }
template<int N>
__device__ __forceinline__ void cp_wait(){ asm volatile("cp.async.wait_group %0;\n" :: "n"(N)); }

__device__ __forceinline__ uint32_t smem_u32(const void* p) {
    uint32_t a;
    asm("{ .reg .u64 t; cvta.to.shared.u64 t, %1; cvt.u32.u64 %0, t; }" : "=r"(a) : "l"(p));
    return a;
}
__device__ __forceinline__ void ldsm_x4(uint32_t* r, uint32_t addr){
    asm volatile("ldmatrix.sync.aligned.m8n8.x4.shared.b16 {%0,%1,%2,%3}, [%4];"
        : "=r"(r[0]),"=r"(r[1]),"=r"(r[2]),"=r"(r[3]) : "r"(addr));
}
__device__ __forceinline__ void mma_bf16(float* c, const uint32_t* a, const uint32_t* b){
    asm volatile("mma.sync.aligned.m16n8k16.row.col.f32.bf16.bf16.f32 "
        "{%0,%1,%2,%3}, {%4,%5,%6,%7}, {%8,%9}, {%0,%1,%2,%3};"
        : "+f"(c[0]),"+f"(c[1]),"+f"(c[2]),"+f"(c[3])
        : "r"(a[0]),"r"(a[1]),"r"(a[2]),"r"(a[3]), "r"(b[0]),"r"(b[1]));
}

// ---------------- reductions ----------------
__device__ __forceinline__ float warp_sum(float v){
    #pragma unroll
    for(int o=16;o;o>>=1) v += __shfl_xor_sync(0xffffffffu, v, o);
    return v;
}
__device__ __forceinline__ float warp_max(float v){
    #pragma unroll
    for(int o=16;o;o>>=1) v = fmaxf(v, __shfl_xor_sync(0xffffffffu, v, o));
    return v;
}
__device__ float block_sum(float v){
    __shared__ float red[33];
    int lane=threadIdx.x&31, w=threadIdx.x>>5, nw=blockDim.x>>5;
    v = warp_sum(v);
    __syncthreads();
    if(lane==0) red[w]=v;
    __syncthreads();
    if(threadIdx.x==0){ float t=0.f; for(int i=0;i<nw;i++) t+=red[i]; red[32]=t; }
    __syncthreads();
    return red[32];
}
__device__ float block_max(float v){
    __shared__ float red[33];
    int lane=threadIdx.x&31, w=threadIdx.x>>5, nw=blockDim.x>>5;
    v = warp_max(v);
    __syncthreads();
    if(lane==0) red[w]=v;
    __syncthreads();
    if(threadIdx.x==0){ float t=red[0]; for(int i=1;i<nw;i++) t=fmaxf(t,red[i]); red[32]=t; }
    __syncthreads();
    return red[32];
}

// ---------------- weight prep: [K,N] fp32 -> [N,K] bf16 hi/lo ----------------
__global__ void prep_w(const float* __restrict__ W, unsigned short* __restrict__ Th,
                       unsigned short* __restrict__ Tl, int K, int N)
{
    __shared__ float t[32][33];
    int nb = blockIdx.x*32, kb = blockIdx.y*32;
    int x = threadIdx.x, y = threadIdx.y;
    for (int i=y;i<32;i+=8)
        t[i][x] = W[(size_t)(kb+i)*N + nb + x];
    __syncthreads();
    for (int i=y;i<32;i+=8) {
        float v = t[x][i];
        __nv_bfloat16 h = __float2bfloat16(v);
        __nv_bfloat16 l = __float2bfloat16(v - __bfloat162float(h));
        size_t dst = (size_t)(nb+i)*K + kb + x;
        Th[dst] = __bfloat16_as_ushort(h);
        Tl[dst] = __bfloat16_as_ushort(l);
    }
}

// ---------------- activation split: fp32 -> bf16 hi/lo ----------------
__global__ void split_kernel(const float4* __restrict__ x, uint2* __restrict__ hi,
                             uint2* __restrict__ lo, int n4)
{
    int i = blockIdx.x*blockDim.x + threadIdx.x;
    if (i >= n4) return;
    float4 f = x[i];
    float vv[4] = {f.x, f.y, f.z, f.w};
    unsigned short ph[4], pl[4];
    #pragma unroll
    for (int j=0;j<4;j++) {
        __nv_bfloat16 h = __float2bfloat16(vv[j]);
        __nv_bfloat16 l = __float2bfloat16(vv[j] - __bfloat162float(h));
        ph[j] = __bfloat16_as_ushort(h);
        pl[j] = __bfloat16_as_ushort(l);
    }
    hi[i] = make_uint2((uint32_t)ph[0] | ((uint32_t)ph[1]<<16),
                       (uint32_t)ph[2] | ((uint32_t)ph[3]<<16));
    lo[i] = make_uint2((uint32_t)pl[0] | ((uint32_t)pl[1]<<16),
                       (uint32_t)pl[2] | ((uint32_t)pl[3]<<16));
}

// ---------------- mma.sync split-bf16 GEMM ----------------
// C[M,N] = A @ B^T, A: bf16 hi/lo [M,K], B: bf16 hi/lo [N,K].
// Tiles: 128x128x32, 8 warps (2x4), warp tile 64x32. M,N,K % 128/128/32 == 0.
#define APAD 40
#define ARR_B  (128*APAD*2)     // 10240 bytes per array
#define STG_B  (4*ARR_B)        // 40960 per stage
#define MMA_SMEM (2*STG_B)      // 81920 total

template<int EPI>
__device__ __forceinline__ void mma_body(const unsigned short* __restrict__ Ah,
                                         const unsigned short* __restrict__ Al,
                                         const unsigned short* __restrict__ Bh,
                                         const unsigned short* __restrict__ Bl,
                                         float* __restrict__ C,
                                         int M, int N, int K)
{
    extern __shared__ char sm[];
    const uint32_t sbase = smem_u32(sm);
    const int tid = threadIdx.x, lane = tid & 31, wid = tid >> 5;
    const int wm = wid >> 2, wn = wid & 3;
    const int rowBlk = blockIdx.y << 7, colBlk = blockIdx.x << 7;

    // cp.async staging indices: 2 chunks (16B = 8 bf16) per thread per array
    int r0 = tid >> 2,        s0 = (tid & 3) << 3;         // chunk tid
    int r1 = (tid+256) >> 2,  s1 = ((tid+256) & 3) << 3;   // chunk tid+256
    const unsigned short* gA[2] = {Ah, Al};
    const unsigned short* gB[2] = {Bh, Bl};

    const int nc = K >> 5;
    // prologue: stage 0
    #pragma unroll
    for (int p=0;p<2;p++) {
        cp16(sbase + p*ARR_B + (uint32_t)(r0*APAD + s0)*2, gA[p] + (size_t)(rowBlk+r0)*K + s0);
        cp16(sbase + p*ARR_B + (uint32_t)(r1*APAD + s1)*2, gA[p] + (size_t)(rowBlk+r1)*K + s1);
        cp16(sbase + (2+p)*ARR_B + (uint32_t)(r0*APAD + s0)*2, gB[p] + (size_t)(colBlk+r0)*K + s0);
        cp16(sbase + (2+p)*ARR_B + (uint32_t)(r1*APAD + s1)*2, gB[p] + (size_t)(colBlk+r1)*K + s1);
    }
    cp_commit();

    // per-thread ldmatrix offsets (element coords within tile arrays)
    const uint32_t aoff = (uint32_t)((wm*64 + (lane & 15))*APAD + 8*(lane >> 4)) * 2;
    const uint32_t boff = (uint32_t)((wn*32 + (lane & 7) + 8*(lane >> 4))*APAD + 8*((lane >> 3) & 1)) * 2;

    float acc[4][4][4] = {};

    for (int c = 0; c < nc; c++) {
        const bool has = (c+1 < nc);
        if (has) {
            int kb = (c+1) << 5;
            uint32_t st = ((c+1) & 1) * STG_B;
            #pragma unroll
            for (int p=0;p<2;p++) {
                cp16(sbase + st + p*ARR_B + (uint32_t)(r0*APAD + s0)*2, gA[p] + (size_t)(rowBlk+r0)*K + kb + s0);
                cp16(sbase + st + p*ARR_B + (uint32_t)(r1*APAD + s1)*2, gA[p] + (size_t)(rowBlk+r1)*K + kb + s1);
                cp16(sbase + st + (2+p)*ARR_B + (uint32_t)(r0*APAD + s0)*2, gB[p] + (size_t)(colBlk+r0)*K + kb + s0);
                cp16(sbase + st + (2+p)*ARR_B + (uint32_t)(r1*APAD + s1)*2, gB[p] + (size_t)(colBlk+r1)*K + kb + s1);
            }
            cp_commit();
            cp_wait<1>();
        } else {
            cp_wait<0>();
        }
        __syncthreads();

        uint32_t st = (c & 1) * STG_B;
        uint32_t aH = sbase + st + aoff;
        uint32_t aL = aH + ARR_B;
        uint32_t bH = sbase + st + 2*ARR_B + boff;
        uint32_t bL = bH + ARR_B;

        #pragma unroll
        for (int ks = 0; ks < 2; ks++) {
            uint32_t ko = (uint32_t)(ks*16*2);
            uint32_t ahf[4][4], alf[4][4], bbf[2][4];
            #pragma unroll
            for (int mt=0;mt<4;mt++) ldsm_x4(ahf[mt], aH + ko + (uint32_t)(mt*16*APAD*2));
            #pragma unroll
            for (int np=0;np<2;np++) ldsm_x4(bbf[np], bH + ko + (uint32_t)(np*16*APAD*2));
            #pragma unroll
            for (int mt=0;mt<4;mt++)
                #pragma unroll
                for (int nt=0;nt<4;nt++)
                    mma_bf16(acc[mt][nt], ahf[mt], &bbf[nt>>1][(nt&1)*2]);
            #pragma unroll
            for (int mt=0;mt<4;mt++) ldsm_x4(alf[mt], aL + ko + (uint32_t)(mt*16*APAD*2));
            #pragma unroll
            for (int mt=0;mt<4;mt++)
                #pragma unroll
                for (int nt=0;nt<4;nt++)
                    mma_bf16(acc[mt][nt], alf[mt], &bbf[nt>>1][(nt&1)*2]);
            #pragma unroll
            for (int np=0;np<2;np++) ldsm_x4(bbf[np], bL + ko + (uint32_t)(np*16*APAD*2));
            #pragma unroll
            for (int mt=0;mt<4;mt++)
                #pragma unroll
                for (int nt=0;nt<4;nt++)
                    mma_bf16(acc[mt][nt], ahf[mt], &bbf[nt>>1][(nt&1)*2]);
        }
        __syncthreads();
    }

    // epilogue
    #pragma unroll
    for (int mt=0;mt<4;mt++) {
        int row = rowBlk + wm*64 + mt*16 + (lane >> 2);
        #pragma unroll
        for (int nt=0;nt<4;nt++) {
            int col = colBlk + wn*32 + nt*8 + (lane & 3)*2;
            float v0 = acc[mt][nt][0], v1 = acc[mt][nt][1];
            float v2 = acc[mt][nt][2], v3 = acc[mt][nt][3];
            if (EPI == 1) {
                v0 = 0.5f*v0*(1.f + tanhf(0.7978845608028654f*(v0 + 0.044715f*v0*v0*v0)));
                v1 = 0.5f*v1*(1.f + tanhf(0.7978845608028654f*(v1 + 0.044715f*v1*v1*v1)));
                v2 = 0.5f*v2*(1.f + tanhf(0.7978845608028654f*(v2 + 0.044715f*v2*v2*v2)));
                v3 = 0.5f*v3*(1.f + tanhf(0.7978845608028654f*(v3 + 0.044715f*v3*v3*v3)));
            }
            *(float2*)(C + (size_t)row*N + col)     = make_float2(v0, v1);
            *(float2*)(C + (size_t)(row+8)*N + col) = make_float2(v2, v3);
        }
    }
}

template<int EPI>
__global__ __launch_bounds__(256, 2) void mma_gemm(const unsigned short* __restrict__ Ah,
                                                   const unsigned short* __restrict__ Al,
                                                   const unsigned short* __restrict__ Bh,
                                                   const unsigned short* __restrict__ Bl,
                                                   float* __restrict__ C,
                                                   int M, int N, int K)
{
    mma_body<EPI>(Ah, Al, Bh, Bl, C, M, N, K);
}

__global__ __launch_bounds__(256, 2) void mma_gemm_qkv(const unsigned short* __restrict__ Ah,
                                                       const unsigned short* __restrict__ Al,
                                                       const unsigned short* __restrict__ Wh,
                                                       const unsigned short* __restrict__ Wl,
                                                       float* __restrict__ Cq,
                                                       float* __restrict__ Ck,
                                                       float* __restrict__ Cv,
                                                       int M)
{
    const unsigned short* bh = Wh + (size_t)blockIdx.z*589824;
    const unsigned short* bl = Wl + (size_t)blockIdx.z*589824;
    float* C = (blockIdx.z==0) ? Cq : (blockIdx.z==1) ? Ck : Cv;
    mma_body<0>(Ah, Al, bh, bl, C, M, DMODEL, DMODEL);
}

// ---------------- prefix build + pooled attention mask ----------------
__global__ void prefix_kernel(const int* __restrict__ sub, const float* __restrict__ mask,
                              const float* __restrict__ amask,
                              float* __restrict__ prefix, float* __restrict__ attn)
{
    __shared__ float P[SEQ*SEQ];
    int bn = blockIdx.x;
    for (int i = threadIdx.x; i < SEQ*SEQ; i += blockDim.x) P[i] = 0.f;
    __syncthreads();
    const int* si = sub + (size_t)bn*SEQ*2;
    for (int s = threadIdx.x; s < SEQ; s += blockDim.x) {
        int i = si[2*s+0], j = si[2*s+1];
        P[i*SEQ + j] = 1.f;
    }
    __syncthreads();
    float m = mask[bn];
    int lane = threadIdx.x & 31, warp = threadIdx.x >> 5;
    for (int i = warp; i < SEQ; i += (blockDim.x >> 5)) {
        float v0 = P[i*SEQ + lane]      * m;
        float v1 = P[i*SEQ + lane + 32] * m;
        float rs = v0 + v1;
        float ad = v0 * amask[bn*SEQ + lane] + v1 * amask[bn*SEQ + lane + 32];
        #pragma unroll
        for (int o=16;o;o>>=1){ rs += __shfl_xor_sync(0xffffffffu,rs,o); ad += __shfl_xor_sync(0xffffffffu,ad,o); }
        float denom = fmaxf(rs, 1e-12f);
        prefix[(size_t)bn*SEQ*SEQ + i*SEQ + lane]      = v0/denom;
        prefix[(size_t)bn*SEQ*SEQ + i*SEQ + lane + 32] = v1/denom;
        if (lane==0) attn[bn*SEQ + i] = ad/denom;
    }
}

// ---------------- embedding gather + prefix pooling ----------------
__global__ void pool_kernel(const float* __restrict__ prefix, const int* __restrict__ enc,
                            const float* __restrict__ emb, float* __restrict__ x)
{
    __shared__ float P[SEQ*SEQ];
    __shared__ int idx[SEQ];
    int bn = blockIdx.x;
    int d  = blockIdx.y*128 + threadIdx.x;
    for (int i = threadIdx.x; i < SEQ*SEQ; i += blockDim.x)
        P[i] = prefix[(size_t)bn*SEQ*SEQ + i];
    if (threadIdx.x < SEQ) idx[threadIdx.x] = enc[(size_t)bn*SEQ + threadIdx.x];
    __syncthreads();
    float acc[SEQ];
    #pragma unroll
    for (int i=0;i<SEQ;i++) acc[i]=0.f;
    for (int j=0;j<SEQ;j++) {
        float e = emb[(size_t)idx[j]*DMODEL + d];
        #pragma unroll
        for (int i=0;i<SEQ;i++) acc[i] = fmaf(P[i*SEQ+j], e, acc[i]);
    }
    for (int i=0;i<SEQ;i++) x[((size_t)bn*SEQ + i)*DMODEL + d] = acc[i];
}

// ---------------- small-M SGEMM (proj): C=tanh(A@B+bias) ----------------
__global__ void sgemm_proj(const float* __restrict__ A, const float* __restrict__ B,
                           float* __restrict__ C, int M, int N, int Kd,
                           const float* __restrict__ bias)
{
    __shared__ float As[16][64];
    __shared__ float Bs[16][68];
    int tid = threadIdx.x;
    int rowBase = blockIdx.y << 6, colBase = blockIdx.x << 6;
    int tx = tid & 15, ty = tid >> 4;
    int am = tid >> 2, ak = (tid & 3) << 2;
    int bk = tid >> 4, bn = (tid & 15) << 2;
    bool aok = (rowBase + am) < M;
    const float* Ap = A + (size_t)(rowBase + am)*Kd + ak;
    const float* Bp = B + (size_t)bk*N + colBase + bn;
    float acc[4][4] = {};
    for (int k0 = 0; k0 < Kd; k0 += 16) {
        float4 a4 = aok ? *(const float4*)Ap : make_float4(0.f,0.f,0.f,0.f);
        As[ak+0][am]=a4.x; As[ak+1][am]=a4.y; As[ak+2][am]=a4.z; As[ak+3][am]=a4.w;
        *(float4*)&Bs[bk][bn] = *(const float4*)Bp;
        __syncthreads();
        #pragma unroll
        for (int kk=0; kk<16; kk++) {
            float av[4], bv[4];
            #pragma unroll
            for (int i=0;i<4;i++) av[i]=As[kk][(ty<<2)+i];
            #pragma unroll
            for (int j=0;j<4;j++) bv[j]=Bs[kk][(tx<<2)+j];
            #pragma unroll
            for (int i=0;i<4;i++)
                #pragma unroll
                for (int j=0;j<4;j++)
                    acc[i][j] = fmaf(av[i], bv[j], acc[i][j]);
        }
        __syncthreads();
        Ap += 16;
        Bp += (size_t)16*N;
    }
    #pragma unroll
    for (int i=0;i<4;i++) {
        int r = rowBase + (ty<<2) + i;
        if (r >= M) continue;
        #pragma unroll
        for (int j=0;j<4;j++) {
            int c = colBase + (tx<<2) + j;
            C[(size_t)r*N + c] = tanhf(acc[i][j] + bias[c]);
        }
    }
}

// ---------------- fused attention for L=64 ----------------
__global__ __launch_bounds__(256, 2) void attn64_kernel(const float* __restrict__ Q,
                                                        const float* __restrict__ Km,
                                                        const float* __restrict__ V,
                                                        const float* __restrict__ mask,
                                                        float* __restrict__ O)
{
    __shared__ float Ts0[64][65];
    __shared__ float Ts1[64][65];
    int n = blockIdx.x, h = blockIdx.y;
    int tid = threadIdx.x, tx = tid & 15, ty = tid >> 4;
    for (int i = tid; i < 64*64; i += 256) {
        int r = i >> 6, c = i & 63;
        Ts0[r][c] = Q [((size_t)n*64 + r)*DMODEL + h*64 + c];
        Ts1[r][c] = Km[((size_t)n*64 + r)*DMODEL + h*64 + c];
    }
    __syncthreads();
    float s[4][4] = {};
    #pragma unroll 8
    for (int d = 0; d < 64; d++) {
        float qv[4], kv[4];
        #pragma unroll
        for (int i=0;i<4;i++) qv[i]=Ts0[(ty<<2)+i][d];
        #pragma unroll
        for (int j=0;j<4;j++) kv[j]=Ts1[(tx<<2)+j][d];
        #pragma unroll
        for (int i=0;i<4;i++)
            #pragma unroll
            for (int j=0;j<4;j++)
                s[i][j] = fmaf(qv[i], kv[j], s[i][j]);
    }
    float bias[4];
    #pragma unroll
    for (int j=0;j<4;j++)
        bias[j] = (mask[(size_t)n*64 + (tx<<2)+j] > 0.f) ? 0.f : -1e9f;
    #pragma unroll
    for (int i=0;i<4;i++)
        #pragma unroll
        for (int j=0;j<4;j++)
            s[i][j] = s[i][j]*0.125f + bias[j];
    float rmax[4], rsum[4];
    #pragma unroll
    for (int i=0;i<4;i++) {
        float m = fmaxf(fmaxf(s[i][0],s[i][1]), fmaxf(s[i][2],s[i][3]));
        #pragma unroll
        for (int o=8;o;o>>=1) m = fmaxf(m, __shfl_xor_sync(0xffffffffu, m, o));
        rmax[i] = m;
    }
    #pragma unroll
    for (int i=0;i<4;i++) {
        float t = 0.f;
        #pragma unroll
        for (int j=0;j<4;j++) { s[i][j] = expf(s[i][j]-rmax[i]); t += s[i][j]; }
        #pragma unroll
        for (int o=8;o;o>>=1) t += __shfl_xor_sync(0xffffffffu, t, o);
        rsum[i] = 1.f/t;
    }
    __syncthreads();
    #pragma unroll
    for (int i=0;i<4;i++)
        #pragma unroll
        for (int j=0;j<4;j++)
            Ts0[(ty<<2)+i][(tx<<2)+j] = s[i][j]*rsum[i];
    for (int i = tid; i < 64*64; i += 256) {
        int r = i >> 6, c = i & 63;
        Ts1[r][c] = V[((size_t)n*64 + r)*DMODEL + h*64 + c];
    }
    __syncthreads();
    float o[4][4] = {};
    #pragma unroll 8
    for (int kk=0; kk<64; kk++) {
        float pv[4], vv[4];
        #pragma unroll
        for (int i=0;i<4;i++) pv[i]=Ts0[(ty<<2)+i][kk];
        #pragma unroll
        for (int j=0;j<4;j++) vv[j]=Ts1[kk][(tx<<2)+j];
        #pragma unroll
        for (int i=0;i<4;i++)
            #pragma unroll
            for (int j=0;j<4;j++)
                o[i][j] = fmaf(pv[i], vv[j], o[i][j]);
    }
    #pragma unroll
    for (int i=0;i<4;i++)
        #pragma unroll
        for (int j=0;j<4;j++)
            O[((size_t)n*64 + (ty<<2)+i)*DMODEL + h*64 + (tx<<2)+j] = o[i][j];
}

// ---------------- attention (generic, user path L=400) ----------------
__global__ void logits_kernel(const float* __restrict__ Q, const float* __restrict__ Kmat,
                              const float* __restrict__ mask, float* __restrict__ lg,
                              int L, int TK)
{
    __shared__ float Qs[64][65];
    __shared__ float Ks[64][65];
    int n = blockIdx.z, h = blockIdx.y;
    int qt = blockIdx.x / TK, kt = blockIdx.x % TK;
    int tid = threadIdx.x;
    for (int i = tid; i < 64*64; i += 256) {
        int r = i >> 6, c = i & 63;
        int lq = qt*64 + r, lk = kt*64 + r;
        Qs[r][c] = (lq < L) ? Q[((size_t)n*L + lq)*DMODEL + h*64 + c] : 0.f;
        Ks[r][c] = (lk < L) ? Kmat[((size_t)n*L + lk)*DMODEL + h*64 + c] : 0.f;
    }
    __syncthreads();
    int tx = tid & 15, ty = tid >> 4;
    float acc[4][4] = {};
    #pragma unroll 8
    for (int d = 0; d < 64; d++) {
        float qv[4], kv[4];
        #pragma unroll
        for (int i=0;i<4;i++) qv[i]=Qs[(ty<<2)+i][d];
        #pragma unroll
        for (int j=0;j<4;j++) kv[j]=Ks[(tx<<2)+j][d];
        #pragma unroll
        for (int i=0;i<4;i++)
            #pragma unroll
            for (int j=0;j<4;j++)
                acc[i][j] = fmaf(qv[i], kv[j], acc[i][j]);
    }
    #pragma unroll
    for (int i=0;i<4;i++) {
        int qr = qt*64 + (ty<<2) + i;
        if (qr >= L) continue;
        #pragma unroll
        for (int j=0;j<4;j++) {
            int kc = kt*64 + (tx<<2) + j;
            if (kc >= L) continue;
            float b = (mask[(size_t)n*L + kc] > 0.f) ? 0.f : -1e9f;
            lg[(((size_t)n*NHEAD + h)*L + qr)*L + kc] = acc[i][j]*0.125f + b;
        }
    }
}

__global__ void softmax_kernel(float* __restrict__ lg, int L)
{
    float* p = lg + (size_t)blockIdx.x * L;
    int tid = threadIdx.x;
    float m = -3.4e38f;
    for (int i=tid;i<L;i+=blockDim.x) m = fmaxf(m, p[i]);
    m = block_max(m);
    float s = 0.f;
    for (int i=tid;i<L;i+=blockDim.x) { float e = expf(p[i]-m); p[i]=e; s+=e; }
    s = block_sum(s);
    float inv = 1.f/s;
    for (int i=tid;i<L;i+=blockDim.x) p[i] *= inv;
}

__global__ void av_kernel(const float* __restrict__ lg, const float* __restrict__ V,
                          float* __restrict__ O, int L, int TK)
{
    __shared__ float As[64][65];
    __shared__ float Vs[64][65];
    int n = blockIdx.z, h = blockIdx.y, qt = blockIdx.x;
    int tid = threadIdx.x, tx = tid & 15, ty = tid >> 4;
    float acc[4][4] = {};
    for (int kt = 0; kt < TK; kt++) {
        for (int i = tid; i < 64*64; i += 256) {
            int r = i >> 6, c = i & 63;
            int qr = qt*64 + r, kc = kt*64 + c, kr = kt*64 + r;
            As[r][c] = (qr < L && kc < L) ? lg[(((size_t)n*NHEAD + h)*L + qr)*L + kc] : 0.f;
            Vs[r][c] = (kr < L) ? V[((size_t)n*L + kr)*DMODEL + h*64 + c] : 0.f;
        }
        __syncthreads();
        #pragma unroll 8
        for (int kk=0; kk<64; kk++) {
            float av[4], vv[4];
            #pragma unroll
            for (int i=0;i<4;i++) av[i]=As[(ty<<2)+i][kk];
            #pragma unroll
            for (int j=0;j<4;j++) vv[j]=Vs[kk][(tx<<2)+j];
            #pragma unroll
            for (int i=0;i<4;i++)
                #pragma unroll
                for (int j=0;j<4;j++)
                    acc[i][j] = fmaf(av[i], vv[j], acc[i][j]);
        }
        __syncthreads();
    }
    #pragma unroll
    for (int i=0;i<4;i++) {
        int qr = qt*64 + (ty<<2) + i;
        if (qr >= L) continue;
        #pragma unroll
        for (int j=0;j<4;j++)
            O[((size_t)n*L + qr)*DMODEL + h*64 + (tx<<2) + j] = acc[i][j];
    }
}

__global__ void ln_kernel(const float* __restrict__ x, const float* __restrict__ o,
                          float* __restrict__ out)
{
    __shared__ float buf[DMODEL];
    size_t row = blockIdx.x;
    int tid = threadIdx.x;
    float ls = 0.f;
    for (int i=tid;i<DMODEL;i+=blockDim.x) {
        float v = x[row*DMODEL+i] + o[row*DMODEL+i];
        buf[i] = v; ls += v;
    }
    float mu = block_sum(ls) * (1.f/DMODEL);
    float lv = 0.f;
    for (int i=tid;i<DMODEL;i+=blockDim.x) { float d = buf[i]-mu; lv += d*d; }
    float var = block_sum(lv) * (1.f/DMODEL);
    float inv = rsqrtf(var + 1e-12f);
    for (int i=tid;i<DMODEL;i+=blockDim.x) out[row*DMODEL+i] = (buf[i]-mu)*inv;
}

__global__ void gather_cls_kernel(const float* __restrict__ h, float* __restrict__ cls, int L)
{
    int n = blockIdx.x;
    for (int d=threadIdx.x; d<DMODEL; d+=blockDim.x)
        cls[(size_t)n*DMODEL + d] = h[(size_t)n*L*DMODEL + d];
}

__global__ void user0_kernel(const float* __restrict__ cls, const float* __restrict__ qU,
                             float* __restrict__ u0)
{
    int b = blockIdx.x;
    __shared__ float w[HISN];
    int lane = threadIdx.x & 31, wp = threadIdx.x >> 5;
    for (int n = wp; n < HISN; n += (blockDim.x >> 5)) {
        const float* c = cls + (size_t)(b*HISN + n)*DMODEL;
        float acc = 0.f;
        for (int d = lane; d < DMODEL; d += 32) acc += c[d]*qU[d];
        acc = warp_sum(acc);
        if (lane==0) w[n] = acc / sqrtf(768.f);
    }
    __syncthreads();
    if (threadIdx.x == 0) {
        float m = w[0];
        for (int n=1;n<HISN;n++) m = fmaxf(m, w[n]);
        float s = 0.f;
        for (int n=0;n<HISN;n++){ w[n] = expf(w[n]-m); s += w[n]; }
        float inv = 1.f/s;
        for (int n=0;n<HISN;n++) w[n] *= inv;
    }
    __syncthreads();
    for (int d=threadIdx.x; d<DMODEL; d+=blockDim.x) {
        float acc = 0.f;
        for (int n=0;n<HISN;n++) acc += w[n]*cls[(size_t)(b*HISN+n)*DMODEL + d];
        u0[b*DMODEL + d] = acc;
    }
}

__global__ void topk_kernel(const float* __restrict__ hidden, const float* __restrict__ u0,
                            const float* __restrict__ attn, int* __restrict__ kid,
                            float* __restrict__ ps, float* __restrict__ psm)
{
    int bn = blockIdx.x;
    int b = bn / HISN, n = bn - b*HISN;
    __shared__ float u[DMODEL];
    __shared__ float sc[SEQ];
    __shared__ int sel[KSEL];
    for (int d=threadIdx.x; d<DMODEL; d+=blockDim.x) u[d] = u0[b*DMODEL + d];
    __syncthreads();
    int lane = threadIdx.x & 31, wp = threadIdx.x >> 5;
    for (int s = wp; s < SEQ; s += (blockDim.x >> 5)) {
        const float* hr = hidden + (size_t)(bn*SEQ + s)*DMODEL;
        float acc = 0.f;
        for (int d = lane; d < DMODEL; d += 32) acc += hr[d]*u[d];
        acc = warp_sum(acc);
        if (lane==0)
            sc[s] = (attn[(size_t)bn*SEQ + s] > 0.f) ? acc / sqrtf(768.f) : -1e9f;
    }
    __syncthreads();
    if (threadIdx.x == 0) {
        bool used[SEQ];
        for (int s=0;s<SEQ;s++) used[s]=false;
        for (int kk=0; kk<KSEL; kk++) {
            float best = -3.4e38f; int bi = 0;
            for (int s=0;s<SEQ;s++)
                if (!used[s] && sc[s] > best) { best = sc[s]; bi = s; }
            used[bi] = true; sel[kk] = bi;
            kid[(size_t)bn*KSEL + kk] = bi;
        }
    }
    __syncthreads();
    for (int kk=0; kk<KSEL; kk++) {
        int s = sel[kk];
        size_t dst = (size_t)(b*LUSR + n*KSEL + kk);
        for (int d=threadIdx.x; d<DMODEL; d+=blockDim.x)
            ps[dst*DMODEL + d] = hidden[(size_t)(bn*SEQ + s)*DMODEL + d];
        if (threadIdx.x == 0) psm[dst] = attn[(size_t)bn*SEQ + s];
    }
}

__global__ void final_kernel(const float* __restrict__ cddr, const float* __restrict__ ur,
                             float* __restrict__ out)
{
    int b = blockIdx.x;
    __shared__ float s[CDDN];
    int lane = threadIdx.x & 31, wp = threadIdx.x >> 5;
    for (int c = wp; c < CDDN; c += (blockDim.x >> 5)) {
        const float* a = cddr + (size_t)(b*CDDN + c)*DMODEL;
        const float* uu = ur + (size_t)b*DMODEL;
        float acc = 0.f;
        for (int d = lane; d < DMODEL; d += 32) acc += a[d]*uu[d];
        acc = warp_sum(acc);
        if (lane==0) s[c] = acc / sqrtf(768.f);
    }
    __syncthreads();
    if (threadIdx.x == 0) {
        float m = s[0];
        for (int c=1;c<CDDN;c++) m = fmaxf(m, s[c]);
        float sum = 0.f;
        for (int c=0;c<CDDN;c++) sum += expf(s[c]-m);
        float lse = m + logf(sum);
        for (int c=0;c<CDDN;c++) out[b*CDDN + c] = s[c] - lse;
    }
}

__global__ void kidout_kernel(const int* __restrict__ kid, float* __restrict__ out)
{
    int i = blockIdx.x*blockDim.x + threadIdx.x;
    if (i < BB*HISN*KSEL) out[NCDD + i] = (float)kid[i];
}

// ---------------- host orchestration ----------------
static unsigned short *s_ah, *s_al;

static void do_split(const float* src, int elems)
{
    int n4 = elems >> 2;
    split_kernel<<<(n4 + 255)/256, 256>>>((const float4*)src, (uint2*)s_ah, (uint2*)s_al, n4);
}

static void mma_launch(const unsigned short* bh, const unsigned short* bl,
                       float* C, int M, int N, int K, int epi)
{
    dim3 g(N/128, M/128);
    if (epi)
        mma_gemm<1><<<g, 256, MMA_SMEM>>>(s_ah, s_al, bh, bl, C, M, N, K);
    else
        mma_gemm<0><<<g, 256, MMA_SMEM>>>(s_ah, s_al, bh, bl, C, M, N, K);
}

static void run_transformer(int N, int L,
    const unsigned short* wh, const unsigned short* wl, const float* attnMask,
    float* x, float* q, float* k, float* v, float* o, float* h, float* ff, float* lg)
{
    int R = N*L;  // multiple of 128
    do_split(x, R*DMODEL);
    mma_gemm_qkv<<<dim3(DMODEL/128, R/128, 3), 256, MMA_SMEM>>>(s_ah, s_al, wh, wl, q, k, v, R);
    if (L == 64) {
        attn64_kernel<<<dim3(N, NHEAD),256>>>(q, k, v, attnMask, o);
    } else {
        int T = (L+63)/64;
        logits_kernel<<<dim3(T*T, NHEAD, N),256>>>(q, k, attnMask, lg, L, T);
        softmax_kernel<<<(unsigned)(N*NHEAD*L),128>>>(lg, L);
        av_kernel<<<dim3(T, NHEAD, N),256>>>(lg, v, o, L, T);
    }
    do_split(o, R*DMODEL);
    mma_launch(wh+WOFF_O, wl+WOFF_O, q, R, DMODEL, DMODEL, 0);
    ln_kernel<<<R,256>>>(x, q, h);
    do_split(h, R*DMODEL);
    mma_launch(wh+WOFF_1, wl+WOFF_1, ff, R, FFDIM, DMODEL, 1);
    do_split(ff, R*FFDIM);
    mma_launch(wh+WOFF_2, wl+WOFF_2, q, R, DMODEL, FFDIM, 0);
    ln_kernel<<<R,256>>>(h, q, h);
}

extern "C" void kernel_launch(void* const* d_in, const int* in_sizes, int n_in,
                              void* d_out, int out_size)
{
    const int*   cdd_sub  = (const int*)d_in[0];
    const int*   his_sub  = (const int*)d_in[1];
    const int*   cdd_enc  = (const int*)d_in[2];
    const int*   his_enc  = (const int*)d_in[3];
    const float* cdd_mask = (const float*)d_in[4];
    const float* his_mask = (const float*)d_in[5];
    const float* cdd_am   = (const float*)d_in[6];
    const float* his_am   = (const float*)d_in[7];
    const float* emb      = (const float*)d_in[8];
    const float* bW[6] = { (const float*)d_in[9],  (const float*)d_in[10],
                           (const float*)d_in[11], (const float*)d_in[12],
                           (const float*)d_in[13], (const float*)d_in[14] };
    const float* eW[6] = { (const float*)d_in[15], (const float*)d_in[16],
                           (const float*)d_in[17], (const float*)d_in[18],
                           (const float*)d_in[19], (const float*)d_in[20] };
    const float* qU    = (const float*)d_in[21];
    const float* projW = (const float*)d_in[22];
    const float* projb = (const float*)d_in[23];
    float* out = (float*)d_out;

    float *x,*q,*k,*v,*o,*h,*ff,*lg,*pre,*atC,*atH,*cls,*cddr,*u0,*ur,*psm; int* kid;
    unsigned short *whi, *wlo;
    cudaGetSymbolAddress((void**)&x,   g_x);
    cudaGetSymbolAddress((void**)&q,   g_q);
    cudaGetSymbolAddress((void**)&k,   g_k);
    cudaGetSymbolAddress((void**)&v,   g_v);
    cudaGetSymbolAddress((void**)&o,   g_o);
    cudaGetSymbolAddress((void**)&h,   g_h);
    cudaGetSymbolAddress((void**)&ff,  g_ff);
    cudaGetSymbolAddress((void**)&lg,  g_lg);
    cudaGetSymbolAddress((void**)&pre, g_pre);
    cudaGetSymbolAddress((void**)&atC, g_atC);
    cudaGetSymbolAddress((void**)&atH, g_atH);
    cudaGetSymbolAddress((void**)&cls, g_cls);
    cudaGetSymbolAddress((void**)&cddr,g_cddr);
    cudaGetSymbolAddress((void**)&u0,  g_u0);
    cudaGetSymbolAddress((void**)&ur,  g_ur);
    cudaGetSymbolAddress((void**)&psm, g_psm);
    cudaGetSymbolAddress((void**)&kid, g_kid);
    cudaGetSymbolAddress((void**)&whi, g_whi);
    cudaGetSymbolAddress((void**)&wlo, g_wlo);
    cudaGetSymbolAddress((void**)&s_ah, g_ah);
    cudaGetSymbolAddress((void**)&s_al, g_al);

    cudaFuncSetAttribute(mma_gemm<0>,  cudaFuncAttributeMaxDynamicSharedMemorySize, MMA_SMEM);
    cudaFuncSetAttribute(mma_gemm<1>,  cudaFuncAttributeMaxDynamicSharedMemorySize, MMA_SMEM);
    cudaFuncSetAttribute(mma_gemm_qkv, cudaFuncAttributeMaxDynamicSharedMemorySize, MMA_SMEM);

    // ---- weight prep: transpose + bf16 hi/lo split ----
    const size_t offs[6] = { WOFF_Q, WOFF_K, WOFF_V, WOFF_O, WOFF_1, WOFF_2 };
    const int kd[6] = { DMODEL, DMODEL, DMODEL, DMODEL, DMODEL, FFDIM };
    const int nd[6] = { DMODEL, DMODEL, DMODEL, DMODEL, FFDIM, DMODEL };
    for (int i = 0; i < 6; i++) {
        prep_w<<<dim3(nd[i]/32, kd[i]/32), dim3(32,8)>>>(bW[i], whi+offs[i], wlo+offs[i], kd[i], nd[i]);
        prep_w<<<dim3(nd[i]/32, kd[i]/32), dim3(32,8)>>>(eW[i], whi+WSET+offs[i], wlo+WSET+offs[i], kd[i], nd[i]);
    }

    // ---- candidate path (BERT weights) ----
    prefix_kernel<<<NCDD,256>>>(cdd_sub, cdd_mask, cdd_am, pre, atC);
    pool_kernel<<<dim3(NCDD, DMODEL/128),128>>>(pre, cdd_enc, emb, x);
    run_transformer(NCDD, SEQ, whi, wlo, atC, x,q,k,v,o,h,ff,lg);
    gather_cls_kernel<<<NCDD,256>>>(h, cls, SEQ);
    sgemm_proj<<<dim3(DMODEL/64, (NCDD+63)/64),256>>>(cls, projW, cddr, NCDD, DMODEL, DMODEL, projb);

    // ---- history path (encN weights) ----
    prefix_kernel<<<NHIS,256>>>(his_sub, his_mask, his_am, pre, atH);
    pool_kernel<<<dim3(NHIS, DMODEL/128),128>>>(pre, his_enc, emb, x);
    run_transformer(NHIS, SEQ, whi+WSET, wlo+WSET, atH, x,q,k,v,o,h,ff,lg);
    gather_cls_kernel<<<NHIS,256>>>(h, cls, SEQ);
    user0_kernel<<<BB,256>>>(cls, qU, u0);
    topk_kernel<<<BB*HISN,256>>>(h, u0, atH, kid, x /*ps_terms*/, psm);

    // ---- user path over selected terms (BERT weights) ----
    run_transformer(BB, LUSR, whi, wlo, psm, x,q,k,v,o,h,ff,lg);
    gather_cls_kernel<<<BB,256>>>(h, cls, LUSR);
    sgemm_proj<<<dim3(DMODEL/64, 1),256>>>(cls, projW, ur, BB, DMODEL, DMODEL, projb);

    // ---- outputs ----
    final_kernel<<<BB,256>>>(cddr, ur, out);
    if (out_size >= NCDD + BB*HISN*KSEL)
        kidout_kernel<<<(BB*HISN*KSEL + 255)/256, 256>>>(kid, out);
}

// round 6
// speedup vs baseline: 2.9287x; 1.0068x over previous
#include <cuda_runtime.h>
#include <cuda_bf16.h>
#include <math.h>
#include <stdint.h>

#define BB     8
#define CDDN   5
#define HISN   50
#define SEQ    64
#define DMODEL 768
#define NHEAD  12
#define FFDIM  3072
#define KSEL   8

#define NCDD   (BB*CDDN)     // 40
#define NHIS   (BB*HISN)     // 400
#define LUSR   (HISN*KSEL)   // 400
#define ROWS_MAX (NHIS*SEQ)  // 25600

#define WOFF_Q  0
#define WOFF_K  589824
#define WOFF_V  1179648
#define WOFF_O  1769472
#define WOFF_1  2359296
#define WOFF_2  4718592
#define WSET    7077888

// ---------------- scratch ----------------
__device__ float g_x [ (size_t)ROWS_MAX*DMODEL ];
__device__ float g_q [ (size_t)ROWS_MAX*DMODEL ];
__device__ float g_k [ (size_t)ROWS_MAX*DMODEL ];
__device__ float g_v [ (size_t)ROWS_MAX*DMODEL ];
__device__ float g_h [ (size_t)ROWS_MAX*DMODEL ];
__device__ float g_lg[ (size_t)BB*NHEAD*LUSR*LUSR ];
__device__ float g_pre[(size_t)NHIS*SEQ*SEQ ];
__device__ float g_atC[ NCDD*SEQ ];
__device__ float g_atH[ NHIS*SEQ ];
__device__ float g_cls[ (size_t)NHIS*DMODEL ];
__device__ float g_cddr[(size_t)NCDD*DMODEL ];
__device__ float g_u0 [ BB*DMODEL ];
__device__ float g_ur [ BB*DMODEL ];
__device__ float g_psm[ BB*LUSR ];
__device__ int   g_kid[ BB*HISN*KSEL ];
// split-bf16 weights [N,K], two sets
__device__ unsigned short g_whi[ (size_t)2*WSET ];
__device__ unsigned short g_wlo[ (size_t)2*WSET ];
// split-bf16 activations by role
__device__ unsigned short g_xh[ (size_t)ROWS_MAX*DMODEL ];
__device__ unsigned short g_xl[ (size_t)ROWS_MAX*DMODEL ];
__device__ unsigned short g_oh[ (size_t)ROWS_MAX*DMODEL ];
__device__ unsigned short g_ol[ (size_t)ROWS_MAX*DMODEL ];
__device__ unsigned short g_hh[ (size_t)ROWS_MAX*DMODEL ];
__device__ unsigned short g_hl[ (size_t)ROWS_MAX*DMODEL ];
__device__ unsigned short g_fh[ (size_t)ROWS_MAX*FFDIM ];
__device__ unsigned short g_fl[ (size_t)ROWS_MAX*FFDIM ];

// ---------------- low-level helpers ----------------
__device__ __forceinline__ void cp16(uint32_t s, const void* g){
    asm volatile("cp.async.ca.shared.global [%0], [%1], 16;\n" :: "r"(s), "l"(g));
}
__device__ __forceinline__ void cp_commit(){ asm volatile("cp.async.commit_group;\n"); }
template<int N>
__device__ __forceinline__ void cp_wait(){ asm volatile("cp.async.wait_group %0;\n" :: "n"(N)); }

__device__ __forceinline__ uint32_t smem_u32(const void* p) {
    uint32_t a;
    asm("{ .reg .u64 t; cvta.to.shared.u64 t, %1; cvt.u32.u64 %0, t; }" : "=r"(a) : "l"(p));
    return a;
}
__device__ __forceinline__ void ldsm_x4(uint32_t* r, uint32_t addr){
    asm volatile("ldmatrix.sync.aligned.m8n8.x4.shared.b16 {%0,%1,%2,%3}, [%4];"
        : "=r"(r[0]),"=r"(r[1]),"=r"(r[2]),"=r"(r[3]) : "r"(addr));
}
__device__ __forceinline__ void mma_bf16(float* c, const uint32_t* a, const uint32_t* b){
    asm volatile("mma.sync.aligned.m16n8k16.row.col.f32.bf16.bf16.f32 "
        "{%0,%1,%2,%3}, {%4,%5,%6,%7}, {%8,%9}, {%0,%1,%2,%3};"
        : "+f"(c[0]),"+f"(c[1]),"+f"(c[2]),"+f"(c[3])
        : "r"(a[0]),"r"(a[1]),"r"(a[2]),"r"(a[3]), "r"(b[0]),"r"(b[1]));
}
__device__ __forceinline__ void split2(float v, unsigned short& h, unsigned short& l){
    __nv_bfloat16 bh = __float2bfloat16(v);
    __nv_bfloat16 bl = __float2bfloat16(v - __bfloat162float(bh));
    h = __bfloat16_as_ushort(bh);
    l = __bfloat16_as_ushort(bl);
}

// ---------------- reductions ----------------
__device__ __forceinline__ float warp_sum(float v){
    #pragma unroll
    for(int o=16;o;o>>=1) v += __shfl_xor_sync(0xffffffffu, v, o);
    return v;
}
__device__ __forceinline__ float warp_max(float v){
    #pragma unroll
    for(int o=16;o;o>>=1) v = fmaxf(v, __shfl_xor_sync(0xffffffffu, v, o));
    return v;
}
__device__ float block_sum(float v){
    __shared__ float red[33];
    int lane=threadIdx.x&31, w=threadIdx.x>>5, nw=blockDim.x>>5;
    v = warp_sum(v);
    __syncthreads();
    if(lane==0) red[w]=v;
    __syncthreads();
    if(threadIdx.x==0){ float t=0.f; for(int i=0;i<nw;i++) t+=red[i]; red[32]=t; }
    __syncthreads();
    return red[32];
}
__device__ float block_max(float v){
    __shared__ float red[33];
    int lane=threadIdx.x&31, w=threadIdx.x>>5, nw=blockDim.x>>5;
    v = warp_max(v);
    __syncthreads();
    if(lane==0) red[w]=v;
    __syncthreads();
    if(threadIdx.x==0){ float t=red[0]; for(int i=1;i<nw;i++) t=fmaxf(t,red[i]); red[32]=t; }
    __syncthreads();
    return red[32];
}

// ---------------- batched weight prep: [K,N] fp32 -> [N,K] bf16 hi/lo ----------------
struct PrepPtrs { const float* p[12]; };
__constant__ size_t c_woffs[6] = { WOFF_Q, WOFF_K, WOFF_V, WOFF_O, WOFF_1, WOFF_2 };

__global__ void prep_all(PrepPtrs ptrs, unsigned short* __restrict__ Th,
                         unsigned short* __restrict__ Tl)
{
    int w = blockIdx.y;
    int wi = w % 6;
    int K = (wi==5) ? FFDIM : DMODEL;
    int N = (wi==4) ? FFDIM : DMODEL;
    int ntx = N >> 5;
    int tiles = (K >> 5) * ntx;
    int t = blockIdx.x;
    if (t >= tiles) return;
    int nb = (t % ntx) << 5, kb = (t / ntx) << 5;
    const float* W = ptrs.p[w];
    size_t base = c_woffs[wi] + (size_t)(w/6)*WSET;

    __shared__ float tbuf[32][33];
    int x = threadIdx.x, y = threadIdx.y;
    for (int i=y;i<32;i+=8)
        tbuf[i][x] = W[(size_t)(kb+i)*N + nb + x];
    __syncthreads();
    for (int i=y;i<32;i+=8) {
        float v = tbuf[x][i];
        unsigned short h, l;
        split2(v, h, l);
        size_t dst = base + (size_t)(nb+i)*K + kb + x;
        Th[dst] = h;
        Tl[dst] = l;
    }
}

// ---------------- mma.sync split-bf16 GEMM ----------------
// C = A@B^T. A: bf16 hi/lo [M,K]; B: bf16 hi/lo [N,K]. M,N,K % 128/128/32 == 0.
// EPI 0: fp32 C.  EPI 1: gelu -> bf16 hi/lo (Ch/Cl), no fp32.
#define APAD 40
#define ARR_B  (128*APAD*2)
#define STG_B  (4*ARR_B)
#define MMA_SMEM (2*STG_B)      // 81920

template<int EPI>
__device__ __forceinline__ void mma_body(const unsigned short* __restrict__ Ah,
                                         const unsigned short* __restrict__ Al,
                                         const unsigned short* __restrict__ Bh,
                                         const unsigned short* __restrict__ Bl,
                                         float* __restrict__ C,
                                         unsigned short* __restrict__ Ch,
                                         unsigned short* __restrict__ Cl,
                                         int M, int N, int K)
{
    extern __shared__ char sm[];
    const uint32_t sbase = smem_u32(sm);
    const int tid = threadIdx.x, lane = tid & 31, wid = tid >> 5;
    const int wm = wid >> 2, wn = wid & 3;
    const int rowBlk = blockIdx.y << 7, colBlk = blockIdx.x << 7;

    int r0 = tid >> 2,        s0 = (tid & 3) << 3;
    int r1 = (tid+256) >> 2,  s1 = ((tid+256) & 3) << 3;
    const unsigned short* gA[2] = {Ah, Al};
    const unsigned short* gB[2] = {Bh, Bl};

    const int nc = K >> 5;
    #pragma unroll
    for (int p=0;p<2;p++) {
        cp16(sbase + p*ARR_B + (uint32_t)(r0*APAD + s0)*2, gA[p] + (size_t)(rowBlk+r0)*K + s0);
        cp16(sbase + p*ARR_B + (uint32_t)(r1*APAD + s1)*2, gA[p] + (size_t)(rowBlk+r1)*K + s1);
        cp16(sbase + (2+p)*ARR_B + (uint32_t)(r0*APAD + s0)*2, gB[p] + (size_t)(colBlk+r0)*K + s0);
        cp16(sbase + (2+p)*ARR_B + (uint32_t)(r1*APAD + s1)*2, gB[p] + (size_t)(colBlk+r1)*K + s1);
    }
    cp_commit();

    const uint32_t aoff = (uint32_t)((wm*64 + (lane & 15))*APAD + 8*(lane >> 4)) * 2;
    const uint32_t boff = (uint32_t)((wn*32 + (lane & 7) + 8*(lane >> 4))*APAD + 8*((lane >> 3) & 1)) * 2;

    float acc[4][4][4] = {};

    for (int c = 0; c < nc; c++) {
        const bool has = (c+1 < nc);
        if (has) {
            int kb = (c+1) << 5;
            uint32_t st = ((c+1) & 1) * STG_B;
            #pragma unroll
            for (int p=0;p<2;p++) {
                cp16(sbase + st + p*ARR_B + (uint32_t)(r0*APAD + s0)*2, gA[p] + (size_t)(rowBlk+r0)*K + kb + s0);
                cp16(sbase + st + p*ARR_B + (uint32_t)(r1*APAD + s1)*2, gA[p] + (size_t)(rowBlk+r1)*K + kb + s1);
                cp16(sbase + st + (2+p)*ARR_B + (uint32_t)(r0*APAD + s0)*2, gB[p] + (size_t)(colBlk+r0)*K + kb + s0);
                cp16(sbase + st + (2+p)*ARR_B + (uint32_t)(r1*APAD + s1)*2, gB[p] + (size_t)(colBlk+r1)*K + kb + s1);
            }
            cp_commit();
            cp_wait<1>();
        } else {
            cp_wait<0>();
        }
        __syncthreads();

        uint32_t st = (c & 1) * STG_B;
        uint32_t aH = sbase + st + aoff;
        uint32_t aL = aH + ARR_B;
        uint32_t bH = sbase + st + 2*ARR_B + boff;
        uint32_t bL = bH + ARR_B;

        #pragma unroll
        for (int ks = 0; ks < 2; ks++) {
            uint32_t ko = (uint32_t)(ks*16*2);
            uint32_t ahf[4][4], alf[4][4], bbf[2][4];
            #pragma unroll
            for (int mt=0;mt<4;mt++) ldsm_x4(ahf[mt], aH + ko + (uint32_t)(mt*16*APAD*2));
            #pragma unroll
            for (int np=0;np<2;np++) ldsm_x4(bbf[np], bH + ko + (uint32_t)(np*16*APAD*2));
            #pragma unroll
            for (int mt=0;mt<4;mt++)
                #pragma unroll
                for (int nt=0;nt<4;nt++)
                    mma_bf16(acc[mt][nt], ahf[mt], &bbf[nt>>1][(nt&1)*2]);
            #pragma unroll
            for (int mt=0;mt<4;mt++) ldsm_x4(alf[mt], aL + ko + (uint32_t)(mt*16*APAD*2));
            #pragma unroll
            for (int mt=0;mt<4;mt++)
                #pragma unroll
                for (int nt=0;nt<4;nt++)
                    mma_bf16(acc[mt][nt], alf[mt], &bbf[nt>>1][(nt&1)*2]);
            #pragma unroll
            for (int np=0;np<2;np++) ldsm_x4(bbf[np], bL + ko + (uint32_t)(np*16*APAD*2));
            #pragma unroll
            for (int mt=0;mt<4;mt++)
                #pragma unroll
                for (int nt=0;nt<4;nt++)
                    mma_bf16(acc[mt][nt], ahf[mt], &bbf[nt>>1][(nt&1)*2]);
        }
        __syncthreads();
    }

    #pragma unroll
    for (int mt=0;mt<4;mt++) {
        int row = rowBlk + wm*64 + mt*16 + (lane >> 2);
        #pragma unroll
        for (int nt=0;nt<4;nt++) {
            int col = colBlk + wn*32 + nt*8 + (lane & 3)*2;
            float v[4] = {acc[mt][nt][0], acc[mt][nt][1], acc[mt][nt][2], acc[mt][nt][3]};
            if (EPI == 0) {
                *(float2*)(C + (size_t)row*N + col)     = make_float2(v[0], v[1]);
                *(float2*)(C + (size_t)(row+8)*N + col) = make_float2(v[2], v[3]);
            } else {
                #pragma unroll
                for (int j=0;j<4;j++) {
                    float t = v[j];
                    v[j] = 0.5f*t*(1.f + tanhf(0.7978845608028654f*(t + 0.044715f*t*t*t)));
                }
                unsigned short h0,l0,h1,l1;
                split2(v[0], h0, l0); split2(v[1], h1, l1);
                *(uint32_t*)(Ch + (size_t)row*N + col) = (uint32_t)h0 | ((uint32_t)h1<<16);
                *(uint32_t*)(Cl + (size_t)row*N + col) = (uint32_t)l0 | ((uint32_t)l1<<16);
                split2(v[2], h0, l0); split2(v[3], h1, l1);
                *(uint32_t*)(Ch + (size_t)(row+8)*N + col) = (uint32_t)h0 | ((uint32_t)h1<<16);
                *(uint32_t*)(Cl + (size_t)(row+8)*N + col) = (uint32_t)l0 | ((uint32_t)l1<<16);
            }
        }
    }
}

__global__ __launch_bounds__(256, 2) void mma_gemm_f(const unsigned short* __restrict__ Ah,
                                                     const unsigned short* __restrict__ Al,
                                                     const unsigned short* __restrict__ Bh,
                                                     const unsigned short* __restrict__ Bl,
                                                     float* __restrict__ C,
                                                     int M, int N, int K)
{
    mma_body<0>(Ah, Al, Bh, Bl, C, nullptr, nullptr, M, N, K);
}

__global__ __launch_bounds__(256, 2) void mma_gemm_gelu(const unsigned short* __restrict__ Ah,
                                                        const unsigned short* __restrict__ Al,
                                                        const unsigned short* __restrict__ Bh,
                                                        const unsigned short* __restrict__ Bl,
                                                        unsigned short* __restrict__ Ch,
                                                        unsigned short* __restrict__ Cl,
                                                        int M, int N, int K)
{
    mma_body<1>(Ah, Al, Bh, Bl, nullptr, Ch, Cl, M, N, K);
}

__global__ __launch_bounds__(256, 2) void mma_gemm_qkv(const unsigned short* __restrict__ Ah,
                                                       const unsigned short* __restrict__ Al,
                                                       const unsigned short* __restrict__ Wh,
                                                       const unsigned short* __restrict__ Wl,
                                                       float* __restrict__ Cq,
                                                       float* __restrict__ Ck,
                                                       float* __restrict__ Cv,
                                                       int M)
{
    const unsigned short* bh = Wh + (size_t)blockIdx.z*589824;
    const unsigned short* bl = Wl + (size_t)blockIdx.z*589824;
    float* C = (blockIdx.z==0) ? Cq : (blockIdx.z==1) ? Ck : Cv;
    mma_body<0>(Ah, Al, bh, bl, C, nullptr, nullptr, M, DMODEL, DMODEL);
}

// ---------------- prefix build + pooled attention mask ----------------
__global__ void prefix_kernel(const int* __restrict__ sub, const float* __restrict__ mask,
                              const float* __restrict__ amask,
                              float* __restrict__ prefix, float* __restrict__ attn)
{
    __shared__ float P[SEQ*SEQ];
    int bn = blockIdx.x;
    for (int i = threadIdx.x; i < SEQ*SEQ; i += blockDim.x) P[i] = 0.f;
    __syncthreads();
    const int* si = sub + (size_t)bn*SEQ*2;
    for (int s = threadIdx.x; s < SEQ; s += blockDim.x) {
        int i = si[2*s+0], j = si[2*s+1];
        P[i*SEQ + j] = 1.f;
    }
    __syncthreads();
    float m = mask[bn];
    int lane = threadIdx.x & 31, warp = threadIdx.x >> 5;
    for (int i = warp; i < SEQ; i += (blockDim.x >> 5)) {
        float v0 = P[i*SEQ + lane]      * m;
        float v1 = P[i*SEQ + lane + 32] * m;
        float rs = v0 + v1;
        float ad = v0 * amask[bn*SEQ + lane] + v1 * amask[bn*SEQ + lane + 32];
        #pragma unroll
        for (int o=16;o;o>>=1){ rs += __shfl_xor_sync(0xffffffffu,rs,o); ad += __shfl_xor_sync(0xffffffffu,ad,o); }
        float denom = fmaxf(rs, 1e-12f);
        prefix[(size_t)bn*SEQ*SEQ + i*SEQ + lane]      = v0/denom;
        prefix[(size_t)bn*SEQ*SEQ + i*SEQ + lane + 32] = v1/denom;
        if (lane==0) attn[bn*SEQ + i] = ad/denom;
    }
}

// ---------------- embedding gather + pooling, emits fp32 + hi/lo ----------------
__global__ void pool_kernel(const float* __restrict__ prefix, const int* __restrict__ enc,
                            const float* __restrict__ emb, float* __restrict__ x,
                            unsigned short* __restrict__ xh, unsigned short* __restrict__ xl)
{
    __shared__ float P[SEQ*SEQ];
    __shared__ int idx[SEQ];
    int bn = blockIdx.x;
    int d  = blockIdx.y*128 + threadIdx.x;
    for (int i = threadIdx.x; i < SEQ*SEQ; i += blockDim.x)
        P[i] = prefix[(size_t)bn*SEQ*SEQ + i];
    if (threadIdx.x < SEQ) idx[threadIdx.x] = enc[(size_t)bn*SEQ + threadIdx.x];
    __syncthreads();
    float acc[SEQ];
    #pragma unroll
    for (int i=0;i<SEQ;i++) acc[i]=0.f;
    for (int j=0;j<SEQ;j++) {
        float e = emb[(size_t)idx[j]*DMODEL + d];
        #pragma unroll
        for (int i=0;i<SEQ;i++) acc[i] = fmaf(P[i*SEQ+j], e, acc[i]);
    }
    for (int i=0;i<SEQ;i++) {
        size_t o = ((size_t)bn*SEQ + i)*DMODEL + d;
        x[o] = acc[i];
        unsigned short h, l;
        split2(acc[i], h, l);
        xh[o] = h; xl[o] = l;
    }
}

// ---------------- strided proj (reads CLS rows directly): C=tanh(A@B+bias) ----------------
__global__ void sgemm_proj(const float* __restrict__ A, size_t lda,
                           const float* __restrict__ B,
                           float* __restrict__ C, int M, int N, int Kd,
                           const float* __restrict__ bias)
{
    __shared__ float As[16][64];
    __shared__ float Bs[16][68];
    int tid = threadIdx.x;
    int rowBase = blockIdx.y << 6, colBase = blockIdx.x << 6;
    int tx = tid & 15, ty = tid >> 4;
    int am = tid >> 2, ak = (tid & 3) << 2;
    int bk = tid >> 4, bn = (tid & 15) << 2;
    bool aok = (rowBase + am) < M;
    const float* Ap = A + (size_t)(rowBase + am)*lda + ak;
    const float* Bp = B + (size_t)bk*N + colBase + bn;
    float acc[4][4] = {};
    for (int k0 = 0; k0 < Kd; k0 += 16) {
        float4 a4 = aok ? *(const float4*)Ap : make_float4(0.f,0.f,0.f,0.f);
        As[ak+0][am]=a4.x; As[ak+1][am]=a4.y; As[ak+2][am]=a4.z; As[ak+3][am]=a4.w;
        *(float4*)&Bs[bk][bn] = *(const float4*)Bp;
        __syncthreads();
        #pragma unroll
        for (int kk=0; kk<16; kk++) {
            float av[4], bv[4];
            #pragma unroll
            for (int i=0;i<4;i++) av[i]=As[kk][(ty<<2)+i];
            #pragma unroll
            for (int j=0;j<4;j++) bv[j]=Bs[kk][(tx<<2)+j];
            #pragma unroll
            for (int i=0;i<4;i++)
                #pragma unroll
                for (int j=0;j<4;j++)
                    acc[i][j] = fmaf(av[i], bv[j], acc[i][j]);
        }
        __syncthreads();
        Ap += 16;
        Bp += (size_t)16*N;
    }
    #pragma unroll
    for (int i=0;i<4;i++) {
        int r = rowBase + (ty<<2) + i;
        if (r >= M) continue;
        #pragma unroll
        for (int j=0;j<4;j++) {
            int c = colBase + (tx<<2) + j;
            C[(size_t)r*N + c] = tanhf(acc[i][j] + bias[c]);
        }
    }
}

// ---------------- fused attention for L=64, emits hi/lo ----------------
__global__ __launch_bounds__(256, 2) void attn64_kernel(const float* __restrict__ Q,
                                                        const float* __restrict__ Km,
                                                        const float* __restrict__ V,
                                                        const float* __restrict__ mask,
                                                        unsigned short* __restrict__ Oh,
                                                        unsigned short* __restrict__ Ol)
{
    __shared__ float Ts0[64][65];
    __shared__ float Ts1[64][65];
    int n = blockIdx.x, h = blockIdx.y;
    int tid = threadIdx.x, tx = tid & 15, ty = tid >> 4;
    for (int i = tid; i < 64*64; i += 256) {
        int r = i >> 6, c = i & 63;
        Ts0[r][c] = Q [((size_t)n*64 + r)*DMODEL + h*64 + c];
        Ts1[r][c] = Km[((size_t)n*64 + r)*DMODEL + h*64 + c];
    }
    __syncthreads();
    float s[4][4] = {};
    #pragma unroll 8
    for (int d = 0; d < 64; d++) {
        float qv[4], kv[4];
        #pragma unroll
        for (int i=0;i<4;i++) qv[i]=Ts0[(ty<<2)+i][d];
        #pragma unroll
        for (int j=0;j<4;j++) kv[j]=Ts1[(tx<<2)+j][d];
        #pragma unroll
        for (int i=0;i<4;i++)
            #pragma unroll
            for (int j=0;j<4;j++)
                s[i][j] = fmaf(qv[i], kv[j], s[i][j]);
    }
    float bias[4];
    #pragma unroll
    for (int j=0;j<4;j++)
        bias[j] = (mask[(size_t)n*64 + (tx<<2)+j] > 0.f) ? 0.f : -1e9f;
    #pragma unroll
    for (int i=0;i<4;i++)
        #pragma unroll
        for (int j=0;j<4;j++)
            s[i][j] = s[i][j]*0.125f + bias[j];
    float rmax[4], rsum[4];
    #pragma unroll
    for (int i=0;i<4;i++) {
        float m = fmaxf(fmaxf(s[i][0],s[i][1]), fmaxf(s[i][2],s[i][3]));
        #pragma unroll
        for (int o=8;o;o>>=1) m = fmaxf(m, __shfl_xor_sync(0xffffffffu, m, o));
        rmax[i] = m;
    }
    #pragma unroll
    for (int i=0;i<4;i++) {
        float t = 0.f;
        #pragma unroll
        for (int j=0;j<4;j++) { s[i][j] = expf(s[i][j]-rmax[i]); t += s[i][j]; }
        #pragma unroll
        for (int o=8;o;o>>=1) t += __shfl_xor_sync(0xffffffffu, t, o);
        rsum[i] = 1.f/t;
    }
    __syncthreads();
    #pragma unroll
    for (int i=0;i<4;i++)
        #pragma unroll
        for (int j=0;j<4;j++)
            Ts0[(ty<<2)+i][(tx<<2)+j] = s[i][j]*rsum[i];
    for (int i = tid; i < 64*64; i += 256) {
        int r = i >> 6, c = i & 63;
        Ts1[r][c] = V[((size_t)n*64 + r)*DMODEL + h*64 + c];
    }
    __syncthreads();
    float o[4][4] = {};
    #pragma unroll 8
    for (int kk=0; kk<64; kk++) {
        float pv[4], vv[4];
        #pragma unroll
        for (int i=0;i<4;i++) pv[i]=Ts0[(ty<<2)+i][kk];
        #pragma unroll
        for (int j=0;j<4;j++) vv[j]=Ts1[kk][(tx<<2)+j];
        #pragma unroll
        for (int i=0;i<4;i++)
            #pragma unroll
            for (int j=0;j<4;j++)
                o[i][j] = fmaf(pv[i], vv[j], o[i][j]);
    }
    #pragma unroll
    for (int i=0;i<4;i++)
        #pragma unroll
        for (int j=0;j<4;j++) {
            size_t off = ((size_t)n*64 + (ty<<2)+i)*DMODEL + h*64 + (tx<<2)+j;
            unsigned short hh, ll;
            split2(o[i][j], hh, ll);
            Oh[off] = hh; Ol[off] = ll;
        }
}

// ---------------- attention (generic, user path L=400) ----------------
__global__ void logits_kernel(const float* __restrict__ Q, const float* __restrict__ Kmat,
                              const float* __restrict__ mask, float* __restrict__ lg,
                              int L, int TK)
{
    __shared__ float Qs[64][65];
    __shared__ float Ks[64][65];
    int n = blockIdx.z, h = blockIdx.y;
    int qt = blockIdx.x / TK, kt = blockIdx.x % TK;
    int tid = threadIdx.x;
    for (int i = tid; i < 64*64; i += 256) {
        int r = i >> 6, c = i & 63;
        int lq = qt*64 + r, lk = kt*64 + r;
        Qs[r][c] = (lq < L) ? Q[((size_t)n*L + lq)*DMODEL + h*64 + c] : 0.f;
        Ks[r][c] = (lk < L) ? Kmat[((size_t)n*L + lk)*DMODEL + h*64 + c] : 0.f;
    }
    __syncthreads();
    int tx = tid & 15, ty = tid >> 4;
    float acc[4][4] = {};
    #pragma unroll 8
    for (int d = 0; d < 64; d++) {
        float qv[4], kv[4];
        #pragma unroll
        for (int i=0;i<4;i++) qv[i]=Qs[(ty<<2)+i][d];
        #pragma unroll
        for (int j=0;j<4;j++) kv[j]=Ks[(tx<<2)+j][d];
        #pragma unroll
        for (int i=0;i<4;i++)
            #pragma unroll
            for (int j=0;j<4;j++)
                acc[i][j] = fmaf(qv[i], kv[j], acc[i][j]);
    }
    #pragma unroll
    for (int i=0;i<4;i++) {
        int qr = qt*64 + (ty<<2) + i;
        if (qr >= L) continue;
        #pragma unroll
        for (int j=0;j<4;j++) {
            int kc = kt*64 + (tx<<2) + j;
            if (kc >= L) continue;
            float b = (mask[(size_t)n*L + kc] > 0.f) ? 0.f : -1e9f;
            lg[(((size_t)n*NHEAD + h)*L + qr)*L + kc] = acc[i][j]*0.125f + b;
        }
    }
}

__global__ void softmax_kernel(float* __restrict__ lg, int L)
{
    float* p = lg + (size_t)blockIdx.x * L;
    int tid = threadIdx.x;
    float m = -3.4e38f;
    for (int i=tid;i<L;i+=blockDim.x) m = fmaxf(m, p[i]);
    m = block_max(m);
    float s = 0.f;
    for (int i=tid;i<L;i+=blockDim.x) { float e = expf(p[i]-m); p[i]=e; s+=e; }
    s = block_sum(s);
    float inv = 1.f/s;
    for (int i=tid;i<L;i+=blockDim.x) p[i] *= inv;
}

__global__ void av_kernel(const float* __restrict__ lg, const float* __restrict__ V,
                          unsigned short* __restrict__ Oh, unsigned short* __restrict__ Ol,
                          int L, int TK)
{
    __shared__ float As[64][65];
    __shared__ float Vs[64][65];
    int n = blockIdx.z, h = blockIdx.y, qt = blockIdx.x;
    int tid = threadIdx.x, tx = tid & 15, ty = tid >> 4;
    float acc[4][4] = {};
    for (int kt = 0; kt < TK; kt++) {
        for (int i = tid; i < 64*64; i += 256) {
            int r = i >> 6, c = i & 63;
            int qr = qt*64 + r, kc = kt*64 + c, kr = kt*64 + r;
            As[r][c] = (qr < L && kc < L) ? lg[(((size_t)n*NHEAD + h)*L + qr)*L + kc] : 0.f;
            Vs[r][c] = (kr < L) ? V[((size_t)n*L + kr)*DMODEL + h*64 + c] : 0.f;
        }
        __syncthreads();
        #pragma unroll 8
        for (int kk=0; kk<64; kk++) {
            float av[4], vv[4];
            #pragma unroll
            for (int i=0;i<4;i++) av[i]=As[(ty<<2)+i][kk];
            #pragma unroll
            for (int j=0;j<4;j++) vv[j]=Vs[kk][(tx<<2)+j];
            #pragma unroll
            for (int i=0;i<4;i++)
                #pragma unroll
                for (int j=0;j<4;j++)
                    acc[i][j] = fmaf(av[i], vv[j], acc[i][j]);
        }
        __syncthreads();
    }
    #pragma unroll
    for (int i=0;i<4;i++) {
        int qr = qt*64 + (ty<<2) + i;
        if (qr >= L) continue;
        #pragma unroll
        for (int j=0;j<4;j++) {
            size_t off = ((size_t)n*L + qr)*DMODEL + h*64 + (tx<<2) + j;
            unsigned short hh, ll;
            split2(acc[i][j], hh, ll);
            Oh[off] = hh; Ol[off] = ll;
        }
    }
}

// LN variants
__global__ void ln_split_kernel(const float* __restrict__ x, const float* __restrict__ o,
                                float* __restrict__ out,
                                unsigned short* __restrict__ oh, unsigned short* __restrict__ ol)
{
    __shared__ float buf[DMODEL];
    size_t row = blockIdx.x;
    int tid = threadIdx.x;
    float ls = 0.f;
    for (int i=tid;i<DMODEL;i+=blockDim.x) {
        float v = x[row*DMODEL+i] + o[row*DMODEL+i];
        buf[i] = v; ls += v;
    }
    float mu = block_sum(ls) * (1.f/DMODEL);
    float lv = 0.f;
    for (int i=tid;i<DMODEL;i+=blockDim.x) { float d = buf[i]-mu; lv += d*d; }
    float var = block_sum(lv) * (1.f/DMODEL);
    float inv = rsqrtf(var + 1e-12f);
    for (int i=tid;i<DMODEL;i+=blockDim.x) {
        float v = (buf[i]-mu)*inv;
        out[row*DMODEL+i] = v;
        unsigned short h, l;
        split2(v, h, l);
        oh[row*DMODEL+i] = h; ol[row*DMODEL+i] = l;
    }
}

__global__ void ln_kernel(const float* __restrict__ x, const float* __restrict__ o,
                          float* __restrict__ out)
{
    __shared__ float buf[DMODEL];
    size_t row = blockIdx.x;
    int tid = threadIdx.x;
    float ls = 0.f;
    for (int i=tid;i<DMODEL;i+=blockDim.x) {
        float v = x[row*DMODEL+i] + o[row*DMODEL+i];
        buf[i] = v; ls += v;
    }
    float mu = block_sum(ls) * (1.f/DMODEL);
    float lv = 0.f;
    for (int i=tid;i<DMODEL;i+=blockDim.x) { float d = buf[i]-mu; lv += d*d; }
    float var = block_sum(lv) * (1.f/DMODEL);
    float inv = rsqrtf(var + 1e-12f);
    for (int i=tid;i<DMODEL;i+=blockDim.x) out[row*DMODEL+i] = (buf[i]-mu)*inv;
}

__global__ void gather_cls_kernel(const float* __restrict__ h, float* __restrict__ cls, int L)
{
    int n = blockIdx.x;
    for (int d=threadIdx.x; d<DMODEL; d+=blockDim.x)
        cls[(size_t)n*DMODEL + d] = h[(size_t)n*L*DMODEL + d];
}

__global__ void user0_kernel(const float* __restrict__ cls, const float* __restrict__ qU,
                             float* __restrict__ u0)
{
    int b = blockIdx.x;
    __shared__ float w[HISN];
    int lane = threadIdx.x & 31, wp = threadIdx.x >> 5;
    for (int n = wp; n < HISN; n += (blockDim.x >> 5)) {
        const float* c = cls + (size_t)(b*HISN + n)*DMODEL;
        float acc = 0.f;
        for (int d = lane; d < DMODEL; d += 32) acc += c[d]*qU[d];
        acc = warp_sum(acc);
        if (lane==0) w[n] = acc / sqrtf(768.f);
    }
    __syncthreads();
    if (threadIdx.x == 0) {
        float m = w[0];
        for (int n=1;n<HISN;n++) m = fmaxf(m, w[n]);
        float s = 0.f;
        for (int n=0;n<HISN;n++){ w[n] = expf(w[n]-m); s += w[n]; }
        float inv = 1.f/s;
        for (int n=0;n<HISN;n++) w[n] *= inv;
    }
    __syncthreads();
    for (int d=threadIdx.x; d<DMODEL; d+=blockDim.x) {
        float acc = 0.f;
        for (int n=0;n<HISN;n++) acc += w[n]*cls[(size_t)(b*HISN+n)*DMODEL + d];
        u0[b*DMODEL + d] = acc;
    }
}

// topk also writes ps splits (feeds user-path QKV)
__global__ void topk_kernel(const float* __restrict__ hidden, const float* __restrict__ u0,
                            const float* __restrict__ attn, int* __restrict__ kid,
                            float* __restrict__ ps,
                            unsigned short* __restrict__ psh, unsigned short* __restrict__ psl,
                            float* __restrict__ psm)
{
    int bn = blockIdx.x;
    int b = bn / HISN, n = bn - b*HISN;
    __shared__ float u[DMODEL];
    __shared__ float sc[SEQ];
    __shared__ int sel[KSEL];
    for (int d=threadIdx.x; d<DMODEL; d+=blockDim.x) u[d] = u0[b*DMODEL + d];
    __syncthreads();
    int lane = threadIdx.x & 31, wp = threadIdx.x >> 5;
    for (int s = wp; s < SEQ; s += (blockDim.x >> 5)) {
        const float* hr = hidden + (size_t)(bn*SEQ + s)*DMODEL;
        float acc = 0.f;
        for (int d = lane; d < DMODEL; d += 32) acc += hr[d]*u[d];
        acc = warp_sum(acc);
        if (lane==0)
            sc[s] = (attn[(size_t)bn*SEQ + s] > 0.f) ? acc / sqrtf(768.f) : -1e9f;
    }
    __syncthreads();
    if (threadIdx.x == 0) {
        bool used[SEQ];
        for (int s=0;s<SEQ;s++) used[s]=false;
        for (int kk=0; kk<KSEL; kk++) {
            float best = -3.4e38f; int bi = 0;
            for (int s=0;s<SEQ;s++)
                if (!used[s] && sc[s] > best) { best = sc[s]; bi = s; }
            used[bi] = true; sel[kk] = bi;
            kid[(size_t)bn*KSEL + kk] = bi;
        }
    }
    __syncthreads();
    for (int kk=0; kk<KSEL; kk++) {
        int s = sel[kk];
        size_t dst = (size_t)(b*LUSR + n*KSEL + kk);
        for (int d=threadIdx.x; d<DMODEL; d+=blockDim.x) {
            float v = hidden[(size_t)(bn*SEQ + s)*DMODEL + d];
            ps[dst*DMODEL + d] = v;
            unsigned short hh, ll;
            split2(v, hh, ll);
            psh[dst*DMODEL + d] = hh; psl[dst*DMODEL + d] = ll;
        }
        if (threadIdx.x == 0) psm[dst] = attn[(size_t)bn*SEQ + s];
    }
}

// final log-softmax + kid emit, merged
__global__ void final_kernel(const float* __restrict__ cddr, const float* __restrict__ ur,
                             const int* __restrict__ kid, float* __restrict__ out)
{
    if (blockIdx.x >= BB) {
        int i = (blockIdx.x - BB)*256 + threadIdx.x;
        if (i < BB*HISN*KSEL) out[NCDD + i] = (float)kid[i];
        return;
    }
    int b = blockIdx.x;
    __shared__ float s[CDDN];
    int lane = threadIdx.x & 31, wp = threadIdx.x >> 5;
    for (int c = wp; c < CDDN; c += (blockDim.x >> 5)) {
        const float* a = cddr + (size_t)(b*CDDN + c)*DMODEL;
        const float* uu = ur + (size_t)b*DMODEL;
        float acc = 0.f;
        for (int d = lane; d < DMODEL; d += 32) acc += a[d]*uu[d];
        acc = warp_sum(acc);
        if (lane==0) s[c] = acc / sqrtf(768.f);
    }
    __syncthreads();
    if (threadIdx.x == 0) {
        float m = s[0];
        for (int c=1;c<CDDN;c++) m = fmaxf(m, s[c]);
        float sum = 0.f;
        for (int c=0;c<CDDN;c++) sum += expf(s[c]-m);
        float lse = m + logf(sum);
        for (int c=0;c<CDDN;c++) out[b*CDDN + c] = s[c] - lse;
    }
}

// ---------------- host orchestration ----------------
struct DevPtrs {
    float *x,*q,*k,*v,*h,*lg,*pre,*atC,*atH,*cls,*cddr,*u0,*ur,*psm;
    int* kid;
    unsigned short *whi,*wlo,*xh,*xl,*oh,*ol,*hh,*hl,*fh,*fl;
};
static DevPtrs P;

static void run_transformer(int N, int L, const unsigned short* wh, const unsigned short* wl,
                            const float* attnMask)
{
    int R = N*L;  // multiple of 128
    mma_gemm_qkv<<<dim3(DMODEL/128, R/128, 3), 256, MMA_SMEM>>>(P.xh, P.xl, wh, wl, P.q, P.k, P.v, R);
    if (L == 64) {
        attn64_kernel<<<dim3(N, NHEAD),256>>>(P.q, P.k, P.v, attnMask, P.oh, P.ol);
    } else {
        int T = (L+63)/64;
        logits_kernel<<<dim3(T*T, NHEAD, N),256>>>(P.q, P.k, attnMask, P.lg, L, T);
        softmax_kernel<<<(unsigned)(N*NHEAD*L),128>>>(P.lg, L);
        av_kernel<<<dim3(T, NHEAD, N),256>>>(P.lg, P.v, P.oh, P.ol, L, T);
    }
    mma_gemm_f<<<dim3(DMODEL/128, R/128), 256, MMA_SMEM>>>(P.oh, P.ol, wh+WOFF_O, wl+WOFF_O, P.q, R, DMODEL, DMODEL);
    ln_split_kernel<<<R,256>>>(P.x, P.q, P.h, P.hh, P.hl);
    mma_gemm_gelu<<<dim3(FFDIM/128, R/128), 256, MMA_SMEM>>>(P.hh, P.hl, wh+WOFF_1, wl+WOFF_1, P.fh, P.fl, R, FFDIM, DMODEL);
    mma_gemm_f<<<dim3(DMODEL/128, R/128), 256, MMA_SMEM>>>(P.fh, P.fl, wh+WOFF_2, wl+WOFF_2, P.q, R, DMODEL, FFDIM);
    ln_kernel<<<R,256>>>(P.h, P.q, P.h);
}

extern "C" void kernel_launch(void* const* d_in, const int* in_sizes, int n_in,
                              void* d_out, int out_size)
{
    const int*   cdd_sub  = (const int*)d_in[0];
    const int*   his_sub  = (const int*)d_in[1];
    const int*   cdd_enc  = (const int*)d_in[2];
    const int*   his_enc  = (const int*)d_in[3];
    const float* cdd_mask = (const float*)d_in[4];
    const float* his_mask = (const float*)d_in[5];
    const float* cdd_am   = (const float*)d_in[6];
    const float* his_am   = (const float*)d_in[7];
    const float* emb      = (const float*)d_in[8];
    const float* qU    = (const float*)d_in[21];
    const float* projW = (const float*)d_in[22];
    const float* projb = (const float*)d_in[23];
    float* out = (float*)d_out;

    cudaGetSymbolAddress((void**)&P.x,   g_x);
    cudaGetSymbolAddress((void**)&P.q,   g_q);
    cudaGetSymbolAddress((void**)&P.k,   g_k);
    cudaGetSymbolAddress((void**)&P.v,   g_v);
    cudaGetSymbolAddress((void**)&P.h,   g_h);
    cudaGetSymbolAddress((void**)&P.lg,  g_lg);
    cudaGetSymbolAddress((void**)&P.pre, g_pre);
    cudaGetSymbolAddress((void**)&P.atC, g_atC);
    cudaGetSymbolAddress((void**)&P.atH, g_atH);
    cudaGetSymbolAddress((void**)&P.cls, g_cls);
    cudaGetSymbolAddress((void**)&P.cddr,g_cddr);
    cudaGetSymbolAddress((void**)&P.u0,  g_u0);
    cudaGetSymbolAddress((void**)&P.ur,  g_ur);
    cudaGetSymbolAddress((void**)&P.psm, g_psm);
    cudaGetSymbolAddress((void**)&P.kid, g_kid);
    cudaGetSymbolAddress((void**)&P.whi, g_whi);
    cudaGetSymbolAddress((void**)&P.wlo, g_wlo);
    cudaGetSymbolAddress((void**)&P.xh,  g_xh);
    cudaGetSymbolAddress((void**)&P.xl,  g_xl);
    cudaGetSymbolAddress((void**)&P.oh,  g_oh);
    cudaGetSymbolAddress((void**)&P.ol,  g_ol);
    cudaGetSymbolAddress((void**)&P.hh,  g_hh);
    cudaGetSymbolAddress((void**)&P.hl,  g_hl);
    cudaGetSymbolAddress((void**)&P.fh,  g_fh);
    cudaGetSymbolAddress((void**)&P.fl,  g_fl);

    cudaFuncSetAttribute(mma_gemm_f,    cudaFuncAttributeMaxDynamicSharedMemorySize, MMA_SMEM);
    cudaFuncSetAttribute(mma_gemm_gelu, cudaFuncAttributeMaxDynamicSharedMemorySize, MMA_SMEM);
    cudaFuncSetAttribute(mma_gemm_qkv,  cudaFuncAttributeMaxDynamicSharedMemorySize, MMA_SMEM);

    // ---- batched weight prep ----
    PrepPtrs pp;
    for (int i = 0; i < 6; i++) { pp.p[i] = (const float*)d_in[9+i]; pp.p[6+i] = (const float*)d_in[15+i]; }
    prep_all<<<dim3(2304, 12), dim3(32,8)>>>(pp, P.whi, P.wlo);

    // ---- candidate path (BERT weights) ----
    prefix_kernel<<<NCDD,256>>>(cdd_sub, cdd_mask, cdd_am, P.pre, P.atC);
    pool_kernel<<<dim3(NCDD, DMODEL/128),128>>>(P.pre, cdd_enc, emb, P.x, P.xh, P.xl);
    run_transformer(NCDD, SEQ, P.whi, P.wlo, P.atC);
    sgemm_proj<<<dim3(DMODEL/64, 1),256>>>(P.h, (size_t)SEQ*DMODEL, projW, P.cddr, NCDD, DMODEL, DMODEL, projb);

    // ---- history path (encN weights) ----
    prefix_kernel<<<NHIS,256>>>(his_sub, his_mask, his_am, P.pre, P.atH);
    pool_kernel<<<dim3(NHIS, DMODEL/128),128>>>(P.pre, his_enc, emb, P.x, P.xh, P.xl);
    run_transformer(NHIS, SEQ, P.whi+WSET, P.wlo+WSET, P.atH);
    gather_cls_kernel<<<NHIS,256>>>(P.h, P.cls, SEQ);
    user0_kernel<<<BB,256>>>(P.cls, qU, P.u0);
    topk_kernel<<<BB*HISN,256>>>(P.h, P.u0, P.atH, P.kid, P.x, P.xh, P.xl, P.psm);

    // ---- user path over selected terms (BERT weights) ----
    run_transformer(BB, LUSR, P.whi, P.wlo, P.psm);
    sgemm_proj<<<dim3(DMODEL/64, 1),256>>>(P.h, (size_t)LUSR*DMODEL, projW, P.ur, BB, DMODEL, DMODEL, projb);

    // ---- outputs ----
    final_kernel<<<BB + (BB*HISN*KSEL + 255)/256, 256>>>(P.cddr, P.ur, P.kid, out);
}

// round 7
// speedup vs baseline: 2.9427x; 1.0048x over previous
#include <cuda_runtime.h>
#include <cuda_bf16.h>
#include <math.h>
#include <stdint.h>

#define BB     8
#define CDDN   5
#define HISN   50
#define SEQ    64
#define DMODEL 768
#define NHEAD  12
#define FFDIM  3072
#define KSEL   8

#define NCDD   (BB*CDDN)     // 40
#define NHIS   (BB*HISN)     // 400
#define LUSR   (HISN*KSEL)   // 400
#define ROWS_MAX (NHIS*SEQ)  // 25600

#define WOFF_Q  0
#define WOFF_K  589824
#define WOFF_V  1179648
#define WOFF_O  1769472
#define WOFF_1  2359296
#define WOFF_2  4718592
#define WSET    7077888

// ---------------- scratch ----------------
__device__ float g_x [ (size_t)ROWS_MAX*DMODEL ];
__device__ float g_q [ (size_t)ROWS_MAX*DMODEL ];
__device__ float g_k [ (size_t)ROWS_MAX*DMODEL ];
__device__ float g_v [ (size_t)ROWS_MAX*DMODEL ];
__device__ float g_h [ (size_t)ROWS_MAX*DMODEL ];
__device__ float g_lg[ (size_t)BB*NHEAD*LUSR*LUSR ];
__device__ float g_pre[(size_t)NHIS*SEQ*SEQ ];
__device__ float g_atC[ NCDD*SEQ ];
__device__ float g_atH[ NHIS*SEQ ];
__device__ float g_cls[ (size_t)NHIS*DMODEL ];
__device__ float g_cddr[(size_t)NCDD*DMODEL ];
__device__ float g_u0 [ BB*DMODEL ];
__device__ float g_ur [ BB*DMODEL ];
__device__ float g_psm[ BB*LUSR ];
__device__ int   g_kid[ BB*HISN*KSEL ];
// split-bf16 weights [N,K], two sets
__device__ unsigned short g_whi[ (size_t)2*WSET ];
__device__ unsigned short g_wlo[ (size_t)2*WSET ];
// split-bf16 activations by role
__device__ unsigned short g_xh[ (size_t)ROWS_MAX*DMODEL ];
__device__ unsigned short g_xl[ (size_t)ROWS_MAX*DMODEL ];
__device__ unsigned short g_oh[ (size_t)ROWS_MAX*DMODEL ];
__device__ unsigned short g_ol[ (size_t)ROWS_MAX*DMODEL ];
__device__ unsigned short g_hh[ (size_t)ROWS_MAX*DMODEL ];
__device__ unsigned short g_hl[ (size_t)ROWS_MAX*DMODEL ];
__device__ unsigned short g_fh[ (size_t)ROWS_MAX*FFDIM ];
__device__ unsigned short g_fl[ (size_t)ROWS_MAX*FFDIM ];

// ---------------- low-level helpers ----------------
__device__ __forceinline__ void cp16(uint32_t s, const void* g){
    asm volatile("cp.async.ca.shared.global [%0], [%1], 16;\n" :: "r"(s), "l"(g));
}
__device__ __forceinline__ void cp_commit(){ asm volatile("cp.async.commit_group;\n"); }
template<int N>
__device__ __forceinline__ void cp_wait(){ asm volatile("cp.async.wait_group %0;\n" :: "n"(N)); }

__device__ __forceinline__ uint32_t smem_u32(const void* p) {
    uint32_t a;
    asm("{ .reg .u64 t; cvta.to.shared.u64 t, %1; cvt.u32.u64 %0, t; }" : "=r"(a) : "l"(p));
    return a;
}
__device__ __forceinline__ void ldsm_x4(uint32_t* r, uint32_t addr){
    asm volatile("ldmatrix.sync.aligned.m8n8.x4.shared.b16 {%0,%1,%2,%3}, [%4];"
        : "=r"(r[0]),"=r"(r[1]),"=r"(r[2]),"=r"(r[3]) : "r"(addr));
}
__device__ __forceinline__ void mma_bf16(float* c, const uint32_t* a, const uint32_t* b){
    asm volatile("mma.sync.aligned.m16n8k16.row.col.f32.bf16.bf16.f32 "
        "{%0,%1,%2,%3}, {%4,%5,%6,%7}, {%8,%9}, {%0,%1,%2,%3};"
        : "+f"(c[0]),"+f"(c[1]),"+f"(c[2]),"+f"(c[3])
        : "r"(a[0]),"r"(a[1]),"r"(a[2]),"r"(a[3]), "r"(b[0]),"r"(b[1]));
}
__device__ __forceinline__ void split2(float v, unsigned short& h, unsigned short& l){
    __nv_bfloat16 bh = __float2bfloat16(v);
    __nv_bfloat16 bl = __float2bfloat16(v - __bfloat162float(bh));
    h = __bfloat16_as_ushort(bh);
    l = __bfloat16_as_ushort(bl);
}

// ---------------- reductions ----------------
__device__ __forceinline__ float warp_sum(float v){
    #pragma unroll
    for(int o=16;o;o>>=1) v += __shfl_xor_sync(0xffffffffu, v, o);
    return v;
}
__device__ __forceinline__ float warp_max(float v){
    #pragma unroll
    for(int o=16;o;o>>=1) v = fmaxf(v, __shfl_xor_sync(0xffffffffu, v, o));
    return v;
}
__device__ float block_sum(float v){
    __shared__ float red[33];
    int lane=threadIdx.x&31, w=threadIdx.x>>5, nw=blockDim.x>>5;
    v = warp_sum(v);
    __syncthreads();
    if(lane==0) red[w]=v;
    __syncthreads();
    if(threadIdx.x==0){ float t=0.f; for(int i=0;i<nw;i++) t+=red[i]; red[32]=t; }
    __syncthreads();
    return red[32];
}
__device__ float block_max(float v){
    __shared__ float red[33];
    int lane=threadIdx.x&31, w=threadIdx.x>>5, nw=blockDim.x>>5;
    v = warp_max(v);
    __syncthreads();
    if(lane==0) red[w]=v;
    __syncthreads();
    if(threadIdx.x==0){ float t=red[0]; for(int i=1;i<nw;i++) t=fmaxf(t,red[i]); red[32]=t; }
    __syncthreads();
    return red[32];
}

// ---------------- batched weight prep: [K,N] fp32 -> [N,K] bf16 hi/lo ----------------
struct PrepPtrs { const float* p[12]; };
__constant__ size_t c_woffs[6] = { WOFF_Q, WOFF_K, WOFF_V, WOFF_O, WOFF_1, WOFF_2 };

__global__ void prep_all(PrepPtrs ptrs, unsigned short* __restrict__ Th,
                         unsigned short* __restrict__ Tl)
{
    int w = blockIdx.y;
    int wi = w % 6;
    int K = (wi==5) ? FFDIM : DMODEL;
    int N = (wi==4) ? FFDIM : DMODEL;
    int ntx = N >> 5;
    int tiles = (K >> 5) * ntx;
    int t = blockIdx.x;
    if (t >= tiles) return;
    int nb = (t % ntx) << 5, kb = (t / ntx) << 5;
    const float* W = ptrs.p[w];
    size_t base = c_woffs[wi] + (size_t)(w/6)*WSET;

    __shared__ float tbuf[32][33];
    int x = threadIdx.x, y = threadIdx.y;
    for (int i=y;i<32;i+=8)
        tbuf[i][x] = W[(size_t)(kb+i)*N + nb + x];
    __syncthreads();
    for (int i=y;i<32;i+=8) {
        float v = tbuf[x][i];
        unsigned short h, l;
        split2(v, h, l);
        size_t dst = base + (size_t)(nb+i)*K + kb + x;
        Th[dst] = h;
        Tl[dst] = l;
    }
}

// ---------------- mma.sync split-bf16 GEMM ----------------
// C = A@B^T. A: bf16 hi/lo [M,K]; B: bf16 hi/lo [N,K]. M,N,K % 128/128/32 == 0.
// EPI 0: fp32 C.  EPI 1: gelu -> bf16 hi/lo (Ch/Cl).
#define APAD 40
#define ARR_B  (128*APAD*2)
#define STG_B  (4*ARR_B)
#define MMA_SMEM (2*STG_B)      // 81920

template<int EPI>
__device__ __forceinline__ void mma_body(const unsigned short* __restrict__ Ah,
                                         const unsigned short* __restrict__ Al,
                                         const unsigned short* __restrict__ Bh,
                                         const unsigned short* __restrict__ Bl,
                                         float* __restrict__ C,
                                         unsigned short* __restrict__ Ch,
                                         unsigned short* __restrict__ Cl,
                                         int M, int N, int K)
{
    extern __shared__ char sm[];
    const uint32_t sbase = smem_u32(sm);
    const int tid = threadIdx.x, lane = tid & 31, wid = tid >> 5;
    const int wm = wid >> 2, wn = wid & 3;
    const int rowBlk = blockIdx.y << 7, colBlk = blockIdx.x << 7;

    int r0 = tid >> 2,        s0 = (tid & 3) << 3;
    int r1 = (tid+256) >> 2,  s1 = ((tid+256) & 3) << 3;
    const unsigned short* gA[2] = {Ah, Al};
    const unsigned short* gB[2] = {Bh, Bl};

    const int nc = K >> 5;
    #pragma unroll
    for (int p=0;p<2;p++) {
        cp16(sbase + p*ARR_B + (uint32_t)(r0*APAD + s0)*2, gA[p] + (size_t)(rowBlk+r0)*K + s0);
        cp16(sbase + p*ARR_B + (uint32_t)(r1*APAD + s1)*2, gA[p] + (size_t)(rowBlk+r1)*K + s1);
        cp16(sbase + (2+p)*ARR_B + (uint32_t)(r0*APAD + s0)*2, gB[p] + (size_t)(colBlk+r0)*K + s0);
        cp16(sbase + (2+p)*ARR_B + (uint32_t)(r1*APAD + s1)*2, gB[p] + (size_t)(colBlk+r1)*K + s1);
    }
    cp_commit();

    const uint32_t aoff = (uint32_t)((wm*64 + (lane & 15))*APAD + 8*(lane >> 4)) * 2;
    const uint32_t boff = (uint32_t)((wn*32 + (lane & 7) + 8*(lane >> 4))*APAD + 8*((lane >> 3) & 1)) * 2;

    float acc[4][4][4] = {};

    for (int c = 0; c < nc; c++) {
        const bool has = (c+1 < nc);
        if (has) {
            int kb = (c+1) << 5;
            uint32_t st = ((c+1) & 1) * STG_B;
            #pragma unroll
            for (int p=0;p<2;p++) {
                cp16(sbase + st + p*ARR_B + (uint32_t)(r0*APAD + s0)*2, gA[p] + (size_t)(rowBlk+r0)*K + kb + s0);
                cp16(sbase + st + p*ARR_B + (uint32_t)(r1*APAD + s1)*2, gA[p] + (size_t)(rowBlk+r1)*K + kb + s1);
                cp16(sbase + st + (2+p)*ARR_B + (uint32_t)(r0*APAD + s0)*2, gB[p] + (size_t)(colBlk+r0)*K + kb + s0);
                cp16(sbase + st + (2+p)*ARR_B + (uint32_t)(r1*APAD + s1)*2, gB[p] + (size_t)(colBlk+r1)*K + kb + s1);
            }
            cp_commit();
            cp_wait<1>();
        } else {
            cp_wait<0>();
        }
        __syncthreads();

        uint32_t st = (c & 1) * STG_B;
        uint32_t aH = sbase + st + aoff;
        uint32_t aL = aH + ARR_B;
        uint32_t bH = sbase + st + 2*ARR_B + boff;
        uint32_t bL = bH + ARR_B;

        #pragma unroll
        for (int ks = 0; ks < 2; ks++) {
            uint32_t ko = (uint32_t)(ks*16*2);
            uint32_t ahf[4][4], alf[4][4], bhf[2][4], blf[2][4];
            // front-load ah, bh, bl fragments
            #pragma unroll
            for (int mt=0;mt<4;mt++) ldsm_x4(ahf[mt], aH + ko + (uint32_t)(mt*16*APAD*2));
            #pragma unroll
            for (int np=0;np<2;np++) ldsm_x4(bhf[np], bH + ko + (uint32_t)(np*16*APAD*2));
            #pragma unroll
            for (int np=0;np<2;np++) ldsm_x4(blf[np], bL + ko + (uint32_t)(np*16*APAD*2));
            // group1: ah x bh (ldsm of al overlaps this group's tail)
            #pragma unroll
            for (int mt=0;mt<4;mt++)
                #pragma unroll
                for (int nt=0;nt<4;nt++)
                    mma_bf16(acc[mt][nt], ahf[mt], &bhf[nt>>1][(nt&1)*2]);
            #pragma unroll
            for (int mt=0;mt<4;mt++) ldsm_x4(alf[mt], aL + ko + (uint32_t)(mt*16*APAD*2));
            // group2: ah x bl — no pending ldsm dependency, dense issue
            #pragma unroll
            for (int mt=0;mt<4;mt++)
                #pragma unroll
                for (int nt=0;nt<4;nt++)
                    mma_bf16(acc[mt][nt], ahf[mt], &blf[nt>>1][(nt&1)*2]);
            // group3: al x bh — dense issue
            #pragma unroll
            for (int mt=0;mt<4;mt++)
                #pragma unroll
                for (int nt=0;nt<4;nt++)
                    mma_bf16(acc[mt][nt], alf[mt], &bhf[nt>>1][(nt&1)*2]);
        }
        __syncthreads();
    }

    #pragma unroll
    for (int mt=0;mt<4;mt++) {
        int row = rowBlk + wm*64 + mt*16 + (lane >> 2);
        #pragma unroll
        for (int nt=0;nt<4;nt++) {
            int col = colBlk + wn*32 + nt*8 + (lane & 3)*2;
            float v[4] = {acc[mt][nt][0], acc[mt][nt][1], acc[mt][nt][2], acc[mt][nt][3]};
            if (EPI == 0) {
                *(float2*)(C + (size_t)row*N + col)     = make_float2(v[0], v[1]);
                *(float2*)(C + (size_t)(row+8)*N + col) = make_float2(v[2], v[3]);
            } else {
                #pragma unroll
                for (int j=0;j<4;j++) {
                    float t = v[j];
                    v[j] = 0.5f*t*(1.f + tanhf(0.7978845608028654f*(t + 0.044715f*t*t*t)));
                }
                unsigned short h0,l0,h1,l1;
                split2(v[0], h0, l0); split2(v[1], h1, l1);
                *(uint32_t*)(Ch + (size_t)row*N + col) = (uint32_t)h0 | ((uint32_t)h1<<16);
                *(uint32_t*)(Cl + (size_t)row*N + col) = (uint32_t)l0 | ((uint32_t)l1<<16);
                split2(v[2], h0, l0); split2(v[3], h1, l1);
                *(uint32_t*)(Ch + (size_t)(row+8)*N + col) = (uint32_t)h0 | ((uint32_t)h1<<16);
                *(uint32_t*)(Cl + (size_t)(row+8)*N + col) = (uint32_t)l0 | ((uint32_t)l1<<16);
            }
        }
    }
}

__global__ __launch_bounds__(256, 2) void mma_gemm_f(const unsigned short* __restrict__ Ah,
                                                     const unsigned short* __restrict__ Al,
                                                     const unsigned short* __restrict__ Bh,
                                                     const unsigned short* __restrict__ Bl,
                                                     float* __restrict__ C,
                                                     int M, int N, int K)
{
    mma_body<0>(Ah, Al, Bh, Bl, C, nullptr, nullptr, M, N, K);
}

__global__ __launch_bounds__(256, 2) void mma_gemm_gelu(const unsigned short* __restrict__ Ah,
                                                        const unsigned short* __restrict__ Al,
                                                        const unsigned short* __restrict__ Bh,
                                                        const unsigned short* __restrict__ Bl,
                                                        unsigned short* __restrict__ Ch,
                                                        unsigned short* __restrict__ Cl,
                                                        int M, int N, int K)
{
    mma_body<1>(Ah, Al, Bh, Bl, nullptr, Ch, Cl, M, N, K);
}

__global__ __launch_bounds__(256, 2) void mma_gemm_qkv(const unsigned short* __restrict__ Ah,
                                                       const unsigned short* __restrict__ Al,
                                                       const unsigned short* __restrict__ Wh,
                                                       const unsigned short* __restrict__ Wl,
                                                       float* __restrict__ Cq,
                                                       float* __restrict__ Ck,
                                                       float* __restrict__ Cv,
                                                       int M)
{
    const unsigned short* bh = Wh + (size_t)blockIdx.z*589824;
    const unsigned short* bl = Wl + (size_t)blockIdx.z*589824;
    float* C = (blockIdx.z==0) ? Cq : (blockIdx.z==1) ? Ck : Cv;
    mma_body<0>(Ah, Al, bh, bl, C, nullptr, nullptr, M, DMODEL, DMODEL);
}

// ---------------- prefix build + pooled attention mask ----------------
__global__ void prefix_kernel(const int* __restrict__ sub, const float* __restrict__ mask,
                              const float* __restrict__ amask,
                              float* __restrict__ prefix, float* __restrict__ attn)
{
    __shared__ float P[SEQ*SEQ];
    int bn = blockIdx.x;
    for (int i = threadIdx.x; i < SEQ*SEQ; i += blockDim.x) P[i] = 0.f;
    __syncthreads();
    const int* si = sub + (size_t)bn*SEQ*2;
    for (int s = threadIdx.x; s < SEQ; s += blockDim.x) {
        int i = si[2*s+0], j = si[2*s+1];
        P[i*SEQ + j] = 1.f;
    }
    __syncthreads();
    float m = mask[bn];
    int lane = threadIdx.x & 31, warp = threadIdx.x >> 5;
    for (int i = warp; i < SEQ; i += (blockDim.x >> 5)) {
        float v0 = P[i*SEQ + lane]      * m;
        float v1 = P[i*SEQ + lane + 32] * m;
        float rs = v0 + v1;
        float ad = v0 * amask[bn*SEQ + lane] + v1 * amask[bn*SEQ + lane + 32];
        #pragma unroll
        for (int o=16;o;o>>=1){ rs += __shfl_xor_sync(0xffffffffu,rs,o); ad += __shfl_xor_sync(0xffffffffu,ad,o); }
        float denom = fmaxf(rs, 1e-12f);
        prefix[(size_t)bn*SEQ*SEQ + i*SEQ + lane]      = v0/denom;
        prefix[(size_t)bn*SEQ*SEQ + i*SEQ + lane + 32] = v1/denom;
        if (lane==0) attn[bn*SEQ + i] = ad/denom;
    }
}

// ---------------- embedding gather + pooling, emits fp32 + hi/lo ----------------
__global__ void pool_kernel(const float* __restrict__ prefix, const int* __restrict__ enc,
                            const float* __restrict__ emb, float* __restrict__ x,
                            unsigned short* __restrict__ xh, unsigned short* __restrict__ xl)
{
    __shared__ float P[SEQ*SEQ];
    __shared__ int idx[SEQ];
    int bn = blockIdx.x;
    int d  = blockIdx.y*128 + threadIdx.x;
    for (int i = threadIdx.x; i < SEQ*SEQ; i += blockDim.x)
        P[i] = prefix[(size_t)bn*SEQ*SEQ + i];
    if (threadIdx.x < SEQ) idx[threadIdx.x] = enc[(size_t)bn*SEQ + threadIdx.x];
    __syncthreads();
    float acc[SEQ];
    #pragma unroll
    for (int i=0;i<SEQ;i++) acc[i]=0.f;
    for (int j=0;j<SEQ;j++) {
        float e = emb[(size_t)idx[j]*DMODEL + d];
        #pragma unroll
        for (int i=0;i<SEQ;i++) acc[i] = fmaf(P[i*SEQ+j], e, acc[i]);
    }
    for (int i=0;i<SEQ;i++) {
        size_t o = ((size_t)bn*SEQ + i)*DMODEL + d;
        x[o] = acc[i];
        unsigned short h, l;
        split2(acc[i], h, l);
        xh[o] = h; xl[o] = l;
    }
}

// ---------------- strided proj: C=tanh(A@B+bias) ----------------
__global__ void sgemm_proj(const float* __restrict__ A, size_t lda,
                           const float* __restrict__ B,
                           float* __restrict__ C, int M, int N, int Kd,
                           const float* __restrict__ bias)
{
    __shared__ float As[16][64];
    __shared__ float Bs[16][68];
    int tid = threadIdx.x;
    int rowBase = blockIdx.y << 6, colBase = blockIdx.x << 6;
    int tx = tid & 15, ty = tid >> 4;
    int am = tid >> 2, ak = (tid & 3) << 2;
    int bk = tid >> 4, bn = (tid & 15) << 2;
    bool aok = (rowBase + am) < M;
    const float* Ap = A + (size_t)(rowBase + am)*lda + ak;
    const float* Bp = B + (size_t)bk*N + colBase + bn;
    float acc[4][4] = {};
    for (int k0 = 0; k0 < Kd; k0 += 16) {
        float4 a4 = aok ? *(const float4*)Ap : make_float4(0.f,0.f,0.f,0.f);
        As[ak+0][am]=a4.x; As[ak+1][am]=a4.y; As[ak+2][am]=a4.z; As[ak+3][am]=a4.w;
        *(float4*)&Bs[bk][bn] = *(const float4*)Bp;
        __syncthreads();
        #pragma unroll
        for (int kk=0; kk<16; kk++) {
            float av[4], bv[4];
            #pragma unroll
            for (int i=0;i<4;i++) av[i]=As[kk][(ty<<2)+i];
            #pragma unroll
            for (int j=0;j<4;j++) bv[j]=Bs[kk][(tx<<2)+j];
            #pragma unroll
            for (int i=0;i<4;i++)
                #pragma unroll
                for (int j=0;j<4;j++)
                    acc[i][j] = fmaf(av[i], bv[j], acc[i][j]);
        }
        __syncthreads();
        Ap += 16;
        Bp += (size_t)16*N;
    }
    #pragma unroll
    for (int i=0;i<4;i++) {
        int r = rowBase + (ty<<2) + i;
        if (r >= M) continue;
        #pragma unroll
        for (int j=0;j<4;j++) {
            int c = colBase + (tx<<2) + j;
            C[(size_t)r*N + c] = tanhf(acc[i][j] + bias[c]);
        }
    }
}

// ---------------- fused attention for L=64, emits hi/lo ----------------
__global__ __launch_bounds__(256, 2) void attn64_kernel(const float* __restrict__ Q,
                                                        const float* __restrict__ Km,
                                                        const float* __restrict__ V,
                                                        const float* __restrict__ mask,
                                                        unsigned short* __restrict__ Oh,
                                                        unsigned short* __restrict__ Ol)
{
    __shared__ float Ts0[64][65];
    __shared__ float Ts1[64][65];
    int n = blockIdx.x, h = blockIdx.y;
    int tid = threadIdx.x, tx = tid & 15, ty = tid >> 4;
    for (int i = tid; i < 64*64; i += 256) {
        int r = i >> 6, c = i & 63;
        Ts0[r][c] = Q [((size_t)n*64 + r)*DMODEL + h*64 + c];
        Ts1[r][c] = Km[((size_t)n*64 + r)*DMODEL + h*64 + c];
    }
    __syncthreads();
    float s[4][4] = {};
    #pragma unroll 8
    for (int d = 0; d < 64; d++) {
        float qv[4], kv[4];
        #pragma unroll
        for (int i=0;i<4;i++) qv[i]=Ts0[(ty<<2)+i][d];
        #pragma unroll
        for (int j=0;j<4;j++) kv[j]=Ts1[(tx<<2)+j][d];
        #pragma unroll
        for (int i=0;i<4;i++)
            #pragma unroll
            for (int j=0;j<4;j++)
                s[i][j] = fmaf(qv[i], kv[j], s[i][j]);
    }
    float bias[4];
    #pragma unroll
    for (int j=0;j<4;j++)
        bias[j] = (mask[(size_t)n*64 + (tx<<2)+j] > 0.f) ? 0.f : -1e9f;
    #pragma unroll
    for (int i=0;i<4;i++)
        #pragma unroll
        for (int j=0;j<4;j++)
            s[i][j] = s[i][j]*0.125f + bias[j];
    float rmax[4], rsum[4];
    #pragma unroll
    for (int i=0;i<4;i++) {
        float m = fmaxf(fmaxf(s[i][0],s[i][1]), fmaxf(s[i][2],s[i][3]));
        #pragma unroll
        for (int o=8;o;o>>=1) m = fmaxf(m, __shfl_xor_sync(0xffffffffu, m, o));
        rmax[i] = m;
    }
    #pragma unroll
    for (int i=0;i<4;i++) {
        float t = 0.f;
        #pragma unroll
        for (int j=0;j<4;j++) { s[i][j] = expf(s[i][j]-rmax[i]); t += s[i][j]; }
        #pragma unroll
        for (int o=8;o;o>>=1) t += __shfl_xor_sync(0xffffffffu, t, o);
        rsum[i] = 1.f/t;
    }
    __syncthreads();
    #pragma unroll
    for (int i=0;i<4;i++)
        #pragma unroll
        for (int j=0;j<4;j++)
            Ts0[(ty<<2)+i][(tx<<2)+j] = s[i][j]*rsum[i];
    for (int i = tid; i < 64*64; i += 256) {
        int r = i >> 6, c = i & 63;
        Ts1[r][c] = V[((size_t)n*64 + r)*DMODEL + h*64 + c];
    }
    __syncthreads();
    float o[4][4] = {};
    #pragma unroll 8
    for (int kk=0; kk<64; kk++) {
        float pv[4], vv[4];
        #pragma unroll
        for (int i=0;i<4;i++) pv[i]=Ts0[(ty<<2)+i][kk];
        #pragma unroll
        for (int j=0;j<4;j++) vv[j]=Ts1[kk][(tx<<2)+j];
        #pragma unroll
        for (int i=0;i<4;i++)
            #pragma unroll
            for (int j=0;j<4;j++)
                o[i][j] = fmaf(pv[i], vv[j], o[i][j]);
    }
    #pragma unroll
    for (int i=0;i<4;i++)
        #pragma unroll
        for (int j=0;j<4;j++) {
            size_t off = ((size_t)n*64 + (ty<<2)+i)*DMODEL + h*64 + (tx<<2)+j;
            unsigned short hh, ll;
            split2(o[i][j], hh, ll);
            Oh[off] = hh; Ol[off] = ll;
        }
}

// ---------------- attention (generic, user path L=400) ----------------
__global__ void logits_kernel(const float* __restrict__ Q, const float* __restrict__ Kmat,
                              const float* __restrict__ mask, float* __restrict__ lg,
                              int L, int TK)
{
    __shared__ float Qs[64][65];
    __shared__ float Ks[64][65];
    int n = blockIdx.z, h = blockIdx.y;
    int qt = blockIdx.x / TK, kt = blockIdx.x % TK;
    int tid = threadIdx.x;
    for (int i = tid; i < 64*64; i += 256) {
        int r = i >> 6, c = i & 63;
        int lq = qt*64 + r, lk = kt*64 + r;
        Qs[r][c] = (lq < L) ? Q[((size_t)n*L + lq)*DMODEL + h*64 + c] : 0.f;
        Ks[r][c] = (lk < L) ? Kmat[((size_t)n*L + lk)*DMODEL + h*64 + c] : 0.f;
    }
    __syncthreads();
    int tx = tid & 15, ty = tid >> 4;
    float acc[4][4] = {};
    #pragma unroll 8
    for (int d = 0; d < 64; d++) {
        float qv[4], kv[4];
        #pragma unroll
        for (int i=0;i<4;i++) qv[i]=Qs[(ty<<2)+i][d];
        #pragma unroll
        for (int j=0;j<4;j++) kv[j]=Ks[(tx<<2)+j][d];
        #pragma unroll
        for (int i=0;i<4;i++)
            #pragma unroll
            for (int j=0;j<4;j++)
                acc[i][j] = fmaf(qv[i], kv[j], acc[i][j]);
    }
    #pragma unroll
    for (int i=0;i<4;i++) {
        int qr = qt*64 + (ty<<2) + i;
        if (qr >= L) continue;
        #pragma unroll
        for (int j=0;j<4;j++) {
            int kc = kt*64 + (tx<<2) + j;
            if (kc >= L) continue;
            float b = (mask[(size_t)n*L + kc] > 0.f) ? 0.f : -1e9f;
            lg[(((size_t)n*NHEAD + h)*L + qr)*L + kc] = acc[i][j]*0.125f + b;
        }
    }
}

__global__ void softmax_kernel(float* __restrict__ lg, int L)
{
    float* p = lg + (size_t)blockIdx.x * L;
    int tid = threadIdx.x;
    float m = -3.4e38f;
    for (int i=tid;i<L;i+=blockDim.x) m = fmaxf(m, p[i]);
    m = block_max(m);
    float s = 0.f;
    for (int i=tid;i<L;i+=blockDim.x) { float e = expf(p[i]-m); p[i]=e; s+=e; }
    s = block_sum(s);
    float inv = 1.f/s;
    for (int i=tid;i<L;i+=blockDim.x) p[i] *= inv;
}

__global__ void av_kernel(const float* __restrict__ lg, const float* __restrict__ V,
                          unsigned short* __restrict__ Oh, unsigned short* __restrict__ Ol,
                          int L, int TK)
{
    __shared__ float As[64][65];
    __shared__ float Vs[64][65];
    int n = blockIdx.z, h = blockIdx.y, qt = blockIdx.x;
    int tid = threadIdx.x, tx = tid & 15, ty = tid >> 4;
    float acc[4][4] = {};
    for (int kt = 0; kt < TK; kt++) {
        for (int i = tid; i < 64*64; i += 256) {
            int r = i >> 6, c = i & 63;
            int qr = qt*64 + r, kc = kt*64 + c, kr = kt*64 + r;
            As[r][c] = (qr < L && kc < L) ? lg[(((size_t)n*NHEAD + h)*L + qr)*L + kc] : 0.f;
            Vs[r][c] = (kr < L) ? V[((size_t)n*L + kr)*DMODEL + h*64 + c] : 0.f;
        }
        __syncthreads();
        #pragma unroll 8
        for (int kk=0; kk<64; kk++) {
            float av[4], vv[4];
            #pragma unroll
            for (int i=0;i<4;i++) av[i]=As[(ty<<2)+i][kk];
            #pragma unroll
            for (int j=0;j<4;j++) vv[j]=Vs[kk][(tx<<2)+j];
            #pragma unroll
            for (int i=0;i<4;i++)
                #pragma unroll
                for (int j=0;j<4;j++)
                    acc[i][j] = fmaf(av[i], vv[j], acc[i][j]);
        }
        __syncthreads();
    }
    #pragma unroll
    for (int i=0;i<4;i++) {
        int qr = qt*64 + (ty<<2) + i;
        if (qr >= L) continue;
        #pragma unroll
        for (int j=0;j<4;j++) {
            size_t off = ((size_t)n*L + qr)*DMODEL + h*64 + (tx<<2) + j;
            unsigned short hh, ll;
            split2(acc[i][j], hh, ll);
            Oh[off] = hh; Ol[off] = ll;
        }
    }
}

// LN variants
__global__ void ln_split_kernel(const float* __restrict__ x, const float* __restrict__ o,
                                float* __restrict__ out,
                                unsigned short* __restrict__ oh, unsigned short* __restrict__ ol)
{
    __shared__ float buf[DMODEL];
    size_t row = blockIdx.x;
    int tid = threadIdx.x;
    float ls = 0.f;
    for (int i=tid;i<DMODEL;i+=blockDim.x) {
        float v = x[row*DMODEL+i] + o[row*DMODEL+i];
        buf[i] = v; ls += v;
    }
    float mu = block_sum(ls) * (1.f/DMODEL);
    float lv = 0.f;
    for (int i=tid;i<DMODEL;i+=blockDim.x) { float d = buf[i]-mu; lv += d*d; }
    float var = block_sum(lv) * (1.f/DMODEL);
    float inv = rsqrtf(var + 1e-12f);
    for (int i=tid;i<DMODEL;i+=blockDim.x) {
        float v = (buf[i]-mu)*inv;
        out[row*DMODEL+i] = v;
        unsigned short h, l;
        split2(v, h, l);
        oh[row*DMODEL+i] = h; ol[row*DMODEL+i] = l;
    }
}

__global__ void ln_kernel(const float* __restrict__ x, const float* __restrict__ o,
                          float* __restrict__ out)
{
    __shared__ float buf[DMODEL];
    size_t row = blockIdx.x;
    int tid = threadIdx.x;
    float ls = 0.f;
    for (int i=tid;i<DMODEL;i+=blockDim.x) {
        float v = x[row*DMODEL+i] + o[row*DMODEL+i];
        buf[i] = v; ls += v;
    }
    float mu = block_sum(ls) * (1.f/DMODEL);
    float lv = 0.f;
    for (int i=tid;i<DMODEL;i+=blockDim.x) { float d = buf[i]-mu; lv += d*d; }
    float var = block_sum(lv) * (1.f/DMODEL);
    float inv = rsqrtf(var + 1e-12f);
    for (int i=tid;i<DMODEL;i+=blockDim.x) out[row*DMODEL+i] = (buf[i]-mu)*inv;
}

__global__ void gather_cls_kernel(const float* __restrict__ h, float* __restrict__ cls, int L)
{
    int n = blockIdx.x;
    for (int d=threadIdx.x; d<DMODEL; d+=blockDim.x)
        cls[(size_t)n*DMODEL + d] = h[(size_t)n*L*DMODEL + d];
}

__global__ void user0_kernel(const float* __restrict__ cls, const float* __restrict__ qU,
                             float* __restrict__ u0)
{
    int b = blockIdx.x;
    __shared__ float w[HISN];
    int lane = threadIdx.x & 31, wp = threadIdx.x >> 5;
    for (int n = wp; n < HISN; n += (blockDim.x >> 5)) {
        const float* c = cls + (size_t)(b*HISN + n)*DMODEL;
        float acc = 0.f;
        for (int d = lane; d < DMODEL; d += 32) acc += c[d]*qU[d];
        acc = warp_sum(acc);
        if (lane==0) w[n] = acc / sqrtf(768.f);
    }
    __syncthreads();
    if (threadIdx.x == 0) {
        float m = w[0];
        for (int n=1;n<HISN;n++) m = fmaxf(m, w[n]);
        float s = 0.f;
        for (int n=0;n<HISN;n++){ w[n] = expf(w[n]-m); s += w[n]; }
        float inv = 1.f/s;
        for (int n=0;n<HISN;n++) w[n] *= inv;
    }
    __syncthreads();
    for (int d=threadIdx.x; d<DMODEL; d+=blockDim.x) {
        float acc = 0.f;
        for (int n=0;n<HISN;n++) acc += w[n]*cls[(size_t)(b*HISN+n)*DMODEL + d];
        u0[b*DMODEL + d] = acc;
    }
}

// topk also writes ps splits (feeds user-path QKV)
__global__ void topk_kernel(const float* __restrict__ hidden, const float* __restrict__ u0,
                            const float* __restrict__ attn, int* __restrict__ kid,
                            float* __restrict__ ps,
                            unsigned short* __restrict__ psh, unsigned short* __restrict__ psl,
                            float* __restrict__ psm)
{
    int bn = blockIdx.x;
    int b = bn / HISN, n = bn - b*HISN;
    __shared__ float u[DMODEL];
    __shared__ float sc[SEQ];
    __shared__ int sel[KSEL];
    for (int d=threadIdx.x; d<DMODEL; d+=blockDim.x) u[d] = u0[b*DMODEL + d];
    __syncthreads();
    int lane = threadIdx.x & 31, wp = threadIdx.x >> 5;
    for (int s = wp; s < SEQ; s += (blockDim.x >> 5)) {
        const float* hr = hidden + (size_t)(bn*SEQ + s)*DMODEL;
        float acc = 0.f;
        for (int d = lane; d < DMODEL; d += 32) acc += hr[d]*u[d];
        acc = warp_sum(acc);
        if (lane==0)
            sc[s] = (attn[(size_t)bn*SEQ + s] > 0.f) ? acc / sqrtf(768.f) : -1e9f;
    }
    __syncthreads();
    if (threadIdx.x == 0) {
        bool used[SEQ];
        for (int s=0;s<SEQ;s++) used[s]=false;
        for (int kk=0; kk<KSEL; kk++) {
            float best = -3.4e38f; int bi = 0;
            for (int s=0;s<SEQ;s++)
                if (!used[s] && sc[s] > best) { best = sc[s]; bi = s; }
            used[bi] = true; sel[kk] = bi;
            kid[(size_t)bn*KSEL + kk] = bi;
        }
    }
    __syncthreads();
    for (int kk=0; kk<KSEL; kk++) {
        int s = sel[kk];
        size_t dst = (size_t)(b*LUSR + n*KSEL + kk);
        for (int d=threadIdx.x; d<DMODEL; d+=blockDim.x) {
            float v = hidden[(size_t)(bn*SEQ + s)*DMODEL + d];
            ps[dst*DMODEL + d] = v;
            unsigned short hh, ll;
            split2(v, hh, ll);
            psh[dst*DMODEL + d] = hh; psl[dst*DMODEL + d] = ll;
        }
        if (threadIdx.x == 0) psm[dst] = attn[(size_t)bn*SEQ + s];
    }
}

// final log-softmax + kid emit, merged
__global__ void final_kernel(const float* __restrict__ cddr, const float* __restrict__ ur,
                             const int* __restrict__ kid, float* __restrict__ out)
{
    if (blockIdx.x >= BB) {
        int i = (blockIdx.x - BB)*256 + threadIdx.x;
        if (i < BB*HISN*KSEL) out[NCDD + i] = (float)kid[i];
        return;
    }
    int b = blockIdx.x;
    __shared__ float s[CDDN];
    int lane = threadIdx.x & 31, wp = threadIdx.x >> 5;
    for (int c = wp; c < CDDN; c += (blockDim.x >> 5)) {
        const float* a = cddr + (size_t)(b*CDDN + c)*DMODEL;
        const float* uu = ur + (size_t)b*DMODEL;
        float acc = 0.f;
        for (int d = lane; d < DMODEL; d += 32) acc += a[d]*uu[d];
        acc = warp_sum(acc);
        if (lane==0) s[c] = acc / sqrtf(768.f);
    }
    __syncthreads();
    if (threadIdx.x == 0) {
        float m = s[0];
        for (int c=1;c<CDDN;c++) m = fmaxf(m, s[c]);
        float sum = 0.f;
        for (int c=0;c<CDDN;c++) sum += expf(s[c]-m);
        float lse = m + logf(sum);
        for (int c=0;c<CDDN;c++) out[b*CDDN + c] = s[c] - lse;
    }
}

// ---------------- host orchestration ----------------
struct DevPtrs {
    float *x,*q,*k,*v,*h,*lg,*pre,*atC,*atH,*cls,*cddr,*u0,*ur,*psm;
    int* kid;
    unsigned short *whi,*wlo,*xh,*xl,*oh,*ol,*hh,*hl,*fh,*fl;
};
static DevPtrs P;

static void run_transformer(int N, int L, const unsigned short* wh, const unsigned short* wl,
                            const float* attnMask)
{
    int R = N*L;  // multiple of 128
    mma_gemm_qkv<<<dim3(DMODEL/128, R/128, 3), 256, MMA_SMEM>>>(P.xh, P.xl, wh, wl, P.q, P.k, P.v, R);
    if (L == 64) {
        attn64_kernel<<<dim3(N, NHEAD),256>>>(P.q, P.k, P.v, attnMask, P.oh, P.ol);
    } else {
        int T = (L+63)/64;
        logits_kernel<<<dim3(T*T, NHEAD, N),256>>>(P.q, P.k, attnMask, P.lg, L, T);
        softmax_kernel<<<(unsigned)(N*NHEAD*L),128>>>(P.lg, L);
        av_kernel<<<dim3(T, NHEAD, N),256>>>(P.lg, P.v, P.oh, P.ol, L, T);
    }
    mma_gemm_f<<<dim3(DMODEL/128, R/128), 256, MMA_SMEM>>>(P.oh, P.ol, wh+WOFF_O, wl+WOFF_O, P.q, R, DMODEL, DMODEL);
    ln_split_kernel<<<R,256>>>(P.x, P.q, P.h, P.hh, P.hl);
    mma_gemm_gelu<<<dim3(FFDIM/128, R/128), 256, MMA_SMEM>>>(P.hh, P.hl, wh+WOFF_1, wl+WOFF_1, P.fh, P.fl, R, FFDIM, DMODEL);
    mma_gemm_f<<<dim3(DMODEL/128, R/128), 256, MMA_SMEM>>>(P.fh, P.fl, wh+WOFF_2, wl+WOFF_2, P.q, R, DMODEL, FFDIM);
    ln_kernel<<<R,256>>>(P.h, P.q, P.h);
}

extern "C" void kernel_launch(void* const* d_in, const int* in_sizes, int n_in,
                              void* d_out, int out_size)
{
    const int*   cdd_sub  = (const int*)d_in[0];
    const int*   his_sub  = (const int*)d_in[1];
    const int*   cdd_enc  = (const int*)d_in[2];
    const int*   his_enc  = (const int*)d_in[3];
    const float* cdd_mask = (const float*)d_in[4];
    const float* his_mask = (const float*)d_in[5];
    const float* cdd_am   = (const float*)d_in[6];
    const float* his_am   = (const float*)d_in[7];
    const float* emb      = (const float*)d_in[8];
    const float* qU    = (const float*)d_in[21];
    const float* projW = (const float*)d_in[22];
    const float* projb = (const float*)d_in[23];
    float* out = (float*)d_out;

    cudaGetSymbolAddress((void**)&P.x,   g_x);
    cudaGetSymbolAddress((void**)&P.q,   g_q);
    cudaGetSymbolAddress((void**)&P.k,   g_k);
    cudaGetSymbolAddress((void**)&P.v,   g_v);
    cudaGetSymbolAddress((void**)&P.h,   g_h);
    cudaGetSymbolAddress((void**)&P.lg,  g_lg);
    cudaGetSymbolAddress((void**)&P.pre, g_pre);
    cudaGetSymbolAddress((void**)&P.atC, g_atC);
    cudaGetSymbolAddress((void**)&P.atH, g_atH);
    cudaGetSymbolAddress((void**)&P.cls, g_cls);
    cudaGetSymbolAddress((void**)&P.cddr,g_cddr);
    cudaGetSymbolAddress((void**)&P.u0,  g_u0);
    cudaGetSymbolAddress((void**)&P.ur,  g_ur);
    cudaGetSymbolAddress((void**)&P.psm, g_psm);
    cudaGetSymbolAddress((void**)&P.kid, g_kid);
    cudaGetSymbolAddress((void**)&P.whi, g_whi);
    cudaGetSymbolAddress((void**)&P.wlo, g_wlo);
    cudaGetSymbolAddress((void**)&P.xh,  g_xh);
    cudaGetSymbolAddress((void**)&P.xl,  g_xl);
    cudaGetSymbolAddress((void**)&P.oh,  g_oh);
    cudaGetSymbolAddress((void**)&P.ol,  g_ol);
    cudaGetSymbolAddress((void**)&P.hh,  g_hh);
    cudaGetSymbolAddress((void**)&P.hl,  g_hl);
    cudaGetSymbolAddress((void**)&P.fh,  g_fh);
    cudaGetSymbolAddress((void**)&P.fl,  g_fl);

    cudaFuncSetAttribute(mma_gemm_f,    cudaFuncAttributeMaxDynamicSharedMemorySize, MMA_SMEM);
    cudaFuncSetAttribute(mma_gemm_gelu, cudaFuncAttributeMaxDynamicSharedMemorySize, MMA_SMEM);
    cudaFuncSetAttribute(mma_gemm_qkv,  cudaFuncAttributeMaxDynamicSharedMemorySize, MMA_SMEM);

    // ---- batched weight prep ----
    PrepPtrs pp;
    for (int i = 0; i < 6; i++) { pp.p[i] = (const float*)d_in[9+i]; pp.p[6+i] = (const float*)d_in[15+i]; }
    prep_all<<<dim3(2304, 12), dim3(32,8)>>>(pp, P.whi, P.wlo);

    // ---- candidate path (BERT weights) ----
    prefix_kernel<<<NCDD,256>>>(cdd_sub, cdd_mask, cdd_am, P.pre, P.atC);
    pool_kernel<<<dim3(NCDD, DMODEL/128),128>>>(P.pre, cdd_enc, emb, P.x, P.xh, P.xl);
    run_transformer(NCDD, SEQ, P.whi, P.wlo, P.atC);
    sgemm_proj<<<dim3(DMODEL/64, 1),256>>>(P.h, (size_t)SEQ*DMODEL, projW, P.cddr, NCDD, DMODEL, DMODEL, projb);

    // ---- history path (encN weights) ----
    prefix_kernel<<<NHIS,256>>>(his_sub, his_mask, his_am, P.pre, P.atH);
    pool_kernel<<<dim3(NHIS, DMODEL/128),128>>>(P.pre, his_enc, emb, P.x, P.xh, P.xl);
    run_transformer(NHIS, SEQ, P.whi+WSET, P.wlo+WSET, P.atH);
    gather_cls_kernel<<<NHIS,256>>>(P.h, P.cls, SEQ);
    user0_kernel<<<BB,256>>>(P.cls, qU, P.u0);
    topk_kernel<<<BB*HISN,256>>>(P.h, P.u0, P.atH, P.kid, P.x, P.xh, P.xl, P.psm);

    // ---- user path over selected terms (BERT weights) ----
    run_transformer(BB, LUSR, P.whi, P.wlo, P.psm);
    sgemm_proj<<<dim3(DMODEL/64, 1),256>>>(P.h, (size_t)LUSR*DMODEL, projW, P.ur, BB, DMODEL, DMODEL, projb);

    // ---- outputs ----
    final_kernel<<<BB + (BB*HISN*KSEL + 255)/256, 256>>>(P.cddr, P.ur, P.kid, out);
}

// round 9
// speedup vs baseline: 3.0958x; 1.0520x over previous
#include <cuda_runtime.h>
#include <cuda_fp16.h>
#include <math.h>
#include <stdint.h>

#define BB     8
#define CDDN   5
#define HISN   50
#define SEQ    64
#define DMODEL 768
#define NHEAD  12
#define FFDIM  3072
#define KSEL   8

#define NCDD   (BB*CDDN)     // 40
#define NHIS   (BB*HISN)     // 400
#define LUSR   (HISN*KSEL)   // 400
#define ROWS_MAX (NHIS*SEQ)  // 25600

#define WOFF_Q  0
#define WOFF_K  589824
#define WOFF_V  1179648
#define WOFF_O  1769472
#define WOFF_1  2359296
#define WOFF_2  4718592
#define WSET    7077888

// ---------------- scratch ----------------
__device__ float g_x [ (size_t)ROWS_MAX*DMODEL ];
__device__ float g_q [ (size_t)ROWS_MAX*DMODEL ];
__device__ float g_k [ (size_t)ROWS_MAX*DMODEL ];
__device__ float g_v [ (size_t)ROWS_MAX*DMODEL ];
__device__ float g_h [ (size_t)ROWS_MAX*DMODEL ];
__device__ float g_lg[ (size_t)BB*NHEAD*LUSR*LUSR ];
__device__ float g_pre[(size_t)NHIS*SEQ*SEQ ];
__device__ float g_atC[ NCDD*SEQ ];
__device__ float g_atH[ NHIS*SEQ ];
__device__ float g_cls[ (size_t)NHIS*DMODEL ];
__device__ float g_cddr[(size_t)NCDD*DMODEL ];
__device__ float g_u0 [ BB*DMODEL ];
__device__ float g_ur [ BB*DMODEL ];
__device__ float g_psm[ BB*LUSR ];
__device__ int   g_kid[ BB*HISN*KSEL ];
// fp16 weights [N,K] hi + lo, two sets (lo used only by 3-term path)
__device__ unsigned short g_whi[ (size_t)2*WSET ];
__device__ unsigned short g_wlo[ (size_t)2*WSET ];
// split-fp16 activations by role (hi + residual lo)
__device__ unsigned short g_xh[ (size_t)ROWS_MAX*DMODEL ];
__device__ unsigned short g_xl[ (size_t)ROWS_MAX*DMODEL ];
__device__ unsigned short g_oh[ (size_t)ROWS_MAX*DMODEL ];
__device__ unsigned short g_ol[ (size_t)ROWS_MAX*DMODEL ];
__device__ unsigned short g_hh[ (size_t)ROWS_MAX*DMODEL ];
__device__ unsigned short g_hl[ (size_t)ROWS_MAX*DMODEL ];
__device__ unsigned short g_fh[ (size_t)ROWS_MAX*FFDIM ];
__device__ unsigned short g_fl[ (size_t)ROWS_MAX*FFDIM ];

// ---------------- low-level helpers ----------------
__device__ __forceinline__ void cp16(uint32_t s, const void* g){
    asm volatile("cp.async.ca.shared.global [%0], [%1], 16;\n" :: "r"(s), "l"(g));
}
__device__ __forceinline__ void cp_commit(){ asm volatile("cp.async.commit_group;\n"); }
template<int N>
__device__ __forceinline__ void cp_wait(){ asm volatile("cp.async.wait_group %0;\n" :: "n"(N)); }

__device__ __forceinline__ uint32_t smem_u32(const void* p) {
    uint32_t a;
    asm("{ .reg .u64 t; cvta.to.shared.u64 t, %1; cvt.u32.u64 %0, t; }" : "=r"(a) : "l"(p));
    return a;
}
__device__ __forceinline__ void ldsm_x4(uint32_t* r, uint32_t addr){
    asm volatile("ldmatrix.sync.aligned.m8n8.x4.shared.b16 {%0,%1,%2,%3}, [%4];"
        : "=r"(r[0]),"=r"(r[1]),"=r"(r[2]),"=r"(r[3]) : "r"(addr));
}
__device__ __forceinline__ void mma_f16(float* c, const uint32_t* a, const uint32_t* b){
    asm volatile("mma.sync.aligned.m16n8k16.row.col.f32.f16.f16.f32 "
        "{%0,%1,%2,%3}, {%4,%5,%6,%7}, {%8,%9}, {%0,%1,%2,%3};"
        : "+f"(c[0]),"+f"(c[1]),"+f"(c[2]),"+f"(c[3])
        : "r"(a[0]),"r"(a[1]),"r"(a[2]),"r"(a[3]), "r"(b[0]),"r"(b[1]));
}
// fp16 hi/lo split
__device__ __forceinline__ void split2(float v, unsigned short& h, unsigned short& l){
    __half hh = __float2half_rn(v);
    __half ll = __float2half_rn(v - __half2float(hh));
    h = __half_as_ushort(hh);
    l = __half_as_ushort(ll);
}

// ---------------- reductions ----------------
__device__ __forceinline__ float warp_sum(float v){
    #pragma unroll
    for(int o=16;o;o>>=1) v += __shfl_xor_sync(0xffffffffu, v, o);
    return v;
}
__device__ __forceinline__ float warp_max(float v){
    #pragma unroll
    for(int o=16;o;o>>=1) v = fmaxf(v, __shfl_xor_sync(0xffffffffu, v, o));
    return v;
}
__device__ float block_sum(float v){
    __shared__ float red[33];
    int lane=threadIdx.x&31, w=threadIdx.x>>5, nw=blockDim.x>>5;
    v = warp_sum(v);
    __syncthreads();
    if(lane==0) red[w]=v;
    __syncthreads();
    if(threadIdx.x==0){ float t=0.f; for(int i=0;i<nw;i++) t+=red[i]; red[32]=t; }
    __syncthreads();
    return red[32];
}
__device__ float block_max(float v){
    __shared__ float red[33];
    int lane=threadIdx.x&31, w=threadIdx.x>>5, nw=blockDim.x>>5;
    v = warp_max(v);
    __syncthreads();
    if(lane==0) red[w]=v;
    __syncthreads();
    if(threadIdx.x==0){ float t=red[0]; for(int i=1;i<nw;i++) t=fmaxf(t,red[i]); red[32]=t; }
    __syncthreads();
    return red[32];
}

// ---------------- batched weight prep: [K,N] fp32 -> [N,K] fp16 hi/lo ----------------
struct PrepPtrs { const float* p[12]; };
__constant__ size_t c_woffs[6] = { WOFF_Q, WOFF_K, WOFF_V, WOFF_O, WOFF_1, WOFF_2 };

__global__ void prep_all(PrepPtrs ptrs, unsigned short* __restrict__ Th,
                         unsigned short* __restrict__ Tl)
{
    int w = blockIdx.y;
    int wi = w % 6;
    int K = (wi==5) ? FFDIM : DMODEL;
    int N = (wi==4) ? FFDIM : DMODEL;
    int ntx = N >> 5;
    int tiles = (K >> 5) * ntx;
    int t = blockIdx.x;
    if (t >= tiles) return;
    int nb = (t % ntx) << 5, kb = (t / ntx) << 5;
    const float* W = ptrs.p[w];
    size_t base = c_woffs[wi] + (size_t)(w/6)*WSET;

    __shared__ float tbuf[32][33];
    int x = threadIdx.x, y = threadIdx.y;
    for (int i=y;i<32;i+=8)
        tbuf[i][x] = W[(size_t)(kb+i)*N + nb + x];
    __syncthreads();
    for (int i=y;i<32;i+=8) {
        unsigned short h, l;
        split2(tbuf[x][i], h, l);
        size_t dst = base + (size_t)(nb+i)*K + kb + x;
        Th[dst] = h;
        Tl[dst] = l;
    }
}

// ---------------- mma.sync split-fp16 GEMM ----------------
// C = A@B^T. A: fp16 hi/lo [M,K]; B: fp16 hi(/lo) [N,K]. M,N,K % 128/128/32 == 0.
// TERMS=3: AhBh + AlBh + AhBl.  TERMS=2: AhBh + AlBh.
// EPI 0: fp32 C.  EPI 1: gelu -> fp16 hi/lo (Ch/Cl).
#define APAD 40
#define ARR_B  (128*APAD*2)
#define SMEM_T(T) (2*((T)+1)*ARR_B)     // T=3: 81920, T=2: 61440
#define MMA_SMEM_MAX SMEM_T(3)

template<int EPI, int TERMS>
__device__ __forceinline__ void mma_body(const unsigned short* __restrict__ Ah,
                                         const unsigned short* __restrict__ Al,
                                         const unsigned short* __restrict__ Bh,
                                         const unsigned short* __restrict__ Bl,
                                         float* __restrict__ C,
                                         unsigned short* __restrict__ Ch,
                                         unsigned short* __restrict__ Cl,
                                         int M, int N, int K)
{
    extern __shared__ char sm[];
    const uint32_t sbase = smem_u32(sm);
    const int tid = threadIdx.x, lane = tid & 31, wid = tid >> 5;
    const int wm = wid >> 2, wn = wid & 3;
    const int rowBlk = blockIdx.y << 7, colBlk = blockIdx.x << 7;
    const uint32_t STG = (TERMS+1)*ARR_B;

    int r0 = tid >> 2,        s0 = (tid & 3) << 3;
    int r1 = (tid+256) >> 2,  s1 = ((tid+256) & 3) << 3;
    const unsigned short* gA[2] = {Ah, Al};

    const int nc = K >> 5;
    #pragma unroll
    for (int p=0;p<2;p++) {
        cp16(sbase + p*ARR_B + (uint32_t)(r0*APAD + s0)*2, gA[p] + (size_t)(rowBlk+r0)*K + s0);
        cp16(sbase + p*ARR_B + (uint32_t)(r1*APAD + s1)*2, gA[p] + (size_t)(rowBlk+r1)*K + s1);
    }
    cp16(sbase + 2*ARR_B + (uint32_t)(r0*APAD + s0)*2, Bh + (size_t)(colBlk+r0)*K + s0);
    cp16(sbase + 2*ARR_B + (uint32_t)(r1*APAD + s1)*2, Bh + (size_t)(colBlk+r1)*K + s1);
    if (TERMS == 3) {
        cp16(sbase + 3*ARR_B + (uint32_t)(r0*APAD + s0)*2, Bl + (size_t)(colBlk+r0)*K + s0);
        cp16(sbase + 3*ARR_B + (uint32_t)(r1*APAD + s1)*2, Bl + (size_t)(colBlk+r1)*K + s1);
    }
    cp_commit();

    const uint32_t aoff = (uint32_t)((wm*64 + (lane & 15))*APAD + 8*(lane >> 4)) * 2;
    const uint32_t boff = (uint32_t)((wn*32 + (lane & 7) + 8*(lane >> 4))*APAD + 8*((lane >> 3) & 1)) * 2;

    float acc[4][4][4] = {};

    for (int c = 0; c < nc; c++) {
        const bool has = (c+1 < nc);
        if (has) {
            int kb = (c+1) << 5;
            uint32_t st = ((c+1) & 1) * STG;
            #pragma unroll
            for (int p=0;p<2;p++) {
                cp16(sbase + st + p*ARR_B + (uint32_t)(r0*APAD + s0)*2, gA[p] + (size_t)(rowBlk+r0)*K + kb + s0);
                cp16(sbase + st + p*ARR_B + (uint32_t)(r1*APAD + s1)*2, gA[p] + (size_t)(rowBlk+r1)*K + kb + s1);
            }
            cp16(sbase + st + 2*ARR_B + (uint32_t)(r0*APAD + s0)*2, Bh + (size_t)(colBlk+r0)*K + kb + s0);
            cp16(sbase + st + 2*ARR_B + (uint32_t)(r1*APAD + s1)*2, Bh + (size_t)(colBlk+r1)*K + kb + s1);
            if (TERMS == 3) {
                cp16(sbase + st + 3*ARR_B + (uint32_t)(r0*APAD + s0)*2, Bl + (size_t)(colBlk+r0)*K + kb + s0);
                cp16(sbase + st + 3*ARR_B + (uint32_t)(r1*APAD + s1)*2, Bl + (size_t)(colBlk+r1)*K + kb + s1);
            }
            cp_commit();
            cp_wait<1>();
        } else {
            cp_wait<0>();
        }
        __syncthreads();

        uint32_t st = (c & 1) * STG;
        uint32_t aH = sbase + st + aoff;
        uint32_t aL = aH + ARR_B;
        uint32_t bH = sbase + st + 2*ARR_B + boff;
        uint32_t bL = bH + ARR_B;

        #pragma unroll
        for (int ks = 0; ks < 2; ks++) {
            uint32_t ko = (uint32_t)(ks*16*2);
            uint32_t ahf[4][4], alf[4][4], bhf[2][4], blf[2][4];
            #pragma unroll
            for (int mt=0;mt<4;mt++) ldsm_x4(ahf[mt], aH + ko + (uint32_t)(mt*16*APAD*2));
            #pragma unroll
            for (int np=0;np<2;np++) ldsm_x4(bhf[np], bH + ko + (uint32_t)(np*16*APAD*2));
            if (TERMS == 3) {
                #pragma unroll
                for (int np=0;np<2;np++) ldsm_x4(blf[np], bL + ko + (uint32_t)(np*16*APAD*2));
            }
            // group1: ah x bh
            #pragma unroll
            for (int mt=0;mt<4;mt++)
                #pragma unroll
                for (int nt=0;nt<4;nt++)
                    mma_f16(acc[mt][nt], ahf[mt], &bhf[nt>>1][(nt&1)*2]);
            #pragma unroll
            for (int mt=0;mt<4;mt++) ldsm_x4(alf[mt], aL + ko + (uint32_t)(mt*16*APAD*2));
            if (TERMS == 3) {
                // group2: ah x bl
                #pragma unroll
                for (int mt=0;mt<4;mt++)
                    #pragma unroll
                    for (int nt=0;nt<4;nt++)
                        mma_f16(acc[mt][nt], ahf[mt], &blf[nt>>1][(nt&1)*2]);
            }
            // group3: al x bh
            #pragma unroll
            for (int mt=0;mt<4;mt++)
                #pragma unroll
                for (int nt=0;nt<4;nt++)
                    mma_f16(acc[mt][nt], alf[mt], &bhf[nt>>1][(nt&1)*2]);
        }
        __syncthreads();
    }

    #pragma unroll
    for (int mt=0;mt<4;mt++) {
        int row = rowBlk + wm*64 + mt*16 + (lane >> 2);
        #pragma unroll
        for (int nt=0;nt<4;nt++) {
            int col = colBlk + wn*32 + nt*8 + (lane & 3)*2;
            float v[4] = {acc[mt][nt][0], acc[mt][nt][1], acc[mt][nt][2], acc[mt][nt][3]};
            if (EPI == 0) {
                *(float2*)(C + (size_t)row*N + col)     = make_float2(v[0], v[1]);
                *(float2*)(C + (size_t)(row+8)*N + col) = make_float2(v[2], v[3]);
            } else {
                #pragma unroll
                for (int j=0;j<4;j++) {
                    float t = v[j];
                    v[j] = 0.5f*t*(1.f + tanhf(0.7978845608028654f*(t + 0.044715f*t*t*t)));
                }
                unsigned short h0,l0,h1,l1;
                split2(v[0], h0, l0); split2(v[1], h1, l1);
                *(uint32_t*)(Ch + (size_t)row*N + col) = (uint32_t)h0 | ((uint32_t)h1<<16);
                *(uint32_t*)(Cl + (size_t)row*N + col) = (uint32_t)l0 | ((uint32_t)l1<<16);
                split2(v[2], h0, l0); split2(v[3], h1, l1);
                *(uint32_t*)(Ch + (size_t)(row+8)*N + col) = (uint32_t)h0 | ((uint32_t)h1<<16);
                *(uint32_t*)(Cl + (size_t)(row+8)*N + col) = (uint32_t)l0 | ((uint32_t)l1<<16);
            }
        }
    }
}

template<int TERMS>
__global__ __launch_bounds__(256, 2) void mma_gemm_f(const unsigned short* __restrict__ Ah,
                                                     const unsigned short* __restrict__ Al,
                                                     const unsigned short* __restrict__ Bh,
                                                     const unsigned short* __restrict__ Bl,
                                                     float* __restrict__ C,
                                                     int M, int N, int K)
{
    mma_body<0, TERMS>(Ah, Al, Bh, Bl, C, nullptr, nullptr, M, N, K);
}

template<int TERMS>
__global__ __launch_bounds__(256, 2) void mma_gemm_gelu(const unsigned short* __restrict__ Ah,
                                                        const unsigned short* __restrict__ Al,
                                                        const unsigned short* __restrict__ Bh,
                                                        const unsigned short* __restrict__ Bl,
                                                        unsigned short* __restrict__ Ch,
                                                        unsigned short* __restrict__ Cl,
                                                        int M, int N, int K)
{
    mma_body<1, TERMS>(Ah, Al, Bh, Bl, nullptr, Ch, Cl, M, N, K);
}

template<int TERMS>
__global__ __launch_bounds__(256, 2) void mma_gemm_qkv(const unsigned short* __restrict__ Ah,
                                                       const unsigned short* __restrict__ Al,
                                                       const unsigned short* __restrict__ Wh,
                                                       const unsigned short* __restrict__ Wl,
                                                       float* __restrict__ Cq,
                                                       float* __restrict__ Ck,
                                                       float* __restrict__ Cv,
                                                       int M)
{
    const unsigned short* bh = Wh + (size_t)blockIdx.z*589824;
    const unsigned short* bl = Wl + (size_t)blockIdx.z*589824;
    float* C = (blockIdx.z==0) ? Cq : (blockIdx.z==1) ? Ck : Cv;
    mma_body<0, TERMS>(Ah, Al, bh, bl, C, nullptr, nullptr, M, DMODEL, DMODEL);
}

// ---------------- prefix build + pooled attention mask ----------------
__global__ void prefix_kernel(const int* __restrict__ sub, const float* __restrict__ mask,
                              const float* __restrict__ amask,
                              float* __restrict__ prefix, float* __restrict__ attn)
{
    __shared__ float P[SEQ*SEQ];
    int bn = blockIdx.x;
    for (int i = threadIdx.x; i < SEQ*SEQ; i += blockDim.x) P[i] = 0.f;
    __syncthreads();
    const int* si = sub + (size_t)bn*SEQ*2;
    for (int s = threadIdx.x; s < SEQ; s += blockDim.x) {
        int i = si[2*s+0], j = si[2*s+1];
        P[i*SEQ + j] = 1.f;
    }
    __syncthreads();
    float m = mask[bn];
    int lane = threadIdx.x & 31, warp = threadIdx.x >> 5;
    for (int i = warp; i < SEQ; i += (blockDim.x >> 5)) {
        float v0 = P[i*SEQ + lane]      * m;
        float v1 = P[i*SEQ + lane + 32] * m;
        float rs = v0 + v1;
        float ad = v0 * amask[bn*SEQ + lane] + v1 * amask[bn*SEQ + lane + 32];
        #pragma unroll
        for (int o=16;o;o>>=1){ rs += __shfl_xor_sync(0xffffffffu,rs,o); ad += __shfl_xor_sync(0xffffffffu,ad,o); }
        float denom = fmaxf(rs, 1e-12f);
        prefix[(size_t)bn*SEQ*SEQ + i*SEQ + lane]      = v0/denom;
        prefix[(size_t)bn*SEQ*SEQ + i*SEQ + lane + 32] = v1/denom;
        if (lane==0) attn[bn*SEQ + i] = ad/denom;
    }
}

// ---------------- embedding gather + pooling, emits fp32 + hi/lo ----------------
__global__ void pool_kernel(const float* __restrict__ prefix, const int* __restrict__ enc,
                            const float* __restrict__ emb, float* __restrict__ x,
                            unsigned short* __restrict__ xh, unsigned short* __restrict__ xl)
{
    __shared__ float P[SEQ*SEQ];
    __shared__ int idx[SEQ];
    int bn = blockIdx.x;
    int d  = blockIdx.y*128 + threadIdx.x;
    for (int i = threadIdx.x; i < SEQ*SEQ; i += blockDim.x)
        P[i] = prefix[(size_t)bn*SEQ*SEQ + i];
    if (threadIdx.x < SEQ) idx[threadIdx.x] = enc[(size_t)bn*SEQ + threadIdx.x];
    __syncthreads();
    float acc[SEQ];
    #pragma unroll
    for (int i=0;i<SEQ;i++) acc[i]=0.f;
    for (int j=0;j<SEQ;j++) {
        float e = emb[(size_t)idx[j]*DMODEL + d];
        #pragma unroll
        for (int i=0;i<SEQ;i++) acc[i] = fmaf(P[i*SEQ+j], e, acc[i]);
    }
    for (int i=0;i<SEQ;i++) {
        size_t o = ((size_t)bn*SEQ + i)*DMODEL + d;
        x[o] = acc[i];
        unsigned short h, l;
        split2(acc[i], h, l);
        xh[o] = h; xl[o] = l;
    }
}

// ---------------- strided proj: C=tanh(A@B+bias) ----------------
__global__ void sgemm_proj(const float* __restrict__ A, size_t lda,
                           const float* __restrict__ B,
                           float* __restrict__ C, int M, int N, int Kd,
                           const float* __restrict__ bias)
{
    __shared__ float As[16][64];
    __shared__ float Bs[16][68];
    int tid = threadIdx.x;
    int rowBase = blockIdx.y << 6, colBase = blockIdx.x << 6;
    int tx = tid & 15, ty = tid >> 4;
    int am = tid >> 2, ak = (tid & 3) << 2;
    int bk = tid >> 4, bn = (tid & 15) << 2;
    bool aok = (rowBase + am) < M;
    const float* Ap = A + (size_t)(rowBase + am)*lda + ak;
    const float* Bp = B + (size_t)bk*N + colBase + bn;
    float acc[4][4] = {};
    for (int k0 = 0; k0 < Kd; k0 += 16) {
        float4 a4 = aok ? *(const float4*)Ap : make_float4(0.f,0.f,0.f,0.f);
        As[ak+0][am]=a4.x; As[ak+1][am]=a4.y; As[ak+2][am]=a4.z; As[ak+3][am]=a4.w;
        *(float4*)&Bs[bk][bn] = *(const float4*)Bp;
        __syncthreads();
        #pragma unroll
        for (int kk=0; kk<16; kk++) {
            float av[4], bv[4];
            #pragma unroll
            for (int i=0;i<4;i++) av[i]=As[kk][(ty<<2)+i];
            #pragma unroll
            for (int j=0;j<4;j++) bv[j]=Bs[kk][(tx<<2)+j];
            #pragma unroll
            for (int i=0;i<4;i++)
                #pragma unroll
                for (int j=0;j<4;j++)
                    acc[i][j] = fmaf(av[i], bv[j], acc[i][j]);
        }
        __syncthreads();
        Ap += 16;
        Bp += (size_t)16*N;
    }
    #pragma unroll
    for (int i=0;i<4;i++) {
        int r = rowBase + (ty<<2) + i;
        if (r >= M) continue;
        #pragma unroll
        for (int j=0;j<4;j++) {
            int c = colBase + (tx<<2) + j;
            C[(size_t)r*N + c] = tanhf(acc[i][j] + bias[c]);
        }
    }
}

// ---------------- fused attention for L=64, emits hi/lo ----------------
__global__ __launch_bounds__(256, 2) void attn64_kernel(const float* __restrict__ Q,
                                                        const float* __restrict__ Km,
                                                        const float* __restrict__ V,
                                                        const float* __restrict__ mask,
                                                        unsigned short* __restrict__ Oh,
                                                        unsigned short* __restrict__ Ol)
{
    __shared__ float Ts0[64][65];
    __shared__ float Ts1[64][65];
    int n = blockIdx.x, h = blockIdx.y;
    int tid = threadIdx.x, tx = tid & 15, ty = tid >> 4;
    for (int i = tid; i < 64*64; i += 256) {
        int r = i >> 6, c = i & 63;
        Ts0[r][c] = Q [((size_t)n*64 + r)*DMODEL + h*64 + c];
        Ts1[r][c] = Km[((size_t)n*64 + r)*DMODEL + h*64 + c];
    }
    __syncthreads();
    float s[4][4] = {};
    #pragma unroll 8
    for (int d = 0; d < 64; d++) {
        float qv[4], kv[4];
        #pragma unroll
        for (int i=0;i<4;i++) qv[i]=Ts0[(ty<<2)+i][d];
        #pragma unroll
        for (int j=0;j<4;j++) kv[j]=Ts1[(tx<<2)+j][d];
        #pragma unroll
        for (int i=0;i<4;i++)
            #pragma unroll
            for (int j=0;j<4;j++)
                s[i][j] = fmaf(qv[i], kv[j], s[i][j]);
    }
    float bias[4];
    #pragma unroll
    for (int j=0;j<4;j++)
        bias[j] = (mask[(size_t)n*64 + (tx<<2)+j] > 0.f) ? 0.f : -1e9f;
    #pragma unroll
    for (int i=0;i<4;i++)
        #pragma unroll
        for (int j=0;j<4;j++)
            s[i][j] = s[i][j]*0.125f + bias[j];
    float rmax[4], rsum[4];
    #pragma unroll
    for (int i=0;i<4;i++) {
        float m = fmaxf(fmaxf(s[i][0],s[i][1]), fmaxf(s[i][2],s[i][3]));
        #pragma unroll
        for (int o=8;o;o>>=1) m = fmaxf(m, __shfl_xor_sync(0xffffffffu, m, o));
        rmax[i] = m;
    }
    #pragma unroll
    for (int i=0;i<4;i++) {
        float t = 0.f;
        #pragma unroll
        for (int j=0;j<4;j++) { s[i][j] = expf(s[i][j]-rmax[i]); t += s[i][j]; }
        #pragma unroll
        for (int o=8;o;o>>=1) t += __shfl_xor_sync(0xffffffffu, t, o);
        rsum[i] = 1.f/t;
    }
    __syncthreads();
    #pragma unroll
    for (int i=0;i<4;i++)
        #pragma unroll
        for (int j=0;j<4;j++)
            Ts0[(ty<<2)+i][(tx<<2)+j] = s[i][j]*rsum[i];
    for (int i = tid; i < 64*64; i += 256) {
        int r = i >> 6, c = i & 63;
        Ts1[r][c] = V[((size_t)n*64 + r)*DMODEL + h*64 + c];
    }
    __syncthreads();
    float o[4][4] = {};
    #pragma unroll 8
    for (int kk=0; kk<64; kk++) {
        float pv[4], vv[4];
        #pragma unroll
        for (int i=0;i<4;i++) pv[i]=Ts0[(ty<<2)+i][kk];
        #pragma unroll
        for (int j=0;j<4;j++) vv[j]=Ts1[kk][(tx<<2)+j];
        #pragma unroll
        for (int i=0;i<4;i++)
            #pragma unroll
            for (int j=0;j<4;j++)
                o[i][j] = fmaf(pv[i], vv[j], o[i][j]);
    }
    #pragma unroll
    for (int i=0;i<4;i++)
        #pragma unroll
        for (int j=0;j<4;j++) {
            size_t off = ((size_t)n*64 + (ty<<2)+i)*DMODEL + h*64 + (tx<<2)+j;
            unsigned short hh, ll;
            split2(o[i][j], hh, ll);
            Oh[off] = hh; Ol[off] = ll;
        }
}

// ---------------- attention (generic, user path L=400) ----------------
__global__ void logits_kernel(const float* __restrict__ Q, const float* __restrict__ Kmat,
                              const float* __restrict__ mask, float* __restrict__ lg,
                              int L, int TK)
{
    __shared__ float Qs[64][65];
    __shared__ float Ks[64][65];
    int n = blockIdx.z, h = blockIdx.y;
    int qt = blockIdx.x / TK, kt = blockIdx.x % TK;
    int tid = threadIdx.x;
    for (int i = tid; i < 64*64; i += 256) {
        int r = i >> 6, c = i & 63;
        int lq = qt*64 + r, lk = kt*64 + r;
        Qs[r][c] = (lq < L) ? Q[((size_t)n*L + lq)*DMODEL + h*64 + c] : 0.f;
        Ks[r][c] = (lk < L) ? Kmat[((size_t)n*L + lk)*DMODEL + h*64 + c] : 0.f;
    }
    __syncthreads();
    int tx = tid & 15, ty = tid >> 4;
    float acc[4][4] = {};
    #pragma unroll 8
    for (int d = 0; d < 64; d++) {
        float qv[4], kv[4];
        #pragma unroll
        for (int i=0;i<4;i++) qv[i]=Qs[(ty<<2)+i][d];
        #pragma unroll
        for (int j=0;j<4;j++) kv[j]=Ks[(tx<<2)+j][d];
        #pragma unroll
        for (int i=0;i<4;i++)
            #pragma unroll
            for (int j=0;j<4;j++)
                acc[i][j] = fmaf(qv[i], kv[j], acc[i][j]);
    }
    #pragma unroll
    for (int i=0;i<4;i++) {
        int qr = qt*64 + (ty<<2) + i;
        if (qr >= L) continue;
        #pragma unroll
        for (int j=0;j<4;j++) {
            int kc = kt*64 + (tx<<2) + j;
            if (kc >= L) continue;
            float b = (mask[(size_t)n*L + kc] > 0.f) ? 0.f : -1e9f;
            lg[(((size_t)n*NHEAD + h)*L + qr)*L + kc] = acc[i][j]*0.125f + b;
        }
    }
}

__global__ void softmax_kernel(float* __restrict__ lg, int L)
{
    float* p = lg + (size_t)blockIdx.x * L;
    int tid = threadIdx.x;
    float m = -3.4e38f;
    for (int i=tid;i<L;i+=blockDim.x) m = fmaxf(m, p[i]);
    m = block_max(m);
    float s = 0.f;
    for (int i=tid;i<L;i+=blockDim.x) { float e = expf(p[i]-m); p[i]=e; s+=e; }
    s = block_sum(s);
    float inv = 1.f/s;
    for (int i=tid;i<L;i+=blockDim.x) p[i] *= inv;
}

__global__ void av_kernel(const float* __restrict__ lg, const float* __restrict__ V,
                          unsigned short* __restrict__ Oh, unsigned short* __restrict__ Ol,
                          int L, int TK)
{
    __shared__ float As[64][65];
    __shared__ float Vs[64][65];
    int n = blockIdx.z, h = blockIdx.y, qt = blockIdx.x;
    int tid = threadIdx.x, tx = tid & 15, ty = tid >> 4;
    float acc[4][4] = {};
    for (int kt = 0; kt < TK; kt++) {
        for (int i = tid; i < 64*64; i += 256) {
            int r = i >> 6, c = i & 63;
            int qr = qt*64 + r, kc = kt*64 + c, kr = kt*64 + r;
            As[r][c] = (qr < L && kc < L) ? lg[(((size_t)n*NHEAD + h)*L + qr)*L + kc] : 0.f;
            Vs[r][c] = (kr < L) ? V[((size_t)n*L + kr)*DMODEL + h*64 + c] : 0.f;
        }
        __syncthreads();
        #pragma unroll 8
        for (int kk=0; kk<64; kk++) {
            float av[4], vv[4];
            #pragma unroll
            for (int i=0;i<4;i++) av[i]=As[(ty<<2)+i][kk];
            #pragma unroll
            for (int j=0;j<4;j++) vv[j]=Vs[kk][(tx<<2)+j];
            #pragma unroll
            for (int i=0;i<4;i++)
                #pragma unroll
                for (int j=0;j<4;j++)
                    acc[i][j] = fmaf(av[i], vv[j], acc[i][j]);
        }
        __syncthreads();
    }
    #pragma unroll
    for (int i=0;i<4;i++) {
        int qr = qt*64 + (ty<<2) + i;
        if (qr >= L) continue;
        #pragma unroll
        for (int j=0;j<4;j++) {
            size_t off = ((size_t)n*L + qr)*DMODEL + h*64 + (tx<<2) + j;
            unsigned short hh, ll;
            split2(acc[i][j], hh, ll);
            Oh[off] = hh; Ol[off] = ll;
        }
    }
}

// LN variants
__global__ void ln_split_kernel(const float* __restrict__ x, const float* __restrict__ o,
                                float* __restrict__ out,
                                unsigned short* __restrict__ oh, unsigned short* __restrict__ ol)
{
    __shared__ float buf[DMODEL];
    size_t row = blockIdx.x;
    int tid = threadIdx.x;
    float ls = 0.f;
    for (int i=tid;i<DMODEL;i+=blockDim.x) {
        float v = x[row*DMODEL+i] + o[row*DMODEL+i];
        buf[i] = v; ls += v;
    }
    float mu = block_sum(ls) * (1.f/DMODEL);
    float lv = 0.f;
    for (int i=tid;i<DMODEL;i+=blockDim.x) { float d = buf[i]-mu; lv += d*d; }
    float var = block_sum(lv) * (1.f/DMODEL);
    float inv = rsqrtf(var + 1e-12f);
    for (int i=tid;i<DMODEL;i+=blockDim.x) {
        float v = (buf[i]-mu)*inv;
        out[row*DMODEL+i] = v;
        unsigned short h, l;
        split2(v, h, l);
        oh[row*DMODEL+i] = h; ol[row*DMODEL+i] = l;
    }
}

__global__ void ln_kernel(const float* __restrict__ x, const float* __restrict__ o,
                          float* __restrict__ out)
{
    __shared__ float buf[DMODEL];
    size_t row = blockIdx.x;
    int tid = threadIdx.x;
    float ls = 0.f;
    for (int i=tid;i<DMODEL;i+=blockDim.x) {
        float v = x[row*DMODEL+i] + o[row*DMODEL+i];
        buf[i] = v; ls += v;
    }
    float mu = block_sum(ls) * (1.f/DMODEL);
    float lv = 0.f;
    for (int i=tid;i<DMODEL;i+=blockDim.x) { float d = buf[i]-mu; lv += d*d; }
    float var = block_sum(lv) * (1.f/DMODEL);
    float inv = rsqrtf(var + 1e-12f);
    for (int i=tid;i<DMODEL;i+=blockDim.x) out[row*DMODEL+i] = (buf[i]-mu)*inv;
}

__global__ void gather_cls_kernel(const float* __restrict__ h, float* __restrict__ cls, int L)
{
    int n = blockIdx.x;
    for (int d=threadIdx.x; d<DMODEL; d+=blockDim.x)
        cls[(size_t)n*DMODEL + d] = h[(size_t)n*L*DMODEL + d];
}

__global__ void user0_kernel(const float* __restrict__ cls, const float* __restrict__ qU,
                             float* __restrict__ u0)
{
    int b = blockIdx.x;
    __shared__ float w[HISN];
    int lane = threadIdx.x & 31, wp = threadIdx.x >> 5;
    for (int n = wp; n < HISN; n += (blockDim.x >> 5)) {
        const float* c = cls + (size_t)(b*HISN + n)*DMODEL;
        float acc = 0.f;
        for (int d = lane; d < DMODEL; d += 32) acc += c[d]*qU[d];
        acc = warp_sum(acc);
        if (lane==0) w[n] = acc / sqrtf(768.f);
    }
    __syncthreads();
    if (threadIdx.x == 0) {
        float m = w[0];
        for (int n=1;n<HISN;n++) m = fmaxf(m, w[n]);
        float s = 0.f;
        for (int n=0;n<HISN;n++){ w[n] = expf(w[n]-m); s += w[n]; }
        float inv = 1.f/s;
        for (int n=0;n<HISN;n++) w[n] *= inv;
    }
    __syncthreads();
    for (int d=threadIdx.x; d<DMODEL; d+=blockDim.x) {
        float acc = 0.f;
        for (int n=0;n<HISN;n++) acc += w[n]*cls[(size_t)(b*HISN+n)*DMODEL + d];
        u0[b*DMODEL + d] = acc;
    }
}

// topk also writes ps splits (feeds user-path QKV)
__global__ void topk_kernel(const float* __restrict__ hidden, const float* __restrict__ u0,
                            const float* __restrict__ attn, int* __restrict__ kid,
                            float* __restrict__ ps,
                            unsigned short* __restrict__ psh, unsigned short* __restrict__ psl,
                            float* __restrict__ psm)
{
    int bn = blockIdx.x;
    int b = bn / HISN, n = bn - b*HISN;
    __shared__ float u[DMODEL];
    __shared__ float sc[SEQ];
    __shared__ int sel[KSEL];
    for (int d=threadIdx.x; d<DMODEL; d+=blockDim.x) u[d] = u0[b*DMODEL + d];
    __syncthreads();
    int lane = threadIdx.x & 31, wp = threadIdx.x >> 5;
    for (int s = wp; s < SEQ; s += (blockDim.x >> 5)) {
        const float* hr = hidden + (size_t)(bn*SEQ + s)*DMODEL;
        float acc = 0.f;
        for (int d = lane; d < DMODEL; d += 32) acc += hr[d]*u[d];
        acc = warp_sum(acc);
        if (lane==0)
            sc[s] = (attn[(size_t)bn*SEQ + s] > 0.f) ? acc / sqrtf(768.f) : -1e9f;
    }
    __syncthreads();
    if (threadIdx.x == 0) {
        bool used[SEQ];
        for (int s=0;s<SEQ;s++) used[s]=false;
        for (int kk=0; kk<KSEL; kk++) {
            float best = -3.4e38f; int bi = 0;
            for (int s=0;s<SEQ;s++)
                if (!used[s] && sc[s] > best) { best = sc[s]; bi = s; }
            used[bi] = true; sel[kk] = bi;
            kid[(size_t)bn*KSEL + kk] = bi;
        }
    }
    __syncthreads();
    for (int kk=0; kk<KSEL; kk++) {
        int s = sel[kk];
        size_t dst = (size_t)(b*LUSR + n*KSEL + kk);
        for (int d=threadIdx.x; d<DMODEL; d+=blockDim.x) {
            float v = hidden[(size_t)(bn*SEQ + s)*DMODEL + d];
            ps[dst*DMODEL + d] = v;
            unsigned short hh, ll;
            split2(v, hh, ll);
            psh[dst*DMODEL + d] = hh; psl[dst*DMODEL + d] = ll;
        }
        if (threadIdx.x == 0) psm[dst] = attn[(size_t)bn*SEQ + s];
    }
}

// final log-softmax + kid emit, merged
__global__ void final_kernel(const float* __restrict__ cddr, const float* __restrict__ ur,
                             const int* __restrict__ kid, float* __restrict__ out)
{
    if (blockIdx.x >= BB) {
        int i = (blockIdx.x - BB)*256 + threadIdx.x;
        if (i < BB*HISN*KSEL) out[NCDD + i] = (float)kid[i];
        return;
    }
    int b = blockIdx.x;
    __shared__ float s[CDDN];
    int lane = threadIdx.x & 31, wp = threadIdx.x >> 5;
    for (int c = wp; c < CDDN; c += (blockDim.x >> 5)) {
        const float* a = cddr + (size_t)(b*CDDN + c)*DMODEL;
        const float* uu = ur + (size_t)b*DMODEL;
        float acc = 0.f;
        for (int d = lane; d < DMODEL; d += 32) acc += a[d]*uu[d];
        acc = warp_sum(acc);
        if (lane==0) s[c] = acc / sqrtf(768.f);
    }
    __syncthreads();
    if (threadIdx.x == 0) {
        float m = s[0];
        for (int c=1;c<CDDN;c++) m = fmaxf(m, s[c]);
        float sum = 0.f;
        for (int c=0;c<CDDN;c++) sum += expf(s[c]-m);
        float lse = m + logf(sum);
        for (int c=0;c<CDDN;c++) out[b*CDDN + c] = s[c] - lse;
    }
}

// ---------------- host orchestration ----------------
struct DevPtrs {
    float *x,*q,*k,*v,*h,*lg,*pre,*atC,*atH,*cls,*cddr,*u0,*ur,*psm;
    int* kid;
    unsigned short *whi,*wlo,*xh,*xl,*oh,*ol,*hh,*hl,*fh,*fl;
};
static DevPtrs P;

template<int TERMS>
static void run_transformer_t(int N, int L, const unsigned short* wh, const unsigned short* wl,
                              const float* attnMask)
{
    int R = N*L;  // multiple of 128
    const int SM = SMEM_T(TERMS);
    mma_gemm_qkv<TERMS><<<dim3(DMODEL/128, R/128, 3), 256, SM>>>(P.xh, P.xl, wh, wl, P.q, P.k, P.v, R);
    if (L == 64) {
        attn64_kernel<<<dim3(N, NHEAD),256>>>(P.q, P.k, P.v, attnMask, P.oh, P.ol);
    } else {
        int T = (L+63)/64;
        logits_kernel<<<dim3(T*T, NHEAD, N),256>>>(P.q, P.k, attnMask, P.lg, L, T);
        softmax_kernel<<<(unsigned)(N*NHEAD*L),128>>>(P.lg, L);
        av_kernel<<<dim3(T, NHEAD, N),256>>>(P.lg, P.v, P.oh, P.ol, L, T);
    }
    mma_gemm_f<TERMS><<<dim3(DMODEL/128, R/128), 256, SM>>>(P.oh, P.ol, wh+WOFF_O, wl+WOFF_O, P.q, R, DMODEL, DMODEL);
    ln_split_kernel<<<R,256>>>(P.x, P.q, P.h, P.hh, P.hl);
    mma_gemm_gelu<TERMS><<<dim3(FFDIM/128, R/128), 256, SM>>>(P.hh, P.hl, wh+WOFF_1, wl+WOFF_1, P.fh, P.fl, R, FFDIM, DMODEL);
    mma_gemm_f<TERMS><<<dim3(DMODEL/128, R/128), 256, SM>>>(P.fh, P.fl, wh+WOFF_2, wl+WOFF_2, P.q, R, DMODEL, FFDIM);
    ln_kernel<<<R,256>>>(P.h, P.q, P.h);
}

extern "C" void kernel_launch(void* const* d_in, const int* in_sizes, int n_in,
                              void* d_out, int out_size)
{
    const int*   cdd_sub  = (const int*)d_in[0];
    const int*   his_sub  = (const int*)d_in[1];
    const int*   cdd_enc  = (const int*)d_in[2];
    const int*   his_enc  = (const int*)d_in[3];
    const float* cdd_mask = (const float*)d_in[4];
    const float* his_mask = (const float*)d_in[5];
    const float* cdd_am   = (const float*)d_in[6];
    const float* his_am   = (const float*)d_in[7];
    const float* emb      = (const float*)d_in[8];
    const float* qU    = (const float*)d_in[21];
    const float* projW = (const float*)d_in[22];
    const float* projb = (const float*)d_in[23];
    float* out = (float*)d_out;

    cudaGetSymbolAddress((void**)&P.x,   g_x);
    cudaGetSymbolAddress((void**)&P.q,   g_q);
    cudaGetSymbolAddress((void**)&P.k,   g_k);
    cudaGetSymbolAddress((void**)&P.v,   g_v);
    cudaGetSymbolAddress((void**)&P.h,   g_h);
    cudaGetSymbolAddress((void**)&P.lg,  g_lg);
    cudaGetSymbolAddress((void**)&P.pre, g_pre);
    cudaGetSymbolAddress((void**)&P.atC, g_atC);
    cudaGetSymbolAddress((void**)&P.atH, g_atH);
    cudaGetSymbolAddress((void**)&P.cls, g_cls);
    cudaGetSymbolAddress((void**)&P.cddr,g_cddr);
    cudaGetSymbolAddress((void**)&P.u0,  g_u0);
    cudaGetSymbolAddress((void**)&P.ur,  g_ur);
    cudaGetSymbolAddress((void**)&P.psm, g_psm);
    cudaGetSymbolAddress((void**)&P.kid, g_kid);
    cudaGetSymbolAddress((void**)&P.whi, g_whi);
    cudaGetSymbolAddress((void**)&P.wlo, g_wlo);
    cudaGetSymbolAddress((void**)&P.xh,  g_xh);
    cudaGetSymbolAddress((void**)&P.xl,  g_xl);
    cudaGetSymbolAddress((void**)&P.oh,  g_oh);
    cudaGetSymbolAddress((void**)&P.ol,  g_ol);
    cudaGetSymbolAddress((void**)&P.hh,  g_hh);
    cudaGetSymbolAddress((void**)&P.hl,  g_hl);
    cudaGetSymbolAddress((void**)&P.fh,  g_fh);
    cudaGetSymbolAddress((void**)&P.fl,  g_fl);

    cudaFuncSetAttribute(mma_gemm_f<2>,    cudaFuncAttributeMaxDynamicSharedMemorySize, SMEM_T(2));
    cudaFuncSetAttribute(mma_gemm_gelu<2>, cudaFuncAttributeMaxDynamicSharedMemorySize, SMEM_T(2));
    cudaFuncSetAttribute(mma_gemm_qkv<2>,  cudaFuncAttributeMaxDynamicSharedMemorySize, SMEM_T(2));
    cudaFuncSetAttribute(mma_gemm_f<3>,    cudaFuncAttributeMaxDynamicSharedMemorySize, SMEM_T(3));
    cudaFuncSetAttribute(mma_gemm_gelu<3>, cudaFuncAttributeMaxDynamicSharedMemorySize, SMEM_T(3));
    cudaFuncSetAttribute(mma_gemm_qkv<3>,  cudaFuncAttributeMaxDynamicSharedMemorySize, SMEM_T(3));

    // ---- batched weight prep (hi + lo) ----
    PrepPtrs pp;
    for (int i = 0; i < 6; i++) { pp.p[i] = (const float*)d_in[9+i]; pp.p[6+i] = (const float*)d_in[15+i]; }
    prep_all<<<dim3(2304, 12), dim3(32,8)>>>(pp, P.whi, P.wlo);

    // ---- candidate path (BERT weights), 2-term: affects prob only ----
    prefix_kernel<<<NCDD,256>>>(cdd_sub, cdd_mask, cdd_am, P.pre, P.atC);
    pool_kernel<<<dim3(NCDD, DMODEL/128),128>>>(P.pre, cdd_enc, emb, P.x, P.xh, P.xl);
    run_transformer_t<2>(NCDD, SEQ, P.whi, P.wlo, P.atC);
    sgemm_proj<<<dim3(DMODEL/64, 1),256>>>(P.h, (size_t)SEQ*DMODEL, projW, P.cddr, NCDD, DMODEL, DMODEL, projb);

    // ---- history path (encN weights), 3-term: determines kid ----
    prefix_kernel<<<NHIS,256>>>(his_sub, his_mask, his_am, P.pre, P.atH);
    pool_kernel<<<dim3(NHIS, DMODEL/128),128>>>(P.pre, his_enc, emb, P.x, P.xh, P.xl);
    run_transformer_t<3>(NHIS, SEQ, P.whi+WSET, P.wlo+WSET, P.atH);
    gather_cls_kernel<<<NHIS,256>>>(P.h, P.cls, SEQ);
    user0_kernel<<<BB,256>>>(P.cls, qU, P.u0);
    topk_kernel<<<BB*HISN,256>>>(P.h, P.u0, P.atH, P.kid, P.x, P.xh, P.xl, P.psm);

    // ---- user path over selected terms (BERT weights), 2-term: prob only ----
    run_transformer_t<2>(BB, LUSR, P.whi, P.wlo, P.psm);
    sgemm_proj<<<dim3(DMODEL/64, 1),256>>>(P.h, (size_t)LUSR*DMODEL, projW, P.ur, BB, DMODEL, DMODEL, projb);

    // ---- outputs ----
    final_kernel<<<BB + (BB*HISN*KSEL + 255)/256, 256>>>(P.cddr, P.ur, P.kid, out);
}

// round 10
// speedup vs baseline: 3.1969x; 1.0326x over previous
#include <cuda_runtime.h>
#include <cuda_fp16.h>
#include <math.h>
#include <stdint.h>

#define BB     8
#define CDDN   5
#define HISN   50
#define SEQ    64
#define DMODEL 768
#define NHEAD  12
#define FFDIM  3072
#define KSEL   8

#define NCDD   (BB*CDDN)     // 40
#define NHIS   (BB*HISN)     // 400
#define LUSR   400           // user seq len
#define LPAD   448
#define ROWS_MAX (NHIS*SEQ)  // 25600

#define WOFF_Q  0
#define WOFF_K  589824
#define WOFF_V  1179648
#define WOFF_O  1769472
#define WOFF_1  2359296
#define WOFF_2  4718592
#define WSET    7077888

// ---------------- scratch ----------------
__device__ float g_x [ (size_t)ROWS_MAX*DMODEL ];
__device__ float g_q [ (size_t)ROWS_MAX*DMODEL ];
__device__ float g_k [ (size_t)ROWS_MAX*DMODEL ];
__device__ float g_v [ (size_t)ROWS_MAX*DMODEL ];
__device__ float g_h [ (size_t)ROWS_MAX*DMODEL ];
__device__ float g_lg[ (size_t)BB*NHEAD*LUSR*LUSR ];
__device__ float g_pre[(size_t)NHIS*SEQ*SEQ ];
__device__ float g_atC[ NCDD*SEQ ];
__device__ float g_atH[ NHIS*SEQ ];
__device__ float g_cls[ (size_t)NHIS*DMODEL ];
__device__ float g_cddr[(size_t)NCDD*DMODEL ];
__device__ float g_u0 [ BB*DMODEL ];
__device__ float g_ur [ BB*DMODEL ];
__device__ float g_psm[ BB*LUSR ];
__device__ int   g_kid[ BB*HISN*KSEL ];
// fp16 weights [N,K] hi + lo, two sets
__device__ unsigned short g_whi[ (size_t)2*WSET ];
__device__ unsigned short g_wlo[ (size_t)2*WSET ];
// split-fp16 activations
__device__ unsigned short g_xh[ (size_t)ROWS_MAX*DMODEL ];
__device__ unsigned short g_xl[ (size_t)ROWS_MAX*DMODEL ];
__device__ unsigned short g_oh[ (size_t)ROWS_MAX*DMODEL ];
__device__ unsigned short g_ol[ (size_t)ROWS_MAX*DMODEL ];
__device__ unsigned short g_hh[ (size_t)ROWS_MAX*DMODEL ];
__device__ unsigned short g_hl[ (size_t)ROWS_MAX*DMODEL ];
__device__ unsigned short g_fh[ (size_t)ROWS_MAX*FFDIM ];
__device__ unsigned short g_fl[ (size_t)ROWS_MAX*FFDIM ];
// user-path fp16 attention buffers
__device__ unsigned short g_q16[ (size_t)BB*LPAD*DMODEL ];
__device__ unsigned short g_k16[ (size_t)BB*LPAD*DMODEL ];
__device__ unsigned short g_vt [ (size_t)BB*DMODEL*LPAD ];
__device__ unsigned short g_p16[ (size_t)BB*NHEAD*LPAD*LPAD ];

// ---------------- low-level helpers ----------------
__device__ __forceinline__ void cp16(uint32_t s, const void* g){
    asm volatile("cp.async.ca.shared.global [%0], [%1], 16;\n" :: "r"(s), "l"(g));
}
__device__ __forceinline__ void cp_commit(){ asm volatile("cp.async.commit_group;\n"); }
template<int N>
__device__ __forceinline__ void cp_wait(){ asm volatile("cp.async.wait_group %0;\n" :: "n"(N)); }

__device__ __forceinline__ uint32_t smem_u32(const void* p) {
    uint32_t a;
    asm("{ .reg .u64 t; cvta.to.shared.u64 t, %1; cvt.u32.u64 %0, t; }" : "=r"(a) : "l"(p));
    return a;
}
__device__ __forceinline__ void ldsm_x4(uint32_t* r, uint32_t addr){
    asm volatile("ldmatrix.sync.aligned.m8n8.x4.shared.b16 {%0,%1,%2,%3}, [%4];"
        : "=r"(r[0]),"=r"(r[1]),"=r"(r[2]),"=r"(r[3]) : "r"(addr));
}
__device__ __forceinline__ void mma_f16(float* c, const uint32_t* a, const uint32_t* b){
    asm volatile("mma.sync.aligned.m16n8k16.row.col.f32.f16.f16.f32 "
        "{%0,%1,%2,%3}, {%4,%5,%6,%7}, {%8,%9}, {%0,%1,%2,%3};"
        : "+f"(c[0]),"+f"(c[1]),"+f"(c[2]),"+f"(c[3])
        : "r"(a[0]),"r"(a[1]),"r"(a[2]),"r"(a[3]), "r"(b[0]),"r"(b[1]));
}
__device__ __forceinline__ void split2(float v, unsigned short& h, unsigned short& l){
    __half hh = __float2half_rn(v);
    __half ll = __float2half_rn(v - __half2float(hh));
    h = __half_as_ushort(hh);
    l = __half_as_ushort(ll);
}
__device__ __forceinline__ unsigned short h16(float v){
    return __half_as_ushort(__float2half_rn(v));
}

// ---------------- reductions ----------------
__device__ __forceinline__ float warp_sum(float v){
    #pragma unroll
    for(int o=16;o;o>>=1) v += __shfl_xor_sync(0xffffffffu, v, o);
    return v;
}
__device__ __forceinline__ float warp_max(float v){
    #pragma unroll
    for(int o=16;o;o>>=1) v = fmaxf(v, __shfl_xor_sync(0xffffffffu, v, o));
    return v;
}
__device__ float block_sum(float v){
    __shared__ float red[33];
    int lane=threadIdx.x&31, w=threadIdx.x>>5, nw=blockDim.x>>5;
    v = warp_sum(v);
    __syncthreads();
    if(lane==0) red[w]=v;
    __syncthreads();
    if(threadIdx.x==0){ float t=0.f; for(int i=0;i<nw;i++) t+=red[i]; red[32]=t; }
    __syncthreads();
    return red[32];
}
__device__ float block_max(float v){
    __shared__ float red[33];
    int lane=threadIdx.x&31, w=threadIdx.x>>5, nw=blockDim.x>>5;
    v = warp_max(v);
    __syncthreads();
    if(lane==0) red[w]=v;
    __syncthreads();
    if(threadIdx.x==0){ float t=red[0]; for(int i=1;i<nw;i++) t=fmaxf(t,red[i]); red[32]=t; }
    __syncthreads();
    return red[32];
}

// ---------------- batched weight prep ----------------
struct PrepPtrs { const float* p[12]; };
__constant__ size_t c_woffs[6] = { WOFF_Q, WOFF_K, WOFF_V, WOFF_O, WOFF_1, WOFF_2 };

__global__ void prep_all(PrepPtrs ptrs, unsigned short* __restrict__ Th,
                         unsigned short* __restrict__ Tl)
{
    int w = blockIdx.y;
    int wi = w % 6;
    int K = (wi==5) ? FFDIM : DMODEL;
    int N = (wi==4) ? FFDIM : DMODEL;
    int ntx = N >> 5;
    int tiles = (K >> 5) * ntx;
    int t = blockIdx.x;
    if (t >= tiles) return;
    int nb = (t % ntx) << 5, kb = (t / ntx) << 5;
    const float* W = ptrs.p[w];
    size_t base = c_woffs[wi] + (size_t)(w/6)*WSET;

    __shared__ float tbuf[32][33];
    int x = threadIdx.x, y = threadIdx.y;
    for (int i=y;i<32;i+=8)
        tbuf[i][x] = W[(size_t)(kb+i)*N + nb + x];
    __syncthreads();
    for (int i=y;i<32;i+=8) {
        unsigned short h, l;
        split2(tbuf[x][i], h, l);
        size_t dst = base + (size_t)(nb+i)*K + kb + x;
        Th[dst] = h;
        Tl[dst] = l;
    }
}

// ---------------- mma.sync split-fp16 GEMM ----------------
// EPI 0: fp32 C.  EPI 1: gelu -> fp16 hi/lo.  EPI 3: fp16 [n][LPAD][768].  EPI 4: fp16 vt [n][768][LPAD].
#define APAD 40
#define ARR_B  (128*APAD*2)
#define SMEM_T(T) (2*((T)+1)*ARR_B)

template<int EPI, int TERMS>
__device__ __forceinline__ void mma_body(const unsigned short* __restrict__ Ah,
                                         const unsigned short* __restrict__ Al,
                                         const unsigned short* __restrict__ Bh,
                                         const unsigned short* __restrict__ Bl,
                                         float* __restrict__ C,
                                         unsigned short* __restrict__ Ch,
                                         unsigned short* __restrict__ Cl,
                                         int M, int N, int K)
{
    extern __shared__ char sm[];
    const uint32_t sbase = smem_u32(sm);
    const int tid = threadIdx.x, lane = tid & 31, wid = tid >> 5;
    const int wm = wid >> 2, wn = wid & 3;
    const int rowBlk = blockIdx.y << 7, colBlk = blockIdx.x << 7;
    const uint32_t STG = (TERMS+1)*ARR_B;

    int r0 = tid >> 2,        s0 = (tid & 3) << 3;
    int r1 = (tid+256) >> 2,  s1 = ((tid+256) & 3) << 3;
    const unsigned short* gA[2] = {Ah, Al};

    const int nc = K >> 5;
    #pragma unroll
    for (int p=0;p<2;p++) {
        cp16(sbase + p*ARR_B + (uint32_t)(r0*APAD + s0)*2, gA[p] + (size_t)(rowBlk+r0)*K + s0);
        cp16(sbase + p*ARR_B + (uint32_t)(r1*APAD + s1)*2, gA[p] + (size_t)(rowBlk+r1)*K + s1);
    }
    cp16(sbase + 2*ARR_B + (uint32_t)(r0*APAD + s0)*2, Bh + (size_t)(colBlk+r0)*K + s0);
    cp16(sbase + 2*ARR_B + (uint32_t)(r1*APAD + s1)*2, Bh + (size_t)(colBlk+r1)*K + s1);
    if (TERMS == 3) {
        cp16(sbase + 3*ARR_B + (uint32_t)(r0*APAD + s0)*2, Bl + (size_t)(colBlk+r0)*K + s0);
        cp16(sbase + 3*ARR_B + (uint32_t)(r1*APAD + s1)*2, Bl + (size_t)(colBlk+r1)*K + s1);
    }
    cp_commit();

    const uint32_t aoff = (uint32_t)((wm*64 + (lane & 15))*APAD + 8*(lane >> 4)) * 2;
    const uint32_t boff = (uint32_t)((wn*32 + (lane & 7) + 8*(lane >> 4))*APAD + 8*((lane >> 3) & 1)) * 2;

    float acc[4][4][4] = {};

    for (int c = 0; c < nc; c++) {
        const bool has = (c+1 < nc);
        if (has) {
            int kb = (c+1) << 5;
            uint32_t st = ((c+1) & 1) * STG;
            #pragma unroll
            for (int p=0;p<2;p++) {
                cp16(sbase + st + p*ARR_B + (uint32_t)(r0*APAD + s0)*2, gA[p] + (size_t)(rowBlk+r0)*K + kb + s0);
                cp16(sbase + st + p*ARR_B + (uint32_t)(r1*APAD + s1)*2, gA[p] + (size_t)(rowBlk+r1)*K + kb + s1);
            }
            cp16(sbase + st + 2*ARR_B + (uint32_t)(r0*APAD + s0)*2, Bh + (size_t)(colBlk+r0)*K + kb + s0);
            cp16(sbase + st + 2*ARR_B + (uint32_t)(r1*APAD + s1)*2, Bh + (size_t)(colBlk+r1)*K + kb + s1);
            if (TERMS == 3) {
                cp16(sbase + st + 3*ARR_B + (uint32_t)(r0*APAD + s0)*2, Bl + (size_t)(colBlk+r0)*K + kb + s0);
                cp16(sbase + st + 3*ARR_B + (uint32_t)(r1*APAD + s1)*2, Bl + (size_t)(colBlk+r1)*K + kb + s1);
            }
            cp_commit();
            cp_wait<1>();
        } else {
            cp_wait<0>();
        }
        __syncthreads();

        uint32_t st = (c & 1) * STG;
        uint32_t aH = sbase + st + aoff;
        uint32_t aL = aH + ARR_B;
        uint32_t bH = sbase + st + 2*ARR_B + boff;
        uint32_t bL = bH + ARR_B;

        #pragma unroll
        for (int ks = 0; ks < 2; ks++) {
            uint32_t ko = (uint32_t)(ks*16*2);
            uint32_t ahf[4][4], alf[4][4], bhf[2][4], blf[2][4];
            #pragma unroll
            for (int mt=0;mt<4;mt++) ldsm_x4(ahf[mt], aH + ko + (uint32_t)(mt*16*APAD*2));
            #pragma unroll
            for (int np=0;np<2;np++) ldsm_x4(bhf[np], bH + ko + (uint32_t)(np*16*APAD*2));
            if (TERMS == 3) {
                #pragma unroll
                for (int np=0;np<2;np++) ldsm_x4(blf[np], bL + ko + (uint32_t)(np*16*APAD*2));
            }
            #pragma unroll
            for (int mt=0;mt<4;mt++)
                #pragma unroll
                for (int nt=0;nt<4;nt++)
                    mma_f16(acc[mt][nt], ahf[mt], &bhf[nt>>1][(nt&1)*2]);
            #pragma unroll
            for (int mt=0;mt<4;mt++) ldsm_x4(alf[mt], aL + ko + (uint32_t)(mt*16*APAD*2));
            if (TERMS == 3) {
                #pragma unroll
                for (int mt=0;mt<4;mt++)
                    #pragma unroll
                    for (int nt=0;nt<4;nt++)
                        mma_f16(acc[mt][nt], ahf[mt], &blf[nt>>1][(nt&1)*2]);
            }
            #pragma unroll
            for (int mt=0;mt<4;mt++)
                #pragma unroll
                for (int nt=0;nt<4;nt++)
                    mma_f16(acc[mt][nt], alf[mt], &bhf[nt>>1][(nt&1)*2]);
        }
        __syncthreads();
    }

    #pragma unroll
    for (int mt=0;mt<4;mt++) {
        int row = rowBlk + wm*64 + mt*16 + (lane >> 2);
        #pragma unroll
        for (int nt=0;nt<4;nt++) {
            int col = colBlk + wn*32 + nt*8 + (lane & 3)*2;
            float v[4] = {acc[mt][nt][0], acc[mt][nt][1], acc[mt][nt][2], acc[mt][nt][3]};
            if (EPI == 0) {
                *(float2*)(C + (size_t)row*N + col)     = make_float2(v[0], v[1]);
                *(float2*)(C + (size_t)(row+8)*N + col) = make_float2(v[2], v[3]);
            } else if (EPI == 1) {
                #pragma unroll
                for (int j=0;j<4;j++) {
                    float t = v[j];
                    v[j] = 0.5f*t*(1.f + tanhf(0.7978845608028654f*(t + 0.044715f*t*t*t)));
                }
                unsigned short h0,l0,h1,l1;
                split2(v[0], h0, l0); split2(v[1], h1, l1);
                *(uint32_t*)(Ch + (size_t)row*N + col) = (uint32_t)h0 | ((uint32_t)h1<<16);
                *(uint32_t*)(Cl + (size_t)row*N + col) = (uint32_t)l0 | ((uint32_t)l1<<16);
                split2(v[2], h0, l0); split2(v[3], h1, l1);
                *(uint32_t*)(Ch + (size_t)(row+8)*N + col) = (uint32_t)h0 | ((uint32_t)h1<<16);
                *(uint32_t*)(Cl + (size_t)(row+8)*N + col) = (uint32_t)l0 | ((uint32_t)l1<<16);
            } else if (EPI == 3) {
                int n0 = row / LUSR, l0i = row - n0*LUSR;
                *(uint32_t*)(Ch + ((size_t)n0*LPAD + l0i)*DMODEL + col) =
                    (uint32_t)h16(v[0]) | ((uint32_t)h16(v[1])<<16);
                int n1 = (row+8) / LUSR, l1i = (row+8) - n1*LUSR;
                *(uint32_t*)(Ch + ((size_t)n1*LPAD + l1i)*DMODEL + col) =
                    (uint32_t)h16(v[2]) | ((uint32_t)h16(v[3])<<16);
            } else { // EPI == 4 : transposed V
                int n0 = row / LUSR, l0i = row - n0*LUSR;
                Ch[((size_t)n0*DMODEL + col  )*LPAD + l0i] = h16(v[0]);
                Ch[((size_t)n0*DMODEL + col+1)*LPAD + l0i] = h16(v[1]);
                int n1 = (row+8) / LUSR, l1i = (row+8) - n1*LUSR;
                Ch[((size_t)n1*DMODEL + col  )*LPAD + l1i] = h16(v[2]);
                Ch[((size_t)n1*DMODEL + col+1)*LPAD + l1i] = h16(v[3]);
            }
        }
    }
}

template<int TERMS>
__global__ __launch_bounds__(256, 2) void mma_gemm_f(const unsigned short* __restrict__ Ah,
                                                     const unsigned short* __restrict__ Al,
                                                     const unsigned short* __restrict__ Bh,
                                                     const unsigned short* __restrict__ Bl,
                                                     float* __restrict__ C,
                                                     int M, int N, int K)
{
    mma_body<0, TERMS>(Ah, Al, Bh, Bl, C, nullptr, nullptr, M, N, K);
}

template<int TERMS>
__global__ __launch_bounds__(256, 2) void mma_gemm_gelu(const unsigned short* __restrict__ Ah,
                                                        const unsigned short* __restrict__ Al,
                                                        const unsigned short* __restrict__ Bh,
                                                        const unsigned short* __restrict__ Bl,
                                                        unsigned short* __restrict__ Ch,
                                                        unsigned short* __restrict__ Cl,
                                                        int M, int N, int K)
{
    mma_body<1, TERMS>(Ah, Al, Bh, Bl, nullptr, Ch, Cl, M, N, K);
}

template<int TERMS>
__global__ __launch_bounds__(256, 2) void mma_gemm_qkv(const unsigned short* __restrict__ Ah,
                                                       const unsigned short* __restrict__ Al,
                                                       const unsigned short* __restrict__ Wh,
                                                       const unsigned short* __restrict__ Wl,
                                                       float* __restrict__ Cq,
                                                       float* __restrict__ Ck,
                                                       float* __restrict__ Cv,
                                                       int M)
{
    const unsigned short* bh = Wh + (size_t)blockIdx.z*589824;
    const unsigned short* bl = Wl + (size_t)blockIdx.z*589824;
    float* C = (blockIdx.z==0) ? Cq : (blockIdx.z==1) ? Ck : Cv;
    mma_body<0, TERMS>(Ah, Al, bh, bl, C, nullptr, nullptr, M, DMODEL, DMODEL);
}

// user-path QKV: emits fp16 q16/k16 ([n][LPAD][768]) and vt ([n][768][LPAD])
__global__ __launch_bounds__(256, 2) void mma_gemm_qkv16(const unsigned short* __restrict__ Ah,
                                                         const unsigned short* __restrict__ Al,
                                                         const unsigned short* __restrict__ Wh,
                                                         const unsigned short* __restrict__ Wl,
                                                         unsigned short* __restrict__ q16,
                                                         unsigned short* __restrict__ k16,
                                                         unsigned short* __restrict__ vt,
                                                         int M)
{
    const unsigned short* bh = Wh + (size_t)blockIdx.z*589824;
    const unsigned short* bl = Wl + (size_t)blockIdx.z*589824;
    if (blockIdx.z == 0)
        mma_body<3, 2>(Ah, Al, bh, bl, nullptr, q16, nullptr, M, DMODEL, DMODEL);
    else if (blockIdx.z == 1)
        mma_body<3, 2>(Ah, Al, bh, bl, nullptr, k16, nullptr, M, DMODEL, DMODEL);
    else
        mma_body<4, 2>(Ah, Al, bh, bl, nullptr, vt, nullptr, M, DMODEL, DMODEL);
}

// ---------------- fp16 tile attention (user path, L=400) ----------------
// logits: C[q,kc] = (Q·K^T)*0.125 + maskbias ; 64x64 tile per block, 4 warps
__global__ __launch_bounds__(128) void logits_mma(const unsigned short* __restrict__ q16,
                                                  const unsigned short* __restrict__ k16,
                                                  const float* __restrict__ mask,
                                                  float* __restrict__ lg)
{
    __shared__ __align__(16) unsigned short Qs[64][72];
    __shared__ __align__(16) unsigned short Ks[64][72];
    int n = blockIdx.z, h = blockIdx.y;
    int qt = blockIdx.x / 7, kt = blockIdx.x % 7;
    int tid = threadIdx.x, lane = tid & 31, wid = tid >> 5;
    int wm = wid >> 1, wn = wid & 1;
    for (int i = tid; i < 64*8; i += 128) {
        int r = i >> 3, cg = (i & 7) << 3;
        *(uint4*)&Qs[r][cg] = *(const uint4*)(q16 + ((size_t)n*LPAD + qt*64 + r)*DMODEL + h*64 + cg);
        *(uint4*)&Ks[r][cg] = *(const uint4*)(k16 + ((size_t)n*LPAD + kt*64 + r)*DMODEL + h*64 + cg);
    }
    __syncthreads();
    uint32_t aoff = smem_u32(Qs) + (uint32_t)((wm*32 + (lane & 15))*72 + 8*(lane >> 4))*2;
    uint32_t boff = smem_u32(Ks) + (uint32_t)((wn*32 + (lane & 7) + 8*(lane >> 4))*72 + 8*((lane >> 3) & 1))*2;
    float acc[2][4][4] = {};
    #pragma unroll
    for (int k0 = 0; k0 < 64; k0 += 16) {
        uint32_t af[2][4], bf[2][4];
        #pragma unroll
        for (int mt=0;mt<2;mt++) ldsm_x4(af[mt], aoff + k0*2 + (uint32_t)(mt*16*72*2));
        #pragma unroll
        for (int np=0;np<2;np++) ldsm_x4(bf[np], boff + k0*2 + (uint32_t)(np*16*72*2));
        #pragma unroll
        for (int mt=0;mt<2;mt++)
            #pragma unroll
            for (int nt=0;nt<4;nt++)
                mma_f16(acc[mt][nt], af[mt], &bf[nt>>1][(nt&1)*2]);
    }
    #pragma unroll
    for (int mt=0;mt<2;mt++) {
        int qr = qt*64 + wm*32 + mt*16 + (lane >> 2);
        #pragma unroll
        for (int nt=0;nt<4;nt++) {
            int kc = kt*64 + wn*32 + nt*8 + (lane & 3)*2;
            #pragma unroll
            for (int half2i=0;half2i<2;half2i++) {
                int qrr = qr + half2i*8;
                if (qrr >= LUSR) continue;
                float* dst = lg + (((size_t)(n*NHEAD + h)*LUSR + qrr)*LUSR);
                float v0 = acc[mt][nt][half2i*2+0], v1 = acc[mt][nt][half2i*2+1];
                if (kc < LUSR)
                    dst[kc]   = v0*0.125f + ((mask[(size_t)n*LUSR + kc]   > 0.f) ? 0.f : -1e9f);
                if (kc+1 < LUSR)
                    dst[kc+1] = v1*0.125f + ((mask[(size_t)n*LUSR + kc+1] > 0.f) ? 0.f : -1e9f);
            }
        }
    }
}

// softmax: reads lg, writes fp16 probs with zero padding to LPAD
__global__ void softmax_p16(const float* __restrict__ lg, unsigned short* __restrict__ p16)
{
    __shared__ float buf[LUSR];
    int bi = blockIdx.x;              // (n*NHEAD+h)*LUSR + q
    int nh = bi / LUSR, q = bi - nh*LUSR;
    const float* p = lg + (size_t)bi * LUSR;
    int tid = threadIdx.x;
    float m = -3.4e38f;
    for (int i=tid;i<LUSR;i+=blockDim.x) { buf[i] = p[i]; m = fmaxf(m, buf[i]); }
    m = block_max(m);
    float s = 0.f;
    for (int i=tid;i<LUSR;i+=blockDim.x) { float e = expf(buf[i]-m); buf[i]=e; s+=e; }
    s = block_sum(s);
    float inv = 1.f/s;
    unsigned short* dst = p16 + ((size_t)nh*LPAD + q)*LPAD;
    for (int i=tid;i<LPAD;i+=blockDim.x)
        dst[i] = h16((i < LUSR) ? buf[i]*inv : 0.f);
}

// av: O[q,d] = sum_k P[q,k] V[k,d]; A = p16 tile, B = vt rows (dhead) x k
__global__ __launch_bounds__(128) void av_mma(const unsigned short* __restrict__ p16,
                                              const unsigned short* __restrict__ vt,
                                              unsigned short* __restrict__ Oh,
                                              unsigned short* __restrict__ Ol)
{
    __shared__ __align__(16) unsigned short As[64][72];
    __shared__ __align__(16) unsigned short Bs[64][72];
    int n = blockIdx.z, h = blockIdx.y, qt = blockIdx.x;
    int tid = threadIdx.x, lane = tid & 31, wid = tid >> 5;
    int wm = wid >> 1, wn = wid & 1;
    uint32_t aoff = smem_u32(As) + (uint32_t)((wm*32 + (lane & 15))*72 + 8*(lane >> 4))*2;
    uint32_t boff = smem_u32(Bs) + (uint32_t)((wn*32 + (lane & 7) + 8*(lane >> 4))*72 + 8*((lane >> 3) & 1))*2;
    float acc[2][4][4] = {};
    for (int c = 0; c < 7; c++) {
        for (int i = tid; i < 64*8; i += 128) {
            int r = i >> 3, cg = (i & 7) << 3;
            *(uint4*)&As[r][cg] = *(const uint4*)(p16 + ((size_t)(n*NHEAD + h)*LPAD + qt*64 + r)*LPAD + c*64 + cg);
            *(uint4*)&Bs[r][cg] = *(const uint4*)(vt  + ((size_t)n*DMODEL + h*64 + r)*LPAD + c*64 + cg);
        }
        __syncthreads();
        #pragma unroll
        for (int k0 = 0; k0 < 64; k0 += 16) {
            uint32_t af[2][4], bf[2][4];
            #pragma unroll
            for (int mt=0;mt<2;mt++) ldsm_x4(af[mt], aoff + k0*2 + (uint32_t)(mt*16*72*2));
            #pragma unroll
            for (int np=0;np<2;np++) ldsm_x4(bf[np], boff + k0*2 + (uint32_t)(np*16*72*2));
            #pragma unroll
            for (int mt=0;mt<2;mt++)
                #pragma unroll
                for (int nt=0;nt<4;nt++)
                    mma_f16(acc[mt][nt], af[mt], &bf[nt>>1][(nt&1)*2]);
        }
        __syncthreads();
    }
    #pragma unroll
    for (int mt=0;mt<2;mt++) {
        int l0 = qt*64 + wm*32 + mt*16 + (lane >> 2);
        #pragma unroll
        for (int nt=0;nt<4;nt++) {
            int d = wn*32 + nt*8 + (lane & 3)*2;
            #pragma unroll
            for (int half2i=0;half2i<2;half2i++) {
                int l = l0 + half2i*8;
                if (l >= LUSR) continue;
                float v0 = acc[mt][nt][half2i*2+0], v1 = acc[mt][nt][half2i*2+1];
                size_t off = ((size_t)n*LUSR + l)*DMODEL + h*64 + d;
                unsigned short hh0, ll0, hh1, ll1;
                split2(v0, hh0, ll0); split2(v1, hh1, ll1);
                *(uint32_t*)(Oh + off) = (uint32_t)hh0 | ((uint32_t)hh1<<16);
                *(uint32_t*)(Ol + off) = (uint32_t)ll0 | ((uint32_t)ll1<<16);
            }
        }
    }
}

// ---------------- prefix build ----------------
__global__ void prefix_kernel(const int* __restrict__ sub, const float* __restrict__ mask,
                              const float* __restrict__ amask,
                              float* __restrict__ prefix, float* __restrict__ attn)
{
    __shared__ float P[SEQ*SEQ];
    int bn = blockIdx.x;
    for (int i = threadIdx.x; i < SEQ*SEQ; i += blockDim.x) P[i] = 0.f;
    __syncthreads();
    const int* si = sub + (size_t)bn*SEQ*2;
    for (int s = threadIdx.x; s < SEQ; s += blockDim.x) {
        int i = si[2*s+0], j = si[2*s+1];
        P[i*SEQ + j] = 1.f;
    }
    __syncthreads();
    float m = mask[bn];
    int lane = threadIdx.x & 31, warp = threadIdx.x >> 5;
    for (int i = warp; i < SEQ; i += (blockDim.x >> 5)) {
        float v0 = P[i*SEQ + lane]      * m;
        float v1 = P[i*SEQ + lane + 32] * m;
        float rs = v0 + v1;
        float ad = v0 * amask[bn*SEQ + lane] + v1 * amask[bn*SEQ + lane + 32];
        #pragma unroll
        for (int o=16;o;o>>=1){ rs += __shfl_xor_sync(0xffffffffu,rs,o); ad += __shfl_xor_sync(0xffffffffu,ad,o); }
        float denom = fmaxf(rs, 1e-12f);
        prefix[(size_t)bn*SEQ*SEQ + i*SEQ + lane]      = v0/denom;
        prefix[(size_t)bn*SEQ*SEQ + i*SEQ + lane + 32] = v1/denom;
        if (lane==0) attn[bn*SEQ + i] = ad/denom;
    }
}

// ---------------- embedding pooling ----------------
__global__ void pool_kernel(const float* __restrict__ prefix, const int* __restrict__ enc,
                            const float* __restrict__ emb, float* __restrict__ x,
                            unsigned short* __restrict__ xh, unsigned short* __restrict__ xl)
{
    __shared__ float P[SEQ*SEQ];
    __shared__ int idx[SEQ];
    int bn = blockIdx.x;
    int d  = blockIdx.y*128 + threadIdx.x;
    for (int i = threadIdx.x; i < SEQ*SEQ; i += blockDim.x)
        P[i] = prefix[(size_t)bn*SEQ*SEQ + i];
    if (threadIdx.x < SEQ) idx[threadIdx.x] = enc[(size_t)bn*SEQ + threadIdx.x];
    __syncthreads();
    float acc[SEQ];
    #pragma unroll
    for (int i=0;i<SEQ;i++) acc[i]=0.f;
    for (int j=0;j<SEQ;j++) {
        float e = emb[(size_t)idx[j]*DMODEL + d];
        #pragma unroll
        for (int i=0;i<SEQ;i++) acc[i] = fmaf(P[i*SEQ+j], e, acc[i]);
    }
    for (int i=0;i<SEQ;i++) {
        size_t o = ((size_t)bn*SEQ + i)*DMODEL + d;
        x[o] = acc[i];
        unsigned short h, l;
        split2(acc[i], h, l);
        xh[o] = h; xl[o] = l;
    }
}

// ---------------- strided proj ----------------
__global__ void sgemm_proj(const float* __restrict__ A, size_t lda,
                           const float* __restrict__ B,
                           float* __restrict__ C, int M, int N, int Kd,
                           const float* __restrict__ bias)
{
    __shared__ float As[16][64];
    __shared__ float Bs[16][68];
    int tid = threadIdx.x;
    int rowBase = blockIdx.y << 6, colBase = blockIdx.x << 6;
    int tx = tid & 15, ty = tid >> 4;
    int am = tid >> 2, ak = (tid & 3) << 2;
    int bk = tid >> 4, bn = (tid & 15) << 2;
    bool aok = (rowBase + am) < M;
    const float* Ap = A + (size_t)(rowBase + am)*lda + ak;
    const float* Bp = B + (size_t)bk*N + colBase + bn;
    float acc[4][4] = {};
    for (int k0 = 0; k0 < Kd; k0 += 16) {
        float4 a4 = aok ? *(const float4*)Ap : make_float4(0.f,0.f,0.f,0.f);
        As[ak+0][am]=a4.x; As[ak+1][am]=a4.y; As[ak+2][am]=a4.z; As[ak+3][am]=a4.w;
        *(float4*)&Bs[bk][bn] = *(const float4*)Bp;
        __syncthreads();
        #pragma unroll
        for (int kk=0; kk<16; kk++) {
            float av[4], bv[4];
            #pragma unroll
            for (int i=0;i<4;i++) av[i]=As[kk][(ty<<2)+i];
            #pragma unroll
            for (int j=0;j<4;j++) bv[j]=Bs[kk][(tx<<2)+j];
            #pragma unroll
            for (int i=0;i<4;i++)
                #pragma unroll
                for (int j=0;j<4;j++)
                    acc[i][j] = fmaf(av[i], bv[j], acc[i][j]);
        }
        __syncthreads();
        Ap += 16;
        Bp += (size_t)16*N;
    }
    #pragma unroll
    for (int i=0;i<4;i++) {
        int r = rowBase + (ty<<2) + i;
        if (r >= M) continue;
        #pragma unroll
        for (int j=0;j<4;j++) {
            int c = colBase + (tx<<2) + j;
            C[(size_t)r*N + c] = tanhf(acc[i][j] + bias[c]);
        }
    }
}

// ---------------- fused attention for L=64 (fp32; his/cdd paths) ----------------
__global__ __launch_bounds__(256, 2) void attn64_kernel(const float* __restrict__ Q,
                                                        const float* __restrict__ Km,
                                                        const float* __restrict__ V,
                                                        const float* __restrict__ mask,
                                                        unsigned short* __restrict__ Oh,
                                                        unsigned short* __restrict__ Ol)
{
    __shared__ float Ts0[64][65];
    __shared__ float Ts1[64][65];
    int n = blockIdx.x, h = blockIdx.y;
    int tid = threadIdx.x, tx = tid & 15, ty = tid >> 4;
    for (int i = tid; i < 64*64; i += 256) {
        int r = i >> 6, c = i & 63;
        Ts0[r][c] = Q [((size_t)n*64 + r)*DMODEL + h*64 + c];
        Ts1[r][c] = Km[((size_t)n*64 + r)*DMODEL + h*64 + c];
    }
    __syncthreads();
    float s[4][4] = {};
    #pragma unroll 8
    for (int d = 0; d < 64; d++) {
        float qv[4], kv[4];
        #pragma unroll
        for (int i=0;i<4;i++) qv[i]=Ts0[(ty<<2)+i][d];
        #pragma unroll
        for (int j=0;j<4;j++) kv[j]=Ts1[(tx<<2)+j][d];
        #pragma unroll
        for (int i=0;i<4;i++)
            #pragma unroll
            for (int j=0;j<4;j++)
                s[i][j] = fmaf(qv[i], kv[j], s[i][j]);
    }
    float bias[4];
    #pragma unroll
    for (int j=0;j<4;j++)
        bias[j] = (mask[(size_t)n*64 + (tx<<2)+j] > 0.f) ? 0.f : -1e9f;
    #pragma unroll
    for (int i=0;i<4;i++)
        #pragma unroll
        for (int j=0;j<4;j++)
            s[i][j] = s[i][j]*0.125f + bias[j];
    float rmax[4], rsum[4];
    #pragma unroll
    for (int i=0;i<4;i++) {
        float m = fmaxf(fmaxf(s[i][0],s[i][1]), fmaxf(s[i][2],s[i][3]));
        #pragma unroll
        for (int o=8;o;o>>=1) m = fmaxf(m, __shfl_xor_sync(0xffffffffu, m, o));
        rmax[i] = m;
    }
    #pragma unroll
    for (int i=0;i<4;i++) {
        float t = 0.f;
        #pragma unroll
        for (int j=0;j<4;j++) { s[i][j] = expf(s[i][j]-rmax[i]); t += s[i][j]; }
        #pragma unroll
        for (int o=8;o;o>>=1) t += __shfl_xor_sync(0xffffffffu, t, o);
        rsum[i] = 1.f/t;
    }
    __syncthreads();
    #pragma unroll
    for (int i=0;i<4;i++)
        #pragma unroll
        for (int j=0;j<4;j++)
            Ts0[(ty<<2)+i][(tx<<2)+j] = s[i][j]*rsum[i];
    for (int i = tid; i < 64*64; i += 256) {
        int r = i >> 6, c = i & 63;
        Ts1[r][c] = V[((size_t)n*64 + r)*DMODEL + h*64 + c];
    }
    __syncthreads();
    float o[4][4] = {};
    #pragma unroll 8
    for (int kk=0; kk<64; kk++) {
        float pv[4], vv[4];
        #pragma unroll
        for (int i=0;i<4;i++) pv[i]=Ts0[(ty<<2)+i][kk];
        #pragma unroll
        for (int j=0;j<4;j++) vv[j]=Ts1[kk][(tx<<2)+j];
        #pragma unroll
        for (int i=0;i<4;i++)
            #pragma unroll
            for (int j=0;j<4;j++)
                o[i][j] = fmaf(pv[i], vv[j], o[i][j]);
    }
    #pragma unroll
    for (int i=0;i<4;i++)
        #pragma unroll
        for (int j=0;j<4;j++) {
            size_t off = ((size_t)n*64 + (ty<<2)+i)*DMODEL + h*64 + (tx<<2)+j;
            unsigned short hh, ll;
            split2(o[i][j], hh, ll);
            Oh[off] = hh; Ol[off] = ll;
        }
}

// LN variants
__global__ void ln_split_kernel(const float* __restrict__ x, const float* __restrict__ o,
                                float* __restrict__ out,
                                unsigned short* __restrict__ oh, unsigned short* __restrict__ ol)
{
    __shared__ float buf[DMODEL];
    size_t row = blockIdx.x;
    int tid = threadIdx.x;
    float ls = 0.f;
    for (int i=tid;i<DMODEL;i+=blockDim.x) {
        float v = x[row*DMODEL+i] + o[row*DMODEL+i];
        buf[i] = v; ls += v;
    }
    float mu = block_sum(ls) * (1.f/DMODEL);
    float lv = 0.f;
    for (int i=tid;i<DMODEL;i+=blockDim.x) { float d = buf[i]-mu; lv += d*d; }
    float var = block_sum(lv) * (1.f/DMODEL);
    float inv = rsqrtf(var + 1e-12f);
    for (int i=tid;i<DMODEL;i+=blockDim.x) {
        float v = (buf[i]-mu)*inv;
        out[row*DMODEL+i] = v;
        unsigned short h, l;
        split2(v, h, l);
        oh[row*DMODEL+i] = h; ol[row*DMODEL+i] = l;
    }
}

__global__ void ln_kernel(const float* __restrict__ x, const float* __restrict__ o,
                          float* __restrict__ out)
{
    __shared__ float buf[DMODEL];
    size_t row = blockIdx.x;
    int tid = threadIdx.x;
    float ls = 0.f;
    for (int i=tid;i<DMODEL;i+=blockDim.x) {
        float v = x[row*DMODEL+i] + o[row*DMODEL+i];
        buf[i] = v; ls += v;
    }
    float mu = block_sum(ls) * (1.f/DMODEL);
    float lv = 0.f;
    for (int i=tid;i<DMODEL;i+=blockDim.x) { float d = buf[i]-mu; lv += d*d; }
    float var = block_sum(lv) * (1.f/DMODEL);
    float inv = rsqrtf(var + 1e-12f);
    for (int i=tid;i<DMODEL;i+=blockDim.x) out[row*DMODEL+i] = (buf[i]-mu)*inv;
}

__global__ void gather_cls_kernel(const float* __restrict__ h, float* __restrict__ cls, int L)
{
    int n = blockIdx.x;
    for (int d=threadIdx.x; d<DMODEL; d+=blockDim.x)
        cls[(size_t)n*DMODEL + d] = h[(size_t)n*L*DMODEL + d];
}

__global__ void user0_kernel(const float* __restrict__ cls, const float* __restrict__ qU,
                             float* __restrict__ u0)
{
    int b = blockIdx.x;
    __shared__ float w[HISN];
    int lane = threadIdx.x & 31, wp = threadIdx.x >> 5;
    for (int n = wp; n < HISN; n += (blockDim.x >> 5)) {
        const float* c = cls + (size_t)(b*HISN + n)*DMODEL;
        float acc = 0.f;
        for (int d = lane; d < DMODEL; d += 32) acc += c[d]*qU[d];
        acc = warp_sum(acc);
        if (lane==0) w[n] = acc / sqrtf(768.f);
    }
    __syncthreads();
    if (threadIdx.x == 0) {
        float m = w[0];
        for (int n=1;n<HISN;n++) m = fmaxf(m, w[n]);
        float s = 0.f;
        for (int n=0;n<HISN;n++){ w[n] = expf(w[n]-m); s += w[n]; }
        float inv = 1.f/s;
        for (int n=0;n<HISN;n++) w[n] *= inv;
    }
    __syncthreads();
    for (int d=threadIdx.x; d<DMODEL; d+=blockDim.x) {
        float acc = 0.f;
        for (int n=0;n<HISN;n++) acc += w[n]*cls[(size_t)(b*HISN+n)*DMODEL + d];
        u0[b*DMODEL + d] = acc;
    }
}

__global__ void topk_kernel(const float* __restrict__ hidden, const float* __restrict__ u0,
                            const float* __restrict__ attn, int* __restrict__ kid,
                            float* __restrict__ ps,
                            unsigned short* __restrict__ psh, unsigned short* __restrict__ psl,
                            float* __restrict__ psm)
{
    int bn = blockIdx.x;
    int b = bn / HISN, n = bn - b*HISN;
    __shared__ float u[DMODEL];
    __shared__ float sc[SEQ];
    __shared__ int sel[KSEL];
    for (int d=threadIdx.x; d<DMODEL; d+=blockDim.x) u[d] = u0[b*DMODEL + d];
    __syncthreads();
    int lane = threadIdx.x & 31, wp = threadIdx.x >> 5;
    for (int s = wp; s < SEQ; s += (blockDim.x >> 5)) {
        const float* hr = hidden + (size_t)(bn*SEQ + s)*DMODEL;
        float acc = 0.f;
        for (int d = lane; d < DMODEL; d += 32) acc += hr[d]*u[d];
        acc = warp_sum(acc);
        if (lane==0)
            sc[s] = (attn[(size_t)bn*SEQ + s] > 0.f) ? acc / sqrtf(768.f) : -1e9f;
    }
    __syncthreads();
    if (threadIdx.x == 0) {
        bool used[SEQ];
        for (int s=0;s<SEQ;s++) used[s]=false;
        for (int kk=0; kk<KSEL; kk++) {
            float best = -3.4e38f; int bi = 0;
            for (int s=0;s<SEQ;s++)
                if (!used[s] && sc[s] > best) { best = sc[s]; bi = s; }
            used[bi] = true; sel[kk] = bi;
            kid[(size_t)bn*KSEL + kk] = bi;
        }
    }
    __syncthreads();
    for (int kk=0; kk<KSEL; kk++) {
        int s = sel[kk];
        size_t dst = (size_t)(b*LUSR + n*KSEL + kk);
        for (int d=threadIdx.x; d<DMODEL; d+=blockDim.x) {
            float v = hidden[(size_t)(bn*SEQ + s)*DMODEL + d];
            ps[dst*DMODEL + d] = v;
            unsigned short hh, ll;
            split2(v, hh, ll);
            psh[dst*DMODEL + d] = hh; psl[dst*DMODEL + d] = ll;
        }
        if (threadIdx.x == 0) psm[dst] = attn[(size_t)bn*SEQ + s];
    }
}

__global__ void final_kernel(const float* __restrict__ cddr, const float* __restrict__ ur,
                             const int* __restrict__ kid, float* __restrict__ out)
{
    if (blockIdx.x >= BB) {
        int i = (blockIdx.x - BB)*256 + threadIdx.x;
        if (i < BB*HISN*KSEL) out[NCDD + i] = (float)kid[i];
        return;
    }
    int b = blockIdx.x;
    __shared__ float s[CDDN];
    int lane = threadIdx.x & 31, wp = threadIdx.x >> 5;
    for (int c = wp; c < CDDN; c += (blockDim.x >> 5)) {
        const float* a = cddr + (size_t)(b*CDDN + c)*DMODEL;
        const float* uu = ur + (size_t)b*DMODEL;
        float acc = 0.f;
        for (int d = lane; d < DMODEL; d += 32) acc += a[d]*uu[d];
        acc = warp_sum(acc);
        if (lane==0) s[c] = acc / sqrtf(768.f);
    }
    __syncthreads();
    if (threadIdx.x == 0) {
        float m = s[0];
        for (int c=1;c<CDDN;c++) m = fmaxf(m, s[c]);
        float sum = 0.f;
        for (int c=0;c<CDDN;c++) sum += expf(s[c]-m);
        float lse = m + logf(sum);
        for (int c=0;c<CDDN;c++) out[b*CDDN + c] = s[c] - lse;
    }
}

// ---------------- host orchestration ----------------
struct DevPtrs {
    float *x,*q,*k,*v,*h,*lg,*pre,*atC,*atH,*cls,*cddr,*u0,*ur,*psm;
    int* kid;
    unsigned short *whi,*wlo,*xh,*xl,*oh,*ol,*hh,*hl,*fh,*fl,*q16,*k16,*vt,*p16;
};
static DevPtrs P;

template<int TERMS>
static void run_transformer_seq64(int N, const unsigned short* wh, const unsigned short* wl,
                                  const float* attnMask)
{
    int R = N*SEQ;
    const int SM = SMEM_T(TERMS);
    mma_gemm_qkv<TERMS><<<dim3(DMODEL/128, R/128, 3), 256, SM>>>(P.xh, P.xl, wh, wl, P.q, P.k, P.v, R);
    attn64_kernel<<<dim3(N, NHEAD),256>>>(P.q, P.k, P.v, attnMask, P.oh, P.ol);
    mma_gemm_f<TERMS><<<dim3(DMODEL/128, R/128), 256, SM>>>(P.oh, P.ol, wh+WOFF_O, wl+WOFF_O, P.q, R, DMODEL, DMODEL);
    ln_split_kernel<<<R,256>>>(P.x, P.q, P.h, P.hh, P.hl);
    mma_gemm_gelu<TERMS><<<dim3(FFDIM/128, R/128), 256, SM>>>(P.hh, P.hl, wh+WOFF_1, wl+WOFF_1, P.fh, P.fl, R, FFDIM, DMODEL);
    mma_gemm_f<TERMS><<<dim3(DMODEL/128, R/128), 256, SM>>>(P.fh, P.fl, wh+WOFF_2, wl+WOFF_2, P.q, R, DMODEL, FFDIM);
    ln_kernel<<<R,256>>>(P.h, P.q, P.h);
}

static void run_transformer_user(const unsigned short* wh, const unsigned short* wl,
                                 const float* attnMask)
{
    const int R = BB*LUSR;  // 3200
    const int SM = SMEM_T(2);
    cudaMemsetAsync(P.q16, 0, sizeof(unsigned short)*(size_t)BB*LPAD*DMODEL);
    cudaMemsetAsync(P.k16, 0, sizeof(unsigned short)*(size_t)BB*LPAD*DMODEL);
    cudaMemsetAsync(P.vt,  0, sizeof(unsigned short)*(size_t)BB*DMODEL*LPAD);
    mma_gemm_qkv16<<<dim3(DMODEL/128, R/128, 3), 256, SM>>>(P.xh, P.xl, wh, wl, P.q16, P.k16, P.vt, R);
    logits_mma<<<dim3(49, NHEAD, BB),128>>>(P.q16, P.k16, attnMask, P.lg);
    softmax_p16<<<BB*NHEAD*LUSR,128>>>(P.lg, P.p16);
    av_mma<<<dim3(7, NHEAD, BB),128>>>(P.p16, P.vt, P.oh, P.ol);
    mma_gemm_f<2><<<dim3(DMODEL/128, R/128), 256, SM>>>(P.oh, P.ol, wh+WOFF_O, wl+WOFF_O, P.q, R, DMODEL, DMODEL);
    ln_split_kernel<<<R,256>>>(P.x, P.q, P.h, P.hh, P.hl);
    mma_gemm_gelu<2><<<dim3(FFDIM/128, R/128), 256, SM>>>(P.hh, P.hl, wh+WOFF_1, wl+WOFF_1, P.fh, P.fl, R, FFDIM, DMODEL);
    mma_gemm_f<2><<<dim3(DMODEL/128, R/128), 256, SM>>>(P.fh, P.fl, wh+WOFF_2, wl+WOFF_2, P.q, R, DMODEL, FFDIM);
    ln_kernel<<<R,256>>>(P.h, P.q, P.h);
}

extern "C" void kernel_launch(void* const* d_in, const int* in_sizes, int n_in,
                              void* d_out, int out_size)
{
    const int*   cdd_sub  = (const int*)d_in[0];
    const int*   his_sub  = (const int*)d_in[1];
    const int*   cdd_enc  = (const int*)d_in[2];
    const int*   his_enc  = (const int*)d_in[3];
    const float* cdd_mask = (const float*)d_in[4];
    const float* his_mask = (const float*)d_in[5];
    const float* cdd_am   = (const float*)d_in[6];
    const float* his_am   = (const float*)d_in[7];
    const float* emb      = (const float*)d_in[8];
    const float* qU    = (const float*)d_in[21];
    const float* projW = (const float*)d_in[22];
    const float* projb = (const float*)d_in[23];
    float* out = (float*)d_out;

    cudaGetSymbolAddress((void**)&P.x,   g_x);
    cudaGetSymbolAddress((void**)&P.q,   g_q);
    cudaGetSymbolAddress((void**)&P.k,   g_k);
    cudaGetSymbolAddress((void**)&P.v,   g_v);
    cudaGetSymbolAddress((void**)&P.h,   g_h);
    cudaGetSymbolAddress((void**)&P.lg,  g_lg);
    cudaGetSymbolAddress((void**)&P.pre, g_pre);
    cudaGetSymbolAddress((void**)&P.atC, g_atC);
    cudaGetSymbolAddress((void**)&P.atH, g_atH);
    cudaGetSymbolAddress((void**)&P.cls, g_cls);
    cudaGetSymbolAddress((void**)&P.cddr,g_cddr);
    cudaGetSymbolAddress((void**)&P.u0,  g_u0);
    cudaGetSymbolAddress((void**)&P.ur,  g_ur);
    cudaGetSymbolAddress((void**)&P.psm, g_psm);
    cudaGetSymbolAddress((void**)&P.kid, g_kid);
    cudaGetSymbolAddress((void**)&P.whi, g_whi);
    cudaGetSymbolAddress((void**)&P.wlo, g_wlo);
    cudaGetSymbolAddress((void**)&P.xh,  g_xh);
    cudaGetSymbolAddress((void**)&P.xl,  g_xl);
    cudaGetSymbolAddress((void**)&P.oh,  g_oh);
    cudaGetSymbolAddress((void**)&P.ol,  g_ol);
    cudaGetSymbolAddress((void**)&P.hh,  g_hh);
    cudaGetSymbolAddress((void**)&P.hl,  g_hl);
    cudaGetSymbolAddress((void**)&P.fh,  g_fh);
    cudaGetSymbolAddress((void**)&P.fl,  g_fl);
    cudaGetSymbolAddress((void**)&P.q16, g_q16);
    cudaGetSymbolAddress((void**)&P.k16, g_k16);
    cudaGetSymbolAddress((void**)&P.vt,  g_vt);
    cudaGetSymbolAddress((void**)&P.p16, g_p16);

    cudaFuncSetAttribute(mma_gemm_f<2>,    cudaFuncAttributeMaxDynamicSharedMemorySize, SMEM_T(2));
    cudaFuncSetAttribute(mma_gemm_gelu<2>, cudaFuncAttributeMaxDynamicSharedMemorySize, SMEM_T(2));
    cudaFuncSetAttribute(mma_gemm_qkv<2>,  cudaFuncAttributeMaxDynamicSharedMemorySize, SMEM_T(2));
    cudaFuncSetAttribute(mma_gemm_qkv16,   cudaFuncAttributeMaxDynamicSharedMemorySize, SMEM_T(2));
    cudaFuncSetAttribute(mma_gemm_f<3>,    cudaFuncAttributeMaxDynamicSharedMemorySize, SMEM_T(3));
    cudaFuncSetAttribute(mma_gemm_gelu<3>, cudaFuncAttributeMaxDynamicSharedMemorySize, SMEM_T(3));
    cudaFuncSetAttribute(mma_gemm_qkv<3>,  cudaFuncAttributeMaxDynamicSharedMemorySize, SMEM_T(3));

    // ---- batched weight prep ----
    PrepPtrs pp;
    for (int i = 0; i < 6; i++) { pp.p[i] = (const float*)d_in[9+i]; pp.p[6+i] = (const float*)d_in[15+i]; }
    prep_all<<<dim3(2304, 12), dim3(32,8)>>>(pp, P.whi, P.wlo);

    // ---- candidate path (BERT weights), 2-term ----
    prefix_kernel<<<NCDD,256>>>(cdd_sub, cdd_mask, cdd_am, P.pre, P.atC);
    pool_kernel<<<dim3(NCDD, DMODEL/128),128>>>(P.pre, cdd_enc, emb, P.x, P.xh, P.xl);
    run_transformer_seq64<2>(NCDD, P.whi, P.wlo, P.atC);
    sgemm_proj<<<dim3(DMODEL/64, 1),256>>>(P.h, (size_t)SEQ*DMODEL, projW, P.cddr, NCDD, DMODEL, DMODEL, projb);

    // ---- history path (encN weights), 3-term (kid-exact) ----
    prefix_kernel<<<NHIS,256>>>(his_sub, his_mask, his_am, P.pre, P.atH);
    pool_kernel<<<dim3(NHIS, DMODEL/128),128>>>(P.pre, his_enc, emb, P.x, P.xh, P.xl);
    run_transformer_seq64<3>(NHIS, P.whi+WSET, P.wlo+WSET, P.atH);
    gather_cls_kernel<<<NHIS,256>>>(P.h, P.cls, SEQ);
    user0_kernel<<<BB,256>>>(P.cls, qU, P.u0);
    topk_kernel<<<BB*HISN,256>>>(P.h, P.u0, P.atH, P.kid, P.x, P.xh, P.xl, P.psm);

    // ---- user path (BERT weights), 2-term + fp16 MMA attention ----
    run_transformer_user(P.whi, P.wlo, P.psm);
    sgemm_proj<<<dim3(DMODEL/64, 1),256>>>(P.h, (size_t)LUSR*DMODEL, projW, P.ur, BB, DMODEL, DMODEL, projb);

    // ---- outputs ----
    final_kernel<<<BB + (BB*HISN*KSEL + 255)/256, 256>>>(P.cddr, P.ur, P.kid, out);
}

// round 11
// speedup vs baseline: 3.2813x; 1.0264x over previous
#include <cuda_runtime.h>
#include <cuda_fp16.h>
#include <math.h>
#include <stdint.h>

#define BB     8
#define CDDN   5
#define HISN   50
#define SEQ    64
#define DMODEL 768
#define NHEAD  12
#define FFDIM  3072
#define KSEL   8

#define NCDD   (BB*CDDN)     // 40
#define NHIS   (BB*HISN)     // 400
#define LUSR   400
#define LPAD   448
#define ROWS_MAX (NHIS*SEQ)  // 25600

#define WOFF_Q  0
#define WOFF_K  589824
#define WOFF_V  1179648
#define WOFF_O  1769472
#define WOFF_1  2359296
#define WOFF_2  4718592
#define WSET    7077888

// ---------------- scratch ----------------
__device__ float g_x [ (size_t)ROWS_MAX*DMODEL ];
__device__ float g_q [ (size_t)ROWS_MAX*DMODEL ];   // aliased as qh/ql fp16
__device__ float g_k [ (size_t)ROWS_MAX*DMODEL ];   // aliased as kh/kl fp16
__device__ float g_v [ (size_t)ROWS_MAX*DMODEL ];   // aliased as vh/vl fp16
__device__ float g_h [ (size_t)ROWS_MAX*DMODEL ];
__device__ float g_lg[ (size_t)BB*NHEAD*LUSR*LUSR ];
__device__ float g_pre[(size_t)NHIS*SEQ*SEQ ];
__device__ float g_atC[ NCDD*SEQ ];
__device__ float g_atH[ NHIS*SEQ ];
__device__ float g_cls[ (size_t)NHIS*DMODEL ];
__device__ float g_cddr[(size_t)NCDD*DMODEL ];
__device__ float g_u0 [ BB*DMODEL ];
__device__ float g_ur [ BB*DMODEL ];
__device__ float g_psm[ BB*LUSR ];
__device__ int   g_kid[ BB*HISN*KSEL ];
__device__ unsigned short g_whi[ (size_t)2*WSET ];
__device__ unsigned short g_wlo[ (size_t)2*WSET ];
__device__ unsigned short g_xh[ (size_t)ROWS_MAX*DMODEL ];
__device__ unsigned short g_xl[ (size_t)ROWS_MAX*DMODEL ];
__device__ unsigned short g_oh[ (size_t)ROWS_MAX*DMODEL ];
__device__ unsigned short g_ol[ (size_t)ROWS_MAX*DMODEL ];
__device__ unsigned short g_hh[ (size_t)ROWS_MAX*DMODEL ];
__device__ unsigned short g_hl[ (size_t)ROWS_MAX*DMODEL ];
__device__ unsigned short g_fh[ (size_t)ROWS_MAX*FFDIM ];
__device__ unsigned short g_fl[ (size_t)ROWS_MAX*FFDIM ];
// user-path fp16 attention buffers
__device__ unsigned short g_q16[ (size_t)BB*LPAD*DMODEL ];
__device__ unsigned short g_k16[ (size_t)BB*LPAD*DMODEL ];
__device__ unsigned short g_vt [ (size_t)BB*DMODEL*LPAD ];
__device__ unsigned short g_p16[ (size_t)BB*NHEAD*LPAD*LPAD ];

// ---------------- low-level helpers ----------------
__device__ __forceinline__ void cp16(uint32_t s, const void* g){
    asm volatile("cp.async.ca.shared.global [%0], [%1], 16;\n" :: "r"(s), "l"(g));
}
__device__ __forceinline__ void cp_commit(){ asm volatile("cp.async.commit_group;\n"); }
template<int N>
__device__ __forceinline__ void cp_wait(){ asm volatile("cp.async.wait_group %0;\n" :: "n"(N)); }

__device__ __forceinline__ uint32_t smem_u32(const void* p) {
    uint32_t a;
    asm("{ .reg .u64 t; cvta.to.shared.u64 t, %1; cvt.u32.u64 %0, t; }" : "=r"(a) : "l"(p));
    return a;
}
__device__ __forceinline__ void ldsm_x4(uint32_t* r, uint32_t addr){
    asm volatile("ldmatrix.sync.aligned.m8n8.x4.shared.b16 {%0,%1,%2,%3}, [%4];"
        : "=r"(r[0]),"=r"(r[1]),"=r"(r[2]),"=r"(r[3]) : "r"(addr));
}
__device__ __forceinline__ void ldsm_x4_t(uint32_t* r, uint32_t addr){
    asm volatile("ldmatrix.sync.aligned.m8n8.x4.trans.shared.b16 {%0,%1,%2,%3}, [%4];"
        : "=r"(r[0]),"=r"(r[1]),"=r"(r[2]),"=r"(r[3]) : "r"(addr));
}
__device__ __forceinline__ void mma_f16(float* c, const uint32_t* a, const uint32_t* b){
    asm volatile("mma.sync.aligned.m16n8k16.row.col.f32.f16.f16.f32 "
        "{%0,%1,%2,%3}, {%4,%5,%6,%7}, {%8,%9}, {%0,%1,%2,%3};"
        : "+f"(c[0]),"+f"(c[1]),"+f"(c[2]),"+f"(c[3])
        : "r"(a[0]),"r"(a[1]),"r"(a[2]),"r"(a[3]), "r"(b[0]),"r"(b[1]));
}
__device__ __forceinline__ void split2(float v, unsigned short& h, unsigned short& l){
    __half hh = __float2half_rn(v);
    __half ll = __float2half_rn(v - __half2float(hh));
    h = __half_as_ushort(hh);
    l = __half_as_ushort(ll);
}
__device__ __forceinline__ unsigned short h16(float v){
    return __half_as_ushort(__float2half_rn(v));
}

// ---------------- reductions ----------------
__device__ __forceinline__ float warp_sum(float v){
    #pragma unroll
    for(int o=16;o;o>>=1) v += __shfl_xor_sync(0xffffffffu, v, o);
    return v;
}
__device__ __forceinline__ float warp_max(float v){
    #pragma unroll
    for(int o=16;o;o>>=1) v = fmaxf(v, __shfl_xor_sync(0xffffffffu, v, o));
    return v;
}
__device__ float block_sum(float v){
    __shared__ float red[33];
    int lane=threadIdx.x&31, w=threadIdx.x>>5, nw=blockDim.x>>5;
    v = warp_sum(v);
    __syncthreads();
    if(lane==0) red[w]=v;
    __syncthreads();
    if(threadIdx.x==0){ float t=0.f; for(int i=0;i<nw;i++) t+=red[i]; red[32]=t; }
    __syncthreads();
    return red[32];
}
__device__ float block_max(float v){
    __shared__ float red[33];
    int lane=threadIdx.x&31, w=threadIdx.x>>5, nw=blockDim.x>>5;
    v = warp_max(v);
    __syncthreads();
    if(lane==0) red[w]=v;
    __syncthreads();
    if(threadIdx.x==0){ float t=red[0]; for(int i=1;i<nw;i++) t=fmaxf(t,red[i]); red[32]=t; }
    __syncthreads();
    return red[32];
}

// ---------------- batched weight prep ----------------
struct PrepPtrs { const float* p[12]; };
__constant__ size_t c_woffs[6] = { WOFF_Q, WOFF_K, WOFF_V, WOFF_O, WOFF_1, WOFF_2 };

__global__ void prep_all(PrepPtrs ptrs, unsigned short* __restrict__ Th,
                         unsigned short* __restrict__ Tl)
{
    int w = blockIdx.y;
    int wi = w % 6;
    int K = (wi==5) ? FFDIM : DMODEL;
    int N = (wi==4) ? FFDIM : DMODEL;
    int ntx = N >> 5;
    int tiles = (K >> 5) * ntx;
    int t = blockIdx.x;
    if (t >= tiles) return;
    int nb = (t % ntx) << 5, kb = (t / ntx) << 5;
    const float* W = ptrs.p[w];
    size_t base = c_woffs[wi] + (size_t)(w/6)*WSET;

    __shared__ float tbuf[32][33];
    int x = threadIdx.x, y = threadIdx.y;
    for (int i=y;i<32;i+=8)
        tbuf[i][x] = W[(size_t)(kb+i)*N + nb + x];
    __syncthreads();
    for (int i=y;i<32;i+=8) {
        unsigned short h, l;
        split2(tbuf[x][i], h, l);
        size_t dst = base + (size_t)(nb+i)*K + kb + x;
        Th[dst] = h;
        Tl[dst] = l;
    }
}

// ---------------- mma.sync split-fp16 GEMM ----------------
// EPI 0: fp32 C.  1: gelu->hi/lo.  3: fp16 [n][LPAD][768].  4: fp16 vt [n][768][LPAD].  5: hi/lo (no act).
#define APAD 40
#define ARR_B  (128*APAD*2)
#define SMEM_T(T) (2*((T)+1)*ARR_B)

template<int EPI, int TERMS>
__device__ __forceinline__ void mma_body(const unsigned short* __restrict__ Ah,
                                         const unsigned short* __restrict__ Al,
                                         const unsigned short* __restrict__ Bh,
                                         const unsigned short* __restrict__ Bl,
                                         float* __restrict__ C,
                                         unsigned short* __restrict__ Ch,
                                         unsigned short* __restrict__ Cl,
                                         int M, int N, int K)
{
    extern __shared__ char sm[];
    const uint32_t sbase = smem_u32(sm);
    const int tid = threadIdx.x, lane = tid & 31, wid = tid >> 5;
    const int wm = wid >> 2, wn = wid & 3;
    const int rowBlk = blockIdx.y << 7, colBlk = blockIdx.x << 7;
    const uint32_t STG = (TERMS+1)*ARR_B;

    int r0 = tid >> 2,        s0 = (tid & 3) << 3;
    int r1 = (tid+256) >> 2,  s1 = ((tid+256) & 3) << 3;
    const unsigned short* gA[2] = {Ah, Al};

    const int nc = K >> 5;
    #pragma unroll
    for (int p=0;p<2;p++) {
        cp16(sbase + p*ARR_B + (uint32_t)(r0*APAD + s0)*2, gA[p] + (size_t)(rowBlk+r0)*K + s0);
        cp16(sbase + p*ARR_B + (uint32_t)(r1*APAD + s1)*2, gA[p] + (size_t)(rowBlk+r1)*K + s1);
    }
    cp16(sbase + 2*ARR_B + (uint32_t)(r0*APAD + s0)*2, Bh + (size_t)(colBlk+r0)*K + s0);
    cp16(sbase + 2*ARR_B + (uint32_t)(r1*APAD + s1)*2, Bh + (size_t)(colBlk+r1)*K + s1);
    if (TERMS == 3) {
        cp16(sbase + 3*ARR_B + (uint32_t)(r0*APAD + s0)*2, Bl + (size_t)(colBlk+r0)*K + s0);
        cp16(sbase + 3*ARR_B + (uint32_t)(r1*APAD + s1)*2, Bl + (size_t)(colBlk+r1)*K + s1);
    }
    cp_commit();

    const uint32_t aoff = (uint32_t)((wm*64 + (lane & 15))*APAD + 8*(lane >> 4)) * 2;
    const uint32_t boff = (uint32_t)((wn*32 + (lane & 7) + 8*(lane >> 4))*APAD + 8*((lane >> 3) & 1)) * 2;

    float acc[4][4][4] = {};

    for (int c = 0; c < nc; c++) {
        const bool has = (c+1 < nc);
        if (has) {
            int kb = (c+1) << 5;
            uint32_t st = ((c+1) & 1) * STG;
            #pragma unroll
            for (int p=0;p<2;p++) {
                cp16(sbase + st + p*ARR_B + (uint32_t)(r0*APAD + s0)*2, gA[p] + (size_t)(rowBlk+r0)*K + kb + s0);
                cp16(sbase + st + p*ARR_B + (uint32_t)(r1*APAD + s1)*2, gA[p] + (size_t)(rowBlk+r1)*K + kb + s1);
            }
            cp16(sbase + st + 2*ARR_B + (uint32_t)(r0*APAD + s0)*2, Bh + (size_t)(colBlk+r0)*K + kb + s0);
            cp16(sbase + st + 2*ARR_B + (uint32_t)(r1*APAD + s1)*2, Bh + (size_t)(colBlk+r1)*K + kb + s1);
            if (TERMS == 3) {
                cp16(sbase + st + 3*ARR_B + (uint32_t)(r0*APAD + s0)*2, Bl + (size_t)(colBlk+r0)*K + kb + s0);
                cp16(sbase + st + 3*ARR_B + (uint32_t)(r1*APAD + s1)*2, Bl + (size_t)(colBlk+r1)*K + kb + s1);
            }
            cp_commit();
            cp_wait<1>();
        } else {
            cp_wait<0>();
        }
        __syncthreads();

        uint32_t st = (c & 1) * STG;
        uint32_t aH = sbase + st + aoff;
        uint32_t aL = aH + ARR_B;
        uint32_t bH = sbase + st + 2*ARR_B + boff;
        uint32_t bL = bH + ARR_B;

        #pragma unroll
        for (int ks = 0; ks < 2; ks++) {
            uint32_t ko = (uint32_t)(ks*16*2);
            uint32_t ahf[4][4], alf[4][4], bhf[2][4], blf[2][4];
            #pragma unroll
            for (int mt=0;mt<4;mt++) ldsm_x4(ahf[mt], aH + ko + (uint32_t)(mt*16*APAD*2));
            #pragma unroll
            for (int np=0;np<2;np++) ldsm_x4(bhf[np], bH + ko + (uint32_t)(np*16*APAD*2));
            if (TERMS == 3) {
                #pragma unroll
                for (int np=0;np<2;np++) ldsm_x4(blf[np], bL + ko + (uint32_t)(np*16*APAD*2));
            }
            #pragma unroll
            for (int mt=0;mt<4;mt++)
                #pragma unroll
                for (int nt=0;nt<4;nt++)
                    mma_f16(acc[mt][nt], ahf[mt], &bhf[nt>>1][(nt&1)*2]);
            #pragma unroll
            for (int mt=0;mt<4;mt++) ldsm_x4(alf[mt], aL + ko + (uint32_t)(mt*16*APAD*2));
            if (TERMS == 3) {
                #pragma unroll
                for (int mt=0;mt<4;mt++)
                    #pragma unroll
                    for (int nt=0;nt<4;nt++)
                        mma_f16(acc[mt][nt], ahf[mt], &blf[nt>>1][(nt&1)*2]);
            }
            #pragma unroll
            for (int mt=0;mt<4;mt++)
                #pragma unroll
                for (int nt=0;nt<4;nt++)
                    mma_f16(acc[mt][nt], alf[mt], &bhf[nt>>1][(nt&1)*2]);
        }
        __syncthreads();
    }

    #pragma unroll
    for (int mt=0;mt<4;mt++) {
        int row = rowBlk + wm*64 + mt*16 + (lane >> 2);
        #pragma unroll
        for (int nt=0;nt<4;nt++) {
            int col = colBlk + wn*32 + nt*8 + (lane & 3)*2;
            float v[4] = {acc[mt][nt][0], acc[mt][nt][1], acc[mt][nt][2], acc[mt][nt][3]};
            if (EPI == 0) {
                *(float2*)(C + (size_t)row*N + col)     = make_float2(v[0], v[1]);
                *(float2*)(C + (size_t)(row+8)*N + col) = make_float2(v[2], v[3]);
            } else if (EPI == 1 || EPI == 5) {
                if (EPI == 1) {
                    #pragma unroll
                    for (int j=0;j<4;j++) {
                        float t = v[j];
                        v[j] = 0.5f*t*(1.f + tanhf(0.7978845608028654f*(t + 0.044715f*t*t*t)));
                    }
                }
                unsigned short h0,l0,h1,l1;
                split2(v[0], h0, l0); split2(v[1], h1, l1);
                *(uint32_t*)(Ch + (size_t)row*N + col) = (uint32_t)h0 | ((uint32_t)h1<<16);
                *(uint32_t*)(Cl + (size_t)row*N + col) = (uint32_t)l0 | ((uint32_t)l1<<16);
                split2(v[2], h0, l0); split2(v[3], h1, l1);
                *(uint32_t*)(Ch + (size_t)(row+8)*N + col) = (uint32_t)h0 | ((uint32_t)h1<<16);
                *(uint32_t*)(Cl + (size_t)(row+8)*N + col) = (uint32_t)l0 | ((uint32_t)l1<<16);
            } else if (EPI == 3) {
                int n0 = row / LUSR, l0i = row - n0*LUSR;
                *(uint32_t*)(Ch + ((size_t)n0*LPAD + l0i)*DMODEL + col) =
                    (uint32_t)h16(v[0]) | ((uint32_t)h16(v[1])<<16);
                int n1 = (row+8) / LUSR, l1i = (row+8) - n1*LUSR;
                *(uint32_t*)(Ch + ((size_t)n1*LPAD + l1i)*DMODEL + col) =
                    (uint32_t)h16(v[2]) | ((uint32_t)h16(v[3])<<16);
            } else { // EPI == 4
                int n0 = row / LUSR, l0i = row - n0*LUSR;
                Ch[((size_t)n0*DMODEL + col  )*LPAD + l0i] = h16(v[0]);
                Ch[((size_t)n0*DMODEL + col+1)*LPAD + l0i] = h16(v[1]);
                int n1 = (row+8) / LUSR, l1i = (row+8) - n1*LUSR;
                Ch[((size_t)n1*DMODEL + col  )*LPAD + l1i] = h16(v[2]);
                Ch[((size_t)n1*DMODEL + col+1)*LPAD + l1i] = h16(v[3]);
            }
        }
    }
}

template<int TERMS>
__global__ __launch_bounds__(256, 2) void mma_gemm_f(const unsigned short* __restrict__ Ah,
                                                     const unsigned short* __restrict__ Al,
                                                     const unsigned short* __restrict__ Bh,
                                                     const unsigned short* __restrict__ Bl,
                                                     float* __restrict__ C,
                                                     int M, int N, int K)
{
    mma_body<0, TERMS>(Ah, Al, Bh, Bl, C, nullptr, nullptr, M, N, K);
}

template<int TERMS>
__global__ __launch_bounds__(256, 2) void mma_gemm_gelu(const unsigned short* __restrict__ Ah,
                                                        const unsigned short* __restrict__ Al,
                                                        const unsigned short* __restrict__ Bh,
                                                        const unsigned short* __restrict__ Bl,
                                                        unsigned short* __restrict__ Ch,
                                                        unsigned short* __restrict__ Cl,
                                                        int M, int N, int K)
{
    mma_body<1, TERMS>(Ah, Al, Bh, Bl, nullptr, Ch, Cl, M, N, K);
}

// QKV for seq64 paths: emits fp16 hi/lo for q,k,v
template<int TERMS>
__global__ __launch_bounds__(256, 2) void mma_gemm_qkv5(const unsigned short* __restrict__ Ah,
                                                        const unsigned short* __restrict__ Al,
                                                        const unsigned short* __restrict__ Wh,
                                                        const unsigned short* __restrict__ Wl,
                                                        unsigned short* __restrict__ qh,
                                                        unsigned short* __restrict__ ql,
                                                        unsigned short* __restrict__ kh,
                                                        unsigned short* __restrict__ kl,
                                                        unsigned short* __restrict__ vh,
                                                        unsigned short* __restrict__ vl,
                                                        int M)
{
    const unsigned short* bh = Wh + (size_t)blockIdx.z*589824;
    const unsigned short* bl = Wl + (size_t)blockIdx.z*589824;
    unsigned short* Ch = (blockIdx.z==0) ? qh : (blockIdx.z==1) ? kh : vh;
    unsigned short* Cl = (blockIdx.z==0) ? ql : (blockIdx.z==1) ? kl : vl;
    mma_body<5, TERMS>(Ah, Al, bh, bl, nullptr, Ch, Cl, M, DMODEL, DMODEL);
}

// user-path QKV: emits fp16 q16/k16 ([n][LPAD][768]) and vt ([n][768][LPAD])
__global__ __launch_bounds__(256, 2) void mma_gemm_qkv16(const unsigned short* __restrict__ Ah,
                                                         const unsigned short* __restrict__ Al,
                                                         const unsigned short* __restrict__ Wh,
                                                         const unsigned short* __restrict__ Wl,
                                                         unsigned short* __restrict__ q16,
                                                         unsigned short* __restrict__ k16,
                                                         unsigned short* __restrict__ vt,
                                                         int M)
{
    const unsigned short* bh = Wh + (size_t)blockIdx.z*589824;
    const unsigned short* bl = Wl + (size_t)blockIdx.z*589824;
    if (blockIdx.z == 0)
        mma_body<3, 2>(Ah, Al, bh, bl, nullptr, q16, nullptr, M, DMODEL, DMODEL);
    else if (blockIdx.z == 1)
        mma_body<3, 2>(Ah, Al, bh, bl, nullptr, k16, nullptr, M, DMODEL, DMODEL);
    else
        mma_body<4, 2>(Ah, Al, bh, bl, nullptr, vt, nullptr, M, DMODEL, DMODEL);
}

// ---------------- fused fp16 3-term MMA attention (seq64, kid-safe) ----------------
// block = 128 (4 warps), grid (n, h). Warp w owns score rows [w*16, w*16+16).
__global__ __launch_bounds__(128) void attn64_mma(
    const unsigned short* __restrict__ qh, const unsigned short* __restrict__ ql,
    const unsigned short* __restrict__ kh, const unsigned short* __restrict__ kl,
    const unsigned short* __restrict__ vh, const unsigned short* __restrict__ vl,
    const float* __restrict__ mask,
    unsigned short* __restrict__ Oh, unsigned short* __restrict__ Ol)
{
    __shared__ __align__(16) unsigned short T[4][64][72];
    __shared__ float msk[64];
    const int n = blockIdx.x, h = blockIdx.y;
    const int tid = threadIdx.x, lane = tid & 31, wid = tid >> 5;
    const uint32_t base = smem_u32(T);
    const uint32_t AR = 64*72*2;

    {
        const unsigned short* src[4] = {qh, ql, kh, kl};
        #pragma unroll
        for (int t = 0; t < 4; t++)
            for (int i = tid; i < 512; i += 128) {
                int r = i >> 3, cg = (i & 7) << 3;
                *(uint4*)&T[t][r][cg] = *(const uint4*)(src[t] + ((size_t)n*64 + r)*DMODEL + h*64 + cg);
            }
        if (tid < 64) msk[tid] = (mask[(size_t)n*64 + tid] > 0.f) ? 0.f : -1e9f;
    }
    __syncthreads();

    // ---- S = QK^T (3 terms) ----
    const uint32_t aoff = base + (uint32_t)((wid*16 + (lane & 15))*72 + 8*(lane >> 4))*2;
    const uint32_t boff = base + 2*AR + (uint32_t)(((lane & 7) + 8*(lane >> 4))*72 + 8*((lane >> 3) & 1))*2;
    float acc[8][4] = {};
    #pragma unroll
    for (int k0 = 0; k0 < 4; k0++) {
        uint32_t aH[4], aL[4], bH[4][4], bL[4][4];
        ldsm_x4(aH, aoff + k0*32);
        ldsm_x4(aL, aoff + AR + k0*32);
        #pragma unroll
        for (int nb = 0; nb < 4; nb++) {
            ldsm_x4(bH[nb], boff + k0*32 + (uint32_t)(nb*16*72*2));
            ldsm_x4(bL[nb], boff + AR + k0*32 + (uint32_t)(nb*16*72*2));
        }
        #pragma unroll
        for (int nb = 0; nb < 4; nb++) {
            mma_f16(acc[nb*2+0], aH, &bH[nb][0]);
            mma_f16(acc[nb*2+1], aH, &bH[nb][2]);
            mma_f16(acc[nb*2+0], aL, &bH[nb][0]);
            mma_f16(acc[nb*2+1], aL, &bH[nb][2]);
            mma_f16(acc[nb*2+0], aH, &bL[nb][0]);
            mma_f16(acc[nb*2+1], aH, &bL[nb][2]);
        }
    }

    // ---- scale + mask + row softmax (rows lo/hi per lane quad) ----
    #pragma unroll
    for (int nf = 0; nf < 8; nf++) {
        int c0 = nf*8 + (lane & 3)*2;
        float b0 = msk[c0], b1 = msk[c0+1];
        acc[nf][0] = acc[nf][0]*0.125f + b0;
        acc[nf][1] = acc[nf][1]*0.125f + b1;
        acc[nf][2] = acc[nf][2]*0.125f + b0;
        acc[nf][3] = acc[nf][3]*0.125f + b1;
    }
    float mlo = -3.4e38f, mhi = -3.4e38f;
    #pragma unroll
    for (int nf = 0; nf < 8; nf++) {
        mlo = fmaxf(mlo, fmaxf(acc[nf][0], acc[nf][1]));
        mhi = fmaxf(mhi, fmaxf(acc[nf][2], acc[nf][3]));
    }
    #pragma unroll
    for (int o = 1; o <= 2; o <<= 1) {
        mlo = fmaxf(mlo, __shfl_xor_sync(0xffffffffu, mlo, o));
        mhi = fmaxf(mhi, __shfl_xor_sync(0xffffffffu, mhi, o));
    }
    float slo = 0.f, shi = 0.f;
    #pragma unroll
    for (int nf = 0; nf < 8; nf++) {
        acc[nf][0] = expf(acc[nf][0]-mlo); acc[nf][1] = expf(acc[nf][1]-mlo);
        acc[nf][2] = expf(acc[nf][2]-mhi); acc[nf][3] = expf(acc[nf][3]-mhi);
        slo += acc[nf][0] + acc[nf][1];
        shi += acc[nf][2] + acc[nf][3];
    }
    #pragma unroll
    for (int o = 1; o <= 2; o <<= 1) {
        slo += __shfl_xor_sync(0xffffffffu, slo, o);
        shi += __shfl_xor_sync(0xffffffffu, shi, o);
    }
    float ilo = 1.f/slo, ihi = 1.f/shi;

    __syncthreads();   // all warps done reading q/k tiles

    // ---- write P hi/lo into T[0]/T[1]; load V hi/lo into T[2]/T[3] ----
    {
        int rlo = wid*16 + (lane >> 2), rhi = rlo + 8;
        #pragma unroll
        for (int nf = 0; nf < 8; nf++) {
            int c0 = nf*8 + (lane & 3)*2;
            unsigned short h0,l0,h1,l1;
            split2(acc[nf][0]*ilo, h0, l0); split2(acc[nf][1]*ilo, h1, l1);
            *(uint32_t*)&T[0][rlo][c0] = (uint32_t)h0 | ((uint32_t)h1<<16);
            *(uint32_t*)&T[1][rlo][c0] = (uint32_t)l0 | ((uint32_t)l1<<16);
            split2(acc[nf][2]*ihi, h0, l0); split2(acc[nf][3]*ihi, h1, l1);
            *(uint32_t*)&T[0][rhi][c0] = (uint32_t)h0 | ((uint32_t)h1<<16);
            *(uint32_t*)&T[1][rhi][c0] = (uint32_t)l0 | ((uint32_t)l1<<16);
        }
        const unsigned short* vsrc[2] = {vh, vl};
        #pragma unroll
        for (int t = 0; t < 2; t++)
            for (int i = tid; i < 512; i += 128) {
                int r = i >> 3, cg = (i & 7) << 3;
                *(uint4*)&T[2+t][r][cg] = *(const uint4*)(vsrc[t] + ((size_t)n*64 + r)*DMODEL + h*64 + cg);
            }
    }
    __syncthreads();

    // ---- O = P V (3 terms), V via ldmatrix.trans ----
    const uint32_t voff = base + 2*AR + (uint32_t)(((lane & 7) + 8*((lane >> 3) & 1))*72 + 8*(lane >> 4))*2;
    float oacc[8][4] = {};
    #pragma unroll
    for (int k0 = 0; k0 < 4; k0++) {
        uint32_t pH[4], pL[4], vH[4][4], vL[4][4];
        ldsm_x4(pH, aoff + k0*32);
        ldsm_x4(pL, aoff + AR + k0*32);
        #pragma unroll
        for (int db = 0; db < 4; db++) {
            ldsm_x4_t(vH[db], voff + (uint32_t)(k0*16*72*2) + db*32);
            ldsm_x4_t(vL[db], voff + AR + (uint32_t)(k0*16*72*2) + db*32);
        }
        #pragma unroll
        for (int db = 0; db < 4; db++) {
            mma_f16(oacc[db*2+0], pH, &vH[db][0]);
            mma_f16(oacc[db*2+1], pH, &vH[db][2]);
            mma_f16(oacc[db*2+0], pL, &vH[db][0]);
            mma_f16(oacc[db*2+1], pL, &vH[db][2]);
            mma_f16(oacc[db*2+0], pH, &vL[db][0]);
            mma_f16(oacc[db*2+1], pH, &vL[db][2]);
        }
    }

    // ---- epilogue: split to Oh/Ol ----
    {
        int rlo = wid*16 + (lane >> 2);
        #pragma unroll
        for (int df = 0; df < 8; df++) {
            int d = df*8 + (lane & 3)*2;
            unsigned short h0,l0,h1,l1;
            split2(oacc[df][0], h0, l0); split2(oacc[df][1], h1, l1);
            size_t off = ((size_t)n*64 + rlo)*DMODEL + h*64 + d;
            *(uint32_t*)(Oh + off) = (uint32_t)h0 | ((uint32_t)h1<<16);
            *(uint32_t*)(Ol + off) = (uint32_t)l0 | ((uint32_t)l1<<16);
            split2(oacc[df][2], h0, l0); split2(oacc[df][3], h1, l1);
            off = ((size_t)n*64 + rlo + 8)*DMODEL + h*64 + d;
            *(uint32_t*)(Oh + off) = (uint32_t)h0 | ((uint32_t)h1<<16);
            *(uint32_t*)(Ol + off) = (uint32_t)l0 | ((uint32_t)l1<<16);
        }
    }
}

// ---------------- fp16 tile attention (user path, L=400) ----------------
__global__ __launch_bounds__(128) void logits_mma(const unsigned short* __restrict__ q16,
                                                  const unsigned short* __restrict__ k16,
                                                  const float* __restrict__ mask,
                                                  float* __restrict__ lg)
{
    __shared__ __align__(16) unsigned short Qs[64][72];
    __shared__ __align__(16) unsigned short Ks[64][72];
    int n = blockIdx.z, h = blockIdx.y;
    int qt = blockIdx.x / 7, kt = blockIdx.x % 7;
    int tid = threadIdx.x, lane = tid & 31, wid = tid >> 5;
    int wm = wid >> 1, wn = wid & 1;
    for (int i = tid; i < 64*8; i += 128) {
        int r = i >> 3, cg = (i & 7) << 3;
        *(uint4*)&Qs[r][cg] = *(const uint4*)(q16 + ((size_t)n*LPAD + qt*64 + r)*DMODEL + h*64 + cg);
        *(uint4*)&Ks[r][cg] = *(const uint4*)(k16 + ((size_t)n*LPAD + kt*64 + r)*DMODEL + h*64 + cg);
    }
    __syncthreads();
    uint32_t aoff = smem_u32(Qs) + (uint32_t)((wm*32 + (lane & 15))*72 + 8*(lane >> 4))*2;
    uint32_t boff = smem_u32(Ks) + (uint32_t)((wn*32 + (lane & 7) + 8*(lane >> 4))*72 + 8*((lane >> 3) & 1))*2;
    float acc[2][4][4] = {};
    #pragma unroll
    for (int k0 = 0; k0 < 64; k0 += 16) {
        uint32_t af[2][4], bf[2][4];
        #pragma unroll
        for (int mt=0;mt<2;mt++) ldsm_x4(af[mt], aoff + k0*2 + (uint32_t)(mt*16*72*2));
        #pragma unroll
        for (int np=0;np<2;np++) ldsm_x4(bf[np], boff + k0*2 + (uint32_t)(np*16*72*2));
        #pragma unroll
        for (int mt=0;mt<2;mt++)
            #pragma unroll
            for (int nt=0;nt<4;nt++)
                mma_f16(acc[mt][nt], af[mt], &bf[nt>>1][(nt&1)*2]);
    }
    #pragma unroll
    for (int mt=0;mt<2;mt++) {
        int qr = qt*64 + wm*32 + mt*16 + (lane >> 2);
        #pragma unroll
        for (int nt=0;nt<4;nt++) {
            int kc = kt*64 + wn*32 + nt*8 + (lane & 3)*2;
            #pragma unroll
            for (int half2i=0;half2i<2;half2i++) {
                int qrr = qr + half2i*8;
                if (qrr >= LUSR) continue;
                float* dst = lg + (((size_t)(n*NHEAD + h)*LUSR + qrr)*LUSR);
                float v0 = acc[mt][nt][half2i*2+0], v1 = acc[mt][nt][half2i*2+1];
                if (kc < LUSR)
                    dst[kc]   = v0*0.125f + ((mask[(size_t)n*LUSR + kc]   > 0.f) ? 0.f : -1e9f);
                if (kc+1 < LUSR)
                    dst[kc+1] = v1*0.125f + ((mask[(size_t)n*LUSR + kc+1] > 0.f) ? 0.f : -1e9f);
            }
        }
    }
}

__global__ void softmax_p16(const float* __restrict__ lg, unsigned short* __restrict__ p16)
{
    __shared__ float buf[LUSR];
    int bi = blockIdx.x;
    int nh = bi / LUSR, q = bi - nh*LUSR;
    const float* p = lg + (size_t)bi * LUSR;
    int tid = threadIdx.x;
    float m = -3.4e38f;
    for (int i=tid;i<LUSR;i+=blockDim.x) { buf[i] = p[i]; m = fmaxf(m, buf[i]); }
    m = block_max(m);
    float s = 0.f;
    for (int i=tid;i<LUSR;i+=blockDim.x) { float e = expf(buf[i]-m); buf[i]=e; s+=e; }
    s = block_sum(s);
    float inv = 1.f/s;
    unsigned short* dst = p16 + ((size_t)nh*LPAD + q)*LPAD;
    for (int i=tid;i<LPAD;i+=blockDim.x)
        dst[i] = h16((i < LUSR) ? buf[i]*inv : 0.f);
}

__global__ __launch_bounds__(128) void av_mma(const unsigned short* __restrict__ p16,
                                              const unsigned short* __restrict__ vt,
                                              unsigned short* __restrict__ Oh,
                                              unsigned short* __restrict__ Ol)
{
    __shared__ __align__(16) unsigned short As[64][72];
    __shared__ __align__(16) unsigned short Bs[64][72];
    int n = blockIdx.z, h = blockIdx.y, qt = blockIdx.x;
    int tid = threadIdx.x, lane = tid & 31, wid = tid >> 5;
    int wm = wid >> 1, wn = wid & 1;
    uint32_t aoff = smem_u32(As) + (uint32_t)((wm*32 + (lane & 15))*72 + 8*(lane >> 4))*2;
    uint32_t boff = smem_u32(Bs) + (uint32_t)((wn*32 + (lane & 7) + 8*(lane >> 4))*72 + 8*((lane >> 3) & 1))*2;
    float acc[2][4][4] = {};
    for (int c = 0; c < 7; c++) {
        for (int i = tid; i < 64*8; i += 128) {
            int r = i >> 3, cg = (i & 7) << 3;
            *(uint4*)&As[r][cg] = *(const uint4*)(p16 + ((size_t)(n*NHEAD + h)*LPAD + qt*64 + r)*LPAD + c*64 + cg);
            *(uint4*)&Bs[r][cg] = *(const uint4*)(vt  + ((size_t)n*DMODEL + h*64 + r)*LPAD + c*64 + cg);
        }
        __syncthreads();
        #pragma unroll
        for (int k0 = 0; k0 < 64; k0 += 16) {
            uint32_t af[2][4], bf[2][4];
            #pragma unroll
            for (int mt=0;mt<2;mt++) ldsm_x4(af[mt], aoff + k0*2 + (uint32_t)(mt*16*72*2));
            #pragma unroll
            for (int np=0;np<2;np++) ldsm_x4(bf[np], boff + k0*2 + (uint32_t)(np*16*72*2));
            #pragma unroll
            for (int mt=0;mt<2;mt++)
                #pragma unroll
                for (int nt=0;nt<4;nt++)
                    mma_f16(acc[mt][nt], af[mt], &bf[nt>>1][(nt&1)*2]);
        }
        __syncthreads();
    }
    #pragma unroll
    for (int mt=0;mt<2;mt++) {
        int l0 = qt*64 + wm*32 + mt*16 + (lane >> 2);
        #pragma unroll
        for (int nt=0;nt<4;nt++) {
            int d = wn*32 + nt*8 + (lane & 3)*2;
            #pragma unroll
            for (int half2i=0;half2i<2;half2i++) {
                int l = l0 + half2i*8;
                if (l >= LUSR) continue;
                float v0 = acc[mt][nt][half2i*2+0], v1 = acc[mt][nt][half2i*2+1];
                size_t off = ((size_t)n*LUSR + l)*DMODEL + h*64 + d;
                unsigned short hh0, ll0, hh1, ll1;
                split2(v0, hh0, ll0); split2(v1, hh1, ll1);
                *(uint32_t*)(Oh + off) = (uint32_t)hh0 | ((uint32_t)hh1<<16);
                *(uint32_t*)(Ol + off) = (uint32_t)ll0 | ((uint32_t)ll1<<16);
            }
        }
    }
}

// ---------------- prefix build ----------------
__global__ void prefix_kernel(const int* __restrict__ sub, const float* __restrict__ mask,
                              const float* __restrict__ amask,
                              float* __restrict__ prefix, float* __restrict__ attn)
{
    __shared__ float P[SEQ*SEQ];
    int bn = blockIdx.x;
    for (int i = threadIdx.x; i < SEQ*SEQ; i += blockDim.x) P[i] = 0.f;
    __syncthreads();
    const int* si = sub + (size_t)bn*SEQ*2;
    for (int s = threadIdx.x; s < SEQ; s += blockDim.x) {
        int i = si[2*s+0], j = si[2*s+1];
        P[i*SEQ + j] = 1.f;
    }
    __syncthreads();
    float m = mask[bn];
    int lane = threadIdx.x & 31, warp = threadIdx.x >> 5;
    for (int i = warp; i < SEQ; i += (blockDim.x >> 5)) {
        float v0 = P[i*SEQ + lane]      * m;
        float v1 = P[i*SEQ + lane + 32] * m;
        float rs = v0 + v1;
        float ad = v0 * amask[bn*SEQ + lane] + v1 * amask[bn*SEQ + lane + 32];
        #pragma unroll
        for (int o=16;o;o>>=1){ rs += __shfl_xor_sync(0xffffffffu,rs,o); ad += __shfl_xor_sync(0xffffffffu,ad,o); }
        float denom = fmaxf(rs, 1e-12f);
        prefix[(size_t)bn*SEQ*SEQ + i*SEQ + lane]      = v0/denom;
        prefix[(size_t)bn*SEQ*SEQ + i*SEQ + lane + 32] = v1/denom;
        if (lane==0) attn[bn*SEQ + i] = ad/denom;
    }
}

// ---------------- embedding pooling ----------------
__global__ void pool_kernel(const float* __restrict__ prefix, const int* __restrict__ enc,
                            const float* __restrict__ emb, float* __restrict__ x,
                            unsigned short* __restrict__ xh, unsigned short* __restrict__ xl)
{
    __shared__ float P[SEQ*SEQ];
    __shared__ int idx[SEQ];
    int bn = blockIdx.x;
    int d  = blockIdx.y*128 + threadIdx.x;
    for (int i = threadIdx.x; i < SEQ*SEQ; i += blockDim.x)
        P[i] = prefix[(size_t)bn*SEQ*SEQ + i];
    if (threadIdx.x < SEQ) idx[threadIdx.x] = enc[(size_t)bn*SEQ + threadIdx.x];
    __syncthreads();
    float acc[SEQ];
    #pragma unroll
    for (int i=0;i<SEQ;i++) acc[i]=0.f;
    for (int j=0;j<SEQ;j++) {
        float e = emb[(size_t)idx[j]*DMODEL + d];
        #pragma unroll
        for (int i=0;i<SEQ;i++) acc[i] = fmaf(P[i*SEQ+j], e, acc[i]);
    }
    for (int i=0;i<SEQ;i++) {
        size_t o = ((size_t)bn*SEQ + i)*DMODEL + d;
        x[o] = acc[i];
        unsigned short h, l;
        split2(acc[i], h, l);
        xh[o] = h; xl[o] = l;
    }
}

// ---------------- strided proj ----------------
__global__ void sgemm_proj(const float* __restrict__ A, size_t lda,
                           const float* __restrict__ B,
                           float* __restrict__ C, int M, int N, int Kd,
                           const float* __restrict__ bias)
{
    __shared__ float As[16][64];
    __shared__ float Bs[16][68];
    int tid = threadIdx.x;
    int rowBase = blockIdx.y << 6, colBase = blockIdx.x << 6;
    int tx = tid & 15, ty = tid >> 4;
    int am = tid >> 2, ak = (tid & 3) << 2;
    int bk = tid >> 4, bn = (tid & 15) << 2;
    bool aok = (rowBase + am) < M;
    const float* Ap = A + (size_t)(rowBase + am)*lda + ak;
    const float* Bp = B + (size_t)bk*N + colBase + bn;
    float acc[4][4] = {};
    for (int k0 = 0; k0 < Kd; k0 += 16) {
        float4 a4 = aok ? *(const float4*)Ap : make_float4(0.f,0.f,0.f,0.f);
        As[ak+0][am]=a4.x; As[ak+1][am]=a4.y; As[ak+2][am]=a4.z; As[ak+3][am]=a4.w;
        *(float4*)&Bs[bk][bn] = *(const float4*)Bp;
        __syncthreads();
        #pragma unroll
        for (int kk=0; kk<16; kk++) {
            float av[4], bv[4];
            #pragma unroll
            for (int i=0;i<4;i++) av[i]=As[kk][(ty<<2)+i];
            #pragma unroll
            for (int j=0;j<4;j++) bv[j]=Bs[kk][(tx<<2)+j];
            #pragma unroll
            for (int i=0;i<4;i++)
                #pragma unroll
                for (int j=0;j<4;j++)
                    acc[i][j] = fmaf(av[i], bv[j], acc[i][j]);
        }
        __syncthreads();
        Ap += 16;
        Bp += (size_t)16*N;
    }
    #pragma unroll
    for (int i=0;i<4;i++) {
        int r = rowBase + (ty<<2) + i;
        if (r >= M) continue;
        #pragma unroll
        for (int j=0;j<4;j++) {
            int c = colBase + (tx<<2) + j;
            C[(size_t)r*N + c] = tanhf(acc[i][j] + bias[c]);
        }
    }
}

// LN variants
__global__ void ln_split_kernel(const float* __restrict__ x, const float* __restrict__ o,
                                float* __restrict__ out,
                                unsigned short* __restrict__ oh, unsigned short* __restrict__ ol)
{
    __shared__ float buf[DMODEL];
    size_t row = blockIdx.x;
    int tid = threadIdx.x;
    float ls = 0.f;
    for (int i=tid;i<DMODEL;i+=blockDim.x) {
        float v = x[row*DMODEL+i] + o[row*DMODEL+i];
        buf[i] = v; ls += v;
    }
    float mu = block_sum(ls) * (1.f/DMODEL);
    float lv = 0.f;
    for (int i=tid;i<DMODEL;i+=blockDim.x) { float d = buf[i]-mu; lv += d*d; }
    float var = block_sum(lv) * (1.f/DMODEL);
    float inv = rsqrtf(var + 1e-12f);
    for (int i=tid;i<DMODEL;i+=blockDim.x) {
        float v = (buf[i]-mu)*inv;
        out[row*DMODEL+i] = v;
        unsigned short h, l;
        split2(v, h, l);
        oh[row*DMODEL+i] = h; ol[row*DMODEL+i] = l;
    }
}

__global__ void ln_kernel(const float* __restrict__ x, const float* __restrict__ o,
                          float* __restrict__ out)
{
    __shared__ float buf[DMODEL];
    size_t row = blockIdx.x;
    int tid = threadIdx.x;
    float ls = 0.f;
    for (int i=tid;i<DMODEL;i+=blockDim.x) {
        float v = x[row*DMODEL+i] + o[row*DMODEL+i];
        buf[i] = v; ls += v;
    }
    float mu = block_sum(ls) * (1.f/DMODEL);
    float lv = 0.f;
    for (int i=tid;i<DMODEL;i+=blockDim.x) { float d = buf[i]-mu; lv += d*d; }
    float var = block_sum(lv) * (1.f/DMODEL);
    float inv = rsqrtf(var + 1e-12f);
    for (int i=tid;i<DMODEL;i+=blockDim.x) out[row*DMODEL+i] = (buf[i]-mu)*inv;
}

__global__ void gather_cls_kernel(const float* __restrict__ h, float* __restrict__ cls, int L)
{
    int n = blockIdx.x;
    for (int d=threadIdx.x; d<DMODEL; d+=blockDim.x)
        cls[(size_t)n*DMODEL + d] = h[(size_t)n*L*DMODEL + d];
}

__global__ void user0_kernel(const float* __restrict__ cls, const float* __restrict__ qU,
                             float* __restrict__ u0)
{
    int b = blockIdx.x;
    __shared__ float w[HISN];
    int lane = threadIdx.x & 31, wp = threadIdx.x >> 5;
    for (int n = wp; n < HISN; n += (blockDim.x >> 5)) {
        const float* c = cls + (size_t)(b*HISN + n)*DMODEL;
        float acc = 0.f;
        for (int d = lane; d < DMODEL; d += 32) acc += c[d]*qU[d];
        acc = warp_sum(acc);
        if (lane==0) w[n] = acc / sqrtf(768.f);
    }
    __syncthreads();
    if (threadIdx.x == 0) {
        float m = w[0];
        for (int n=1;n<HISN;n++) m = fmaxf(m, w[n]);
        float s = 0.f;
        for (int n=0;n<HISN;n++){ w[n] = expf(w[n]-m); s += w[n]; }
        float inv = 1.f/s;
        for (int n=0;n<HISN;n++) w[n] *= inv;
    }
    __syncthreads();
    for (int d=threadIdx.x; d<DMODEL; d+=blockDim.x) {
        float acc = 0.f;
        for (int n=0;n<HISN;n++) acc += w[n]*cls[(size_t)(b*HISN+n)*DMODEL + d];
        u0[b*DMODEL + d] = acc;
    }
}

__global__ void topk_kernel(const float* __restrict__ hidden, const float* __restrict__ u0,
                            const float* __restrict__ attn, int* __restrict__ kid,
                            float* __restrict__ ps,
                            unsigned short* __restrict__ psh, unsigned short* __restrict__ psl,
                            float* __restrict__ psm)
{
    int bn = blockIdx.x;
    int b = bn / HISN, n = bn - b*HISN;
    __shared__ float u[DMODEL];
    __shared__ float sc[SEQ];
    __shared__ int sel[KSEL];
    for (int d=threadIdx.x; d<DMODEL; d+=blockDim.x) u[d] = u0[b*DMODEL + d];
    __syncthreads();
    int lane = threadIdx.x & 31, wp = threadIdx.x >> 5;
    for (int s = wp; s < SEQ; s += (blockDim.x >> 5)) {
        const float* hr = hidden + (size_t)(bn*SEQ + s)*DMODEL;
        float acc = 0.f;
        for (int d = lane; d < DMODEL; d += 32) acc += hr[d]*u[d];
        acc = warp_sum(acc);
        if (lane==0)
            sc[s] = (attn[(size_t)bn*SEQ + s] > 0.f) ? acc / sqrtf(768.f) : -1e9f;
    }
    __syncthreads();
    if (threadIdx.x == 0) {
        bool used[SEQ];
        for (int s=0;s<SEQ;s++) used[s]=false;
        for (int kk=0; kk<KSEL; kk++) {
            float best = -3.4e38f; int bi = 0;
            for (int s=0;s<SEQ;s++)
                if (!used[s] && sc[s] > best) { best = sc[s]; bi = s; }
            used[bi] = true; sel[kk] = bi;
            kid[(size_t)bn*KSEL + kk] = bi;
        }
    }
    __syncthreads();
    for (int kk=0; kk<KSEL; kk++) {
        int s = sel[kk];
        size_t dst = (size_t)(b*LUSR + n*KSEL + kk);
        for (int d=threadIdx.x; d<DMODEL; d+=blockDim.x) {
            float v = hidden[(size_t)(bn*SEQ + s)*DMODEL + d];
            ps[dst*DMODEL + d] = v;
            unsigned short hh, ll;
            split2(v, hh, ll);
            psh[dst*DMODEL + d] = hh; psl[dst*DMODEL + d] = ll;
        }
        if (threadIdx.x == 0) psm[dst] = attn[(size_t)bn*SEQ + s];
    }
}

__global__ void final_kernel(const float* __restrict__ cddr, const float* __restrict__ ur,
                             const int* __restrict__ kid, float* __restrict__ out)
{
    if (blockIdx.x >= BB) {
        int i = (blockIdx.x - BB)*256 + threadIdx.x;
        if (i < BB*HISN*KSEL) out[NCDD + i] = (float)kid[i];
        return;
    }
    int b = blockIdx.x;
    __shared__ float s[CDDN];
    int lane = threadIdx.x & 31, wp = threadIdx.x >> 5;
    for (int c = wp; c < CDDN; c += (blockDim.x >> 5)) {
        const float* a = cddr + (size_t)(b*CDDN + c)*DMODEL;
        const float* uu = ur + (size_t)b*DMODEL;
        float acc = 0.f;
        for (int d = lane; d < DMODEL; d += 32) acc += a[d]*uu[d];
        acc = warp_sum(acc);
        if (lane==0) s[c] = acc / sqrtf(768.f);
    }
    __syncthreads();
    if (threadIdx.x == 0) {
        float m = s[0];
        for (int c=1;c<CDDN;c++) m = fmaxf(m, s[c]);
        float sum = 0.f;
        for (int c=0;c<CDDN;c++) sum += expf(s[c]-m);
        float lse = m + logf(sum);
        for (int c=0;c<CDDN;c++) out[b*CDDN + c] = s[c] - lse;
    }
}

// ---------------- host orchestration ----------------
struct DevPtrs {
    float *x,*q,*k,*v,*h,*lg,*pre,*atC,*atH,*cls,*cddr,*u0,*ur,*psm;
    int* kid;
    unsigned short *whi,*wlo,*xh,*xl,*oh,*ol,*hh,*hl,*fh,*fl,*q16,*k16,*vt,*p16;
    unsigned short *qhA,*qlA,*khA,*klA,*vhA,*vlA;   // fp16 aliases of q/k/v
};
static DevPtrs P;

template<int TERMS>
static void run_transformer_seq64(int N, const unsigned short* wh, const unsigned short* wl,
                                  const float* attnMask)
{
    int R = N*SEQ;
    const int SM = SMEM_T(TERMS);
    mma_gemm_qkv5<TERMS><<<dim3(DMODEL/128, R/128, 3), 256, SM>>>(
        P.xh, P.xl, wh, wl, P.qhA, P.qlA, P.khA, P.klA, P.vhA, P.vlA, R);
    attn64_mma<<<dim3(N, NHEAD),128>>>(P.qhA, P.qlA, P.khA, P.klA, P.vhA, P.vlA, attnMask, P.oh, P.ol);
    mma_gemm_f<TERMS><<<dim3(DMODEL/128, R/128), 256, SM>>>(P.oh, P.ol, wh+WOFF_O, wl+WOFF_O, P.q, R, DMODEL, DMODEL);
    ln_split_kernel<<<R,256>>>(P.x, P.q, P.h, P.hh, P.hl);
    mma_gemm_gelu<TERMS><<<dim3(FFDIM/128, R/128), 256, SM>>>(P.hh, P.hl, wh+WOFF_1, wl+WOFF_1, P.fh, P.fl, R, FFDIM, DMODEL);
    mma_gemm_f<TERMS><<<dim3(DMODEL/128, R/128), 256, SM>>>(P.fh, P.fl, wh+WOFF_2, wl+WOFF_2, P.q, R, DMODEL, FFDIM);
    ln_kernel<<<R,256>>>(P.h, P.q, P.h);
}

static void run_transformer_user(const unsigned short* wh, const unsigned short* wl,
                                 const float* attnMask)
{
    const int R = BB*LUSR;  // 3200
    const int SM = SMEM_T(2);
    cudaMemsetAsync(P.q16, 0, sizeof(unsigned short)*(size_t)BB*LPAD*DMODEL);
    cudaMemsetAsync(P.k16, 0, sizeof(unsigned short)*(size_t)BB*LPAD*DMODEL);
    cudaMemsetAsync(P.vt,  0, sizeof(unsigned short)*(size_t)BB*DMODEL*LPAD);
    mma_gemm_qkv16<<<dim3(DMODEL/128, R/128, 3), 256, SM>>>(P.xh, P.xl, wh, wl, P.q16, P.k16, P.vt, R);
    logits_mma<<<dim3(49, NHEAD, BB),128>>>(P.q16, P.k16, attnMask, P.lg);
    softmax_p16<<<BB*NHEAD*LUSR,128>>>(P.lg, P.p16);
    av_mma<<<dim3(7, NHEAD, BB),128>>>(P.p16, P.vt, P.oh, P.ol);
    mma_gemm_f<2><<<dim3(DMODEL/128, R/128), 256, SM>>>(P.oh, P.ol, wh+WOFF_O, wl+WOFF_O, P.q, R, DMODEL, DMODEL);
    ln_split_kernel<<<R,256>>>(P.x, P.q, P.h, P.hh, P.hl);
    mma_gemm_gelu<2><<<dim3(FFDIM/128, R/128), 256, SM>>>(P.hh, P.hl, wh+WOFF_1, wl+WOFF_1, P.fh, P.fl, R, FFDIM, DMODEL);
    mma_gemm_f<2><<<dim3(DMODEL/128, R/128), 256, SM>>>(P.fh, P.fl, wh+WOFF_2, wl+WOFF_2, P.q, R, DMODEL, FFDIM);
    ln_kernel<<<R,256>>>(P.h, P.q, P.h);
}

extern "C" void kernel_launch(void* const* d_in, const int* in_sizes, int n_in,
                              void* d_out, int out_size)
{
    const int*   cdd_sub  = (const int*)d_in[0];
    const int*   his_sub  = (const int*)d_in[1];
    const int*   cdd_enc  = (const int*)d_in[2];
    const int*   his_enc  = (const int*)d_in[3];
    const float* cdd_mask = (const float*)d_in[4];
    const float* his_mask = (const float*)d_in[5];
    const float* cdd_am   = (const float*)d_in[6];
    const float* his_am   = (const float*)d_in[7];
    const float* emb      = (const float*)d_in[8];
    const float* qU    = (const float*)d_in[21];
    const float* projW = (const float*)d_in[22];
    const float* projb = (const float*)d_in[23];
    float* out = (float*)d_out;

    cudaGetSymbolAddress((void**)&P.x,   g_x);
    cudaGetSymbolAddress((void**)&P.q,   g_q);
    cudaGetSymbolAddress((void**)&P.k,   g_k);
    cudaGetSymbolAddress((void**)&P.v,   g_v);
    cudaGetSymbolAddress((void**)&P.h,   g_h);
    cudaGetSymbolAddress((void**)&P.lg,  g_lg);
    cudaGetSymbolAddress((void**)&P.pre, g_pre);
    cudaGetSymbolAddress((void**)&P.atC, g_atC);
    cudaGetSymbolAddress((void**)&P.atH, g_atH);
    cudaGetSymbolAddress((void**)&P.cls, g_cls);
    cudaGetSymbolAddress((void**)&P.cddr,g_cddr);
    cudaGetSymbolAddress((void**)&P.u0,  g_u0);
    cudaGetSymbolAddress((void**)&P.ur,  g_ur);
    cudaGetSymbolAddress((void**)&P.psm, g_psm);
    cudaGetSymbolAddress((void**)&P.kid, g_kid);
    cudaGetSymbolAddress((void**)&P.whi, g_whi);
    cudaGetSymbolAddress((void**)&P.wlo, g_wlo);
    cudaGetSymbolAddress((void**)&P.xh,  g_xh);
    cudaGetSymbolAddress((void**)&P.xl,  g_xl);
    cudaGetSymbolAddress((void**)&P.oh,  g_oh);
    cudaGetSymbolAddress((void**)&P.ol,  g_ol);
    cudaGetSymbolAddress((void**)&P.hh,  g_hh);
    cudaGetSymbolAddress((void**)&P.hl,  g_hl);
    cudaGetSymbolAddress((void**)&P.fh,  g_fh);
    cudaGetSymbolAddress((void**)&P.fl,  g_fl);
    cudaGetSymbolAddress((void**)&P.q16, g_q16);
    cudaGetSymbolAddress((void**)&P.k16, g_k16);
    cudaGetSymbolAddress((void**)&P.vt,  g_vt);
    cudaGetSymbolAddress((void**)&P.p16, g_p16);
    // fp16 aliases of the fp32 q/k/v scratch
    P.qhA = (unsigned short*)P.q;  P.qlA = P.qhA + (size_t)ROWS_MAX*DMODEL;
    P.khA = (unsigned short*)P.k;  P.klA = P.khA + (size_t)ROWS_MAX*DMODEL;
    P.vhA = (unsigned short*)P.v;  P.vlA = P.vhA + (size_t)ROWS_MAX*DMODEL;

    cudaFuncSetAttribute(mma_gemm_f<2>,    cudaFuncAttributeMaxDynamicSharedMemorySize, SMEM_T(2));
    cudaFuncSetAttribute(mma_gemm_gelu<2>, cudaFuncAttributeMaxDynamicSharedMemorySize, SMEM_T(2));
    cudaFuncSetAttribute(mma_gemm_qkv5<2>, cudaFuncAttributeMaxDynamicSharedMemorySize, SMEM_T(2));
    cudaFuncSetAttribute(mma_gemm_qkv16,   cudaFuncAttributeMaxDynamicSharedMemorySize, SMEM_T(2));
    cudaFuncSetAttribute(mma_gemm_f<3>,    cudaFuncAttributeMaxDynamicSharedMemorySize, SMEM_T(3));
    cudaFuncSetAttribute(mma_gemm_gelu<3>, cudaFuncAttributeMaxDynamicSharedMemorySize, SMEM_T(3));
    cudaFuncSetAttribute(mma_gemm_qkv5<3>, cudaFuncAttributeMaxDynamicSharedMemorySize, SMEM_T(3));

    // ---- batched weight prep ----
    PrepPtrs pp;
    for (int i = 0; i < 6; i++) { pp.p[i] = (const float*)d_in[9+i]; pp.p[6+i] = (const float*)d_in[15+i]; }
    prep_all<<<dim3(2304, 12), dim3(32,8)>>>(pp, P.whi, P.wlo);

    // ---- candidate path (BERT weights), 2-term GEMMs + 3-term mma attention ----
    prefix_kernel<<<NCDD,256>>>(cdd_sub, cdd_mask, cdd_am, P.pre, P.atC);
    pool_kernel<<<dim3(NCDD, DMODEL/128),128>>>(P.pre, cdd_enc, emb, P.x, P.xh, P.xl);
    run_transformer_seq64<2>(NCDD, P.whi, P.wlo, P.atC);
    sgemm_proj<<<dim3(DMODEL/64, 1),256>>>(P.h, (size_t)SEQ*DMODEL, projW, P.cddr, NCDD, DMODEL, DMODEL, projb);

    // ---- history path (encN weights), 3-term everywhere (kid-exact) ----
    prefix_kernel<<<NHIS,256>>>(his_sub, his_mask, his_am, P.pre, P.atH);
    pool_kernel<<<dim3(NHIS, DMODEL/128),128>>>(P.pre, his_enc, emb, P.x, P.xh, P.xl);
    run_transformer_seq64<3>(NHIS, P.whi+WSET, P.wlo+WSET, P.atH);
    gather_cls_kernel<<<NHIS,256>>>(P.h, P.cls, SEQ);
    user0_kernel<<<BB,256>>>(P.cls, qU, P.u0);
    topk_kernel<<<BB*HISN,256>>>(P.h, P.u0, P.atH, P.kid, P.x, P.xh, P.xl, P.psm);

    // ---- user path (BERT weights), 2-term + fp16 MMA attention ----
    run_transformer_user(P.whi, P.wlo, P.psm);
    sgemm_proj<<<dim3(DMODEL/64, 1),256>>>(P.h, (size_t)LUSR*DMODEL, projW, P.ur, BB, DMODEL, DMODEL, projb);

    // ---- outputs ----
    final_kernel<<<BB + (BB*HISN*KSEL + 255)/256, 256>>>(P.cddr, P.ur, P.kid, out);
}

// round 12
// speedup vs baseline: 3.3647x; 1.0254x over previous
#include <cuda_runtime.h>
#include <cuda_fp16.h>
#include <math.h>
#include <stdint.h>

#define BB     8
#define CDDN   5
#define HISN   50
#define SEQ    64
#define DMODEL 768
#define NHEAD  12
#define FFDIM  3072
#define KSEL   8

#define NCDD   (BB*CDDN)     // 40
#define NHIS   (BB*HISN)     // 400
#define LUSR   400
#define LPAD   448
#define ROWS_MAX (NHIS*SEQ)  // 25600
#define CROWS  (NCDD*SEQ)    // 2560

#define WOFF_Q  0
#define WOFF_K  589824
#define WOFF_V  1179648
#define WOFF_O  1769472
#define WOFF_1  2359296
#define WOFF_2  4718592
#define WSET    7077888

// ---------------- scratch (his/user paths) ----------------
__device__ float g_x [ (size_t)ROWS_MAX*DMODEL ];
__device__ float g_q [ (size_t)ROWS_MAX*DMODEL ];   // aliased fp16 qh/ql
__device__ float g_k [ (size_t)ROWS_MAX*DMODEL ];
__device__ float g_v [ (size_t)ROWS_MAX*DMODEL ];
__device__ float g_h [ (size_t)ROWS_MAX*DMODEL ];
__device__ float g_lg[ (size_t)BB*NHEAD*LUSR*LUSR ];
__device__ float g_pre[(size_t)NHIS*SEQ*SEQ ];
__device__ float g_atC[ NCDD*SEQ ];
__device__ float g_atH[ NHIS*SEQ ];
__device__ float g_cls[ (size_t)NHIS*DMODEL ];
__device__ float g_cddr[(size_t)NCDD*DMODEL ];
__device__ float g_u0 [ BB*DMODEL ];
__device__ float g_ur [ BB*DMODEL ];
__device__ float g_psm[ BB*LUSR ];
__device__ int   g_kid[ BB*HISN*KSEL ];
__device__ unsigned short g_whi[ (size_t)2*WSET ];
__device__ unsigned short g_wlo[ (size_t)2*WSET ];
__device__ unsigned short g_xh[ (size_t)ROWS_MAX*DMODEL ];
__device__ unsigned short g_xl[ (size_t)ROWS_MAX*DMODEL ];
__device__ unsigned short g_oh[ (size_t)ROWS_MAX*DMODEL ];
__device__ unsigned short g_ol[ (size_t)ROWS_MAX*DMODEL ];
__device__ unsigned short g_hh[ (size_t)ROWS_MAX*DMODEL ];
__device__ unsigned short g_hl[ (size_t)ROWS_MAX*DMODEL ];
__device__ unsigned short g_fh[ (size_t)ROWS_MAX*FFDIM ];
__device__ unsigned short g_fl[ (size_t)ROWS_MAX*FFDIM ];
// user-path fp16 attention buffers
__device__ unsigned short g_q16[ (size_t)BB*LPAD*DMODEL ];
__device__ unsigned short g_k16[ (size_t)BB*LPAD*DMODEL ];
__device__ unsigned short g_vt [ (size_t)BB*DMODEL*LPAD ];
__device__ unsigned short g_p16[ (size_t)BB*NHEAD*LPAD*LPAD ];
// ---------------- private scratch for the overlapped cdd path ----------------
__device__ float g_cpre[(size_t)NCDD*SEQ*SEQ ];
__device__ float g_cx [ (size_t)CROWS*DMODEL ];
__device__ float g_cq [ (size_t)CROWS*DMODEL ];
__device__ float g_ck [ (size_t)CROWS*DMODEL ];
__device__ float g_cv [ (size_t)CROWS*DMODEL ];
__device__ float g_ch [ (size_t)CROWS*DMODEL ];
__device__ unsigned short g_cxh[ (size_t)CROWS*DMODEL ];
__device__ unsigned short g_cxl[ (size_t)CROWS*DMODEL ];
__device__ unsigned short g_coh[ (size_t)CROWS*DMODEL ];
__device__ unsigned short g_col[ (size_t)CROWS*DMODEL ];
__device__ unsigned short g_chh[ (size_t)CROWS*DMODEL ];
__device__ unsigned short g_chl[ (size_t)CROWS*DMODEL ];
__device__ unsigned short g_cfh[ (size_t)CROWS*FFDIM ];
__device__ unsigned short g_cfl[ (size_t)CROWS*FFDIM ];

// ---------------- low-level helpers ----------------
__device__ __forceinline__ void cp16(uint32_t s, const void* g){
    asm volatile("cp.async.ca.shared.global [%0], [%1], 16;\n" :: "r"(s), "l"(g));
}
__device__ __forceinline__ void cp_commit(){ asm volatile("cp.async.commit_group;\n"); }
template<int N>
__device__ __forceinline__ void cp_wait(){ asm volatile("cp.async.wait_group %0;\n" :: "n"(N)); }

__device__ __forceinline__ uint32_t smem_u32(const void* p) {
    uint32_t a;
    asm("{ .reg .u64 t; cvta.to.shared.u64 t, %1; cvt.u32.u64 %0, t; }" : "=r"(a) : "l"(p));
    return a;
}
__device__ __forceinline__ void ldsm_x4(uint32_t* r, uint32_t addr){
    asm volatile("ldmatrix.sync.aligned.m8n8.x4.shared.b16 {%0,%1,%2,%3}, [%4];"
        : "=r"(r[0]),"=r"(r[1]),"=r"(r[2]),"=r"(r[3]) : "r"(addr));
}
__device__ __forceinline__ void ldsm_x4_t(uint32_t* r, uint32_t addr){
    asm volatile("ldmatrix.sync.aligned.m8n8.x4.trans.shared.b16 {%0,%1,%2,%3}, [%4];"
        : "=r"(r[0]),"=r"(r[1]),"=r"(r[2]),"=r"(r[3]) : "r"(addr));
}
__device__ __forceinline__ void mma_f16(float* c, const uint32_t* a, const uint32_t* b){
    asm volatile("mma.sync.aligned.m16n8k16.row.col.f32.f16.f16.f32 "
        "{%0,%1,%2,%3}, {%4,%5,%6,%7}, {%8,%9}, {%0,%1,%2,%3};"
        : "+f"(c[0]),"+f"(c[1]),"+f"(c[2]),"+f"(c[3])
        : "r"(a[0]),"r"(a[1]),"r"(a[2]),"r"(a[3]), "r"(b[0]),"r"(b[1]));
}
__device__ __forceinline__ void split2(float v, unsigned short& h, unsigned short& l){
    __half hh = __float2half_rn(v);
    __half ll = __float2half_rn(v - __half2float(hh));
    h = __half_as_ushort(hh);
    l = __half_as_ushort(ll);
}
__device__ __forceinline__ unsigned short h16(float v){
    return __half_as_ushort(__float2half_rn(v));
}

// ---------------- reductions ----------------
__device__ __forceinline__ float warp_sum(float v){
    #pragma unroll
    for(int o=16;o;o>>=1) v += __shfl_xor_sync(0xffffffffu, v, o);
    return v;
}
__device__ __forceinline__ float warp_max(float v){
    #pragma unroll
    for(int o=16;o;o>>=1) v = fmaxf(v, __shfl_xor_sync(0xffffffffu, v, o));
    return v;
}
__device__ float block_sum(float v){
    __shared__ float red[33];
    int lane=threadIdx.x&31, w=threadIdx.x>>5, nw=blockDim.x>>5;
    v = warp_sum(v);
    __syncthreads();
    if(lane==0) red[w]=v;
    __syncthreads();
    if(threadIdx.x==0){ float t=0.f; for(int i=0;i<nw;i++) t+=red[i]; red[32]=t; }
    __syncthreads();
    return red[32];
}
__device__ float block_max(float v){
    __shared__ float red[33];
    int lane=threadIdx.x&31, w=threadIdx.x>>5, nw=blockDim.x>>5;
    v = warp_max(v);
    __syncthreads();
    if(lane==0) red[w]=v;
    __syncthreads();
    if(threadIdx.x==0){ float t=red[0]; for(int i=1;i<nw;i++) t=fmaxf(t,red[i]); red[32]=t; }
    __syncthreads();
    return red[32];
}

// ---------------- batched weight prep ----------------
struct PrepPtrs { const float* p[12]; };
__constant__ size_t c_woffs[6] = { WOFF_Q, WOFF_K, WOFF_V, WOFF_O, WOFF_1, WOFF_2 };

__global__ void prep_all(PrepPtrs ptrs, unsigned short* __restrict__ Th,
                         unsigned short* __restrict__ Tl)
{
    int w = blockIdx.y;
    int wi = w % 6;
    int K = (wi==5) ? FFDIM : DMODEL;
    int N = (wi==4) ? FFDIM : DMODEL;
    int ntx = N >> 5;
    int tiles = (K >> 5) * ntx;
    int t = blockIdx.x;
    if (t >= tiles) return;
    int nb = (t % ntx) << 5, kb = (t / ntx) << 5;
    const float* W = ptrs.p[w];
    size_t base = c_woffs[wi] + (size_t)(w/6)*WSET;

    __shared__ float tbuf[32][33];
    int x = threadIdx.x, y = threadIdx.y;
    for (int i=y;i<32;i+=8)
        tbuf[i][x] = W[(size_t)(kb+i)*N + nb + x];
    __syncthreads();
    for (int i=y;i<32;i+=8) {
        unsigned short h, l;
        split2(tbuf[x][i], h, l);
        size_t dst = base + (size_t)(nb+i)*K + kb + x;
        Th[dst] = h;
        Tl[dst] = l;
    }
}

// ---------------- mma.sync split-fp16 GEMM ----------------
#define APAD 40
#define ARR_B  (128*APAD*2)
#define SMEM_T(T) (2*((T)+1)*ARR_B)

template<int EPI, int TERMS>
__device__ __forceinline__ void mma_body(const unsigned short* __restrict__ Ah,
                                         const unsigned short* __restrict__ Al,
                                         const unsigned short* __restrict__ Bh,
                                         const unsigned short* __restrict__ Bl,
                                         float* __restrict__ C,
                                         unsigned short* __restrict__ Ch,
                                         unsigned short* __restrict__ Cl,
                                         int M, int N, int K)
{
    extern __shared__ char sm[];
    const uint32_t sbase = smem_u32(sm);
    const int tid = threadIdx.x, lane = tid & 31, wid = tid >> 5;
    const int wm = wid >> 2, wn = wid & 3;
    const int rowBlk = blockIdx.y << 7, colBlk = blockIdx.x << 7;
    const uint32_t STG = (TERMS+1)*ARR_B;

    int r0 = tid >> 2,        s0 = (tid & 3) << 3;
    int r1 = (tid+256) >> 2,  s1 = ((tid+256) & 3) << 3;
    const unsigned short* gA[2] = {Ah, Al};

    const int nc = K >> 5;
    #pragma unroll
    for (int p=0;p<2;p++) {
        cp16(sbase + p*ARR_B + (uint32_t)(r0*APAD + s0)*2, gA[p] + (size_t)(rowBlk+r0)*K + s0);
        cp16(sbase + p*ARR_B + (uint32_t)(r1*APAD + s1)*2, gA[p] + (size_t)(rowBlk+r1)*K + s1);
    }
    cp16(sbase + 2*ARR_B + (uint32_t)(r0*APAD + s0)*2, Bh + (size_t)(colBlk+r0)*K + s0);
    cp16(sbase + 2*ARR_B + (uint32_t)(r1*APAD + s1)*2, Bh + (size_t)(colBlk+r1)*K + s1);
    if (TERMS == 3) {
        cp16(sbase + 3*ARR_B + (uint32_t)(r0*APAD + s0)*2, Bl + (size_t)(colBlk+r0)*K + s0);
        cp16(sbase + 3*ARR_B + (uint32_t)(r1*APAD + s1)*2, Bl + (size_t)(colBlk+r1)*K + s1);
    }
    cp_commit();

    const uint32_t aoff = (uint32_t)((wm*64 + (lane & 15))*APAD + 8*(lane >> 4)) * 2;
    const uint32_t boff = (uint32_t)((wn*32 + (lane & 7) + 8*(lane >> 4))*APAD + 8*((lane >> 3) & 1)) * 2;

    float acc[4][4][4] = {};

    for (int c = 0; c < nc; c++) {
        const bool has = (c+1 < nc);
        if (has) {
            int kb = (c+1) << 5;
            uint32_t st = ((c+1) & 1) * STG;
            #pragma unroll
            for (int p=0;p<2;p++) {
                cp16(sbase + st + p*ARR_B + (uint32_t)(r0*APAD + s0)*2, gA[p] + (size_t)(rowBlk+r0)*K + kb + s0);
                cp16(sbase + st + p*ARR_B + (uint32_t)(r1*APAD + s1)*2, gA[p] + (size_t)(rowBlk+r1)*K + kb + s1);
            }
            cp16(sbase + st + 2*ARR_B + (uint32_t)(r0*APAD + s0)*2, Bh + (size_t)(colBlk+r0)*K + kb + s0);
            cp16(sbase + st + 2*ARR_B + (uint32_t)(r1*APAD + s1)*2, Bh + (size_t)(colBlk+r1)*K + kb + s1);
            if (TERMS == 3) {
                cp16(sbase + st + 3*ARR_B + (uint32_t)(r0*APAD + s0)*2, Bl + (size_t)(colBlk+r0)*K + kb + s0);
                cp16(sbase + st + 3*ARR_B + (uint32_t)(r1*APAD + s1)*2, Bl + (size_t)(colBlk+r1)*K + kb + s1);
            }
            cp_commit();
            cp_wait<1>();
        } else {
            cp_wait<0>();
        }
        __syncthreads();

        uint32_t st = (c & 1) * STG;
        uint32_t aH = sbase + st + aoff;
        uint32_t aL = aH + ARR_B;
        uint32_t bH = sbase + st + 2*ARR_B + boff;
        uint32_t bL = bH + ARR_B;

        #pragma unroll
        for (int ks = 0; ks < 2; ks++) {
            uint32_t ko = (uint32_t)(ks*16*2);
            uint32_t ahf[4][4], alf[4][4], bhf[2][4], blf[2][4];
            #pragma unroll
            for (int mt=0;mt<4;mt++) ldsm_x4(ahf[mt], aH + ko + (uint32_t)(mt*16*APAD*2));
            #pragma unroll
            for (int np=0;np<2;np++) ldsm_x4(bhf[np], bH + ko + (uint32_t)(np*16*APAD*2));
            if (TERMS == 3) {
                #pragma unroll
                for (int np=0;np<2;np++) ldsm_x4(blf[np], bL + ko + (uint32_t)(np*16*APAD*2));
            }
            #pragma unroll
            for (int mt=0;mt<4;mt++)
                #pragma unroll
                for (int nt=0;nt<4;nt++)
                    mma_f16(acc[mt][nt], ahf[mt], &bhf[nt>>1][(nt&1)*2]);
            #pragma unroll
            for (int mt=0;mt<4;mt++) ldsm_x4(alf[mt], aL + ko + (uint32_t)(mt*16*APAD*2));
            if (TERMS == 3) {
                #pragma unroll
                for (int mt=0;mt<4;mt++)
                    #pragma unroll
                    for (int nt=0;nt<4;nt++)
                        mma_f16(acc[mt][nt], ahf[mt], &blf[nt>>1][(nt&1)*2]);
            }
            #pragma unroll
            for (int mt=0;mt<4;mt++)
                #pragma unroll
                for (int nt=0;nt<4;nt++)
                    mma_f16(acc[mt][nt], alf[mt], &bhf[nt>>1][(nt&1)*2]);
        }
        __syncthreads();
    }

    #pragma unroll
    for (int mt=0;mt<4;mt++) {
        int row = rowBlk + wm*64 + mt*16 + (lane >> 2);
        #pragma unroll
        for (int nt=0;nt<4;nt++) {
            int col = colBlk + wn*32 + nt*8 + (lane & 3)*2;
            float v[4] = {acc[mt][nt][0], acc[mt][nt][1], acc[mt][nt][2], acc[mt][nt][3]};
            if (EPI == 0) {
                *(float2*)(C + (size_t)row*N + col)     = make_float2(v[0], v[1]);
                *(float2*)(C + (size_t)(row+8)*N + col) = make_float2(v[2], v[3]);
            } else if (EPI == 1 || EPI == 5) {
                if (EPI == 1) {
                    #pragma unroll
                    for (int j=0;j<4;j++) {
                        float t = v[j];
                        v[j] = 0.5f*t*(1.f + tanhf(0.7978845608028654f*(t + 0.044715f*t*t*t)));
                    }
                }
                unsigned short h0,l0,h1,l1;
                split2(v[0], h0, l0); split2(v[1], h1, l1);
                *(uint32_t*)(Ch + (size_t)row*N + col) = (uint32_t)h0 | ((uint32_t)h1<<16);
                *(uint32_t*)(Cl + (size_t)row*N + col) = (uint32_t)l0 | ((uint32_t)l1<<16);
                split2(v[2], h0, l0); split2(v[3], h1, l1);
                *(uint32_t*)(Ch + (size_t)(row+8)*N + col) = (uint32_t)h0 | ((uint32_t)h1<<16);
                *(uint32_t*)(Cl + (size_t)(row+8)*N + col) = (uint32_t)l0 | ((uint32_t)l1<<16);
            } else if (EPI == 3) {
                int n0 = row / LUSR, l0i = row - n0*LUSR;
                *(uint32_t*)(Ch + ((size_t)n0*LPAD + l0i)*DMODEL + col) =
                    (uint32_t)h16(v[0]) | ((uint32_t)h16(v[1])<<16);
                int n1 = (row+8) / LUSR, l1i = (row+8) - n1*LUSR;
                *(uint32_t*)(Ch + ((size_t)n1*LPAD + l1i)*DMODEL + col) =
                    (uint32_t)h16(v[2]) | ((uint32_t)h16(v[3])<<16);
            } else { // EPI == 4
                int n0 = row / LUSR, l0i = row - n0*LUSR;
                Ch[((size_t)n0*DMODEL + col  )*LPAD + l0i] = h16(v[0]);
                Ch[((size_t)n0*DMODEL + col+1)*LPAD + l0i] = h16(v[1]);
                int n1 = (row+8) / LUSR, l1i = (row+8) - n1*LUSR;
                Ch[((size_t)n1*DMODEL + col  )*LPAD + l1i] = h16(v[2]);
                Ch[((size_t)n1*DMODEL + col+1)*LPAD + l1i] = h16(v[3]);
            }
        }
    }
}

template<int TERMS>
__global__ __launch_bounds__(256, 2) void mma_gemm_f(const unsigned short* __restrict__ Ah,
                                                     const unsigned short* __restrict__ Al,
                                                     const unsigned short* __restrict__ Bh,
                                                     const unsigned short* __restrict__ Bl,
                                                     float* __restrict__ C,
                                                     int M, int N, int K)
{
    mma_body<0, TERMS>(Ah, Al, Bh, Bl, C, nullptr, nullptr, M, N, K);
}

template<int TERMS>
__global__ __launch_bounds__(256, 2) void mma_gemm_gelu(const unsigned short* __restrict__ Ah,
                                                        const unsigned short* __restrict__ Al,
                                                        const unsigned short* __restrict__ Bh,
                                                        const unsigned short* __restrict__ Bl,
                                                        unsigned short* __restrict__ Ch,
                                                        unsigned short* __restrict__ Cl,
                                                        int M, int N, int K)
{
    mma_body<1, TERMS>(Ah, Al, Bh, Bl, nullptr, Ch, Cl, M, N, K);
}

template<int TERMS>
__global__ __launch_bounds__(256, 2) void mma_gemm_qkv5(const unsigned short* __restrict__ Ah,
                                                        const unsigned short* __restrict__ Al,
                                                        const unsigned short* __restrict__ Wh,
                                                        const unsigned short* __restrict__ Wl,
                                                        unsigned short* __restrict__ qh,
                                                        unsigned short* __restrict__ ql,
                                                        unsigned short* __restrict__ kh,
                                                        unsigned short* __restrict__ kl,
                                                        unsigned short* __restrict__ vh,
                                                        unsigned short* __restrict__ vl,
                                                        int M)
{
    const unsigned short* bh = Wh + (size_t)blockIdx.z*589824;
    const unsigned short* bl = Wl + (size_t)blockIdx.z*589824;
    unsigned short* Ch = (blockIdx.z==0) ? qh : (blockIdx.z==1) ? kh : vh;
    unsigned short* Cl = (blockIdx.z==0) ? ql : (blockIdx.z==1) ? kl : vl;
    mma_body<5, TERMS>(Ah, Al, bh, bl, nullptr, Ch, Cl, M, DMODEL, DMODEL);
}

__global__ __launch_bounds__(256, 2) void mma_gemm_qkv16(const unsigned short* __restrict__ Ah,
                                                         const unsigned short* __restrict__ Al,
                                                         const unsigned short* __restrict__ Wh,
                                                         const unsigned short* __restrict__ Wl,
                                                         unsigned short* __restrict__ q16,
                                                         unsigned short* __restrict__ k16,
                                                         unsigned short* __restrict__ vt,
                                                         int M)
{
    const unsigned short* bh = Wh + (size_t)blockIdx.z*589824;
    const unsigned short* bl = Wl + (size_t)blockIdx.z*589824;
    if (blockIdx.z == 0)
        mma_body<3, 2>(Ah, Al, bh, bl, nullptr, q16, nullptr, M, DMODEL, DMODEL);
    else if (blockIdx.z == 1)
        mma_body<3, 2>(Ah, Al, bh, bl, nullptr, k16, nullptr, M, DMODEL, DMODEL);
    else
        mma_body<4, 2>(Ah, Al, bh, bl, nullptr, vt, nullptr, M, DMODEL, DMODEL);
}

// ---------------- fused fp16 3-term MMA attention (seq64, kid-safe) ----------------
__global__ __launch_bounds__(128) void attn64_mma(
    const unsigned short* __restrict__ qh, const unsigned short* __restrict__ ql,
    const unsigned short* __restrict__ kh, const unsigned short* __restrict__ kl,
    const unsigned short* __restrict__ vh, const unsigned short* __restrict__ vl,
    const float* __restrict__ mask,
    unsigned short* __restrict__ Oh, unsigned short* __restrict__ Ol)
{
    __shared__ __align__(16) unsigned short T[4][64][72];
    __shared__ float msk[64];
    const int n = blockIdx.x, h = blockIdx.y;
    const int tid = threadIdx.x, lane = tid & 31, wid = tid >> 5;
    const uint32_t base = smem_u32(T);
    const uint32_t AR = 64*72*2;

    {
        const unsigned short* src[4] = {qh, ql, kh, kl};
        #pragma unroll
        for (int t = 0; t < 4; t++)
            for (int i = tid; i < 512; i += 128) {
                int r = i >> 3, cg = (i & 7) << 3;
                *(uint4*)&T[t][r][cg] = *(const uint4*)(src[t] + ((size_t)n*64 + r)*DMODEL + h*64 + cg);
            }
        if (tid < 64) msk[tid] = (mask[(size_t)n*64 + tid] > 0.f) ? 0.f : -1e9f;
    }
    __syncthreads();

    const uint32_t aoff = base + (uint32_t)((wid*16 + (lane & 15))*72 + 8*(lane >> 4))*2;
    const uint32_t boff = base + 2*AR + (uint32_t)(((lane & 7) + 8*(lane >> 4))*72 + 8*((lane >> 3) & 1))*2;
    float acc[8][4] = {};
    #pragma unroll
    for (int k0 = 0; k0 < 4; k0++) {
        uint32_t aH[4], aL[4], bH[4][4], bL[4][4];
        ldsm_x4(aH, aoff + k0*32);
        ldsm_x4(aL, aoff + AR + k0*32);
        #pragma unroll
        for (int nb = 0; nb < 4; nb++) {
            ldsm_x4(bH[nb], boff + k0*32 + (uint32_t)(nb*16*72*2));
            ldsm_x4(bL[nb], boff + AR + k0*32 + (uint32_t)(nb*16*72*2));
        }
        #pragma unroll
        for (int nb = 0; nb < 4; nb++) {
            mma_f16(acc[nb*2+0], aH, &bH[nb][0]);
            mma_f16(acc[nb*2+1], aH, &bH[nb][2]);
            mma_f16(acc[nb*2+0], aL, &bH[nb][0]);
            mma_f16(acc[nb*2+1], aL, &bH[nb][2]);
            mma_f16(acc[nb*2+0], aH, &bL[nb][0]);
            mma_f16(acc[nb*2+1], aH, &bL[nb][2]);
        }
    }

    #pragma unroll
    for (int nf = 0; nf < 8; nf++) {
        int c0 = nf*8 + (lane & 3)*2;
        float b0 = msk[c0], b1 = msk[c0+1];
        acc[nf][0] = acc[nf][0]*0.125f + b0;
        acc[nf][1] = acc[nf][1]*0.125f + b1;
        acc[nf][2] = acc[nf][2]*0.125f + b0;
        acc[nf][3] = acc[nf][3]*0.125f + b1;
    }
    float mlo = -3.4e38f, mhi = -3.4e38f;
    #pragma unroll
    for (int nf = 0; nf < 8; nf++) {
        mlo = fmaxf(mlo, fmaxf(acc[nf][0], acc[nf][1]));
        mhi = fmaxf(mhi, fmaxf(acc[nf][2], acc[nf][3]));
    }
    #pragma unroll
    for (int o = 1; o <= 2; o <<= 1) {
        mlo = fmaxf(mlo, __shfl_xor_sync(0xffffffffu, mlo, o));
        mhi = fmaxf(mhi, __shfl_xor_sync(0xffffffffu, mhi, o));
    }
    float slo = 0.f, shi = 0.f;
    #pragma unroll
    for (int nf = 0; nf < 8; nf++) {
        acc[nf][0] = expf(acc[nf][0]-mlo); acc[nf][1] = expf(acc[nf][1]-mlo);
        acc[nf][2] = expf(acc[nf][2]-mhi); acc[nf][3] = expf(acc[nf][3]-mhi);
        slo += acc[nf][0] + acc[nf][1];
        shi += acc[nf][2] + acc[nf][3];
    }
    #pragma unroll
    for (int o = 1; o <= 2; o <<= 1) {
        slo += __shfl_xor_sync(0xffffffffu, slo, o);
        shi += __shfl_xor_sync(0xffffffffu, shi, o);
    }
    float ilo = 1.f/slo, ihi = 1.f/shi;

    __syncthreads();

    {
        int rlo = wid*16 + (lane >> 2), rhi = rlo + 8;
        #pragma unroll
        for (int nf = 0; nf < 8; nf++) {
            int c0 = nf*8 + (lane & 3)*2;
            unsigned short h0,l0,h1,l1;
            split2(acc[nf][0]*ilo, h0, l0); split2(acc[nf][1]*ilo, h1, l1);
            *(uint32_t*)&T[0][rlo][c0] = (uint32_t)h0 | ((uint32_t)h1<<16);
            *(uint32_t*)&T[1][rlo][c0] = (uint32_t)l0 | ((uint32_t)l1<<16);
            split2(acc[nf][2]*ihi, h0, l0); split2(acc[nf][3]*ihi, h1, l1);
            *(uint32_t*)&T[0][rhi][c0] = (uint32_t)h0 | ((uint32_t)h1<<16);
            *(uint32_t*)&T[1][rhi][c0] = (uint32_t)l0 | ((uint32_t)l1<<16);
        }
        const unsigned short* vsrc[2] = {vh, vl};
        #pragma unroll
        for (int t = 0; t < 2; t++)
            for (int i = tid; i < 512; i += 128) {
                int r = i >> 3, cg = (i & 7) << 3;
                *(uint4*)&T[2+t][r][cg] = *(const uint4*)(vsrc[t] + ((size_t)n*64 + r)*DMODEL + h*64 + cg);
            }
    }
    __syncthreads();

    const uint32_t voff = base + 2*AR + (uint32_t)(((lane & 7) + 8*((lane >> 3) & 1))*72 + 8*(lane >> 4))*2;
    float oacc[8][4] = {};
    #pragma unroll
    for (int k0 = 0; k0 < 4; k0++) {
        uint32_t pH[4], pL[4], vH[4][4], vL[4][4];
        ldsm_x4(pH, aoff + k0*32);
        ldsm_x4(pL, aoff + AR + k0*32);
        #pragma unroll
        for (int db = 0; db < 4; db++) {
            ldsm_x4_t(vH[db], voff + (uint32_t)(k0*16*72*2) + db*32);
            ldsm_x4_t(vL[db], voff + AR + (uint32_t)(k0*16*72*2) + db*32);
        }
        #pragma unroll
        for (int db = 0; db < 4; db++) {
            mma_f16(oacc[db*2+0], pH, &vH[db][0]);
            mma_f16(oacc[db*2+1], pH, &vH[db][2]);
            mma_f16(oacc[db*2+0], pL, &vH[db][0]);
            mma_f16(oacc[db*2+1], pL, &vH[db][2]);
            mma_f16(oacc[db*2+0], pH, &vL[db][0]);
            mma_f16(oacc[db*2+1], pH, &vL[db][2]);
        }
    }

    {
        int rlo = wid*16 + (lane >> 2);
        #pragma unroll
        for (int df = 0; df < 8; df++) {
            int d = df*8 + (lane & 3)*2;
            unsigned short h0,l0,h1,l1;
            split2(oacc[df][0], h0, l0); split2(oacc[df][1], h1, l1);
            size_t off = ((size_t)n*64 + rlo)*DMODEL + h*64 + d;
            *(uint32_t*)(Oh + off) = (uint32_t)h0 | ((uint32_t)h1<<16);
            *(uint32_t*)(Ol + off) = (uint32_t)l0 | ((uint32_t)l1<<16);
            split2(oacc[df][2], h0, l0); split2(oacc[df][3], h1, l1);
            off = ((size_t)n*64 + rlo + 8)*DMODEL + h*64 + d;
            *(uint32_t*)(Oh + off) = (uint32_t)h0 | ((uint32_t)h1<<16);
            *(uint32_t*)(Ol + off) = (uint32_t)l0 | ((uint32_t)l1<<16);
        }
    }
}

// ---------------- fp16 tile attention (user path, L=400) ----------------
__global__ __launch_bounds__(128) void logits_mma(const unsigned short* __restrict__ q16,
                                                  const unsigned short* __restrict__ k16,
                                                  const float* __restrict__ mask,
                                                  float* __restrict__ lg)
{
    __shared__ __align__(16) unsigned short Qs[64][72];
    __shared__ __align__(16) unsigned short Ks[64][72];
    int n = blockIdx.z, h = blockIdx.y;
    int qt = blockIdx.x / 7, kt = blockIdx.x % 7;
    int tid = threadIdx.x, lane = tid & 31, wid = tid >> 5;
    int wm = wid >> 1, wn = wid & 1;
    for (int i = tid; i < 64*8; i += 128) {
        int r = i >> 3, cg = (i & 7) << 3;
        *(uint4*)&Qs[r][cg] = *(const uint4*)(q16 + ((size_t)n*LPAD + qt*64 + r)*DMODEL + h*64 + cg);
        *(uint4*)&Ks[r][cg] = *(const uint4*)(k16 + ((size_t)n*LPAD + kt*64 + r)*DMODEL + h*64 + cg);
    }
    __syncthreads();
    uint32_t aoff = smem_u32(Qs) + (uint32_t)((wm*32 + (lane & 15))*72 + 8*(lane >> 4))*2;
    uint32_t boff = smem_u32(Ks) + (uint32_t)((wn*32 + (lane & 7) + 8*(lane >> 4))*72 + 8*((lane >> 3) & 1))*2;
    float acc[2][4][4] = {};
    #pragma unroll
    for (int k0 = 0; k0 < 64; k0 += 16) {
        uint32_t af[2][4], bf[2][4];
        #pragma unroll
        for (int mt=0;mt<2;mt++) ldsm_x4(af[mt], aoff + k0*2 + (uint32_t)(mt*16*72*2));
        #pragma unroll
        for (int np=0;np<2;np++) ldsm_x4(bf[np], boff + k0*2 + (uint32_t)(np*16*72*2));
        #pragma unroll
        for (int mt=0;mt<2;mt++)
            #pragma unroll
            for (int nt=0;nt<4;nt++)
                mma_f16(acc[mt][nt], af[mt], &bf[nt>>1][(nt&1)*2]);
    }
    #pragma unroll
    for (int mt=0;mt<2;mt++) {
        int qr = qt*64 + wm*32 + mt*16 + (lane >> 2);
        #pragma unroll
        for (int nt=0;nt<4;nt++) {
            int kc = kt*64 + wn*32 + nt*8 + (lane & 3)*2;
            #pragma unroll
            for (int half2i=0;half2i<2;half2i++) {
                int qrr = qr + half2i*8;
                if (qrr >= LUSR) continue;
                float* dst = lg + (((size_t)(n*NHEAD + h)*LUSR + qrr)*LUSR);
                float v0 = acc[mt][nt][half2i*2+0], v1 = acc[mt][nt][half2i*2+1];
                if (kc < LUSR)
                    dst[kc]   = v0*0.125f + ((mask[(size_t)n*LUSR + kc]   > 0.f) ? 0.f : -1e9f);
                if (kc+1 < LUSR)
                    dst[kc+1] = v1*0.125f + ((mask[(size_t)n*LUSR + kc+1] > 0.f) ? 0.f : -1e9f);
            }
        }
    }
}

__global__ void softmax_p16(const float* __restrict__ lg, unsigned short* __restrict__ p16)
{
    __shared__ float buf[LUSR];
    int bi = blockIdx.x;
    int nh = bi / LUSR, q = bi - nh*LUSR;
    const float* p = lg + (size_t)bi * LUSR;
    int tid = threadIdx.x;
    float m = -3.4e38f;
    for (int i=tid;i<LUSR;i+=blockDim.x) { buf[i] = p[i]; m = fmaxf(m, buf[i]); }
    m = block_max(m);
    float s = 0.f;
    for (int i=tid;i<LUSR;i+=blockDim.x) { float e = expf(buf[i]-m); buf[i]=e; s+=e; }
    s = block_sum(s);
    float inv = 1.f/s;
    unsigned short* dst = p16 + ((size_t)nh*LPAD + q)*LPAD;
    for (int i=tid;i<LPAD;i+=blockDim.x)
        dst[i] = h16((i < LUSR) ? buf[i]*inv : 0.f);
}

__global__ __launch_bounds__(128) void av_mma(const unsigned short* __restrict__ p16,
                                              const unsigned short* __restrict__ vt,
                                              unsigned short* __restrict__ Oh,
                                              unsigned short* __restrict__ Ol)
{
    __shared__ __align__(16) unsigned short As[64][72];
    __shared__ __align__(16) unsigned short Bs[64][72];
    int n = blockIdx.z, h = blockIdx.y, qt = blockIdx.x;
    int tid = threadIdx.x, lane = tid & 31, wid = tid >> 5;
    int wm = wid >> 1, wn = wid & 1;
    uint32_t aoff = smem_u32(As) + (uint32_t)((wm*32 + (lane & 15))*72 + 8*(lane >> 4))*2;
    uint32_t boff = smem_u32(Bs) + (uint32_t)((wn*32 + (lane & 7) + 8*(lane >> 4))*72 + 8*((lane >> 3) & 1))*2;
    float acc[2][4][4] = {};
    for (int c = 0; c < 7; c++) {
        for (int i = tid; i < 64*8; i += 128) {
            int r = i >> 3, cg = (i & 7) << 3;
            *(uint4*)&As[r][cg] = *(const uint4*)(p16 + ((size_t)(n*NHEAD + h)*LPAD + qt*64 + r)*LPAD + c*64 + cg);
            *(uint4*)&Bs[r][cg] = *(const uint4*)(vt  + ((size_t)n*DMODEL + h*64 + r)*LPAD + c*64 + cg);
        }
        __syncthreads();
        #pragma unroll
        for (int k0 = 0; k0 < 64; k0 += 16) {
            uint32_t af[2][4], bf[2][4];
            #pragma unroll
            for (int mt=0;mt<2;mt++) ldsm_x4(af[mt], aoff + k0*2 + (uint32_t)(mt*16*72*2));
            #pragma unroll
            for (int np=0;np<2;np++) ldsm_x4(bf[np], boff + k0*2 + (uint32_t)(np*16*72*2));
            #pragma unroll
            for (int mt=0;mt<2;mt++)
                #pragma unroll
                for (int nt=0;nt<4;nt++)
                    mma_f16(acc[mt][nt], af[mt], &bf[nt>>1][(nt&1)*2]);
        }
        __syncthreads();
    }
    #pragma unroll
    for (int mt=0;mt<2;mt++) {
        int l0 = qt*64 + wm*32 + mt*16 + (lane >> 2);
        #pragma unroll
        for (int nt=0;nt<4;nt++) {
            int d = wn*32 + nt*8 + (lane & 3)*2;
            #pragma unroll
            for (int half2i=0;half2i<2;half2i++) {
                int l = l0 + half2i*8;
                if (l >= LUSR) continue;
                float v0 = acc[mt][nt][half2i*2+0], v1 = acc[mt][nt][half2i*2+1];
                size_t off = ((size_t)n*LUSR + l)*DMODEL + h*64 + d;
                unsigned short hh0, ll0, hh1, ll1;
                split2(v0, hh0, ll0); split2(v1, hh1, ll1);
                *(uint32_t*)(Oh + off) = (uint32_t)hh0 | ((uint32_t)hh1<<16);
                *(uint32_t*)(Ol + off) = (uint32_t)ll0 | ((uint32_t)ll1<<16);
            }
        }
    }
}

// ---------------- prefix build ----------------
__global__ void prefix_kernel(const int* __restrict__ sub, const float* __restrict__ mask,
                              const float* __restrict__ amask,
                              float* __restrict__ prefix, float* __restrict__ attn)
{
    __shared__ float P[SEQ*SEQ];
    int bn = blockIdx.x;
    for (int i = threadIdx.x; i < SEQ*SEQ; i += blockDim.x) P[i] = 0.f;
    __syncthreads();
    const int* si = sub + (size_t)bn*SEQ*2;
    for (int s = threadIdx.x; s < SEQ; s += blockDim.x) {
        int i = si[2*s+0], j = si[2*s+1];
        P[i*SEQ + j] = 1.f;
    }
    __syncthreads();
    float m = mask[bn];
    int lane = threadIdx.x & 31, warp = threadIdx.x >> 5;
    for (int i = warp; i < SEQ; i += (blockDim.x >> 5)) {
        float v0 = P[i*SEQ + lane]      * m;
        float v1 = P[i*SEQ + lane + 32] * m;
        float rs = v0 + v1;
        float ad = v0 * amask[bn*SEQ + lane] + v1 * amask[bn*SEQ + lane + 32];
        #pragma unroll
        for (int o=16;o;o>>=1){ rs += __shfl_xor_sync(0xffffffffu,rs,o); ad += __shfl_xor_sync(0xffffffffu,ad,o); }
        float denom = fmaxf(rs, 1e-12f);
        prefix[(size_t)bn*SEQ*SEQ + i*SEQ + lane]      = v0/denom;
        prefix[(size_t)bn*SEQ*SEQ + i*SEQ + lane + 32] = v1/denom;
        if (lane==0) attn[bn*SEQ + i] = ad/denom;
    }
}

// ---------------- embedding pooling ----------------
__global__ void pool_kernel(const float* __restrict__ prefix, const int* __restrict__ enc,
                            const float* __restrict__ emb, float* __restrict__ x,
                            unsigned short* __restrict__ xh, unsigned short* __restrict__ xl)
{
    __shared__ float P[SEQ*SEQ];
    __shared__ int idx[SEQ];
    int bn = blockIdx.x;
    int d  = blockIdx.y*128 + threadIdx.x;
    for (int i = threadIdx.x; i < SEQ*SEQ; i += blockDim.x)
        P[i] = prefix[(size_t)bn*SEQ*SEQ + i];
    if (threadIdx.x < SEQ) idx[threadIdx.x] = enc[(size_t)bn*SEQ + threadIdx.x];
    __syncthreads();
    float acc[SEQ];
    #pragma unroll
    for (int i=0;i<SEQ;i++) acc[i]=0.f;
    for (int j=0;j<SEQ;j++) {
        float e = emb[(size_t)idx[j]*DMODEL + d];
        #pragma unroll
        for (int i=0;i<SEQ;i++) acc[i] = fmaf(P[i*SEQ+j], e, acc[i]);
    }
    for (int i=0;i<SEQ;i++) {
        size_t o = ((size_t)bn*SEQ + i)*DMODEL + d;
        x[o] = acc[i];
        unsigned short h, l;
        split2(acc[i], h, l);
        xh[o] = h; xl[o] = l;
    }
}

// ---------------- strided proj ----------------
__global__ void sgemm_proj(const float* __restrict__ A, size_t lda,
                           const float* __restrict__ B,
                           float* __restrict__ C, int M, int N, int Kd,
                           const float* __restrict__ bias)
{
    __shared__ float As[16][64];
    __shared__ float Bs[16][68];
    int tid = threadIdx.x;
    int rowBase = blockIdx.y << 6, colBase = blockIdx.x << 6;
    int tx = tid & 15, ty = tid >> 4;
    int am = tid >> 2, ak = (tid & 3) << 2;
    int bk = tid >> 4, bn = (tid & 15) << 2;
    bool aok = (rowBase + am) < M;
    const float* Ap = A + (size_t)(rowBase + am)*lda + ak;
    const float* Bp = B + (size_t)bk*N + colBase + bn;
    float acc[4][4] = {};
    for (int k0 = 0; k0 < Kd; k0 += 16) {
        float4 a4 = aok ? *(const float4*)Ap : make_float4(0.f,0.f,0.f,0.f);
        As[ak+0][am]=a4.x; As[ak+1][am]=a4.y; As[ak+2][am]=a4.z; As[ak+3][am]=a4.w;
        *(float4*)&Bs[bk][bn] = *(const float4*)Bp;
        __syncthreads();
        #pragma unroll
        for (int kk=0; kk<16; kk++) {
            float av[4], bv[4];
            #pragma unroll
            for (int i=0;i<4;i++) av[i]=As[kk][(ty<<2)+i];
            #pragma unroll
            for (int j=0;j<4;j++) bv[j]=Bs[kk][(tx<<2)+j];
            #pragma unroll
            for (int i=0;i<4;i++)
                #pragma unroll
                for (int j=0;j<4;j++)
                    acc[i][j] = fmaf(av[i], bv[j], acc[i][j]);
        }
        __syncthreads();
        Ap += 16;
        Bp += (size_t)16*N;
    }
    #pragma unroll
    for (int i=0;i<4;i++) {
        int r = rowBase + (ty<<2) + i;
        if (r >= M) continue;
        #pragma unroll
        for (int j=0;j<4;j++) {
            int c = colBase + (tx<<2) + j;
            C[(size_t)r*N + c] = tanhf(acc[i][j] + bias[c]);
        }
    }
}

// LN variants
__global__ void ln_split_kernel(const float* __restrict__ x, const float* __restrict__ o,
                                float* __restrict__ out,
                                unsigned short* __restrict__ oh, unsigned short* __restrict__ ol)
{
    __shared__ float buf[DMODEL];
    size_t row = blockIdx.x;
    int tid = threadIdx.x;
    float ls = 0.f;
    for (int i=tid;i<DMODEL;i+=blockDim.x) {
        float v = x[row*DMODEL+i] + o[row*DMODEL+i];
        buf[i] = v; ls += v;
    }
    float mu = block_sum(ls) * (1.f/DMODEL);
    float lv = 0.f;
    for (int i=tid;i<DMODEL;i+=blockDim.x) { float d = buf[i]-mu; lv += d*d; }
    float var = block_sum(lv) * (1.f/DMODEL);
    float inv = rsqrtf(var + 1e-12f);
    for (int i=tid;i<DMODEL;i+=blockDim.x) {
        float v = (buf[i]-mu)*inv;
        out[row*DMODEL+i] = v;
        unsigned short h, l;
        split2(v, h, l);
        oh[row*DMODEL+i] = h; ol[row*DMODEL+i] = l;
    }
}

__global__ void ln_kernel(const float* __restrict__ x, const float* __restrict__ o,
                          float* __restrict__ out)
{
    __shared__ float buf[DMODEL];
    size_t row = blockIdx.x;
    int tid = threadIdx.x;
    float ls = 0.f;
    for (int i=tid;i<DMODEL;i+=blockDim.x) {
        float v = x[row*DMODEL+i] + o[row*DMODEL+i];
        buf[i] = v; ls += v;
    }
    float mu = block_sum(ls) * (1.f/DMODEL);
    float lv = 0.f;
    for (int i=tid;i<DMODEL;i+=blockDim.x) { float d = buf[i]-mu; lv += d*d; }
    float var = block_sum(lv) * (1.f/DMODEL);
    float inv = rsqrtf(var + 1e-12f);
    for (int i=tid;i<DMODEL;i+=blockDim.x) out[row*DMODEL+i] = (buf[i]-mu)*inv;
}

__global__ void gather_cls_kernel(const float* __restrict__ h, float* __restrict__ cls, int L)
{
    int n = blockIdx.x;
    for (int d=threadIdx.x; d<DMODEL; d+=blockDim.x)
        cls[(size_t)n*DMODEL + d] = h[(size_t)n*L*DMODEL + d];
}

__global__ void user0_kernel(const float* __restrict__ cls, const float* __restrict__ qU,
                             float* __restrict__ u0)
{
    int b = blockIdx.x;
    __shared__ float w[HISN];
    int lane = threadIdx.x & 31, wp = threadIdx.x >> 5;
    for (int n = wp; n < HISN; n += (blockDim.x >> 5)) {
        const float* c = cls + (size_t)(b*HISN + n)*DMODEL;
        float acc = 0.f;
        for (int d = lane; d < DMODEL; d += 32) acc += c[d]*qU[d];
        acc = warp_sum(acc);
        if (lane==0) w[n] = acc / sqrtf(768.f);
    }
    __syncthreads();
    if (threadIdx.x == 0) {
        float m = w[0];
        for (int n=1;n<HISN;n++) m = fmaxf(m, w[n]);
        float s = 0.f;
        for (int n=0;n<HISN;n++){ w[n] = expf(w[n]-m); s += w[n]; }
        float inv = 1.f/s;
        for (int n=0;n<HISN;n++) w[n] *= inv;
    }
    __syncthreads();
    for (int d=threadIdx.x; d<DMODEL; d+=blockDim.x) {
        float acc = 0.f;
        for (int n=0;n<HISN;n++) acc += w[n]*cls[(size_t)(b*HISN+n)*DMODEL + d];
        u0[b*DMODEL + d] = acc;
    }
}

__global__ void topk_kernel(const float* __restrict__ hidden, const float* __restrict__ u0,
                            const float* __restrict__ attn, int* __restrict__ kid,
                            float* __restrict__ ps,
                            unsigned short* __restrict__ psh, unsigned short* __restrict__ psl,
                            float* __restrict__ psm)
{
    int bn = blockIdx.x;
    int b = bn / HISN, n = bn - b*HISN;
    __shared__ float u[DMODEL];
    __shared__ float sc[SEQ];
    __shared__ int sel[KSEL];
    for (int d=threadIdx.x; d<DMODEL; d+=blockDim.x) u[d] = u0[b*DMODEL + d];
    __syncthreads();
    int lane = threadIdx.x & 31, wp = threadIdx.x >> 5;
    for (int s = wp; s < SEQ; s += (blockDim.x >> 5)) {
        const float* hr = hidden + (size_t)(bn*SEQ + s)*DMODEL;
        float acc = 0.f;
        for (int d = lane; d < DMODEL; d += 32) acc += hr[d]*u[d];
        acc = warp_sum(acc);
        if (lane==0)
            sc[s] = (attn[(size_t)bn*SEQ + s] > 0.f) ? acc / sqrtf(768.f) : -1e9f;
    }
    __syncthreads();
    if (threadIdx.x == 0) {
        bool used[SEQ];
        for (int s=0;s<SEQ;s++) used[s]=false;
        for (int kk=0; kk<KSEL; kk++) {
            float best = -3.4e38f; int bi = 0;
            for (int s=0;s<SEQ;s++)
                if (!used[s] && sc[s] > best) { best = sc[s]; bi = s; }
            used[bi] = true; sel[kk] = bi;
            kid[(size_t)bn*KSEL + kk] = bi;
        }
    }
    __syncthreads();
    for (int kk=0; kk<KSEL; kk++) {
        int s = sel[kk];
        size_t dst = (size_t)(b*LUSR + n*KSEL + kk);
        for (int d=threadIdx.x; d<DMODEL; d+=blockDim.x) {
            float v = hidden[(size_t)(bn*SEQ + s)*DMODEL + d];
            ps[dst*DMODEL + d] = v;
            unsigned short hh, ll;
            split2(v, hh, ll);
            psh[dst*DMODEL + d] = hh; psl[dst*DMODEL + d] = ll;
        }
        if (threadIdx.x == 0) psm[dst] = attn[(size_t)bn*SEQ + s];
    }
}

__global__ void final_kernel(const float* __restrict__ cddr, const float* __restrict__ ur,
                             const int* __restrict__ kid, float* __restrict__ out)
{
    if (blockIdx.x >= BB) {
        int i = (blockIdx.x - BB)*256 + threadIdx.x;
        if (i < BB*HISN*KSEL) out[NCDD + i] = (float)kid[i];
        return;
    }
    int b = blockIdx.x;
    __shared__ float s[CDDN];
    int lane = threadIdx.x & 31, wp = threadIdx.x >> 5;
    for (int c = wp; c < CDDN; c += (blockDim.x >> 5)) {
        const float* a = cddr + (size_t)(b*CDDN + c)*DMODEL;
        const float* uu = ur + (size_t)b*DMODEL;
        float acc = 0.f;
        for (int d = lane; d < DMODEL; d += 32) acc += a[d]*uu[d];
        acc = warp_sum(acc);
        if (lane==0) s[c] = acc / sqrtf(768.f);
    }
    __syncthreads();
    if (threadIdx.x == 0) {
        float m = s[0];
        for (int c=1;c<CDDN;c++) m = fmaxf(m, s[c]);
        float sum = 0.f;
        for (int c=0;c<CDDN;c++) sum += expf(s[c]-m);
        float lse = m + logf(sum);
        for (int c=0;c<CDDN;c++) out[b*CDDN + c] = s[c] - lse;
    }
}

// ---------------- host orchestration ----------------
struct TB {
    float *x; unsigned short *xh,*xl;
    float *qf; unsigned short *qh,*ql,*kh,*kl,*vh,*vl;
    unsigned short *oh,*ol;
    float *h; unsigned short *hh,*hl,*fh,*fl;
};

struct DevPtrs {
    float *lg,*pre,*cpre,*atC,*atH,*cls,*cddr,*u0,*ur,*psm;
    int* kid;
    unsigned short *whi,*wlo,*q16,*k16,*vt,*p16;
};
static DevPtrs P;
static TB HB, CB;   // his/user buffers, cdd buffers

template<int TERMS>
static void run_transformer_seq64(int N, const unsigned short* wh, const unsigned short* wl,
                                  const float* attnMask, const TB& b, cudaStream_t st)
{
    int R = N*SEQ;
    const int SM = SMEM_T(TERMS);
    mma_gemm_qkv5<TERMS><<<dim3(DMODEL/128, R/128, 3), 256, SM, st>>>(
        b.xh, b.xl, wh, wl, b.qh, b.ql, b.kh, b.kl, b.vh, b.vl, R);
    attn64_mma<<<dim3(N, NHEAD),128,0,st>>>(b.qh, b.ql, b.kh, b.kl, b.vh, b.vl, attnMask, b.oh, b.ol);
    mma_gemm_f<TERMS><<<dim3(DMODEL/128, R/128), 256, SM, st>>>(b.oh, b.ol, wh+WOFF_O, wl+WOFF_O, b.qf, R, DMODEL, DMODEL);
    ln_split_kernel<<<R,256,0,st>>>(b.x, b.qf, b.h, b.hh, b.hl);
    mma_gemm_gelu<TERMS><<<dim3(FFDIM/128, R/128), 256, SM, st>>>(b.hh, b.hl, wh+WOFF_1, wl+WOFF_1, b.fh, b.fl, R, FFDIM, DMODEL);
    mma_gemm_f<TERMS><<<dim3(DMODEL/128, R/128), 256, SM, st>>>(b.fh, b.fl, wh+WOFF_2, wl+WOFF_2, b.qf, R, DMODEL, FFDIM);
    ln_kernel<<<R,256,0,st>>>(b.h, b.qf, b.h);
}

static void run_transformer_user(const unsigned short* wh, const unsigned short* wl,
                                 const float* attnMask)
{
    const int R = BB*LUSR;
    const int SM = SMEM_T(2);
    cudaMemsetAsync(P.q16, 0, sizeof(unsigned short)*(size_t)BB*LPAD*DMODEL);
    cudaMemsetAsync(P.k16, 0, sizeof(unsigned short)*(size_t)BB*LPAD*DMODEL);
    cudaMemsetAsync(P.vt,  0, sizeof(unsigned short)*(size_t)BB*DMODEL*LPAD);
    mma_gemm_qkv16<<<dim3(DMODEL/128, R/128, 3), 256, SM>>>(HB.xh, HB.xl, wh, wl, P.q16, P.k16, P.vt, R);
    logits_mma<<<dim3(49, NHEAD, BB),128>>>(P.q16, P.k16, attnMask, P.lg);
    softmax_p16<<<BB*NHEAD*LUSR,128>>>(P.lg, P.p16);
    av_mma<<<dim3(7, NHEAD, BB),128>>>(P.p16, P.vt, HB.oh, HB.ol);
    mma_gemm_f<2><<<dim3(DMODEL/128, R/128), 256, SM>>>(HB.oh, HB.ol, wh+WOFF_O, wl+WOFF_O, HB.qf, R, DMODEL, DMODEL);
    ln_split_kernel<<<R,256>>>(HB.x, HB.qf, HB.h, HB.hh, HB.hl);
    mma_gemm_gelu<2><<<dim3(FFDIM/128, R/128), 256, SM>>>(HB.hh, HB.hl, wh+WOFF_1, wl+WOFF_1, HB.fh, HB.fl, R, FFDIM, DMODEL);
    mma_gemm_f<2><<<dim3(DMODEL/128, R/128), 256, SM>>>(HB.fh, HB.fl, wh+WOFF_2, wl+WOFF_2, HB.qf, R, DMODEL, FFDIM);
    ln_kernel<<<R,256>>>(HB.h, HB.qf, HB.h);
}

extern "C" void kernel_launch(void* const* d_in, const int* in_sizes, int n_in,
                              void* d_out, int out_size)
{
    const int*   cdd_sub  = (const int*)d_in[0];
    const int*   his_sub  = (const int*)d_in[1];
    const int*   cdd_enc  = (const int*)d_in[2];
    const int*   his_enc  = (const int*)d_in[3];
    const float* cdd_mask = (const float*)d_in[4];
    const float* his_mask = (const float*)d_in[5];
    const float* cdd_am   = (const float*)d_in[6];
    const float* his_am   = (const float*)d_in[7];
    const float* emb      = (const float*)d_in[8];
    const float* qU    = (const float*)d_in[21];
    const float* projW = (const float*)d_in[22];
    const float* projb = (const float*)d_in[23];
    float* out = (float*)d_out;

    float *xf,*qf,*kf,*vf,*hf;
    cudaGetSymbolAddress((void**)&xf,   g_x);
    cudaGetSymbolAddress((void**)&qf,   g_q);
    cudaGetSymbolAddress((void**)&kf,   g_k);
    cudaGetSymbolAddress((void**)&vf,   g_v);
    cudaGetSymbolAddress((void**)&hf,   g_h);
    cudaGetSymbolAddress((void**)&P.lg,  g_lg);
    cudaGetSymbolAddress((void**)&P.pre, g_pre);
    cudaGetSymbolAddress((void**)&P.cpre,g_cpre);
    cudaGetSymbolAddress((void**)&P.atC, g_atC);
    cudaGetSymbolAddress((void**)&P.atH, g_atH);
    cudaGetSymbolAddress((void**)&P.cls, g_cls);
    cudaGetSymbolAddress((void**)&P.cddr,g_cddr);
    cudaGetSymbolAddress((void**)&P.u0,  g_u0);
    cudaGetSymbolAddress((void**)&P.ur,  g_ur);
    cudaGetSymbolAddress((void**)&P.psm, g_psm);
    cudaGetSymbolAddress((void**)&P.kid, g_kid);
    cudaGetSymbolAddress((void**)&P.whi, g_whi);
    cudaGetSymbolAddress((void**)&P.wlo, g_wlo);
    cudaGetSymbolAddress((void**)&P.q16, g_q16);
    cudaGetSymbolAddress((void**)&P.k16, g_k16);
    cudaGetSymbolAddress((void**)&P.vt,  g_vt);
    cudaGetSymbolAddress((void**)&P.p16, g_p16);

    HB.x = xf; HB.qf = qf; HB.h = hf;
    cudaGetSymbolAddress((void**)&HB.xh, g_xh);
    cudaGetSymbolAddress((void**)&HB.xl, g_xl);
    cudaGetSymbolAddress((void**)&HB.oh, g_oh);
    cudaGetSymbolAddress((void**)&HB.ol, g_ol);
    cudaGetSymbolAddress((void**)&HB.hh, g_hh);
    cudaGetSymbolAddress((void**)&HB.hl, g_hl);
    cudaGetSymbolAddress((void**)&HB.fh, g_fh);
    cudaGetSymbolAddress((void**)&HB.fl, g_fl);
    HB.qh = (unsigned short*)qf;  HB.ql = HB.qh + (size_t)ROWS_MAX*DMODEL;
    HB.kh = (unsigned short*)kf;  HB.kl = HB.kh + (size_t)ROWS_MAX*DMODEL;
    HB.vh = (unsigned short*)vf;  HB.vl = HB.vh + (size_t)ROWS_MAX*DMODEL;

    float *cx,*cq,*ck,*cv,*ch;
    cudaGetSymbolAddress((void**)&cx, g_cx);
    cudaGetSymbolAddress((void**)&cq, g_cq);
    cudaGetSymbolAddress((void**)&ck, g_ck);
    cudaGetSymbolAddress((void**)&cv, g_cv);
    cudaGetSymbolAddress((void**)&ch, g_ch);
    CB.x = cx; CB.qf = cq; CB.h = ch;
    cudaGetSymbolAddress((void**)&CB.xh, g_cxh);
    cudaGetSymbolAddress((void**)&CB.xl, g_cxl);
    cudaGetSymbolAddress((void**)&CB.oh, g_coh);
    cudaGetSymbolAddress((void**)&CB.ol, g_col);
    cudaGetSymbolAddress((void**)&CB.hh, g_chh);
    cudaGetSymbolAddress((void**)&CB.hl, g_chl);
    cudaGetSymbolAddress((void**)&CB.fh, g_cfh);
    cudaGetSymbolAddress((void**)&CB.fl, g_cfl);
    CB.qh = (unsigned short*)cq;  CB.ql = CB.qh + (size_t)CROWS*DMODEL;
    CB.kh = (unsigned short*)ck;  CB.kl = CB.kh + (size_t)CROWS*DMODEL;
    CB.vh = (unsigned short*)cv;  CB.vl = CB.vh + (size_t)CROWS*DMODEL;

    cudaFuncSetAttribute(mma_gemm_f<2>,    cudaFuncAttributeMaxDynamicSharedMemorySize, SMEM_T(2));
    cudaFuncSetAttribute(mma_gemm_gelu<2>, cudaFuncAttributeMaxDynamicSharedMemorySize, SMEM_T(2));
    cudaFuncSetAttribute(mma_gemm_qkv5<2>, cudaFuncAttributeMaxDynamicSharedMemorySize, SMEM_T(2));
    cudaFuncSetAttribute(mma_gemm_qkv16,   cudaFuncAttributeMaxDynamicSharedMemorySize, SMEM_T(2));
    cudaFuncSetAttribute(mma_gemm_f<3>,    cudaFuncAttributeMaxDynamicSharedMemorySize, SMEM_T(3));
    cudaFuncSetAttribute(mma_gemm_gelu<3>, cudaFuncAttributeMaxDynamicSharedMemorySize, SMEM_T(3));
    cudaFuncSetAttribute(mma_gemm_qkv5<3>, cudaFuncAttributeMaxDynamicSharedMemorySize, SMEM_T(3));

    // stream/event objects (host-side; created per call, capture-safe)
    cudaStream_t s1;
    cudaStreamCreateWithFlags(&s1, cudaStreamNonBlocking);
    cudaEvent_t evPrep, evCdd;
    cudaEventCreateWithFlags(&evPrep, cudaEventDisableTiming);
    cudaEventCreateWithFlags(&evCdd,  cudaEventDisableTiming);

    // ---- batched weight prep (stream 0) ----
    PrepPtrs pp;
    for (int i = 0; i < 6; i++) { pp.p[i] = (const float*)d_in[9+i]; pp.p[6+i] = (const float*)d_in[15+i]; }
    prep_all<<<dim3(2304, 12), dim3(32,8)>>>(pp, P.whi, P.wlo);
    cudaEventRecord(evPrep, 0);

    // ---- cdd path forked onto s1 (private buffers, BERT weights, 2-term) ----
    cudaStreamWaitEvent(s1, evPrep, 0);
    prefix_kernel<<<NCDD,256,0,s1>>>(cdd_sub, cdd_mask, cdd_am, P.cpre, P.atC);
    pool_kernel<<<dim3(NCDD, DMODEL/128),128,0,s1>>>(P.cpre, cdd_enc, emb, CB.x, CB.xh, CB.xl);
    run_transformer_seq64<2>(NCDD, P.whi, P.wlo, P.atC, CB, s1);
    sgemm_proj<<<dim3(DMODEL/64, 1),256,0,s1>>>(CB.h, (size_t)SEQ*DMODEL, projW, P.cddr, NCDD, DMODEL, DMODEL, projb);
    cudaEventRecord(evCdd, s1);

    // ---- history path (encN weights), 3-term (kid-exact), stream 0 ----
    prefix_kernel<<<NHIS,256>>>(his_sub, his_mask, his_am, P.pre, P.atH);
    pool_kernel<<<dim3(NHIS, DMODEL/128),128>>>(P.pre, his_enc, emb, HB.x, HB.xh, HB.xl);
    run_transformer_seq64<3>(NHIS, P.whi+WSET, P.wlo+WSET, P.atH, HB, 0);
    gather_cls_kernel<<<NHIS,256>>>(HB.h, P.cls, SEQ);
    user0_kernel<<<BB,256>>>(P.cls, qU, P.u0);
    topk_kernel<<<BB*HISN,256>>>(HB.h, P.u0, P.atH, P.kid, HB.x, HB.xh, HB.xl, P.psm);

    // ---- user path (BERT weights), 2-term + fp16 MMA attention, stream 0 ----
    run_transformer_user(P.whi, P.wlo, P.psm);
    sgemm_proj<<<dim3(DMODEL/64, 1),256>>>(HB.h, (size_t)LUSR*DMODEL, projW, P.ur, BB, DMODEL, DMODEL, projb);

    // ---- join + outputs ----
    cudaStreamWaitEvent(0, evCdd, 0);
    final_kernel<<<BB + (BB*HISN*KSEL + 255)/256, 256>>>(P.cddr, P.ur, P.kid, out);
}